// round 1
// baseline (speedup 1.0000x reference)
#include <cuda_runtime.h>
#include <math.h>

#define Bb  2
#define Ss  4096
#define DIMm 2048
#define Hh  16
#define HKk 8
#define HDd 128
#define Mm  128

#define INV_SQRT_M 0.08838834764831845f   // 128^{-0.5}
#define SCALE_QD   0.2973017787506803f    // 128^{-0.25}
#define EPSF 1e-6f

// ---------------- scratch (device globals; no allocations allowed) ----------
__device__ float g_q   [Bb*Ss*Hh*HDd];     // [b,s,h,d]
__device__ float g_k   [Bb*Ss*HKk*HDd];
__device__ float g_v   [Bb*Ss*HKk*HDd];
__device__ float g_qx  [Bb*Hh*Ss*HDd];     // normed+roped+scaled, [b,h,s,d]
__device__ float g_kx  [Bb*HKk*Ss*HDd];
__device__ float g_sqq [Bb*Hh*Ss];
__device__ float g_sqk [Bb*HKk*Ss];
__device__ float g_qphi[Bb*Hh*Ss*Mm];      // [b,h,s,m]
__device__ float g_kxp [Bb*HKk*Ss*Mm];     // pre-exp key features
__device__ float g_kmaxp[Bb*HKk*32*Mm];
__device__ float g_kmax[Bb*HKk*Mm];
__device__ float g_kv  [Bb*HKk*Mm*HDd];
__device__ float g_ksum[Bb*HKk*Mm];
__device__ float g_ao  [Bb*Ss*Hh*HDd];     // attention out, [b,s,h*d]

// ---------------- generic fp32 GEMM:  C[M,N] = A[M,K] @ W[N,K]^T ------------
__global__ __launch_bounds__(256) void gemm_nt(
    const float* __restrict__ A, const float* __restrict__ W,
    float* __restrict__ C, int K, int N)
{
    __shared__ float As[16][128];
    __shared__ float Ws[16][128];
    int tid = threadIdx.x;
    int rowBase = blockIdx.y * 128;
    int colBase = blockIdx.x * 128;
    int tr = tid >> 4, tc = tid & 15;
    int lRow = tid >> 2;
    int lCol = (tid & 3) << 2;
    const float* Ag = A + (size_t)rowBase * K;
    const float* Wg = W + (size_t)colBase * K;
    float acc[8][8];
    #pragma unroll
    for (int i = 0; i < 8; i++)
        #pragma unroll
        for (int j = 0; j < 8; j++) acc[i][j] = 0.f;

    for (int k0 = 0; k0 < K; k0 += 16) {
        #pragma unroll
        for (int r = 0; r < 128; r += 64) {
            float4 a4 = *(const float4*)(Ag + (size_t)(lRow + r) * K + k0 + lCol);
            As[lCol+0][lRow+r]=a4.x; As[lCol+1][lRow+r]=a4.y;
            As[lCol+2][lRow+r]=a4.z; As[lCol+3][lRow+r]=a4.w;
            float4 w4 = *(const float4*)(Wg + (size_t)(lRow + r) * K + k0 + lCol);
            Ws[lCol+0][lRow+r]=w4.x; Ws[lCol+1][lRow+r]=w4.y;
            Ws[lCol+2][lRow+r]=w4.z; Ws[lCol+3][lRow+r]=w4.w;
        }
        __syncthreads();
        #pragma unroll
        for (int kk = 0; kk < 16; kk++) {
            float ra[8], rb[8];
            #pragma unroll
            for (int i = 0; i < 8; i++) ra[i] = As[kk][tr*8+i];
            #pragma unroll
            for (int j = 0; j < 8; j++) rb[j] = Ws[kk][tc*8+j];
            #pragma unroll
            for (int i = 0; i < 8; i++)
                #pragma unroll
                for (int j = 0; j < 8; j++) acc[i][j] += ra[i]*rb[j];
        }
        __syncthreads();
    }
    #pragma unroll
    for (int i = 0; i < 8; i++) {
        float* Cp = C + (size_t)(rowBase + tr*8 + i) * N + colBase + tc*8;
        #pragma unroll
        for (int j = 0; j < 8; j += 4) {
            float4 o4 = make_float4(acc[i][j], acc[i][j+1], acc[i][j+2], acc[i][j+3]);
            *(float4*)(Cp + j) = o4;
        }
    }
}

// ------------- RMSNorm + RoPE + d^{-1/4} scale, transpose to [b,h,s,d] ------
__global__ __launch_bounds__(128) void normrope_kernel(
    const float* __restrict__ qkv, const float* __restrict__ fc,
    const float* __restrict__ g, float* __restrict__ xout,
    float* __restrict__ sqout, int nh)
{
    int bs = blockIdx.x;          // b*S + s
    int h  = blockIdx.y;
    int d  = threadIdx.x;
    float val = qkv[(size_t)bs * nh * HDd + h * HDd + d];

    float ss = val * val;
    #pragma unroll
    for (int o = 16; o > 0; o >>= 1) ss += __shfl_xor_sync(0xffffffffu, ss, o);
    __shared__ float wsum[4];
    int wid = d >> 5, lane = d & 31;
    if (lane == 0) wsum[wid] = ss;
    __syncthreads();
    float tot = wsum[0] + wsum[1] + wsum[2] + wsum[3];
    float inv = rsqrtf(tot * (1.0f / HDd) + 1e-5f);
    float xn = val * inv * g[d];

    __shared__ float row[HDd];
    row[d] = xn;
    __syncthreads();
    int i = d >> 1;
    float c  = fc[((size_t)bs * (HDd/2) + i) * 2 + 0];
    float sn = fc[((size_t)bs * (HDd/2) + i) * 2 + 1];
    float a  = row[2*i], b2 = row[2*i + 1];
    float r  = (d & 1) ? (a * sn + b2 * c) : (a * c - b2 * sn);
    r *= SCALE_QD;

    float s2 = r * r;
    #pragma unroll
    for (int o = 16; o > 0; o >>= 1) s2 += __shfl_xor_sync(0xffffffffu, s2, o);
    __syncthreads();
    if (lane == 0) wsum[wid] = s2;
    __syncthreads();
    float tot2 = wsum[0] + wsum[1] + wsum[2] + wsum[3];

    int b = bs / Ss, s = bs % Ss;
    xout[(((size_t)b * nh + h) * Ss + s) * HDd + d] = r;
    if (d == 0) sqout[((size_t)b * nh + h) * Ss + s] = 0.5f * tot2;
}

// ---------- FAVOR feature projection: xp[s,m] = X[s,:]·proj[m,:] ------------
__global__ __launch_bounds__(256) void feat_kernel(
    const float* __restrict__ X, const float* __restrict__ proj,
    const float* __restrict__ sq, float* __restrict__ out, int isQuery)
{
    __shared__ float As[16][128];
    __shared__ float Ws[16][128];
    __shared__ float red[128][16];
    __shared__ float rowmax_s[128];
    int bh = blockIdx.y;
    int s0 = blockIdx.x * 128;
    int tid = threadIdx.x;
    int tr = tid >> 4, tc = tid & 15;
    int lRow = tid >> 2, lCol = (tid & 3) << 2;
    const float* A = X + ((size_t)bh * Ss + s0) * HDd;
    float acc[8][8];
    #pragma unroll
    for (int i=0;i<8;i++)
        #pragma unroll
        for (int j=0;j<8;j++) acc[i][j]=0.f;

    for (int k0 = 0; k0 < HDd; k0 += 16) {
        #pragma unroll
        for (int r = 0; r < 128; r += 64) {
            float4 a4 = *(const float4*)(A + (size_t)(lRow + r) * HDd + k0 + lCol);
            As[lCol+0][lRow+r]=a4.x; As[lCol+1][lRow+r]=a4.y;
            As[lCol+2][lRow+r]=a4.z; As[lCol+3][lRow+r]=a4.w;
            float4 w4 = *(const float4*)(proj + (size_t)(lRow + r) * HDd + k0 + lCol);
            Ws[lCol+0][lRow+r]=w4.x; Ws[lCol+1][lRow+r]=w4.y;
            Ws[lCol+2][lRow+r]=w4.z; Ws[lCol+3][lRow+r]=w4.w;
        }
        __syncthreads();
        #pragma unroll
        for (int kk = 0; kk < 16; kk++) {
            float ra[8], rb[8];
            #pragma unroll
            for (int i=0;i<8;i++) ra[i]=As[kk][tr*8+i];
            #pragma unroll
            for (int j=0;j<8;j++) rb[j]=Ws[kk][tc*8+j];
            #pragma unroll
            for (int i=0;i<8;i++)
                #pragma unroll
                for (int j=0;j<8;j++) acc[i][j] += ra[i]*rb[j];
        }
        __syncthreads();
    }

    if (isQuery) {
        // -0.5||x||^2 cancels against the per-row max subtraction
        #pragma unroll
        for (int i = 0; i < 8; i++) {
            float mx = acc[i][0];
            #pragma unroll
            for (int j = 1; j < 8; j++) mx = fmaxf(mx, acc[i][j]);
            red[tr*8+i][tc] = mx;
        }
        __syncthreads();
        if (tid < 128) {
            float mx = red[tid][0];
            #pragma unroll
            for (int j = 1; j < 16; j++) mx = fmaxf(mx, red[tid][j]);
            rowmax_s[tid] = mx;
        }
        __syncthreads();
        #pragma unroll
        for (int i = 0; i < 8; i++) {
            float rm = rowmax_s[tr*8+i];
            float* op = out + ((size_t)bh * Ss + s0 + tr*8 + i) * Mm + tc*8;
            #pragma unroll
            for (int j = 0; j < 8; j++)
                op[j] = expf(acc[i][j] - rm) * INV_SQRT_M + EPSF;
        }
    } else {
        #pragma unroll
        for (int i = 0; i < 8; i++) {
            float sv = sq[(size_t)bh * Ss + s0 + tr*8 + i];
            float* op = out + ((size_t)bh * Ss + s0 + tr*8 + i) * Mm + tc*8;
            #pragma unroll
            for (int j = 0; j < 8; j++) op[j] = acc[i][j] - sv;
        }
    }
}

// ---------------- key column-max over S (two-stage) -------------------------
__global__ void kmax1_kernel() {
    int bh = blockIdx.x, ch = blockIdx.y, m = threadIdx.x;
    const float* p = g_kxp + ((size_t)bh * Ss + ch * 128) * Mm + m;
    float mx = -1e30f;
    #pragma unroll 4
    for (int s = 0; s < 128; s++) mx = fmaxf(mx, p[(size_t)s * Mm]);
    g_kmaxp[((size_t)bh * 32 + ch) * Mm + m] = mx;
}
__global__ void kmax2_kernel() {
    int bh = blockIdx.x, m = threadIdx.x;
    float mx = -1e30f;
    for (int c = 0; c < 32; c++) mx = fmaxf(mx, g_kmaxp[((size_t)bh*32 + c)*Mm + m]);
    g_kmax[bh * Mm + m] = mx;
}

__global__ void zero_kernel() {
    int i = blockIdx.x * blockDim.x + threadIdx.x;
    if (i < Bb*HKk*Mm*HDd) g_kv[i] = 0.f;
    if (i < Bb*HKk*Mm)     g_ksum[i] = 0.f;
}

// ----- kv[m,d] += sum_s phi_k[s,m]*v[s,d] ; ksum[m] += sum_s phi_k[s,m] -----
__global__ __launch_bounds__(256) void kv_kernel(const int* __restrict__ mask)
{
    __shared__ float kps[16][128];
    __shared__ float vs [16][128];
    __shared__ float kmx[128];
    __shared__ float vmask[128];
    int bh = blockIdx.y;             // b*HK + hk
    int b = bh / HKk, hk = bh % HKk;
    int s0 = blockIdx.x * 128;
    int tid = threadIdx.x;
    int tr = tid >> 4, tc = tid & 15;
    if (tid < 128) {
        kmx[tid] = g_kmax[bh * Mm + tid];
        vmask[tid] = (mask[b * Ss + s0 + tid] > 0) ? 1.f : 0.f;
    }
    __syncthreads();

    const float* KX = g_kxp + ((size_t)bh * Ss + s0) * Mm;
    const float* V  = g_v + ((size_t)(b * Ss + s0)) * (HKk*HDd) + hk * HDd;
    float acc[8][8];
    #pragma unroll
    for (int i=0;i<8;i++)
        #pragma unroll
        for (int j=0;j<8;j++) acc[i][j]=0.f;
    float ksacc = 0.f;

    for (int sc = 0; sc < 128; sc += 16) {
        #pragma unroll
        for (int it = 0; it < 2; it++) {
            int idx = tid + it * 256;        // 0..511
            int r = idx >> 5;
            int c4 = (idx & 31) << 2;
            float vm = vmask[sc + r];
            float4 x4 = *(const float4*)(KX + (size_t)(sc + r) * Mm + c4);
            kps[r][c4+0] = (expf(x4.x - kmx[c4+0]) * INV_SQRT_M + EPSF) * vm;
            kps[r][c4+1] = (expf(x4.y - kmx[c4+1]) * INV_SQRT_M + EPSF) * vm;
            kps[r][c4+2] = (expf(x4.z - kmx[c4+2]) * INV_SQRT_M + EPSF) * vm;
            kps[r][c4+3] = (expf(x4.w - kmx[c4+3]) * INV_SQRT_M + EPSF) * vm;
            float4 v4 = *(const float4*)(V + (size_t)(sc + r) * (HKk*HDd) + c4);
            vs[r][c4+0]=v4.x; vs[r][c4+1]=v4.y; vs[r][c4+2]=v4.z; vs[r][c4+3]=v4.w;
        }
        __syncthreads();
        #pragma unroll
        for (int ssi = 0; ssi < 16; ssi++) {
            float ra[8], rb[8];
            #pragma unroll
            for (int i=0;i<8;i++) ra[i]=kps[ssi][tr*8+i];
            #pragma unroll
            for (int j=0;j<8;j++) rb[j]=vs[ssi][tc*8+j];
            #pragma unroll
            for (int i=0;i<8;i++)
                #pragma unroll
                for (int j=0;j<8;j++) acc[i][j] += ra[i]*rb[j];
        }
        if (tid < 128) {
            #pragma unroll
            for (int ssi = 0; ssi < 16; ssi++) ksacc += kps[ssi][tid];
        }
        __syncthreads();
    }
    float* KV = g_kv + (size_t)bh * Mm * HDd;
    #pragma unroll
    for (int i = 0; i < 8; i++)
        #pragma unroll
        for (int j = 0; j < 8; j++)
            atomicAdd(&KV[(size_t)(tr*8+i)*HDd + tc*8+j], acc[i][j]);
    if (tid < 128) atomicAdd(&g_ksum[bh * Mm + tid], ksacc);
}

// ---- out[s,d] = (phi_q[s,:]·kv[:,d]) / (phi_q[s,:]·ksum + eps) * valid -----
__global__ __launch_bounds__(256) void out_kernel(const int* __restrict__ mask)
{
    __shared__ float As[16][128];
    __shared__ float Bs[16][128];
    __shared__ float kss[16];
    __shared__ float vmask[128];
    int bh = blockIdx.y;             // b*H + h
    int b = bh / Hh, h = bh % Hh;
    int hk = h / (Hh / HKk);
    int bhk = b * HKk + hk;
    int s0 = blockIdx.x * 128;
    int tid = threadIdx.x;
    int tr = tid >> 4, tc = tid & 15;
    int lRow = tid >> 2, lCol = (tid & 3) << 2;
    if (tid < 128) vmask[tid] = (mask[b * Ss + s0 + tid] > 0) ? 1.f : 0.f;

    const float* QP = g_qphi + ((size_t)bh * Ss + s0) * Mm;
    const float* KV = g_kv + (size_t)bhk * Mm * HDd;
    float acc[8][8];
    #pragma unroll
    for (int i=0;i<8;i++)
        #pragma unroll
        for (int j=0;j<8;j++) acc[i][j]=0.f;
    float dn[8];
    #pragma unroll
    for (int i=0;i<8;i++) dn[i]=0.f;

    for (int k0 = 0; k0 < Mm; k0 += 16) {
        #pragma unroll
        for (int r = 0; r < 128; r += 64) {
            float4 a4 = *(const float4*)(QP + (size_t)(lRow + r) * Mm + k0 + lCol);
            As[lCol+0][lRow+r]=a4.x; As[lCol+1][lRow+r]=a4.y;
            As[lCol+2][lRow+r]=a4.z; As[lCol+3][lRow+r]=a4.w;
        }
        #pragma unroll
        for (int it = 0; it < 2; it++) {
            int idx = tid + it * 256;
            int r = idx >> 5;
            int c4 = (idx & 31) << 2;
            float4 k4 = *(const float4*)(KV + (size_t)(k0 + r) * HDd + c4);
            Bs[r][c4+0]=k4.x; Bs[r][c4+1]=k4.y; Bs[r][c4+2]=k4.z; Bs[r][c4+3]=k4.w;
        }
        if (tid < 16) kss[tid] = g_ksum[bhk * Mm + k0 + tid];
        __syncthreads();
        #pragma unroll
        for (int kk = 0; kk < 16; kk++) {
            float ra[8], rb[8];
            float ks = kss[kk];
            #pragma unroll
            for (int i=0;i<8;i++) ra[i]=As[kk][tr*8+i];
            #pragma unroll
            for (int j=0;j<8;j++) rb[j]=Bs[kk][tc*8+j];
            #pragma unroll
            for (int i=0;i<8;i++) {
                dn[i] += ra[i]*ks;
                #pragma unroll
                for (int j=0;j<8;j++) acc[i][j] += ra[i]*rb[j];
            }
        }
        __syncthreads();
    }
    #pragma unroll
    for (int i = 0; i < 8; i++) {
        float scale = vmask[tr*8+i] / (dn[i] + EPSF);
        float* op = g_ao + (size_t)(b * Ss + s0 + tr*8 + i) * (Hh*HDd) + h * HDd + tc*8;
        #pragma unroll
        for (int j = 0; j < 8; j += 4) {
            float4 o4 = make_float4(acc[i][j]*scale, acc[i][j+1]*scale,
                                    acc[i][j+2]*scale, acc[i][j+3]*scale);
            *(float4*)(op + j) = o4;
        }
    }
}

// ------------------------------- launch -------------------------------------
extern "C" void kernel_launch(void* const* d_in, const int* in_sizes, int n_in,
                              void* d_out, int out_size)
{
    const float* x    = (const float*)d_in[0];
    const int*   mask = (const int*)  d_in[1];
    const float* fc   = (const float*)d_in[2];
    const float* wq   = (const float*)d_in[3];
    const float* wk   = (const float*)d_in[4];
    const float* wv   = (const float*)d_in[5];
    const float* wo   = (const float*)d_in[6];
    const float* gq   = (const float*)d_in[7];
    const float* gk   = (const float*)d_in[8];
    const float* proj = (const float*)d_in[9];
    float* out = (float*)d_out;

    float *pq, *pk, *pv, *pqx, *pkx, *psqq, *psqk, *pqphi, *pkxp, *pao;
    cudaGetSymbolAddress((void**)&pq,   g_q);
    cudaGetSymbolAddress((void**)&pk,   g_k);
    cudaGetSymbolAddress((void**)&pv,   g_v);
    cudaGetSymbolAddress((void**)&pqx,  g_qx);
    cudaGetSymbolAddress((void**)&pkx,  g_kx);
    cudaGetSymbolAddress((void**)&psqq, g_sqq);
    cudaGetSymbolAddress((void**)&psqk, g_sqk);
    cudaGetSymbolAddress((void**)&pqphi,g_qphi);
    cudaGetSymbolAddress((void**)&pkxp, g_kxp);
    cudaGetSymbolAddress((void**)&pao,  g_ao);

    // QKV projections
    gemm_nt<<<dim3(DIMm/128, (Bb*Ss)/128), 256>>>(x, wq, pq, DIMm, Hh*HDd);
    gemm_nt<<<dim3((HKk*HDd)/128, (Bb*Ss)/128), 256>>>(x, wk, pk, DIMm, HKk*HDd);
    gemm_nt<<<dim3((HKk*HDd)/128, (Bb*Ss)/128), 256>>>(x, wv, pv, DIMm, HKk*HDd);

    // RMSNorm + RoPE + scale (+ 0.5||x||^2)
    normrope_kernel<<<dim3(Bb*Ss, Hh),  128>>>(pq, fc, gq, pqx, psqq, Hh);
    normrope_kernel<<<dim3(Bb*Ss, HKk), 128>>>(pk, fc, gk, pkx, psqk, HKk);

    // FAVOR feature projections
    feat_kernel<<<dim3(Ss/128, Bb*Hh),  256>>>(pqx, proj, psqq, pqphi, 1);
    feat_kernel<<<dim3(Ss/128, Bb*HKk), 256>>>(pkx, proj, psqk, pkxp, 0);

    // key column max over S
    kmax1_kernel<<<dim3(Bb*HKk, 32), 128>>>();
    kmax2_kernel<<<Bb*HKk, 128>>>();

    // kv / ksum contraction (split over S, atomics)
    zero_kernel<<<(Bb*HKk*Mm*HDd + 255)/256, 256>>>();
    kv_kernel<<<dim3(Ss/128, Bb*HKk), 256>>>(mask);

    // attention output + denominator
    out_kernel<<<dim3(Ss/128, Bb*Hh), 256>>>(mask);

    // output projection
    gemm_nt<<<dim3(DIMm/128, (Bb*Ss)/128), 256>>>(pao, wo, out, Hh*HDd, DIMm);
}

// round 3
// speedup vs baseline: 1.1861x; 1.1861x over previous
#include <cuda_runtime.h>
#include <math.h>

#define Bb  2
#define Ss  4096
#define DIMm 2048
#define Hh  16
#define HKk 8
#define HDd 128
#define Mm  128

#define INV_SQRT_M 0.08838834764831845f   // 128^{-0.5}
#define SCALE_QD   0.2973017787506803f    // 128^{-0.25}
#define EPSF 1e-6f

// ---------------- scratch (device globals; no allocations allowed) ----------
__device__ float g_q   [Bb*Ss*Hh*HDd];     // [b,s,h,d]
__device__ float g_k   [Bb*Ss*HKk*HDd];
__device__ float g_v   [Bb*Ss*HKk*HDd];
__device__ float g_qx  [Bb*Hh*Ss*HDd];     // normed+roped+scaled, [b,h,s,d]
__device__ float g_kx  [Bb*HKk*Ss*HDd];
__device__ float g_sqq [Bb*Hh*Ss];
__device__ float g_sqk [Bb*HKk*Ss];
__device__ float g_qphi[Bb*Hh*Ss*Mm];      // [b,h,s,m]
__device__ float g_kxp [Bb*HKk*Ss*Mm];     // pre-exp key features
__device__ float g_kmaxp[Bb*HKk*32*Mm];
__device__ float g_kmax[Bb*HKk*Mm];
__device__ float g_kv  [Bb*HKk*Mm*HDd];
__device__ float g_ksum[Bb*HKk*Mm];
__device__ float g_ao  [Bb*Ss*Hh*HDd];     // attention out, [b,s,h*d]

// ---------------------------- tf32 helpers ----------------------------------
__device__ __forceinline__ unsigned f2tf(float x) {
    unsigned u; asm("cvt.rna.tf32.f32 %0, %1;" : "=r"(u) : "f"(x)); return u;
}
// split x into hi (tf32) + lo (tf32 of residual)
__device__ __forceinline__ void tfsplit(float x, unsigned& hi, unsigned& lo) {
    hi = f2tf(x);
    lo = f2tf(x - __uint_as_float(hi));
}

__device__ __forceinline__ void mma_tf32(float* d, const unsigned* a, const unsigned* b) {
    asm volatile(
        "mma.sync.aligned.m16n8k8.row.col.f32.tf32.tf32.f32 "
        "{%0,%1,%2,%3}, {%4,%5,%6,%7}, {%8,%9}, {%0,%1,%2,%3};\n"
        : "+f"(d[0]), "+f"(d[1]), "+f"(d[2]), "+f"(d[3])
        : "r"(a[0]), "r"(a[1]), "r"(a[2]), "r"(a[3]),
          "r"(b[0]), "r"(b[1]));
}

// ------- 3xTF32 tensor-core GEMM:  C[M,N] = A[M,K] @ W[N,K]^T  (fp32-acc) ---
// 128x128x16 tile, 256 threads, 8 warps (2x4), warp tile 64x32.
// A*B ~= Ah*Bh + Al*Bh + Ah*Bl  (error ~2^-22, fp32-class)
#define LDT 136
__global__ __launch_bounds__(256) void gemm_3xtf32(
    const float* __restrict__ A, const float* __restrict__ W,
    float* __restrict__ C, int K, int N)
{
    __shared__ unsigned Ah[16][LDT];
    __shared__ unsigned Al[16][LDT];
    __shared__ unsigned Bh[16][LDT];
    __shared__ unsigned Bl[16][LDT];
    int tid  = threadIdx.x;
    int lane = tid & 31;
    int warp = tid >> 5;
    int rowBase = blockIdx.y * 128;
    int colBase = blockIdx.x * 128;
    int warpM = (warp >> 2) * 64;
    int warpN = (warp & 3) * 32;
    const float* Ag = A + (size_t)rowBase * K;
    const float* Wg = W + (size_t)colBase * K;
    int ldRow = tid >> 1;           // 0..127
    int ldCol = (tid & 1) * 8;      // 0 or 8

    float acc[4][4][4];
    #pragma unroll
    for (int mi = 0; mi < 4; mi++)
        #pragma unroll
        for (int ni = 0; ni < 4; ni++)
            #pragma unroll
            for (int e = 0; e < 4; e++) acc[mi][ni][e] = 0.f;

    int kTiles = K >> 4;

    float ar[8], br[8];
    // preload tile 0 into regs
    {
        float4 a0 = *(const float4*)(Ag + (size_t)ldRow * K + ldCol);
        float4 a1 = *(const float4*)(Ag + (size_t)ldRow * K + ldCol + 4);
        float4 b0 = *(const float4*)(Wg + (size_t)ldRow * K + ldCol);
        float4 b1 = *(const float4*)(Wg + (size_t)ldRow * K + ldCol + 4);
        ar[0]=a0.x; ar[1]=a0.y; ar[2]=a0.z; ar[3]=a0.w;
        ar[4]=a1.x; ar[5]=a1.y; ar[6]=a1.z; ar[7]=a1.w;
        br[0]=b0.x; br[1]=b0.y; br[2]=b0.z; br[3]=b0.w;
        br[4]=b1.x; br[5]=b1.y; br[6]=b1.z; br[7]=b1.w;
    }

    for (int t = 0; t < kTiles; t++) {
        __syncthreads();   // smem free (previous compute done)
        #pragma unroll
        for (int e = 0; e < 8; e++) {
            unsigned hi, lo;
            tfsplit(ar[e], hi, lo);
            Ah[ldCol+e][ldRow] = hi;
            Al[ldCol+e][ldRow] = lo;
            tfsplit(br[e], hi, lo);
            Bh[ldCol+e][ldRow] = hi;
            Bl[ldCol+e][ldRow] = lo;
        }
        __syncthreads();

        if (t + 1 < kTiles) {
            int k0 = (t + 1) << 4;
            float4 a0 = *(const float4*)(Ag + (size_t)ldRow * K + k0 + ldCol);
            float4 a1 = *(const float4*)(Ag + (size_t)ldRow * K + k0 + ldCol + 4);
            float4 b0 = *(const float4*)(Wg + (size_t)ldRow * K + k0 + ldCol);
            float4 b1 = *(const float4*)(Wg + (size_t)ldRow * K + k0 + ldCol + 4);
            ar[0]=a0.x; ar[1]=a0.y; ar[2]=a0.z; ar[3]=a0.w;
            ar[4]=a1.x; ar[5]=a1.y; ar[6]=a1.z; ar[7]=a1.w;
            br[0]=b0.x; br[1]=b0.y; br[2]=b0.z; br[3]=b0.w;
            br[4]=b1.x; br[5]=b1.y; br[6]=b1.z; br[7]=b1.w;
        }

        #pragma unroll
        for (int ks = 0; ks < 2; ks++) {
            int kc = ks * 8 + (lane & 3);
            int mo = lane >> 2;
            unsigned afh[4][4], afl[4][4], bfh[4][2], bfl[4][2];
            #pragma unroll
            for (int mi = 0; mi < 4; mi++) {
                int m = warpM + mi * 16 + mo;
                afh[mi][0] = Ah[kc    ][m];
                afh[mi][1] = Ah[kc    ][m + 8];
                afh[mi][2] = Ah[kc + 4][m];
                afh[mi][3] = Ah[kc + 4][m + 8];
                afl[mi][0] = Al[kc    ][m];
                afl[mi][1] = Al[kc    ][m + 8];
                afl[mi][2] = Al[kc + 4][m];
                afl[mi][3] = Al[kc + 4][m + 8];
            }
            #pragma unroll
            for (int ni = 0; ni < 4; ni++) {
                int n = warpN + ni * 8 + mo;
                bfh[ni][0] = Bh[kc    ][n];
                bfh[ni][1] = Bh[kc + 4][n];
                bfl[ni][0] = Bl[kc    ][n];
                bfl[ni][1] = Bl[kc + 4][n];
            }
            #pragma unroll
            for (int mi = 0; mi < 4; mi++)
                #pragma unroll
                for (int ni = 0; ni < 4; ni++) {
                    mma_tf32(acc[mi][ni], afh[mi], bfh[ni]);
                    mma_tf32(acc[mi][ni], afl[mi], bfh[ni]);
                    mma_tf32(acc[mi][ni], afh[mi], bfl[ni]);
                }
        }
    }

    #pragma unroll
    for (int mi = 0; mi < 4; mi++) {
        int r = rowBase + warpM + mi * 16 + (lane >> 2);
        #pragma unroll
        for (int ni = 0; ni < 4; ni++) {
            int c = colBase + warpN + ni * 8 + (lane & 3) * 2;
            *(float2*)(C + (size_t)r * N + c) =
                make_float2(acc[mi][ni][0], acc[mi][ni][1]);
            *(float2*)(C + (size_t)(r + 8) * N + c) =
                make_float2(acc[mi][ni][2], acc[mi][ni][3]);
        }
    }
}

// ------------- RMSNorm + RoPE + d^{-1/4} scale, transpose to [b,h,s,d] ------
__global__ __launch_bounds__(128) void normrope_kernel(
    const float* __restrict__ qkv, const float* __restrict__ fc,
    const float* __restrict__ g, float* __restrict__ xout,
    float* __restrict__ sqout, int nh)
{
    int bs = blockIdx.x;          // b*S + s
    int h  = blockIdx.y;
    int d  = threadIdx.x;
    float val = qkv[(size_t)bs * nh * HDd + h * HDd + d];

    float ss = val * val;
    #pragma unroll
    for (int o = 16; o > 0; o >>= 1) ss += __shfl_xor_sync(0xffffffffu, ss, o);
    __shared__ float wsum[4];
    int wid = d >> 5, lane = d & 31;
    if (lane == 0) wsum[wid] = ss;
    __syncthreads();
    float tot = wsum[0] + wsum[1] + wsum[2] + wsum[3];
    float inv = rsqrtf(tot * (1.0f / HDd) + 1e-5f);
    float xn = val * inv * g[d];

    __shared__ float row[HDd];
    row[d] = xn;
    __syncthreads();
    int i = d >> 1;
    float c  = fc[((size_t)bs * (HDd/2) + i) * 2 + 0];
    float sn = fc[((size_t)bs * (HDd/2) + i) * 2 + 1];
    float a  = row[2*i], b2 = row[2*i + 1];
    float r  = (d & 1) ? (a * sn + b2 * c) : (a * c - b2 * sn);
    r *= SCALE_QD;

    float s2 = r * r;
    #pragma unroll
    for (int o = 16; o > 0; o >>= 1) s2 += __shfl_xor_sync(0xffffffffu, s2, o);
    __syncthreads();
    if (lane == 0) wsum[wid] = s2;
    __syncthreads();
    float tot2 = wsum[0] + wsum[1] + wsum[2] + wsum[3];

    int b = bs / Ss, s = bs % Ss;
    xout[(((size_t)b * nh + h) * Ss + s) * HDd + d] = r;
    if (d == 0) sqout[((size_t)b * nh + h) * Ss + s] = 0.5f * tot2;
}

// ---------- FAVOR feature projection: xp[s,m] = X[s,:]·proj[m,:] ------------
__global__ __launch_bounds__(256) void feat_kernel(
    const float* __restrict__ X, const float* __restrict__ proj,
    const float* __restrict__ sq, float* __restrict__ out, int isQuery)
{
    __shared__ float As[16][128];
    __shared__ float Ws[16][128];
    __shared__ float red[128][16];
    __shared__ float rowmax_s[128];
    int bh = blockIdx.y;
    int s0 = blockIdx.x * 128;
    int tid = threadIdx.x;
    int tr = tid >> 4, tc = tid & 15;
    int lRow = tid >> 2, lCol = (tid & 3) << 2;
    const float* A = X + ((size_t)bh * Ss + s0) * HDd;
    float acc[8][8];
    #pragma unroll
    for (int i=0;i<8;i++)
        #pragma unroll
        for (int j=0;j<8;j++) acc[i][j]=0.f;

    for (int k0 = 0; k0 < HDd; k0 += 16) {
        #pragma unroll
        for (int r = 0; r < 128; r += 64) {
            float4 a4 = *(const float4*)(A + (size_t)(lRow + r) * HDd + k0 + lCol);
            As[lCol+0][lRow+r]=a4.x; As[lCol+1][lRow+r]=a4.y;
            As[lCol+2][lRow+r]=a4.z; As[lCol+3][lRow+r]=a4.w;
            float4 w4 = *(const float4*)(proj + (size_t)(lRow + r) * HDd + k0 + lCol);
            Ws[lCol+0][lRow+r]=w4.x; Ws[lCol+1][lRow+r]=w4.y;
            Ws[lCol+2][lRow+r]=w4.z; Ws[lCol+3][lRow+r]=w4.w;
        }
        __syncthreads();
        #pragma unroll
        for (int kk = 0; kk < 16; kk++) {
            float ra[8], rb[8];
            #pragma unroll
            for (int i=0;i<8;i++) ra[i]=As[kk][tr*8+i];
            #pragma unroll
            for (int j=0;j<8;j++) rb[j]=Ws[kk][tc*8+j];
            #pragma unroll
            for (int i=0;i<8;i++)
                #pragma unroll
                for (int j=0;j<8;j++) acc[i][j] += ra[i]*rb[j];
        }
        __syncthreads();
    }

    if (isQuery) {
        // -0.5||x||^2 cancels against the per-row max subtraction
        #pragma unroll
        for (int i = 0; i < 8; i++) {
            float mx = acc[i][0];
            #pragma unroll
            for (int j = 1; j < 8; j++) mx = fmaxf(mx, acc[i][j]);
            red[tr*8+i][tc] = mx;
        }
        __syncthreads();
        if (tid < 128) {
            float mx = red[tid][0];
            #pragma unroll
            for (int j = 1; j < 16; j++) mx = fmaxf(mx, red[tid][j]);
            rowmax_s[tid] = mx;
        }
        __syncthreads();
        #pragma unroll
        for (int i = 0; i < 8; i++) {
            float rm = rowmax_s[tr*8+i];
            float* op = out + ((size_t)bh * Ss + s0 + tr*8 + i) * Mm + tc*8;
            #pragma unroll
            for (int j = 0; j < 8; j++)
                op[j] = expf(acc[i][j] - rm) * INV_SQRT_M + EPSF;
        }
    } else {
        #pragma unroll
        for (int i = 0; i < 8; i++) {
            float sv = sq[(size_t)bh * Ss + s0 + tr*8 + i];
            float* op = out + ((size_t)bh * Ss + s0 + tr*8 + i) * Mm + tc*8;
            #pragma unroll
            for (int j = 0; j < 8; j++) op[j] = acc[i][j] - sv;
        }
    }
}

// ---------------- key column-max over S (two-stage) -------------------------
__global__ void kmax1_kernel() {
    int bh = blockIdx.x, ch = blockIdx.y, m = threadIdx.x;
    const float* p = g_kxp + ((size_t)bh * Ss + ch * 128) * Mm + m;
    float mx = -1e30f;
    #pragma unroll 4
    for (int s = 0; s < 128; s++) mx = fmaxf(mx, p[(size_t)s * Mm]);
    g_kmaxp[((size_t)bh * 32 + ch) * Mm + m] = mx;
}
__global__ void kmax2_kernel() {
    int bh = blockIdx.x, m = threadIdx.x;
    float mx = -1e30f;
    for (int c = 0; c < 32; c++) mx = fmaxf(mx, g_kmaxp[((size_t)bh*32 + c)*Mm + m]);
    g_kmax[bh * Mm + m] = mx;
}

__global__ void zero_kernel() {
    int i = blockIdx.x * blockDim.x + threadIdx.x;
    if (i < Bb*HKk*Mm*HDd) g_kv[i] = 0.f;
    if (i < Bb*HKk*Mm)     g_ksum[i] = 0.f;
}

// ----- kv[m,d] += sum_s phi_k[s,m]*v[s,d] ; ksum[m] += sum_s phi_k[s,m] -----
__global__ __launch_bounds__(256) void kv_kernel(const int* __restrict__ mask)
{
    __shared__ float kps[16][128];
    __shared__ float vs [16][128];
    __shared__ float kmx[128];
    __shared__ float vmask[128];
    int bh = blockIdx.y;             // b*HK + hk
    int b = bh / HKk, hk = bh % HKk;
    int s0 = blockIdx.x * 128;
    int tid = threadIdx.x;
    int tr = tid >> 4, tc = tid & 15;
    if (tid < 128) {
        kmx[tid] = g_kmax[bh * Mm + tid];
        vmask[tid] = (mask[b * Ss + s0 + tid] > 0) ? 1.f : 0.f;
    }
    __syncthreads();

    const float* KX = g_kxp + ((size_t)bh * Ss + s0) * Mm;
    const float* V  = g_v + ((size_t)(b * Ss + s0)) * (HKk*HDd) + hk * HDd;
    float acc[8][8];
    #pragma unroll
    for (int i=0;i<8;i++)
        #pragma unroll
        for (int j=0;j<8;j++) acc[i][j]=0.f;
    float ksacc = 0.f;

    for (int sc = 0; sc < 128; sc += 16) {
        #pragma unroll
        for (int it = 0; it < 2; it++) {
            int idx = tid + it * 256;        // 0..511
            int r = idx >> 5;
            int c4 = (idx & 31) << 2;
            float vm = vmask[sc + r];
            float4 x4 = *(const float4*)(KX + (size_t)(sc + r) * Mm + c4);
            kps[r][c4+0] = (expf(x4.x - kmx[c4+0]) * INV_SQRT_M + EPSF) * vm;
            kps[r][c4+1] = (expf(x4.y - kmx[c4+1]) * INV_SQRT_M + EPSF) * vm;
            kps[r][c4+2] = (expf(x4.z - kmx[c4+2]) * INV_SQRT_M + EPSF) * vm;
            kps[r][c4+3] = (expf(x4.w - kmx[c4+3]) * INV_SQRT_M + EPSF) * vm;
            float4 v4 = *(const float4*)(V + (size_t)(sc + r) * (HKk*HDd) + c4);
            vs[r][c4+0]=v4.x; vs[r][c4+1]=v4.y; vs[r][c4+2]=v4.z; vs[r][c4+3]=v4.w;
        }
        __syncthreads();
        #pragma unroll
        for (int ssi = 0; ssi < 16; ssi++) {
            float ra[8], rb[8];
            #pragma unroll
            for (int i=0;i<8;i++) ra[i]=kps[ssi][tr*8+i];
            #pragma unroll
            for (int j=0;j<8;j++) rb[j]=vs[ssi][tc*8+j];
            #pragma unroll
            for (int i=0;i<8;i++)
                #pragma unroll
                for (int j=0;j<8;j++) acc[i][j] += ra[i]*rb[j];
        }
        if (tid < 128) {
            #pragma unroll
            for (int ssi = 0; ssi < 16; ssi++) ksacc += kps[ssi][tid];
        }
        __syncthreads();
    }
    float* KV = g_kv + (size_t)bh * Mm * HDd;
    #pragma unroll
    for (int i = 0; i < 8; i++)
        #pragma unroll
        for (int j = 0; j < 8; j++)
            atomicAdd(&KV[(size_t)(tr*8+i)*HDd + tc*8+j], acc[i][j]);
    if (tid < 128) atomicAdd(&g_ksum[bh * Mm + tid], ksacc);
}

// ---- out[s,d] = (phi_q[s,:]·kv[:,d]) / (phi_q[s,:]·ksum + eps) * valid -----
__global__ __launch_bounds__(256) void out_kernel(const int* __restrict__ mask)
{
    __shared__ float As[16][128];
    __shared__ float Bs[16][128];
    __shared__ float kss[16];
    __shared__ float vmask[128];
    int bh = blockIdx.y;             // b*H + h
    int b = bh / Hh, h = bh % Hh;
    int hk = h / (Hh / HKk);
    int bhk = b * HKk + hk;
    int s0 = blockIdx.x * 128;
    int tid = threadIdx.x;
    int tr = tid >> 4, tc = tid & 15;
    int lRow = tid >> 2, lCol = (tid & 3) << 2;
    if (tid < 128) vmask[tid] = (mask[b * Ss + s0 + tid] > 0) ? 1.f : 0.f;

    const float* QP = g_qphi + ((size_t)bh * Ss + s0) * Mm;
    const float* KV = g_kv + (size_t)bhk * Mm * HDd;
    float acc[8][8];
    #pragma unroll
    for (int i=0;i<8;i++)
        #pragma unroll
        for (int j=0;j<8;j++) acc[i][j]=0.f;
    float dn[8];
    #pragma unroll
    for (int i=0;i<8;i++) dn[i]=0.f;

    for (int k0 = 0; k0 < Mm; k0 += 16) {
        #pragma unroll
        for (int r = 0; r < 128; r += 64) {
            float4 a4 = *(const float4*)(QP + (size_t)(lRow + r) * Mm + k0 + lCol);
            As[lCol+0][lRow+r]=a4.x; As[lCol+1][lRow+r]=a4.y;
            As[lCol+2][lRow+r]=a4.z; As[lCol+3][lRow+r]=a4.w;
        }
        #pragma unroll
        for (int it = 0; it < 2; it++) {
            int idx = tid + it * 256;
            int r = idx >> 5;
            int c4 = (idx & 31) << 2;
            float4 k4 = *(const float4*)(KV + (size_t)(k0 + r) * HDd + c4);
            Bs[r][c4+0]=k4.x; Bs[r][c4+1]=k4.y; Bs[r][c4+2]=k4.z; Bs[r][c4+3]=k4.w;
        }
        if (tid < 16) kss[tid] = g_ksum[bhk * Mm + k0 + tid];
        __syncthreads();
        #pragma unroll
        for (int kk = 0; kk < 16; kk++) {
            float ra[8], rb[8];
            float ks = kss[kk];
            #pragma unroll
            for (int i=0;i<8;i++) ra[i]=As[kk][tr*8+i];
            #pragma unroll
            for (int j=0;j<8;j++) rb[j]=Bs[kk][tc*8+j];
            #pragma unroll
            for (int i=0;i<8;i++) {
                dn[i] += ra[i]*ks;
                #pragma unroll
                for (int j=0;j<8;j++) acc[i][j] += ra[i]*rb[j];
            }
        }
        __syncthreads();
    }
    #pragma unroll
    for (int i = 0; i < 8; i++) {
        float scale = vmask[tr*8+i] / (dn[i] + EPSF);
        float* op = g_ao + (size_t)(b * Ss + s0 + tr*8 + i) * (Hh*HDd) + h * HDd + tc*8;
        #pragma unroll
        for (int j = 0; j < 8; j += 4) {
            float4 o4 = make_float4(acc[i][j]*scale, acc[i][j+1]*scale,
                                    acc[i][j+2]*scale, acc[i][j+3]*scale);
            *(float4*)(op + j) = o4;
        }
    }
}

// ------------------------------- launch -------------------------------------
extern "C" void kernel_launch(void* const* d_in, const int* in_sizes, int n_in,
                              void* d_out, int out_size)
{
    const float* x    = (const float*)d_in[0];
    const int*   mask = (const int*)  d_in[1];
    const float* fc   = (const float*)d_in[2];
    const float* wq   = (const float*)d_in[3];
    const float* wk   = (const float*)d_in[4];
    const float* wv   = (const float*)d_in[5];
    const float* wo   = (const float*)d_in[6];
    const float* gq   = (const float*)d_in[7];
    const float* gk   = (const float*)d_in[8];
    const float* proj = (const float*)d_in[9];
    float* out = (float*)d_out;

    float *pq, *pk, *pv, *pqx, *pkx, *psqq, *psqk, *pqphi, *pkxp, *pao;
    cudaGetSymbolAddress((void**)&pq,   g_q);
    cudaGetSymbolAddress((void**)&pk,   g_k);
    cudaGetSymbolAddress((void**)&pv,   g_v);
    cudaGetSymbolAddress((void**)&pqx,  g_qx);
    cudaGetSymbolAddress((void**)&pkx,  g_kx);
    cudaGetSymbolAddress((void**)&psqq, g_sqq);
    cudaGetSymbolAddress((void**)&psqk, g_sqk);
    cudaGetSymbolAddress((void**)&pqphi,g_qphi);
    cudaGetSymbolAddress((void**)&pkxp, g_kxp);
    cudaGetSymbolAddress((void**)&pao,  g_ao);

    // QKV projections (3xTF32 tensor cores, fp32-class accuracy)
    gemm_3xtf32<<<dim3((Hh*HDd)/128,  (Bb*Ss)/128), 256>>>(x, wq, pq, DIMm, Hh*HDd);
    gemm_3xtf32<<<dim3((HKk*HDd)/128, (Bb*Ss)/128), 256>>>(x, wk, pk, DIMm, HKk*HDd);
    gemm_3xtf32<<<dim3((HKk*HDd)/128, (Bb*Ss)/128), 256>>>(x, wv, pv, DIMm, HKk*HDd);

    // RMSNorm + RoPE + scale (+ 0.5||x||^2)
    normrope_kernel<<<dim3(Bb*Ss, Hh),  128>>>(pq, fc, gq, pqx, psqq, Hh);
    normrope_kernel<<<dim3(Bb*Ss, HKk), 128>>>(pk, fc, gk, pkx, psqk, HKk);

    // FAVOR feature projections
    feat_kernel<<<dim3(Ss/128, Bb*Hh),  256>>>(pqx, proj, psqq, pqphi, 1);
    feat_kernel<<<dim3(Ss/128, Bb*HKk), 256>>>(pkx, proj, psqk, pkxp, 0);

    // key column max over S
    kmax1_kernel<<<dim3(Bb*HKk, 32), 128>>>();
    kmax2_kernel<<<Bb*HKk, 128>>>();

    // kv / ksum contraction (split over S, atomics)
    zero_kernel<<<(Bb*HKk*Mm*HDd + 255)/256, 256>>>();
    kv_kernel<<<dim3(Ss/128, Bb*HKk), 256>>>(mask);

    // attention output + denominator
    out_kernel<<<dim3(Ss/128, Bb*Hh), 256>>>(mask);

    // output projection (3xTF32 tensor cores)
    gemm_3xtf32<<<dim3(DIMm/128, (Bb*Ss)/128), 256>>>(pao, wo, out, Hh*HDd, DIMm);
}

// round 4
// speedup vs baseline: 1.7509x; 1.4761x over previous
#include <cuda_runtime.h>
#include <cuda_bf16.h>
#include <math.h>

#define Bb  2
#define Ss  4096
#define DIMm 2048
#define Hh  16
#define HKk 8
#define HDd 128
#define Mm  128

#define INV_SQRT_M 0.08838834764831845f   // 128^{-0.5}
#define SCALE_QD   0.2973017787506803f    // 128^{-0.25}
#define EPSF 1e-6f

// ---------------- scratch (device globals; no allocations allowed) ----------
__device__ float g_q   [Bb*Ss*Hh*HDd];     // [b,s,h,d]
__device__ float g_k   [Bb*Ss*HKk*HDd];
__device__ float g_v   [Bb*Ss*HKk*HDd];
__device__ float g_qx  [Bb*Hh*Ss*HDd];     // normed+roped+scaled, [b,h,s,d]
__device__ float g_kx  [Bb*HKk*Ss*HDd];
__device__ float g_sqq [Bb*Hh*Ss];
__device__ float g_sqk [Bb*HKk*Ss];
__device__ float g_qphi[Bb*Hh*Ss*Mm];      // [b,h,s,m]
__device__ float g_kxp [Bb*HKk*Ss*Mm];     // pre-exp key features
__device__ float g_kmaxp[Bb*HKk*32*Mm];
__device__ float g_kmax[Bb*HKk*Mm];
__device__ float g_kv  [Bb*HKk*Mm*HDd];
__device__ float g_ksum[Bb*HKk*Mm];
__device__ float g_ao  [Bb*Ss*Hh*HDd];     // attention out, [b,s,h*d]

// ---------------------------- bf16 split helpers ----------------------------
// pack (x0,x1) -> bf16x2 hi word and bf16x2 lo (residual) word
__device__ __forceinline__ void bfsplit2(float x0, float x1, unsigned& hi, unsigned& lo) {
    __nv_bfloat162 h2 = __floats2bfloat162_rn(x0, x1);
    float2 hf = __bfloat1622float2(h2);
    __nv_bfloat162 l2 = __floats2bfloat162_rn(x0 - hf.x, x1 - hf.y);
    hi = *reinterpret_cast<unsigned*>(&h2);
    lo = *reinterpret_cast<unsigned*>(&l2);
}

__device__ __forceinline__ void mma_bf16(float* d, const unsigned* a, const unsigned* b) {
    asm volatile(
        "mma.sync.aligned.m16n8k16.row.col.f32.bf16.bf16.f32 "
        "{%0,%1,%2,%3}, {%4,%5,%6,%7}, {%8,%9}, {%0,%1,%2,%3};\n"
        : "+f"(d[0]), "+f"(d[1]), "+f"(d[2]), "+f"(d[3])
        : "r"(a[0]), "r"(a[1]), "r"(a[2]), "r"(a[3]),
          "r"(b[0]), "r"(b[1]));
}

// ------- 3xBF16 tensor-core GEMM: C[M,N] = A[M,K] @ W[N,K]^T (fp32-acc) -----
// 128x128x16 tile, 256 threads, 8 warps (2x4), warp tile 64x32, m16n8k16.
// A*B ~= Ah*Bh + Al*Bh + Ah*Bl   (residual ~2^-18 relative)
// smem rows are k-PAIRS (8 per 16-deep tile), entries are packed bf16x2.
#define LDT 136
__global__ __launch_bounds__(256) void gemm_3xbf16(
    const float* __restrict__ A, const float* __restrict__ W,
    float* __restrict__ C, int K, int N)
{
    __shared__ unsigned Ah[2][8][LDT];
    __shared__ unsigned Al[2][8][LDT];
    __shared__ unsigned Bh[2][8][LDT];
    __shared__ unsigned Bl[2][8][LDT];
    int tid  = threadIdx.x;
    int lane = tid & 31;
    int warp = tid >> 5;
    int rowBase = blockIdx.y * 128;
    int colBase = blockIdx.x * 128;
    int warpM = (warp >> 2) * 64;
    int warpN = (warp & 3) * 32;
    const float* Ag = A + (size_t)rowBase * K;
    const float* Wg = W + (size_t)colBase * K;
    int ldRow  = tid >> 1;          // 0..127
    int ldCol  = (tid & 1) * 8;     // k offset 0 or 8
    int kpBase = (tid & 1) * 4;     // k-pair offset 0 or 4

    float acc[4][4][4];
    #pragma unroll
    for (int mi = 0; mi < 4; mi++)
        #pragma unroll
        for (int ni = 0; ni < 4; ni++)
            #pragma unroll
            for (int e = 0; e < 4; e++) acc[mi][ni][e] = 0.f;

    int kTiles = K >> 4;
    float ar[8], br[8];

    // load tile 0
    {
        float4 a0 = *(const float4*)(Ag + (size_t)ldRow * K + ldCol);
        float4 a1 = *(const float4*)(Ag + (size_t)ldRow * K + ldCol + 4);
        float4 b0 = *(const float4*)(Wg + (size_t)ldRow * K + ldCol);
        float4 b1 = *(const float4*)(Wg + (size_t)ldRow * K + ldCol + 4);
        ar[0]=a0.x; ar[1]=a0.y; ar[2]=a0.z; ar[3]=a0.w;
        ar[4]=a1.x; ar[5]=a1.y; ar[6]=a1.z; ar[7]=a1.w;
        br[0]=b0.x; br[1]=b0.y; br[2]=b0.z; br[3]=b0.w;
        br[4]=b1.x; br[5]=b1.y; br[6]=b1.z; br[7]=b1.w;
    }
    // store tile 0 -> buf 0
    #pragma unroll
    for (int e = 0; e < 4; e++) {
        unsigned hi, lo;
        bfsplit2(ar[2*e], ar[2*e+1], hi, lo);
        Ah[0][kpBase+e][ldRow] = hi;  Al[0][kpBase+e][ldRow] = lo;
        bfsplit2(br[2*e], br[2*e+1], hi, lo);
        Bh[0][kpBase+e][ldRow] = hi;  Bl[0][kpBase+e][ldRow] = lo;
    }
    __syncthreads();

    for (int t = 0; t < kTiles; t++) {
        int buf = t & 1;
        bool has = (t + 1 < kTiles);
        if (has) {
            int k0 = (t + 1) << 4;
            float4 a0 = *(const float4*)(Ag + (size_t)ldRow * K + k0 + ldCol);
            float4 a1 = *(const float4*)(Ag + (size_t)ldRow * K + k0 + ldCol + 4);
            float4 b0 = *(const float4*)(Wg + (size_t)ldRow * K + k0 + ldCol);
            float4 b1 = *(const float4*)(Wg + (size_t)ldRow * K + k0 + ldCol + 4);
            ar[0]=a0.x; ar[1]=a0.y; ar[2]=a0.z; ar[3]=a0.w;
            ar[4]=a1.x; ar[5]=a1.y; ar[6]=a1.z; ar[7]=a1.w;
            br[0]=b0.x; br[1]=b0.y; br[2]=b0.z; br[3]=b0.w;
            br[4]=b1.x; br[5]=b1.y; br[6]=b1.z; br[7]=b1.w;
        }

        // compute on buf: one m16n8k16 step covers the whole 16-deep tile
        {
            int kc = lane & 3;          // k-pair index
            int mo = lane >> 2;
            unsigned afh[4][4], afl[4][4], bfh[4][2], bfl[4][2];
            #pragma unroll
            for (int mi = 0; mi < 4; mi++) {
                int m = warpM + mi * 16 + mo;
                afh[mi][0] = Ah[buf][kc    ][m];
                afh[mi][1] = Ah[buf][kc    ][m + 8];
                afh[mi][2] = Ah[buf][kc + 4][m];
                afh[mi][3] = Ah[buf][kc + 4][m + 8];
                afl[mi][0] = Al[buf][kc    ][m];
                afl[mi][1] = Al[buf][kc    ][m + 8];
                afl[mi][2] = Al[buf][kc + 4][m];
                afl[mi][3] = Al[buf][kc + 4][m + 8];
            }
            #pragma unroll
            for (int ni = 0; ni < 4; ni++) {
                int n = warpN + ni * 8 + mo;
                bfh[ni][0] = Bh[buf][kc    ][n];
                bfh[ni][1] = Bh[buf][kc + 4][n];
                bfl[ni][0] = Bl[buf][kc    ][n];
                bfl[ni][1] = Bl[buf][kc + 4][n];
            }
            #pragma unroll
            for (int mi = 0; mi < 4; mi++)
                #pragma unroll
                for (int ni = 0; ni < 4; ni++) {
                    mma_bf16(acc[mi][ni], afh[mi], bfh[ni]);
                    mma_bf16(acc[mi][ni], afl[mi], bfh[ni]);
                    mma_bf16(acc[mi][ni], afh[mi], bfl[ni]);
                }
        }

        if (has) {
            int nb = buf ^ 1;
            #pragma unroll
            for (int e = 0; e < 4; e++) {
                unsigned hi, lo;
                bfsplit2(ar[2*e], ar[2*e+1], hi, lo);
                Ah[nb][kpBase+e][ldRow] = hi;  Al[nb][kpBase+e][ldRow] = lo;
                bfsplit2(br[2*e], br[2*e+1], hi, lo);
                Bh[nb][kpBase+e][ldRow] = hi;  Bl[nb][kpBase+e][ldRow] = lo;
            }
        }
        __syncthreads();
    }

    #pragma unroll
    for (int mi = 0; mi < 4; mi++) {
        int r = rowBase + warpM + mi * 16 + (lane >> 2);
        #pragma unroll
        for (int ni = 0; ni < 4; ni++) {
            int c = colBase + warpN + ni * 8 + (lane & 3) * 2;
            *(float2*)(C + (size_t)r * N + c) =
                make_float2(acc[mi][ni][0], acc[mi][ni][1]);
            *(float2*)(C + (size_t)(r + 8) * N + c) =
                make_float2(acc[mi][ni][2], acc[mi][ni][3]);
        }
    }
}

// ------------- RMSNorm + RoPE + d^{-1/4} scale, transpose to [b,h,s,d] ------
__global__ __launch_bounds__(128) void normrope_kernel(
    const float* __restrict__ qkv, const float* __restrict__ fc,
    const float* __restrict__ g, float* __restrict__ xout,
    float* __restrict__ sqout, int nh)
{
    int bs = blockIdx.x;          // b*S + s
    int h  = blockIdx.y;
    int d  = threadIdx.x;
    float val = qkv[(size_t)bs * nh * HDd + h * HDd + d];

    float ss = val * val;
    #pragma unroll
    for (int o = 16; o > 0; o >>= 1) ss += __shfl_xor_sync(0xffffffffu, ss, o);
    __shared__ float wsum[4];
    int wid = d >> 5, lane = d & 31;
    if (lane == 0) wsum[wid] = ss;
    __syncthreads();
    float tot = wsum[0] + wsum[1] + wsum[2] + wsum[3];
    float inv = rsqrtf(tot * (1.0f / HDd) + 1e-5f);
    float xn = val * inv * g[d];

    __shared__ float row[HDd];
    row[d] = xn;
    __syncthreads();
    int i = d >> 1;
    float c  = fc[((size_t)bs * (HDd/2) + i) * 2 + 0];
    float sn = fc[((size_t)bs * (HDd/2) + i) * 2 + 1];
    float a  = row[2*i], b2 = row[2*i + 1];
    float r  = (d & 1) ? (a * sn + b2 * c) : (a * c - b2 * sn);
    r *= SCALE_QD;

    float s2 = r * r;
    #pragma unroll
    for (int o = 16; o > 0; o >>= 1) s2 += __shfl_xor_sync(0xffffffffu, s2, o);
    __syncthreads();
    if (lane == 0) wsum[wid] = s2;
    __syncthreads();
    float tot2 = wsum[0] + wsum[1] + wsum[2] + wsum[3];

    int b = bs / Ss, s = bs % Ss;
    xout[(((size_t)b * nh + h) * Ss + s) * HDd + d] = r;
    if (d == 0) sqout[((size_t)b * nh + h) * Ss + s] = 0.5f * tot2;
}

// ---------- FAVOR feature projection: xp[s,m] = X[s,:]·proj[m,:] ------------
__global__ __launch_bounds__(256) void feat_kernel(
    const float* __restrict__ X, const float* __restrict__ proj,
    const float* __restrict__ sq, float* __restrict__ out, int isQuery)
{
    __shared__ float As[16][128];
    __shared__ float Ws[16][128];
    __shared__ float red[128][16];
    __shared__ float rowmax_s[128];
    int bh = blockIdx.y;
    int s0 = blockIdx.x * 128;
    int tid = threadIdx.x;
    int tr = tid >> 4, tc = tid & 15;
    int lRow = tid >> 2, lCol = (tid & 3) << 2;
    const float* A = X + ((size_t)bh * Ss + s0) * HDd;
    float acc[8][8];
    #pragma unroll
    for (int i=0;i<8;i++)
        #pragma unroll
        for (int j=0;j<8;j++) acc[i][j]=0.f;

    for (int k0 = 0; k0 < HDd; k0 += 16) {
        #pragma unroll
        for (int r = 0; r < 128; r += 64) {
            float4 a4 = *(const float4*)(A + (size_t)(lRow + r) * HDd + k0 + lCol);
            As[lCol+0][lRow+r]=a4.x; As[lCol+1][lRow+r]=a4.y;
            As[lCol+2][lRow+r]=a4.z; As[lCol+3][lRow+r]=a4.w;
            float4 w4 = *(const float4*)(proj + (size_t)(lRow + r) * HDd + k0 + lCol);
            Ws[lCol+0][lRow+r]=w4.x; Ws[lCol+1][lRow+r]=w4.y;
            Ws[lCol+2][lRow+r]=w4.z; Ws[lCol+3][lRow+r]=w4.w;
        }
        __syncthreads();
        #pragma unroll
        for (int kk = 0; kk < 16; kk++) {
            float ra[8], rb[8];
            #pragma unroll
            for (int i=0;i<8;i++) ra[i]=As[kk][tr*8+i];
            #pragma unroll
            for (int j=0;j<8;j++) rb[j]=Ws[kk][tc*8+j];
            #pragma unroll
            for (int i=0;i<8;i++)
                #pragma unroll
                for (int j=0;j<8;j++) acc[i][j] += ra[i]*rb[j];
        }
        __syncthreads();
    }

    if (isQuery) {
        // -0.5||x||^2 cancels against the per-row max subtraction
        #pragma unroll
        for (int i = 0; i < 8; i++) {
            float mx = acc[i][0];
            #pragma unroll
            for (int j = 1; j < 8; j++) mx = fmaxf(mx, acc[i][j]);
            red[tr*8+i][tc] = mx;
        }
        __syncthreads();
        if (tid < 128) {
            float mx = red[tid][0];
            #pragma unroll
            for (int j = 1; j < 16; j++) mx = fmaxf(mx, red[tid][j]);
            rowmax_s[tid] = mx;
        }
        __syncthreads();
        #pragma unroll
        for (int i = 0; i < 8; i++) {
            float rm = rowmax_s[tr*8+i];
            float* op = out + ((size_t)bh * Ss + s0 + tr*8 + i) * Mm + tc*8;
            #pragma unroll
            for (int j = 0; j < 8; j++)
                op[j] = expf(acc[i][j] - rm) * INV_SQRT_M + EPSF;
        }
    } else {
        #pragma unroll
        for (int i = 0; i < 8; i++) {
            float sv = sq[(size_t)bh * Ss + s0 + tr*8 + i];
            float* op = out + ((size_t)bh * Ss + s0 + tr*8 + i) * Mm + tc*8;
            #pragma unroll
            for (int j = 0; j < 8; j++) op[j] = acc[i][j] - sv;
        }
    }
}

// ---------------- key column-max over S (two-stage) -------------------------
__global__ void kmax1_kernel() {
    int bh = blockIdx.x, ch = blockIdx.y, m = threadIdx.x;
    const float* p = g_kxp + ((size_t)bh * Ss + ch * 128) * Mm + m;
    float mx = -1e30f;
    #pragma unroll 4
    for (int s = 0; s < 128; s++) mx = fmaxf(mx, p[(size_t)s * Mm]);
    g_kmaxp[((size_t)bh * 32 + ch) * Mm + m] = mx;
}
__global__ void kmax2_kernel() {
    int bh = blockIdx.x, m = threadIdx.x;
    float mx = -1e30f;
    for (int c = 0; c < 32; c++) mx = fmaxf(mx, g_kmaxp[((size_t)bh*32 + c)*Mm + m]);
    g_kmax[bh * Mm + m] = mx;
}

__global__ void zero_kernel() {
    int i = blockIdx.x * blockDim.x + threadIdx.x;
    if (i < Bb*HKk*Mm*HDd) g_kv[i] = 0.f;
    if (i < Bb*HKk*Mm)     g_ksum[i] = 0.f;
}

// ----- kv[m,d] += sum_s phi_k[s,m]*v[s,d] ; ksum[m] += sum_s phi_k[s,m] -----
__global__ __launch_bounds__(256) void kv_kernel(const int* __restrict__ mask)
{
    __shared__ float kps[16][128];
    __shared__ float vs [16][128];
    __shared__ float kmx[128];
    __shared__ float vmask[128];
    int bh = blockIdx.y;             // b*HK + hk
    int b = bh / HKk, hk = bh % HKk;
    int s0 = blockIdx.x * 128;
    int tid = threadIdx.x;
    int tr = tid >> 4, tc = tid & 15;
    if (tid < 128) {
        kmx[tid] = g_kmax[bh * Mm + tid];
        vmask[tid] = (mask[b * Ss + s0 + tid] > 0) ? 1.f : 0.f;
    }
    __syncthreads();

    const float* KX = g_kxp + ((size_t)bh * Ss + s0) * Mm;
    const float* V  = g_v + ((size_t)(b * Ss + s0)) * (HKk*HDd) + hk * HDd;
    float acc[8][8];
    #pragma unroll
    for (int i=0;i<8;i++)
        #pragma unroll
        for (int j=0;j<8;j++) acc[i][j]=0.f;
    float ksacc = 0.f;

    for (int sc = 0; sc < 128; sc += 16) {
        #pragma unroll
        for (int it = 0; it < 2; it++) {
            int idx = tid + it * 256;        // 0..511
            int r = idx >> 5;
            int c4 = (idx & 31) << 2;
            float vm = vmask[sc + r];
            float4 x4 = *(const float4*)(KX + (size_t)(sc + r) * Mm + c4);
            kps[r][c4+0] = (expf(x4.x - kmx[c4+0]) * INV_SQRT_M + EPSF) * vm;
            kps[r][c4+1] = (expf(x4.y - kmx[c4+1]) * INV_SQRT_M + EPSF) * vm;
            kps[r][c4+2] = (expf(x4.z - kmx[c4+2]) * INV_SQRT_M + EPSF) * vm;
            kps[r][c4+3] = (expf(x4.w - kmx[c4+3]) * INV_SQRT_M + EPSF) * vm;
            float4 v4 = *(const float4*)(V + (size_t)(sc + r) * (HKk*HDd) + c4);
            vs[r][c4+0]=v4.x; vs[r][c4+1]=v4.y; vs[r][c4+2]=v4.z; vs[r][c4+3]=v4.w;
        }
        __syncthreads();
        #pragma unroll
        for (int ssi = 0; ssi < 16; ssi++) {
            float ra[8], rb[8];
            #pragma unroll
            for (int i=0;i<8;i++) ra[i]=kps[ssi][tr*8+i];
            #pragma unroll
            for (int j=0;j<8;j++) rb[j]=vs[ssi][tc*8+j];
            #pragma unroll
            for (int i=0;i<8;i++)
                #pragma unroll
                for (int j=0;j<8;j++) acc[i][j] += ra[i]*rb[j];
        }
        if (tid < 128) {
            #pragma unroll
            for (int ssi = 0; ssi < 16; ssi++) ksacc += kps[ssi][tid];
        }
        __syncthreads();
    }
    float* KV = g_kv + (size_t)bh * Mm * HDd;
    #pragma unroll
    for (int i = 0; i < 8; i++)
        #pragma unroll
        for (int j = 0; j < 8; j++)
            atomicAdd(&KV[(size_t)(tr*8+i)*HDd + tc*8+j], acc[i][j]);
    if (tid < 128) atomicAdd(&g_ksum[bh * Mm + tid], ksacc);
}

// ---- out[s,d] = (phi_q[s,:]·kv[:,d]) / (phi_q[s,:]·ksum + eps) * valid -----
__global__ __launch_bounds__(256) void out_kernel(const int* __restrict__ mask)
{
    __shared__ float As[16][128];
    __shared__ float Bs[16][128];
    __shared__ float kss[16];
    __shared__ float vmask[128];
    int bh = blockIdx.y;             // b*H + h
    int b = bh / Hh, h = bh % Hh;
    int hk = h / (Hh / HKk);
    int bhk = b * HKk + hk;
    int s0 = blockIdx.x * 128;
    int tid = threadIdx.x;
    int tr = tid >> 4, tc = tid & 15;
    int lRow = tid >> 2, lCol = (tid & 3) << 2;
    if (tid < 128) vmask[tid] = (mask[b * Ss + s0 + tid] > 0) ? 1.f : 0.f;

    const float* QP = g_qphi + ((size_t)bh * Ss + s0) * Mm;
    const float* KV = g_kv + (size_t)bhk * Mm * HDd;
    float acc[8][8];
    #pragma unroll
    for (int i=0;i<8;i++)
        #pragma unroll
        for (int j=0;j<8;j++) acc[i][j]=0.f;
    float dn[8];
    #pragma unroll
    for (int i=0;i<8;i++) dn[i]=0.f;

    for (int k0 = 0; k0 < Mm; k0 += 16) {
        #pragma unroll
        for (int r = 0; r < 128; r += 64) {
            float4 a4 = *(const float4*)(QP + (size_t)(lRow + r) * Mm + k0 + lCol);
            As[lCol+0][lRow+r]=a4.x; As[lCol+1][lRow+r]=a4.y;
            As[lCol+2][lRow+r]=a4.z; As[lCol+3][lRow+r]=a4.w;
        }
        #pragma unroll
        for (int it = 0; it < 2; it++) {
            int idx = tid + it * 256;
            int r = idx >> 5;
            int c4 = (idx & 31) << 2;
            float4 k4 = *(const float4*)(KV + (size_t)(k0 + r) * HDd + c4);
            Bs[r][c4+0]=k4.x; Bs[r][c4+1]=k4.y; Bs[r][c4+2]=k4.z; Bs[r][c4+3]=k4.w;
        }
        if (tid < 16) kss[tid] = g_ksum[bhk * Mm + k0 + tid];
        __syncthreads();
        #pragma unroll
        for (int kk = 0; kk < 16; kk++) {
            float ra[8], rb[8];
            float ks = kss[kk];
            #pragma unroll
            for (int i=0;i<8;i++) ra[i]=As[kk][tr*8+i];
            #pragma unroll
            for (int j=0;j<8;j++) rb[j]=Bs[kk][tc*8+j];
            #pragma unroll
            for (int i=0;i<8;i++) {
                dn[i] += ra[i]*ks;
                #pragma unroll
                for (int j=0;j<8;j++) acc[i][j] += ra[i]*rb[j];
            }
        }
        __syncthreads();
    }
    #pragma unroll
    for (int i = 0; i < 8; i++) {
        float scale = vmask[tr*8+i] / (dn[i] + EPSF);
        float* op = g_ao + (size_t)(b * Ss + s0 + tr*8 + i) * (Hh*HDd) + h * HDd + tc*8;
        #pragma unroll
        for (int j = 0; j < 8; j += 4) {
            float4 o4 = make_float4(acc[i][j]*scale, acc[i][j+1]*scale,
                                    acc[i][j+2]*scale, acc[i][j+3]*scale);
            *(float4*)(op + j) = o4;
        }
    }
}

// ------------------------------- launch -------------------------------------
extern "C" void kernel_launch(void* const* d_in, const int* in_sizes, int n_in,
                              void* d_out, int out_size)
{
    const float* x    = (const float*)d_in[0];
    const int*   mask = (const int*)  d_in[1];
    const float* fc   = (const float*)d_in[2];
    const float* wq   = (const float*)d_in[3];
    const float* wk   = (const float*)d_in[4];
    const float* wv   = (const float*)d_in[5];
    const float* wo   = (const float*)d_in[6];
    const float* gq   = (const float*)d_in[7];
    const float* gk   = (const float*)d_in[8];
    const float* proj = (const float*)d_in[9];
    float* out = (float*)d_out;

    float *pq, *pk, *pv, *pqx, *pkx, *psqq, *psqk, *pqphi, *pkxp, *pao;
    cudaGetSymbolAddress((void**)&pq,   g_q);
    cudaGetSymbolAddress((void**)&pk,   g_k);
    cudaGetSymbolAddress((void**)&pv,   g_v);
    cudaGetSymbolAddress((void**)&pqx,  g_qx);
    cudaGetSymbolAddress((void**)&pkx,  g_kx);
    cudaGetSymbolAddress((void**)&psqq, g_sqq);
    cudaGetSymbolAddress((void**)&psqk, g_sqk);
    cudaGetSymbolAddress((void**)&pqphi,g_qphi);
    cudaGetSymbolAddress((void**)&pkxp, g_kxp);
    cudaGetSymbolAddress((void**)&pao,  g_ao);

    // QKV projections (3xBF16 tensor cores, fp32-class accuracy)
    gemm_3xbf16<<<dim3((Hh*HDd)/128,  (Bb*Ss)/128), 256>>>(x, wq, pq, DIMm, Hh*HDd);
    gemm_3xbf16<<<dim3((HKk*HDd)/128, (Bb*Ss)/128), 256>>>(x, wk, pk, DIMm, HKk*HDd);
    gemm_3xbf16<<<dim3((HKk*HDd)/128, (Bb*Ss)/128), 256>>>(x, wv, pv, DIMm, HKk*HDd);

    // RMSNorm + RoPE + scale (+ 0.5||x||^2)
    normrope_kernel<<<dim3(Bb*Ss, Hh),  128>>>(pq, fc, gq, pqx, psqq, Hh);
    normrope_kernel<<<dim3(Bb*Ss, HKk), 128>>>(pk, fc, gk, pkx, psqk, HKk);

    // FAVOR feature projections
    feat_kernel<<<dim3(Ss/128, Bb*Hh),  256>>>(pqx, proj, psqq, pqphi, 1);
    feat_kernel<<<dim3(Ss/128, Bb*HKk), 256>>>(pkx, proj, psqk, pkxp, 0);

    // key column max over S
    kmax1_kernel<<<dim3(Bb*HKk, 32), 128>>>();
    kmax2_kernel<<<Bb*HKk, 128>>>();

    // kv / ksum contraction (split over S, atomics)
    zero_kernel<<<(Bb*HKk*Mm*HDd + 255)/256, 256>>>();
    kv_kernel<<<dim3(Ss/128, Bb*HKk), 256>>>(mask);

    // attention output + denominator
    out_kernel<<<dim3(Ss/128, Bb*Hh), 256>>>(mask);

    // output projection (3xBF16 tensor cores)
    gemm_3xbf16<<<dim3(DIMm/128, (Bb*Ss)/128), 256>>>(pao, wo, out, Hh*HDd, DIMm);
}

// round 6
// speedup vs baseline: 1.9288x; 1.1016x over previous
#include <cuda_runtime.h>
#include <cuda_bf16.h>
#include <math.h>
#include <stdint.h>

#define Bb  2
#define Ss  4096
#define DIMm 2048
#define Hh  16
#define HKk 8
#define HDd 128
#define Mm  128

#define INV_SQRT_M 0.08838834764831845f   // 128^{-0.5}
#define SCALE_QD   0.2973017787506803f    // 128^{-0.25}
#define EPSF 1e-6f

// ---------------- scratch (device globals; no allocations allowed) ----------
__device__ float g_q   [Bb*Ss*Hh*HDd];     // [b,s,h,d]
__device__ float g_k   [Bb*Ss*HKk*HDd];
__device__ float g_v   [Bb*Ss*HKk*HDd];
__device__ float g_qx  [Bb*Hh*Ss*HDd];     // normed+roped+scaled, [b,h,s,d]
__device__ float g_kx  [Bb*HKk*Ss*HDd];
__device__ float g_sqq [Bb*Hh*Ss];
__device__ float g_sqk [Bb*HKk*Ss];
__device__ float g_qphi[Bb*Hh*Ss*Mm];      // [b,h,s,m]
__device__ float g_kxp [Bb*HKk*Ss*Mm];     // pre-exp key features
__device__ float g_kmaxp[Bb*HKk*32*Mm];
__device__ float g_kmax[Bb*HKk*Mm];
__device__ float g_kvT [Bb*HKk*HDd*Mm];    // TRANSPOSED kv: [d][m]
__device__ float g_ksum[Bb*HKk*Mm];
__device__ float g_dn  [Bb*Hh*Ss];         // denominators
__device__ float g_ao  [Bb*Ss*Hh*HDd];     // attention out, [b,s,h*d]

// ---------------------------- bf16 split helpers ----------------------------
__device__ __forceinline__ void bfsplit2(float x0, float x1, unsigned& hi, unsigned& lo) {
    __nv_bfloat162 h2 = __floats2bfloat162_rn(x0, x1);
    float2 hf = __bfloat1622float2(h2);
    __nv_bfloat162 l2 = __floats2bfloat162_rn(x0 - hf.x, x1 - hf.y);
    hi = *reinterpret_cast<unsigned*>(&h2);
    lo = *reinterpret_cast<unsigned*>(&l2);
}

__device__ __forceinline__ void mma_bf16(float* d, const unsigned* a, const unsigned* b) {
    asm volatile(
        "mma.sync.aligned.m16n8k16.row.col.f32.bf16.bf16.f32 "
        "{%0,%1,%2,%3}, {%4,%5,%6,%7}, {%8,%9}, {%0,%1,%2,%3};\n"
        : "+f"(d[0]), "+f"(d[1]), "+f"(d[2]), "+f"(d[3])
        : "r"(a[0]), "r"(a[1]), "r"(a[2]), "r"(a[3]),
          "r"(b[0]), "r"(b[1]));
}

// smem layout (dynamic, unsigned units): per array 2 bufs x 16 kpairs x LDT
#define LDT 136
#define SOFF_AH(b) ((unsigned)(b)*2176u)
#define SOFF_AL(b) (4352u  + (unsigned)(b)*2176u)
#define SOFF_BH(b) (8704u  + (unsigned)(b)*2176u)
#define SOFF_BL(b) (13056u + (unsigned)(b)*2176u)
#define DSMEM_BYTES (17408*4)   // 69632

// ---- shared macro bodies for the 3xbf16 mma core (k-depth 32) --------------
#define CORE_LOAD_REGS(k0)                                                     \
    {                                                                          \
        const float* ap = Ag + (size_t)ldRow * K + (k0) + ldCol;               \
        const float* bp = Wg + (size_t)ldRow * K + (k0) + ldCol;               \
        float4 t;                                                              \
        t = *(const float4*)(ap);      ar[0]=t.x; ar[1]=t.y; ar[2]=t.z; ar[3]=t.w;   \
        t = *(const float4*)(ap + 4);  ar[4]=t.x; ar[5]=t.y; ar[6]=t.z; ar[7]=t.w;   \
        t = *(const float4*)(ap + 8);  ar[8]=t.x; ar[9]=t.y; ar[10]=t.z; ar[11]=t.w; \
        t = *(const float4*)(ap + 12); ar[12]=t.x; ar[13]=t.y; ar[14]=t.z; ar[15]=t.w;\
        t = *(const float4*)(bp);      br[0]=t.x; br[1]=t.y; br[2]=t.z; br[3]=t.w;   \
        t = *(const float4*)(bp + 4);  br[4]=t.x; br[5]=t.y; br[6]=t.z; br[7]=t.w;   \
        t = *(const float4*)(bp + 8);  br[8]=t.x; br[9]=t.y; br[10]=t.z; br[11]=t.w; \
        t = *(const float4*)(bp + 12); br[12]=t.x; br[13]=t.y; br[14]=t.z; br[15]=t.w;\
    }

#define CORE_STORE_SMEM(bufn)                                                  \
    {                                                                          \
        _Pragma("unroll")                                                      \
        for (int e = 0; e < 8; e++) {                                          \
            unsigned hi, lo;                                                   \
            bfsplit2(ar[2*e], ar[2*e+1], hi, lo);                              \
            sm[SOFF_AH(bufn) + (kpBase+e)*LDT + ldRow] = hi;                   \
            sm[SOFF_AL(bufn) + (kpBase+e)*LDT + ldRow] = lo;                   \
            bfsplit2(br[2*e], br[2*e+1], hi, lo);                              \
            sm[SOFF_BH(bufn) + (kpBase+e)*LDT + ldRow] = hi;                   \
            sm[SOFF_BL(bufn) + (kpBase+e)*LDT + ldRow] = lo;                   \
        }                                                                      \
    }

#define CORE_COMPUTE(bufn)                                                     \
    {                                                                          \
        _Pragma("unroll")                                                      \
        for (int h = 0; h < 2; h++) {                                          \
            int kc = h*8 + (lane & 3);                                         \
            int mo = lane >> 2;                                                \
            unsigned afh[4][4], afl[4][4], bfh[4][2], bfl[4][2];               \
            _Pragma("unroll")                                                  \
            for (int mi = 0; mi < 4; mi++) {                                   \
                int m = warpM + mi * 16 + mo;                                  \
                afh[mi][0] = sm[SOFF_AH(bufn) + kc*LDT + m];                   \
                afh[mi][1] = sm[SOFF_AH(bufn) + kc*LDT + m + 8];               \
                afh[mi][2] = sm[SOFF_AH(bufn) + (kc+4)*LDT + m];               \
                afh[mi][3] = sm[SOFF_AH(bufn) + (kc+4)*LDT + m + 8];           \
                afl[mi][0] = sm[SOFF_AL(bufn) + kc*LDT + m];                   \
                afl[mi][1] = sm[SOFF_AL(bufn) + kc*LDT + m + 8];               \
                afl[mi][2] = sm[SOFF_AL(bufn) + (kc+4)*LDT + m];               \
                afl[mi][3] = sm[SOFF_AL(bufn) + (kc+4)*LDT + m + 8];           \
            }                                                                  \
            _Pragma("unroll")                                                  \
            for (int ni = 0; ni < 4; ni++) {                                   \
                int n = warpN + ni * 8 + mo;                                   \
                bfh[ni][0] = sm[SOFF_BH(bufn) + kc*LDT + n];                   \
                bfh[ni][1] = sm[SOFF_BH(bufn) + (kc+4)*LDT + n];               \
                bfl[ni][0] = sm[SOFF_BL(bufn) + kc*LDT + n];                   \
                bfl[ni][1] = sm[SOFF_BL(bufn) + (kc+4)*LDT + n];               \
            }                                                                  \
            _Pragma("unroll")                                                  \
            for (int mi = 0; mi < 4; mi++)                                     \
                _Pragma("unroll")                                              \
                for (int ni = 0; ni < 4; ni++) {                               \
                    mma_bf16(acc[mi][ni], afh[mi], bfh[ni]);                   \
                    mma_bf16(acc[mi][ni], afl[mi], bfh[ni]);                   \
                    mma_bf16(acc[mi][ni], afh[mi], bfl[ni]);                   \
                }                                                              \
        }                                                                      \
    }

#define CORE_PROLOG_VARS                                                       \
    int tid  = threadIdx.x;                                                    \
    int lane = tid & 31;                                                       \
    int warp = tid >> 5;                                                       \
    int warpM = (warp >> 2) * 64;                                              \
    int warpN = (warp & 3) * 32;                                               \
    int ldRow  = tid >> 1;                                                     \
    int ldCol  = (tid & 1) * 16;                                               \
    int kpBase = (tid & 1) * 8;                                                \
    float acc[4][4][4];                                                        \
    _Pragma("unroll")                                                          \
    for (int mi = 0; mi < 4; mi++)                                             \
        _Pragma("unroll")                                                      \
        for (int ni = 0; ni < 4; ni++)                                         \
            _Pragma("unroll")                                                  \
            for (int e = 0; e < 4; e++) acc[mi][ni][e] = 0.f;                  \
    float ar[16], br[16];

#define CORE_MAINLOOP(KTILES)                                                  \
    CORE_LOAD_REGS(0);                                                         \
    CORE_STORE_SMEM(0);                                                        \
    __syncthreads();                                                           \
    for (int t = 0; t < (KTILES); t++) {                                       \
        int buf = t & 1;                                                       \
        bool has = (t + 1 < (KTILES));                                         \
        if (has) CORE_LOAD_REGS((t + 1) << 5);                                 \
        CORE_COMPUTE(buf);                                                     \
        if (has) CORE_STORE_SMEM(buf ^ 1);                                     \
        __syncthreads();                                                       \
    }

// ------- 3xBF16 mma GEMM: C[M,N] = A[M,K] @ W[N,K]^T (fp32-class acc) -------
__global__ __launch_bounds__(256) void gemm_tc2(
    const float* __restrict__ A, const float* __restrict__ W,
    float* __restrict__ C, int K, int N)
{
    extern __shared__ unsigned sm[];
    int rowBase = blockIdx.y * 128;
    int colBase = blockIdx.x * 128;
    const float* Ag = A + (size_t)rowBase * K;
    const float* Wg = W + (size_t)colBase * K;
    CORE_PROLOG_VARS;
    int kTiles = K >> 5;
    CORE_MAINLOOP(kTiles);

    #pragma unroll
    for (int mi = 0; mi < 4; mi++) {
        int r = rowBase + warpM + mi * 16 + (lane >> 2);
        #pragma unroll
        for (int ni = 0; ni < 4; ni++) {
            int c = colBase + warpN + ni * 8 + (lane & 3) * 2;
            *(float2*)(C + (size_t)r * N + c) =
                make_float2(acc[mi][ni][0], acc[mi][ni][1]);
            *(float2*)(C + (size_t)(r + 8) * N + c) =
                make_float2(acc[mi][ni][2], acc[mi][ni][3]);
        }
    }
}

// ---- FAVOR tensor-core kernel: C = A[M,128] @ B[128,128]^T + epilogue ------
// mode 0: featQ (row-max + exp)   A=g_qx  B=proj  out=g_qphi
// mode 1: featK (subtract sq)     A=g_kx  B=proj  out=g_kxp
// mode 2: out   (mask / denom)    A=g_qphi B=g_kvT[bhk] out=g_ao (interleaved)
__global__ __launch_bounds__(256) void favor_tc(
    const float* __restrict__ A, const float* __restrict__ Bglob,
    const float* __restrict__ sq, const int* __restrict__ mask,
    float* __restrict__ out, int mode)
{
    extern __shared__ unsigned sm[];
    __shared__ float red[128][4];
    int rowBase = blockIdx.y * 128;
    const int K = 128, N = 128;
    const float* Wg;
    if (mode == 2) {
        int bh = blockIdx.y >> 5;            // 32 bands of 128 rows per bh
        int b = bh >> 4, h = bh & 15;
        int bhk = b * 8 + (h >> 1);
        Wg = Bglob + (size_t)bhk * 128 * 128;
    } else {
        Wg = Bglob;
    }
    const float* Ag = A + (size_t)rowBase * K;
    CORE_PROLOG_VARS;
    CORE_MAINLOOP(4);

    int mo = lane >> 2;
    if (mode == 0) {
        #pragma unroll
        for (int mi = 0; mi < 4; mi++) {
            float m0 = -1e30f, m1 = -1e30f;
            #pragma unroll
            for (int ni = 0; ni < 4; ni++) {
                m0 = fmaxf(m0, fmaxf(acc[mi][ni][0], acc[mi][ni][1]));
                m1 = fmaxf(m1, fmaxf(acc[mi][ni][2], acc[mi][ni][3]));
            }
            m0 = fmaxf(m0, __shfl_xor_sync(0xffffffffu, m0, 1));
            m0 = fmaxf(m0, __shfl_xor_sync(0xffffffffu, m0, 2));
            m1 = fmaxf(m1, __shfl_xor_sync(0xffffffffu, m1, 1));
            m1 = fmaxf(m1, __shfl_xor_sync(0xffffffffu, m1, 2));
            if ((lane & 3) == 0) {
                red[warpM + mi*16 + mo][warp & 3] = m0;
                red[warpM + mi*16 + mo + 8][warp & 3] = m1;
            }
        }
        __syncthreads();
        #pragma unroll
        for (int mi = 0; mi < 4; mi++) {
            int rl = warpM + mi*16 + mo;
            float rm0 = fmaxf(fmaxf(red[rl][0], red[rl][1]),
                              fmaxf(red[rl][2], red[rl][3]));
            float rm1 = fmaxf(fmaxf(red[rl+8][0], red[rl+8][1]),
                              fmaxf(red[rl+8][2], red[rl+8][3]));
            #pragma unroll
            for (int ni = 0; ni < 4; ni++) {
                int c = warpN + ni*8 + (lane & 3)*2;
                *(float2*)(out + (size_t)(rowBase + rl) * N + c) =
                    make_float2(expf(acc[mi][ni][0]-rm0)*INV_SQRT_M + EPSF,
                                expf(acc[mi][ni][1]-rm0)*INV_SQRT_M + EPSF);
                *(float2*)(out + (size_t)(rowBase + rl + 8) * N + c) =
                    make_float2(expf(acc[mi][ni][2]-rm1)*INV_SQRT_M + EPSF,
                                expf(acc[mi][ni][3]-rm1)*INV_SQRT_M + EPSF);
            }
        }
    } else if (mode == 1) {
        #pragma unroll
        for (int mi = 0; mi < 4; mi++) {
            int r0 = rowBase + warpM + mi*16 + mo;
            float s0 = sq[r0], s1 = sq[r0 + 8];
            #pragma unroll
            for (int ni = 0; ni < 4; ni++) {
                int c = warpN + ni*8 + (lane & 3)*2;
                *(float2*)(out + (size_t)r0 * N + c) =
                    make_float2(acc[mi][ni][0]-s0, acc[mi][ni][1]-s0);
                *(float2*)(out + (size_t)(r0 + 8) * N + c) =
                    make_float2(acc[mi][ni][2]-s1, acc[mi][ni][3]-s1);
            }
        }
    } else {
        #pragma unroll
        for (int mi = 0; mi < 4; mi++) {
            int rg = rowBase + warpM + mi*16 + mo;
            #pragma unroll
            for (int half = 0; half < 2; half++) {
                int r = rg + half * 8;
                int s = r & 4095;
                int bh = r >> 12;
                int b = bh >> 4, h = bh & 15;
                float vm = (mask[b * Ss + s] > 0) ? 1.f : 0.f;
                float scale = vm / (sq[r] + EPSF);   // sq carries g_dn here
                float* op = out + ((size_t)(b * Ss + s) * (Hh*HDd)) + h * HDd;
                #pragma unroll
                for (int ni = 0; ni < 4; ni++) {
                    int c = warpN + ni*8 + (lane & 3)*2;
                    *(float2*)(op + c) =
                        make_float2(acc[mi][ni][2*half]*scale,
                                    acc[mi][ni][2*half+1]*scale);
                }
            }
        }
    }
}

// ------------- RMSNorm + RoPE + d^{-1/4} scale, transpose to [b,h,s,d] ------
__global__ __launch_bounds__(128) void normrope_kernel(
    const float* __restrict__ qkv, const float* __restrict__ fc,
    const float* __restrict__ g, float* __restrict__ xout,
    float* __restrict__ sqout, int nh)
{
    int bs = blockIdx.x;
    int h  = blockIdx.y;
    int d  = threadIdx.x;
    float val = qkv[(size_t)bs * nh * HDd + h * HDd + d];

    float ss = val * val;
    #pragma unroll
    for (int o = 16; o > 0; o >>= 1) ss += __shfl_xor_sync(0xffffffffu, ss, o);
    __shared__ float wsum[4];
    int wid = d >> 5, lane = d & 31;
    if (lane == 0) wsum[wid] = ss;
    __syncthreads();
    float tot = wsum[0] + wsum[1] + wsum[2] + wsum[3];
    float inv = rsqrtf(tot * (1.0f / HDd) + 1e-5f);
    float xn = val * inv * g[d];

    __shared__ float row[HDd];
    row[d] = xn;
    __syncthreads();
    int i = d >> 1;
    float c  = fc[((size_t)bs * (HDd/2) + i) * 2 + 0];
    float sn = fc[((size_t)bs * (HDd/2) + i) * 2 + 1];
    float a  = row[2*i], b2 = row[2*i + 1];
    float r  = (d & 1) ? (a * sn + b2 * c) : (a * c - b2 * sn);
    r *= SCALE_QD;

    float s2 = r * r;
    #pragma unroll
    for (int o = 16; o > 0; o >>= 1) s2 += __shfl_xor_sync(0xffffffffu, s2, o);
    __syncthreads();
    if (lane == 0) wsum[wid] = s2;
    __syncthreads();
    float tot2 = wsum[0] + wsum[1] + wsum[2] + wsum[3];

    int b = bs / Ss, s = bs % Ss;
    xout[(((size_t)b * nh + h) * Ss + s) * HDd + d] = r;
    if (d == 0) sqout[((size_t)b * nh + h) * Ss + s] = 0.5f * tot2;
}

// ---------------- key column-max over S (two-stage) -------------------------
__global__ void kmax1_kernel() {
    int bh = blockIdx.x, ch = blockIdx.y, m = threadIdx.x;
    const float* p = g_kxp + ((size_t)bh * Ss + ch * 128) * Mm + m;
    float mx = -1e30f;
    #pragma unroll 4
    for (int s = 0; s < 128; s++) mx = fmaxf(mx, p[(size_t)s * Mm]);
    g_kmaxp[((size_t)bh * 32 + ch) * Mm + m] = mx;
}
__global__ void kmax2_kernel() {
    int bh = blockIdx.x, m = threadIdx.x;
    float mx = -1e30f;
    for (int c = 0; c < 32; c++) mx = fmaxf(mx, g_kmaxp[((size_t)bh*32 + c)*Mm + m]);
    g_kmax[bh * Mm + m] = mx;
}

__global__ void zero_kernel() {
    int i = blockIdx.x * blockDim.x + threadIdx.x;
    if (i < Bb*HKk*Mm*HDd) g_kvT[i] = 0.f;
    if (i < Bb*HKk*Mm)     g_ksum[i] = 0.f;
}

// -- kvT[d,m] += sum_s phi_k[s,m]*v[s,d] ; ksum[m] += sum_s phi_k[s,m] -------
__global__ __launch_bounds__(256) void kv_kernel(const int* __restrict__ mask)
{
    __shared__ float kps[16][128];
    __shared__ float vs [16][128];
    __shared__ float kmx[128];
    __shared__ float vmask[128];
    int bh = blockIdx.y;
    int b = bh / HKk, hk = bh % HKk;
    int s0 = blockIdx.x * 128;
    int tid = threadIdx.x;
    int tr = tid >> 4, tc = tid & 15;
    if (tid < 128) {
        kmx[tid] = g_kmax[bh * Mm + tid];
        vmask[tid] = (mask[b * Ss + s0 + tid] > 0) ? 1.f : 0.f;
    }
    __syncthreads();

    const float* KX = g_kxp + ((size_t)bh * Ss + s0) * Mm;
    const float* V  = g_v + ((size_t)(b * Ss + s0)) * (HKk*HDd) + hk * HDd;
    float acc[8][8];
    #pragma unroll
    for (int i=0;i<8;i++)
        #pragma unroll
        for (int j=0;j<8;j++) acc[i][j]=0.f;
    float ksacc = 0.f;

    for (int sc = 0; sc < 128; sc += 16) {
        #pragma unroll
        for (int it = 0; it < 2; it++) {
            int idx = tid + it * 256;
            int r = idx >> 5;
            int c4 = (idx & 31) << 2;
            float vm = vmask[sc + r];
            float4 x4 = *(const float4*)(KX + (size_t)(sc + r) * Mm + c4);
            kps[r][c4+0] = (expf(x4.x - kmx[c4+0]) * INV_SQRT_M + EPSF) * vm;
            kps[r][c4+1] = (expf(x4.y - kmx[c4+1]) * INV_SQRT_M + EPSF) * vm;
            kps[r][c4+2] = (expf(x4.z - kmx[c4+2]) * INV_SQRT_M + EPSF) * vm;
            kps[r][c4+3] = (expf(x4.w - kmx[c4+3]) * INV_SQRT_M + EPSF) * vm;
            float4 v4 = *(const float4*)(V + (size_t)(sc + r) * (HKk*HDd) + c4);
            vs[r][c4+0]=v4.x; vs[r][c4+1]=v4.y; vs[r][c4+2]=v4.z; vs[r][c4+3]=v4.w;
        }
        __syncthreads();
        #pragma unroll
        for (int ssi = 0; ssi < 16; ssi++) {
            float ra[8], rb[8];
            #pragma unroll
            for (int i=0;i<8;i++) ra[i]=kps[ssi][tr*8+i];
            #pragma unroll
            for (int j=0;j<8;j++) rb[j]=vs[ssi][tc*8+j];
            #pragma unroll
            for (int i=0;i<8;i++)
                #pragma unroll
                for (int j=0;j<8;j++) acc[i][j] += ra[i]*rb[j];
        }
        if (tid < 128) {
            #pragma unroll
            for (int ssi = 0; ssi < 16; ssi++) ksacc += kps[ssi][tid];
        }
        __syncthreads();
    }
    // store TRANSPOSED: kvT[d][m]
    float* KV = g_kvT + (size_t)bh * Mm * HDd;
    #pragma unroll
    for (int i = 0; i < 8; i++)
        #pragma unroll
        for (int j = 0; j < 8; j++)
            atomicAdd(&KV[(size_t)(tc*8+j)*Mm + tr*8+i], acc[i][j]);
    if (tid < 128) atomicAdd(&g_ksum[bh * Mm + tid], ksacc);
}

// -------------- denominators: dn[row] = qphi[row,:]·ksum[bhk,:] -------------
__global__ __launch_bounds__(256) void dn_kernel() {
    int warp = threadIdx.x >> 5, lane = threadIdx.x & 31;
    int row = blockIdx.x * 8 + warp;
    int bh = row >> 12;
    int b = bh >> 4, h = bh & 15;
    int bhk = b * 8 + (h >> 1);
    float4 q = *(const float4*)(g_qphi + (size_t)row * Mm + lane * 4);
    float4 s = *(const float4*)(g_ksum + bhk * Mm + lane * 4);
    float v = q.x*s.x + q.y*s.y + q.z*s.z + q.w*s.w;
    #pragma unroll
    for (int o = 16; o > 0; o >>= 1) v += __shfl_xor_sync(0xffffffffu, v, o);
    if (lane == 0) g_dn[row] = v;
}

// ------------------------------- launch -------------------------------------
extern "C" void kernel_launch(void* const* d_in, const int* in_sizes, int n_in,
                              void* d_out, int out_size)
{
    const float* x    = (const float*)d_in[0];
    const int*   mask = (const int*)  d_in[1];
    const float* fc   = (const float*)d_in[2];
    const float* wq   = (const float*)d_in[3];
    const float* wk   = (const float*)d_in[4];
    const float* wv   = (const float*)d_in[5];
    const float* wo   = (const float*)d_in[6];
    const float* gq   = (const float*)d_in[7];
    const float* gk   = (const float*)d_in[8];
    const float* proj = (const float*)d_in[9];
    float* out = (float*)d_out;

    float *pq, *pk, *pv, *pqx, *pkx, *psqq, *psqk, *pqphi, *pkxp, *pkvT, *pdn, *pao;
    cudaGetSymbolAddress((void**)&pq,   g_q);
    cudaGetSymbolAddress((void**)&pk,   g_k);
    cudaGetSymbolAddress((void**)&pv,   g_v);
    cudaGetSymbolAddress((void**)&pqx,  g_qx);
    cudaGetSymbolAddress((void**)&pkx,  g_kx);
    cudaGetSymbolAddress((void**)&psqq, g_sqq);
    cudaGetSymbolAddress((void**)&psqk, g_sqk);
    cudaGetSymbolAddress((void**)&pqphi,g_qphi);
    cudaGetSymbolAddress((void**)&pkxp, g_kxp);
    cudaGetSymbolAddress((void**)&pkvT, g_kvT);
    cudaGetSymbolAddress((void**)&pdn,  g_dn);
    cudaGetSymbolAddress((void**)&pao,  g_ao);

    cudaFuncSetAttribute(gemm_tc2, cudaFuncAttributeMaxDynamicSharedMemorySize, DSMEM_BYTES);
    cudaFuncSetAttribute(favor_tc, cudaFuncAttributeMaxDynamicSharedMemorySize, DSMEM_BYTES);

    // QKV projections (3xBF16 mma, k-depth 32)
    gemm_tc2<<<dim3((Hh*HDd)/128,  (Bb*Ss)/128), 256, DSMEM_BYTES>>>(x, wq, pq, DIMm, Hh*HDd);
    gemm_tc2<<<dim3((HKk*HDd)/128, (Bb*Ss)/128), 256, DSMEM_BYTES>>>(x, wk, pk, DIMm, HKk*HDd);
    gemm_tc2<<<dim3((HKk*HDd)/128, (Bb*Ss)/128), 256, DSMEM_BYTES>>>(x, wv, pv, DIMm, HKk*HDd);

    // RMSNorm + RoPE + scale
    normrope_kernel<<<dim3(Bb*Ss, Hh),  128>>>(pq, fc, gq, pqx, psqq, Hh);
    normrope_kernel<<<dim3(Bb*Ss, HKk), 128>>>(pk, fc, gk, pkx, psqk, HKk);

    // FAVOR feature projections on tensor cores
    favor_tc<<<dim3(1, (Bb*Hh*Ss)/128),  256, DSMEM_BYTES>>>(pqx, proj, psqq, mask, pqphi, 0);
    favor_tc<<<dim3(1, (Bb*HKk*Ss)/128), 256, DSMEM_BYTES>>>(pkx, proj, psqk, mask, pkxp, 1);

    // key column max over S
    kmax1_kernel<<<dim3(Bb*HKk, 32), 128>>>();
    kmax2_kernel<<<Bb*HKk, 128>>>();

    // kv / ksum contraction (kv stored transposed)
    zero_kernel<<<(Bb*HKk*Mm*HDd + 255)/256, 256>>>();
    kv_kernel<<<dim3(Ss/128, Bb*HKk), 256>>>(mask);

    // denominators, then attention output on tensor cores
    dn_kernel<<<(Bb*Hh*Ss)/8, 256>>>();
    favor_tc<<<dim3(1, (Bb*Hh*Ss)/128), 256, DSMEM_BYTES>>>(pqphi, pkvT, pdn, mask, pao, 2);

    // output projection
    gemm_tc2<<<dim3(DIMm/128, (Bb*Ss)/128), 256, DSMEM_BYTES>>>(pao, wo, out, Hh*HDd, DIMm);
}

// round 7
// speedup vs baseline: 2.1324x; 1.1055x over previous
#include <cuda_runtime.h>
#include <cuda_bf16.h>
#include <cuda_fp16.h>
#include <math.h>
#include <stdint.h>

#define Bb  2
#define Ss  4096
#define DIMm 2048
#define Hh  16
#define HKk 8
#define HDd 128
#define Mm  128

#define INV_SQRT_M 0.08838834764831845f   // 128^{-0.5}
#define SCALE_QD   0.2973017787506803f    // 128^{-0.25}
#define EPSF 1e-6f

// ---------------- scratch (device globals; no allocations allowed) ----------
__device__ float g_q   [Bb*Ss*Hh*HDd];     // [b,s,h,d]
__device__ float g_k   [Bb*Ss*HKk*HDd];
__device__ float g_v   [Bb*Ss*HKk*HDd];
__device__ float g_qx  [Bb*Hh*Ss*HDd];     // normed+roped+scaled, [b,h,s,d]
__device__ float g_kx  [Bb*HKk*Ss*HDd];
__device__ float g_sqq [Bb*Hh*Ss];
__device__ float g_sqk [Bb*HKk*Ss];
__device__ float g_qphi[Bb*Hh*Ss*Mm];      // [b,h,s,m]
__device__ float g_kxp [Bb*HKk*Ss*Mm];     // pre-exp key features
__device__ float g_kmaxp[Bb*HKk*32*Mm];
__device__ float g_kmax[Bb*HKk*Mm];
__device__ float g_kvT [Bb*HKk*HDd*Mm];    // TRANSPOSED kv: [d][m]
__device__ float g_ksum[Bb*HKk*Mm];
__device__ float g_dn  [Bb*Hh*Ss];         // denominators
__device__ float g_ao  [Bb*Ss*Hh*HDd];     // attention out, [b,s,h*d]

// ---------------------------- split helpers ---------------------------------
__device__ __forceinline__ void bfsplit2(float x0, float x1, unsigned& hi, unsigned& lo) {
    __nv_bfloat162 h2 = __floats2bfloat162_rn(x0, x1);
    float2 hf = __bfloat1622float2(h2);
    __nv_bfloat162 l2 = __floats2bfloat162_rn(x0 - hf.x, x1 - hf.y);
    hi = *reinterpret_cast<unsigned*>(&h2);
    lo = *reinterpret_cast<unsigned*>(&l2);
}
__device__ __forceinline__ void hsplit2(float x0, float x1, unsigned& hi, unsigned& lo) {
    __half2 h2 = __floats2half2_rn(x0, x1);
    float2 hf = __half22float2(h2);
    __half2 l2 = __floats2half2_rn(x0 - hf.x, x1 - hf.y);
    hi = *reinterpret_cast<unsigned*>(&h2);
    lo = *reinterpret_cast<unsigned*>(&l2);
}

__device__ __forceinline__ void mma_bf16(float* d, const unsigned* a, const unsigned* b) {
    asm volatile(
        "mma.sync.aligned.m16n8k16.row.col.f32.bf16.bf16.f32 "
        "{%0,%1,%2,%3}, {%4,%5,%6,%7}, {%8,%9}, {%0,%1,%2,%3};\n"
        : "+f"(d[0]), "+f"(d[1]), "+f"(d[2]), "+f"(d[3])
        : "r"(a[0]), "r"(a[1]), "r"(a[2]), "r"(a[3]),
          "r"(b[0]), "r"(b[1]));
}
__device__ __forceinline__ void mma_f16(float* d, const unsigned* a, const unsigned* b) {
    asm volatile(
        "mma.sync.aligned.m16n8k16.row.col.f32.f16.f16.f32 "
        "{%0,%1,%2,%3}, {%4,%5,%6,%7}, {%8,%9}, {%0,%1,%2,%3};\n"
        : "+f"(d[0]), "+f"(d[1]), "+f"(d[2]), "+f"(d[3])
        : "r"(a[0]), "r"(a[1]), "r"(a[2]), "r"(a[3]),
          "r"(b[0]), "r"(b[1]));
}

// smem layout (dynamic, unsigned units): per array 2 bufs x 16 kpairs x LDT
#define LDT 136
#define SOFF_AH(b) ((unsigned)(b)*2176u)
#define SOFF_AL(b) (4352u  + (unsigned)(b)*2176u)
#define SOFF_BH(b) (8704u  + (unsigned)(b)*2176u)
#define SOFF_BL(b) (13056u + (unsigned)(b)*2176u)
#define DSMEM_BYTES (17408*4)   // 69632 (4 arrays, 3-term bf16)
#define DSMEM2_BYTES (13056*4)  // 52224 (3 arrays, 2-term fp16)

// ---- shared macro bodies for the mma cores (k-depth 32) --------------------
#define CORE_LOAD_REGS(k0)                                                     \
    {                                                                          \
        const float* ap = Ag + (size_t)ldRow * K + (k0) + ldCol;               \
        const float* bp = Wg + (size_t)ldRow * K + (k0) + ldCol;               \
        float4 t;                                                              \
        t = *(const float4*)(ap);      ar[0]=t.x; ar[1]=t.y; ar[2]=t.z; ar[3]=t.w;   \
        t = *(const float4*)(ap + 4);  ar[4]=t.x; ar[5]=t.y; ar[6]=t.z; ar[7]=t.w;   \
        t = *(const float4*)(ap + 8);  ar[8]=t.x; ar[9]=t.y; ar[10]=t.z; ar[11]=t.w; \
        t = *(const float4*)(ap + 12); ar[12]=t.x; ar[13]=t.y; ar[14]=t.z; ar[15]=t.w;\
        t = *(const float4*)(bp);      br[0]=t.x; br[1]=t.y; br[2]=t.z; br[3]=t.w;   \
        t = *(const float4*)(bp + 4);  br[4]=t.x; br[5]=t.y; br[6]=t.z; br[7]=t.w;   \
        t = *(const float4*)(bp + 8);  br[8]=t.x; br[9]=t.y; br[10]=t.z; br[11]=t.w; \
        t = *(const float4*)(bp + 12); br[12]=t.x; br[13]=t.y; br[14]=t.z; br[15]=t.w;\
    }

#define CORE_STORE_SMEM(bufn)                                                  \
    {                                                                          \
        _Pragma("unroll")                                                      \
        for (int e = 0; e < 8; e++) {                                          \
            unsigned hi, lo;                                                   \
            bfsplit2(ar[2*e], ar[2*e+1], hi, lo);                              \
            sm[SOFF_AH(bufn) + (kpBase+e)*LDT + ldRow] = hi;                   \
            sm[SOFF_AL(bufn) + (kpBase+e)*LDT + ldRow] = lo;                   \
            bfsplit2(br[2*e], br[2*e+1], hi, lo);                              \
            sm[SOFF_BH(bufn) + (kpBase+e)*LDT + ldRow] = hi;                   \
            sm[SOFF_BL(bufn) + (kpBase+e)*LDT + ldRow] = lo;                   \
        }                                                                      \
    }

#define CORE_COMPUTE(bufn)                                                     \
    {                                                                          \
        _Pragma("unroll")                                                      \
        for (int h = 0; h < 2; h++) {                                          \
            int kc = h*8 + (lane & 3);                                         \
            int mo = lane >> 2;                                                \
            unsigned afh[4][4], afl[4][4], bfh[4][2], bfl[4][2];               \
            _Pragma("unroll")                                                  \
            for (int mi = 0; mi < 4; mi++) {                                   \
                int m = warpM + mi * 16 + mo;                                  \
                afh[mi][0] = sm[SOFF_AH(bufn) + kc*LDT + m];                   \
                afh[mi][1] = sm[SOFF_AH(bufn) + kc*LDT + m + 8];               \
                afh[mi][2] = sm[SOFF_AH(bufn) + (kc+4)*LDT + m];               \
                afh[mi][3] = sm[SOFF_AH(bufn) + (kc+4)*LDT + m + 8];           \
                afl[mi][0] = sm[SOFF_AL(bufn) + kc*LDT + m];                   \
                afl[mi][1] = sm[SOFF_AL(bufn) + kc*LDT + m + 8];               \
                afl[mi][2] = sm[SOFF_AL(bufn) + (kc+4)*LDT + m];               \
                afl[mi][3] = sm[SOFF_AL(bufn) + (kc+4)*LDT + m + 8];           \
            }                                                                  \
            _Pragma("unroll")                                                  \
            for (int ni = 0; ni < 4; ni++) {                                   \
                int n = warpN + ni * 8 + mo;                                   \
                bfh[ni][0] = sm[SOFF_BH(bufn) + kc*LDT + n];                   \
                bfh[ni][1] = sm[SOFF_BH(bufn) + (kc+4)*LDT + n];               \
                bfl[ni][0] = sm[SOFF_BL(bufn) + kc*LDT + n];                   \
                bfl[ni][1] = sm[SOFF_BL(bufn) + (kc+4)*LDT + n];               \
            }                                                                  \
            _Pragma("unroll")                                                  \
            for (int mi = 0; mi < 4; mi++)                                     \
                _Pragma("unroll")                                              \
                for (int ni = 0; ni < 4; ni++) {                               \
                    mma_bf16(acc[mi][ni], afh[mi], bfh[ni]);                   \
                    mma_bf16(acc[mi][ni], afl[mi], bfh[ni]);                   \
                    mma_bf16(acc[mi][ni], afh[mi], bfl[ni]);                   \
                }                                                              \
        }                                                                      \
    }

#define CORE_PROLOG_VARS                                                       \
    int tid  = threadIdx.x;                                                    \
    int lane = tid & 31;                                                       \
    int warp = tid >> 5;                                                       \
    int warpM = (warp >> 2) * 64;                                              \
    int warpN = (warp & 3) * 32;                                               \
    int ldRow  = tid >> 1;                                                     \
    int ldCol  = (tid & 1) * 16;                                               \
    int kpBase = (tid & 1) * 8;                                                \
    float acc[4][4][4];                                                        \
    _Pragma("unroll")                                                          \
    for (int mi = 0; mi < 4; mi++)                                             \
        _Pragma("unroll")                                                      \
        for (int ni = 0; ni < 4; ni++)                                         \
            _Pragma("unroll")                                                  \
            for (int e = 0; e < 4; e++) acc[mi][ni][e] = 0.f;                  \
    float ar[16], br[16];

#define CORE_MAINLOOP(KTILES)                                                  \
    CORE_LOAD_REGS(0);                                                         \
    CORE_STORE_SMEM(0);                                                        \
    __syncthreads();                                                           \
    for (int t = 0; t < (KTILES); t++) {                                       \
        int buf = t & 1;                                                       \
        bool has = (t + 1 < (KTILES));                                         \
        if (has) CORE_LOAD_REGS((t + 1) << 5);                                 \
        CORE_COMPUTE(buf);                                                     \
        if (has) CORE_STORE_SMEM(buf ^ 1);                                     \
        __syncthreads();                                                       \
    }

// ---- 2-term fp16 variant: store A hi/lo + B hi only ------------------------
#define F16_STORE_SMEM(bufn)                                                   \
    {                                                                          \
        _Pragma("unroll")                                                      \
        for (int e = 0; e < 8; e++) {                                          \
            unsigned hi, lo;                                                   \
            hsplit2(ar[2*e], ar[2*e+1], hi, lo);                               \
            sm[SOFF_AH(bufn) + (kpBase+e)*LDT + ldRow] = hi;                   \
            sm[SOFF_AL(bufn) + (kpBase+e)*LDT + ldRow] = lo;                   \
            __half2 b2 = __floats2half2_rn(br[2*e], br[2*e+1]);                \
            sm[SOFF_BH(bufn) + (kpBase+e)*LDT + ldRow] =                       \
                *reinterpret_cast<unsigned*>(&b2);                             \
        }                                                                      \
    }

#define F16_COMPUTE(bufn)                                                      \
    {                                                                          \
        _Pragma("unroll")                                                      \
        for (int h = 0; h < 2; h++) {                                          \
            int kc = h*8 + (lane & 3);                                         \
            int mo = lane >> 2;                                                \
            unsigned afh[4][4], afl[4][4], bfh[4][2];                          \
            _Pragma("unroll")                                                  \
            for (int mi = 0; mi < 4; mi++) {                                   \
                int m = warpM + mi * 16 + mo;                                  \
                afh[mi][0] = sm[SOFF_AH(bufn) + kc*LDT + m];                   \
                afh[mi][1] = sm[SOFF_AH(bufn) + kc*LDT + m + 8];               \
                afh[mi][2] = sm[SOFF_AH(bufn) + (kc+4)*LDT + m];               \
                afh[mi][3] = sm[SOFF_AH(bufn) + (kc+4)*LDT + m + 8];           \
                afl[mi][0] = sm[SOFF_AL(bufn) + kc*LDT + m];                   \
                afl[mi][1] = sm[SOFF_AL(bufn) + kc*LDT + m + 8];               \
                afl[mi][2] = sm[SOFF_AL(bufn) + (kc+4)*LDT + m];               \
                afl[mi][3] = sm[SOFF_AL(bufn) + (kc+4)*LDT + m + 8];           \
            }                                                                  \
            _Pragma("unroll")                                                  \
            for (int ni = 0; ni < 4; ni++) {                                   \
                int n = warpN + ni * 8 + mo;                                   \
                bfh[ni][0] = sm[SOFF_BH(bufn) + kc*LDT + n];                   \
                bfh[ni][1] = sm[SOFF_BH(bufn) + (kc+4)*LDT + n];               \
            }                                                                  \
            _Pragma("unroll")                                                  \
            for (int mi = 0; mi < 4; mi++)                                     \
                _Pragma("unroll")                                              \
                for (int ni = 0; ni < 4; ni++) {                               \
                    mma_f16(acc[mi][ni], afh[mi], bfh[ni]);                    \
                    mma_f16(acc[mi][ni], afl[mi], bfh[ni]);                    \
                }                                                              \
        }                                                                      \
    }

// ------- 3xBF16 mma GEMM: C[M,N] = A[M,K] @ W[N,K]^T (fp32-class acc) -------
__global__ __launch_bounds__(256) void gemm_tc2(
    const float* __restrict__ A, const float* __restrict__ W,
    float* __restrict__ C, int K, int N)
{
    extern __shared__ unsigned sm[];
    int rowBase = blockIdx.y * 128;
    int colBase = blockIdx.x * 128;
    const float* Ag = A + (size_t)rowBase * K;
    const float* Wg = W + (size_t)colBase * K;
    CORE_PROLOG_VARS;
    int kTiles = K >> 5;
    CORE_MAINLOOP(kTiles);

    #pragma unroll
    for (int mi = 0; mi < 4; mi++) {
        int r = rowBase + warpM + mi * 16 + (lane >> 2);
        #pragma unroll
        for (int ni = 0; ni < 4; ni++) {
            int c = colBase + warpN + ni * 8 + (lane & 3) * 2;
            *(float2*)(C + (size_t)r * N + c) =
                make_float2(acc[mi][ni][0], acc[mi][ni][1]);
            *(float2*)(C + (size_t)(r + 8) * N + c) =
                make_float2(acc[mi][ni][2], acc[mi][ni][3]);
        }
    }
}

// ---- 2-term fp16 mma GEMM (A split hi/lo, B hi only): linear paths ---------
__global__ __launch_bounds__(256) void gemm_f16_2t(
    const float* __restrict__ A, const float* __restrict__ W,
    float* __restrict__ C, int K, int N)
{
    extern __shared__ unsigned sm[];
    int rowBase = blockIdx.y * 128;
    int colBase = blockIdx.x * 128;
    const float* Ag = A + (size_t)rowBase * K;
    const float* Wg = W + (size_t)colBase * K;
    CORE_PROLOG_VARS;
    int kTiles = K >> 5;

    CORE_LOAD_REGS(0);
    F16_STORE_SMEM(0);
    __syncthreads();
    for (int t = 0; t < kTiles; t++) {
        int buf = t & 1;
        bool has = (t + 1 < kTiles);
        if (has) CORE_LOAD_REGS((t + 1) << 5);
        F16_COMPUTE(buf);
        if (has) F16_STORE_SMEM(buf ^ 1);
        __syncthreads();
    }

    #pragma unroll
    for (int mi = 0; mi < 4; mi++) {
        int r = rowBase + warpM + mi * 16 + (lane >> 2);
        #pragma unroll
        for (int ni = 0; ni < 4; ni++) {
            int c = colBase + warpN + ni * 8 + (lane & 3) * 2;
            *(float2*)(C + (size_t)r * N + c) =
                make_float2(acc[mi][ni][0], acc[mi][ni][1]);
            *(float2*)(C + (size_t)(r + 8) * N + c) =
                make_float2(acc[mi][ni][2], acc[mi][ni][3]);
        }
    }
}

// ---- FAVOR tensor-core kernel: C = A[M,128] @ B[128,128]^T + epilogue ------
__global__ __launch_bounds__(256) void favor_tc(
    const float* __restrict__ A, const float* __restrict__ Bglob,
    const float* __restrict__ sq, const int* __restrict__ mask,
    float* __restrict__ out, int mode)
{
    extern __shared__ unsigned sm[];
    __shared__ float red[128][4];
    int rowBase = blockIdx.y * 128;
    const int K = 128, N = 128;
    const float* Wg;
    if (mode == 2) {
        int bh = blockIdx.y >> 5;
        int b = bh >> 4, h = bh & 15;
        int bhk = b * 8 + (h >> 1);
        Wg = Bglob + (size_t)bhk * 128 * 128;
    } else {
        Wg = Bglob;
    }
    const float* Ag = A + (size_t)rowBase * K;
    CORE_PROLOG_VARS;
    CORE_MAINLOOP(4);

    int mo = lane >> 2;
    if (mode == 0) {
        #pragma unroll
        for (int mi = 0; mi < 4; mi++) {
            float m0 = -1e30f, m1 = -1e30f;
            #pragma unroll
            for (int ni = 0; ni < 4; ni++) {
                m0 = fmaxf(m0, fmaxf(acc[mi][ni][0], acc[mi][ni][1]));
                m1 = fmaxf(m1, fmaxf(acc[mi][ni][2], acc[mi][ni][3]));
            }
            m0 = fmaxf(m0, __shfl_xor_sync(0xffffffffu, m0, 1));
            m0 = fmaxf(m0, __shfl_xor_sync(0xffffffffu, m0, 2));
            m1 = fmaxf(m1, __shfl_xor_sync(0xffffffffu, m1, 1));
            m1 = fmaxf(m1, __shfl_xor_sync(0xffffffffu, m1, 2));
            if ((lane & 3) == 0) {
                red[warpM + mi*16 + mo][warp & 3] = m0;
                red[warpM + mi*16 + mo + 8][warp & 3] = m1;
            }
        }
        __syncthreads();
        #pragma unroll
        for (int mi = 0; mi < 4; mi++) {
            int rl = warpM + mi*16 + mo;
            float rm0 = fmaxf(fmaxf(red[rl][0], red[rl][1]),
                              fmaxf(red[rl][2], red[rl][3]));
            float rm1 = fmaxf(fmaxf(red[rl+8][0], red[rl+8][1]),
                              fmaxf(red[rl+8][2], red[rl+8][3]));
            #pragma unroll
            for (int ni = 0; ni < 4; ni++) {
                int c = warpN + ni*8 + (lane & 3)*2;
                *(float2*)(out + (size_t)(rowBase + rl) * N + c) =
                    make_float2(expf(acc[mi][ni][0]-rm0)*INV_SQRT_M + EPSF,
                                expf(acc[mi][ni][1]-rm0)*INV_SQRT_M + EPSF);
                *(float2*)(out + (size_t)(rowBase + rl + 8) * N + c) =
                    make_float2(expf(acc[mi][ni][2]-rm1)*INV_SQRT_M + EPSF,
                                expf(acc[mi][ni][3]-rm1)*INV_SQRT_M + EPSF);
            }
        }
    } else if (mode == 1) {
        #pragma unroll
        for (int mi = 0; mi < 4; mi++) {
            int r0 = rowBase + warpM + mi*16 + mo;
            float s0 = sq[r0], s1 = sq[r0 + 8];
            #pragma unroll
            for (int ni = 0; ni < 4; ni++) {
                int c = warpN + ni*8 + (lane & 3)*2;
                *(float2*)(out + (size_t)r0 * N + c) =
                    make_float2(acc[mi][ni][0]-s0, acc[mi][ni][1]-s0);
                *(float2*)(out + (size_t)(r0 + 8) * N + c) =
                    make_float2(acc[mi][ni][2]-s1, acc[mi][ni][3]-s1);
            }
        }
    } else {
        #pragma unroll
        for (int mi = 0; mi < 4; mi++) {
            int rg = rowBase + warpM + mi*16 + mo;
            #pragma unroll
            for (int half = 0; half < 2; half++) {
                int r = rg + half * 8;
                int s = r & 4095;
                int bh = r >> 12;
                int b = bh >> 4, h = bh & 15;
                float vm = (mask[b * Ss + s] > 0) ? 1.f : 0.f;
                float scale = vm / (sq[r] + EPSF);   // sq carries g_dn here
                float* op = out + ((size_t)(b * Ss + s) * (Hh*HDd)) + h * HDd;
                #pragma unroll
                for (int ni = 0; ni < 4; ni++) {
                    int c = warpN + ni*8 + (lane & 3)*2;
                    *(float2*)(op + c) =
                        make_float2(acc[mi][ni][2*half]*scale,
                                    acc[mi][ni][2*half+1]*scale);
                }
            }
        }
    }
}

// ------------- RMSNorm + RoPE + d^{-1/4} scale, transpose to [b,h,s,d] ------
__global__ __launch_bounds__(128) void normrope_kernel(
    const float* __restrict__ qkv, const float* __restrict__ fc,
    const float* __restrict__ g, float* __restrict__ xout,
    float* __restrict__ sqout, int nh)
{
    int bs = blockIdx.x;
    int h  = blockIdx.y;
    int d  = threadIdx.x;
    float val = qkv[(size_t)bs * nh * HDd + h * HDd + d];

    float ss = val * val;
    #pragma unroll
    for (int o = 16; o > 0; o >>= 1) ss += __shfl_xor_sync(0xffffffffu, ss, o);
    __shared__ float wsum[4];
    int wid = d >> 5, lane = d & 31;
    if (lane == 0) wsum[wid] = ss;
    __syncthreads();
    float tot = wsum[0] + wsum[1] + wsum[2] + wsum[3];
    float inv = rsqrtf(tot * (1.0f / HDd) + 1e-5f);
    float xn = val * inv * g[d];

    __shared__ float row[HDd];
    row[d] = xn;
    __syncthreads();
    int i = d >> 1;
    float c  = fc[((size_t)bs * (HDd/2) + i) * 2 + 0];
    float sn = fc[((size_t)bs * (HDd/2) + i) * 2 + 1];
    float a  = row[2*i], b2 = row[2*i + 1];
    float r  = (d & 1) ? (a * sn + b2 * c) : (a * c - b2 * sn);
    r *= SCALE_QD;

    float s2 = r * r;
    #pragma unroll
    for (int o = 16; o > 0; o >>= 1) s2 += __shfl_xor_sync(0xffffffffu, s2, o);
    __syncthreads();
    if (lane == 0) wsum[wid] = s2;
    __syncthreads();
    float tot2 = wsum[0] + wsum[1] + wsum[2] + wsum[3];

    int b = bs / Ss, s = bs % Ss;
    xout[(((size_t)b * nh + h) * Ss + s) * HDd + d] = r;
    if (d == 0) sqout[((size_t)b * nh + h) * Ss + s] = 0.5f * tot2;
}

// ---------------- key column-max over S (two-stage) -------------------------
__global__ void kmax1_kernel() {
    int bh = blockIdx.x, ch = blockIdx.y, m = threadIdx.x;
    const float* p = g_kxp + ((size_t)bh * Ss + ch * 128) * Mm + m;
    float mx = -1e30f;
    #pragma unroll 4
    for (int s = 0; s < 128; s++) mx = fmaxf(mx, p[(size_t)s * Mm]);
    g_kmaxp[((size_t)bh * 32 + ch) * Mm + m] = mx;
}
__global__ void kmax2_kernel() {
    int bh = blockIdx.x, m = threadIdx.x;
    float mx = -1e30f;
    for (int c = 0; c < 32; c++) mx = fmaxf(mx, g_kmaxp[((size_t)bh*32 + c)*Mm + m]);
    g_kmax[bh * Mm + m] = mx;
}

__global__ void zero_kernel() {
    int i = blockIdx.x * blockDim.x + threadIdx.x;
    if (i < Bb*HKk*Mm*HDd) g_kvT[i] = 0.f;
    if (i < Bb*HKk*Mm)     g_ksum[i] = 0.f;
}

// -- kvT[d,m] += sum_s phi_k[s,m]*v[s,d] ; ksum[m] += sum_s phi_k[s,m] -------
__global__ __launch_bounds__(256) void kv_kernel(const int* __restrict__ mask)
{
    __shared__ float kps[16][128];
    __shared__ float vs [16][128];
    __shared__ float kmx[128];
    __shared__ float vmask[128];
    int bh = blockIdx.y;
    int b = bh / HKk, hk = bh % HKk;
    int s0 = blockIdx.x * 128;
    int tid = threadIdx.x;
    int tr = tid >> 4, tc = tid & 15;
    if (tid < 128) {
        kmx[tid] = g_kmax[bh * Mm + tid];
        vmask[tid] = (mask[b * Ss + s0 + tid] > 0) ? 1.f : 0.f;
    }
    __syncthreads();

    const float* KX = g_kxp + ((size_t)bh * Ss + s0) * Mm;
    const float* V  = g_v + ((size_t)(b * Ss + s0)) * (HKk*HDd) + hk * HDd;
    float acc[8][8];
    #pragma unroll
    for (int i=0;i<8;i++)
        #pragma unroll
        for (int j=0;j<8;j++) acc[i][j]=0.f;
    float ksacc = 0.f;

    for (int sc = 0; sc < 128; sc += 16) {
        #pragma unroll
        for (int it = 0; it < 2; it++) {
            int idx = tid + it * 256;
            int r = idx >> 5;
            int c4 = (idx & 31) << 2;
            float vm = vmask[sc + r];
            float4 x4 = *(const float4*)(KX + (size_t)(sc + r) * Mm + c4);
            kps[r][c4+0] = (expf(x4.x - kmx[c4+0]) * INV_SQRT_M + EPSF) * vm;
            kps[r][c4+1] = (expf(x4.y - kmx[c4+1]) * INV_SQRT_M + EPSF) * vm;
            kps[r][c4+2] = (expf(x4.z - kmx[c4+2]) * INV_SQRT_M + EPSF) * vm;
            kps[r][c4+3] = (expf(x4.w - kmx[c4+3]) * INV_SQRT_M + EPSF) * vm;
            float4 v4 = *(const float4*)(V + (size_t)(sc + r) * (HKk*HDd) + c4);
            vs[r][c4+0]=v4.x; vs[r][c4+1]=v4.y; vs[r][c4+2]=v4.z; vs[r][c4+3]=v4.w;
        }
        __syncthreads();
        #pragma unroll
        for (int ssi = 0; ssi < 16; ssi++) {
            float ra[8], rb[8];
            #pragma unroll
            for (int i=0;i<8;i++) ra[i]=kps[ssi][tr*8+i];
            #pragma unroll
            for (int j=0;j<8;j++) rb[j]=vs[ssi][tc*8+j];
            #pragma unroll
            for (int i=0;i<8;i++)
                #pragma unroll
                for (int j=0;j<8;j++) acc[i][j] += ra[i]*rb[j];
        }
        if (tid < 128) {
            #pragma unroll
            for (int ssi = 0; ssi < 16; ssi++) ksacc += kps[ssi][tid];
        }
        __syncthreads();
    }
    float* KV = g_kvT + (size_t)bh * Mm * HDd;
    #pragma unroll
    for (int i = 0; i < 8; i++)
        #pragma unroll
        for (int j = 0; j < 8; j++)
            atomicAdd(&KV[(size_t)(tc*8+j)*Mm + tr*8+i], acc[i][j]);
    if (tid < 128) atomicAdd(&g_ksum[bh * Mm + tid], ksacc);
}

// -------------- denominators: dn[row] = qphi[row,:]·ksum[bhk,:] -------------
__global__ __launch_bounds__(256) void dn_kernel() {
    int warp = threadIdx.x >> 5, lane = threadIdx.x & 31;
    int row = blockIdx.x * 8 + warp;
    int bh = row >> 12;
    int b = bh >> 4, h = bh & 15;
    int bhk = b * 8 + (h >> 1);
    float4 q = *(const float4*)(g_qphi + (size_t)row * Mm + lane * 4);
    float4 s = *(const float4*)(g_ksum + bhk * Mm + lane * 4);
    float v = q.x*s.x + q.y*s.y + q.z*s.z + q.w*s.w;
    #pragma unroll
    for (int o = 16; o > 0; o >>= 1) v += __shfl_xor_sync(0xffffffffu, v, o);
    if (lane == 0) g_dn[row] = v;
}

// ------------------------------- launch -------------------------------------
extern "C" void kernel_launch(void* const* d_in, const int* in_sizes, int n_in,
                              void* d_out, int out_size)
{
    const float* x    = (const float*)d_in[0];
    const int*   mask = (const int*)  d_in[1];
    const float* fc   = (const float*)d_in[2];
    const float* wq   = (const float*)d_in[3];
    const float* wk   = (const float*)d_in[4];
    const float* wv   = (const float*)d_in[5];
    const float* wo   = (const float*)d_in[6];
    const float* gq   = (const float*)d_in[7];
    const float* gk   = (const float*)d_in[8];
    const float* proj = (const float*)d_in[9];
    float* out = (float*)d_out;

    float *pq, *pk, *pv, *pqx, *pkx, *psqq, *psqk, *pqphi, *pkxp, *pkvT, *pdn, *pao;
    cudaGetSymbolAddress((void**)&pq,   g_q);
    cudaGetSymbolAddress((void**)&pk,   g_k);
    cudaGetSymbolAddress((void**)&pv,   g_v);
    cudaGetSymbolAddress((void**)&pqx,  g_qx);
    cudaGetSymbolAddress((void**)&pkx,  g_kx);
    cudaGetSymbolAddress((void**)&psqq, g_sqq);
    cudaGetSymbolAddress((void**)&psqk, g_sqk);
    cudaGetSymbolAddress((void**)&pqphi,g_qphi);
    cudaGetSymbolAddress((void**)&pkxp, g_kxp);
    cudaGetSymbolAddress((void**)&pkvT, g_kvT);
    cudaGetSymbolAddress((void**)&pdn,  g_dn);
    cudaGetSymbolAddress((void**)&pao,  g_ao);

    cudaFuncSetAttribute(gemm_tc2,   cudaFuncAttributeMaxDynamicSharedMemorySize, DSMEM_BYTES);
    cudaFuncSetAttribute(gemm_f16_2t,cudaFuncAttributeMaxDynamicSharedMemorySize, DSMEM2_BYTES);
    cudaFuncSetAttribute(favor_tc,   cudaFuncAttributeMaxDynamicSharedMemorySize, DSMEM_BYTES);

    // Q,K projections: 3-term bf16 (exp-sensitive path)
    gemm_tc2<<<dim3((Hh*HDd)/128,  (Bb*Ss)/128), 256, DSMEM_BYTES>>>(x, wq, pq, DIMm, Hh*HDd);
    gemm_tc2<<<dim3((HKk*HDd)/128, (Bb*Ss)/128), 256, DSMEM_BYTES>>>(x, wk, pk, DIMm, HKk*HDd);
    // V projection: 2-term fp16 (linear path)
    gemm_f16_2t<<<dim3((HKk*HDd)/128, (Bb*Ss)/128), 256, DSMEM2_BYTES>>>(x, wv, pv, DIMm, HKk*HDd);

    // RMSNorm + RoPE + scale
    normrope_kernel<<<dim3(Bb*Ss, Hh),  128>>>(pq, fc, gq, pqx, psqq, Hh);
    normrope_kernel<<<dim3(Bb*Ss, HKk), 128>>>(pk, fc, gk, pkx, psqk, HKk);

    // FAVOR feature projections on tensor cores
    favor_tc<<<dim3(1, (Bb*Hh*Ss)/128),  256, DSMEM_BYTES>>>(pqx, proj, psqq, mask, pqphi, 0);
    favor_tc<<<dim3(1, (Bb*HKk*Ss)/128), 256, DSMEM_BYTES>>>(pkx, proj, psqk, mask, pkxp, 1);

    // key column max over S
    kmax1_kernel<<<dim3(Bb*HKk, 32), 128>>>();
    kmax2_kernel<<<Bb*HKk, 128>>>();

    // kv / ksum contraction (kv stored transposed)
    zero_kernel<<<(Bb*HKk*Mm*HDd + 255)/256, 256>>>();
    kv_kernel<<<dim3(Ss/128, Bb*HKk), 256>>>(mask);

    // denominators, then attention output on tensor cores
    dn_kernel<<<(Bb*Hh*Ss)/8, 256>>>();
    favor_tc<<<dim3(1, (Bb*Hh*Ss)/128), 256, DSMEM_BYTES>>>(pqphi, pkvT, pdn, mask, pao, 2);

    // output projection: 2-term fp16 (linear path)
    gemm_f16_2t<<<dim3(DIMm/128, (Bb*Ss)/128), 256, DSMEM2_BYTES>>>(pao, wo, out, Hh*HDd, DIMm);
}

// round 8
// speedup vs baseline: 2.2474x; 1.0539x over previous
#include <cuda_runtime.h>
#include <cuda_bf16.h>
#include <cuda_fp16.h>
#include <math.h>
#include <stdint.h>

#define Bb  2
#define Ss  4096
#define DIMm 2048
#define Hh  16
#define HKk 8
#define HDd 128
#define Mm  128

#define INV_SQRT_M 0.08838834764831845f   // 128^{-0.5}
#define SCALE_QD   0.2973017787506803f    // 128^{-0.25}
#define EPSF 1e-6f

// ---------------- scratch (device globals; no allocations allowed) ----------
__device__ float g_q   [Bb*Ss*Hh*HDd];     // [b,s,h,d]
__device__ float g_k   [Bb*Ss*HKk*HDd];
__device__ float g_v   [Bb*Ss*HKk*HDd];
__device__ float g_qx  [Bb*Hh*Ss*HDd];     // normed+roped+scaled, [b,h,s,d]
__device__ float g_kx  [Bb*HKk*Ss*HDd];
__device__ float g_sqq [Bb*Hh*Ss];
__device__ float g_sqk [Bb*HKk*Ss];
__device__ float g_qphi[Bb*Hh*Ss*Mm];      // [b,h,s,m]
__device__ float g_kxp [Bb*HKk*Ss*Mm];     // pre-exp key features
__device__ float g_kmaxp[Bb*HKk*32*Mm];
__device__ float g_kmax[Bb*HKk*Mm];
__device__ float g_kvT [Bb*HKk*HDd*Mm];    // TRANSPOSED kv: [d][m]
__device__ float g_ksum[Bb*HKk*Mm];
__device__ float g_dn  [Bb*Hh*Ss];         // denominators
__device__ float g_ao  [Bb*Ss*Hh*HDd];     // attention out, [b,s,h*d]

// pre-split operand arrays (packed x2 words, stored as unsigned)
#define XW (Bb*Ss*DIMm/2)
__device__ unsigned g_xbh [XW];            // x bf16 hi  (q,k GEMMs)
__device__ unsigned g_xbl [XW];            // x bf16 lo
__device__ unsigned g_xfh [XW];            // x fp16 hi  (v GEMM)
__device__ unsigned g_xfl [XW];            // x fp16 lo
__device__ unsigned g_wqh [Hh*HDd*DIMm/2];
__device__ unsigned g_wql [Hh*HDd*DIMm/2];
__device__ unsigned g_wkh [HKk*HDd*DIMm/2];
__device__ unsigned g_wkl [HKk*HDd*DIMm/2];
__device__ unsigned g_wvh [HKk*HDd*DIMm/2];   // fp16 (2-term: hi only used for B)
__device__ unsigned g_woh [DIMm*Hh*HDd/2];    // fp16
__device__ unsigned g_aoh [Bb*Ss*Hh*HDd/2];   // fp16
__device__ unsigned g_aol [Bb*Ss*Hh*HDd/2];   // fp16

// ---------------------------- split helpers ---------------------------------
__device__ __forceinline__ void bfsplit2(float x0, float x1, unsigned& hi, unsigned& lo) {
    __nv_bfloat162 h2 = __floats2bfloat162_rn(x0, x1);
    float2 hf = __bfloat1622float2(h2);
    __nv_bfloat162 l2 = __floats2bfloat162_rn(x0 - hf.x, x1 - hf.y);
    hi = *reinterpret_cast<unsigned*>(&h2);
    lo = *reinterpret_cast<unsigned*>(&l2);
}
__device__ __forceinline__ void hsplit2(float x0, float x1, unsigned& hi, unsigned& lo) {
    __half2 h2 = __floats2half2_rn(x0, x1);
    float2 hf = __half22float2(h2);
    __half2 l2 = __floats2half2_rn(x0 - hf.x, x1 - hf.y);
    hi = *reinterpret_cast<unsigned*>(&h2);
    lo = *reinterpret_cast<unsigned*>(&l2);
}

__device__ __forceinline__ void mma_bf16(float* d, const unsigned* a, const unsigned* b) {
    asm volatile(
        "mma.sync.aligned.m16n8k16.row.col.f32.bf16.bf16.f32 "
        "{%0,%1,%2,%3}, {%4,%5,%6,%7}, {%8,%9}, {%0,%1,%2,%3};\n"
        : "+f"(d[0]), "+f"(d[1]), "+f"(d[2]), "+f"(d[3])
        : "r"(a[0]), "r"(a[1]), "r"(a[2]), "r"(a[3]),
          "r"(b[0]), "r"(b[1]));
}
__device__ __forceinline__ void mma_f16(float* d, const unsigned* a, const unsigned* b) {
    asm volatile(
        "mma.sync.aligned.m16n8k16.row.col.f32.f16.f16.f32 "
        "{%0,%1,%2,%3}, {%4,%5,%6,%7}, {%8,%9}, {%0,%1,%2,%3};\n"
        : "+f"(d[0]), "+f"(d[1]), "+f"(d[2]), "+f"(d[3])
        : "r"(a[0]), "r"(a[1]), "r"(a[2]), "r"(a[3]),
          "r"(b[0]), "r"(b[1]));
}

// smem layout (dynamic, unsigned units): per array 2 bufs x 16 kpairs x LDT
#define LDT 136
#define SOFF_AH(b) ((unsigned)(b)*2176u)
#define SOFF_AL(b) (4352u  + (unsigned)(b)*2176u)
#define SOFF_BH(b) (8704u  + (unsigned)(b)*2176u)
#define SOFF_BL(b) (13056u + (unsigned)(b)*2176u)
#define DSMEM_BYTES (17408*4)   // 69632 (4 arrays)
#define DSMEM2_BYTES (13056*4)  // 52224 (3 arrays)

// ============ fp32-input core (used by favor_tc only) =======================
#define CORE_LOAD_REGS(k0)                                                     \
    {                                                                          \
        const float* ap = Ag + (size_t)ldRow * K + (k0) + ldCol;               \
        const float* bp = Wg + (size_t)ldRow * K + (k0) + ldCol;               \
        float4 t;                                                              \
        t = *(const float4*)(ap);      ar[0]=t.x; ar[1]=t.y; ar[2]=t.z; ar[3]=t.w;   \
        t = *(const float4*)(ap + 4);  ar[4]=t.x; ar[5]=t.y; ar[6]=t.z; ar[7]=t.w;   \
        t = *(const float4*)(ap + 8);  ar[8]=t.x; ar[9]=t.y; ar[10]=t.z; ar[11]=t.w; \
        t = *(const float4*)(ap + 12); ar[12]=t.x; ar[13]=t.y; ar[14]=t.z; ar[15]=t.w;\
        t = *(const float4*)(bp);      br[0]=t.x; br[1]=t.y; br[2]=t.z; br[3]=t.w;   \
        t = *(const float4*)(bp + 4);  br[4]=t.x; br[5]=t.y; br[6]=t.z; br[7]=t.w;   \
        t = *(const float4*)(bp + 8);  br[8]=t.x; br[9]=t.y; br[10]=t.z; br[11]=t.w; \
        t = *(const float4*)(bp + 12); br[12]=t.x; br[13]=t.y; br[14]=t.z; br[15]=t.w;\
    }

#define CORE_STORE_SMEM(bufn)                                                  \
    {                                                                          \
        _Pragma("unroll")                                                      \
        for (int e = 0; e < 8; e++) {                                          \
            unsigned hi, lo;                                                   \
            bfsplit2(ar[2*e], ar[2*e+1], hi, lo);                              \
            sm[SOFF_AH(bufn) + (kpBase+e)*LDT + ldRow] = hi;                   \
            sm[SOFF_AL(bufn) + (kpBase+e)*LDT + ldRow] = lo;                   \
            bfsplit2(br[2*e], br[2*e+1], hi, lo);                              \
            sm[SOFF_BH(bufn) + (kpBase+e)*LDT + ldRow] = hi;                   \
            sm[SOFF_BL(bufn) + (kpBase+e)*LDT + ldRow] = lo;                   \
        }                                                                      \
    }

#define CORE_COMPUTE_GEN(bufn, MMAOP, DO_BL)                                   \
    {                                                                          \
        _Pragma("unroll")                                                      \
        for (int h = 0; h < 2; h++) {                                          \
            int kc = h*8 + (lane & 3);                                         \
            int mo = lane >> 2;                                                \
            unsigned afh[4][4], afl[4][4], bfh[4][2], bfl[4][2];               \
            _Pragma("unroll")                                                  \
            for (int mi = 0; mi < 4; mi++) {                                   \
                int m = warpM + mi * 16 + mo;                                  \
                afh[mi][0] = sm[SOFF_AH(bufn) + kc*LDT + m];                   \
                afh[mi][1] = sm[SOFF_AH(bufn) + kc*LDT + m + 8];               \
                afh[mi][2] = sm[SOFF_AH(bufn) + (kc+4)*LDT + m];               \
                afh[mi][3] = sm[SOFF_AH(bufn) + (kc+4)*LDT + m + 8];           \
                afl[mi][0] = sm[SOFF_AL(bufn) + kc*LDT + m];                   \
                afl[mi][1] = sm[SOFF_AL(bufn) + kc*LDT + m + 8];               \
                afl[mi][2] = sm[SOFF_AL(bufn) + (kc+4)*LDT + m];               \
                afl[mi][3] = sm[SOFF_AL(bufn) + (kc+4)*LDT + m + 8];           \
            }                                                                  \
            _Pragma("unroll")                                                  \
            for (int ni = 0; ni < 4; ni++) {                                   \
                int n = warpN + ni * 8 + mo;                                   \
                bfh[ni][0] = sm[SOFF_BH(bufn) + kc*LDT + n];                   \
                bfh[ni][1] = sm[SOFF_BH(bufn) + (kc+4)*LDT + n];               \
                if (DO_BL) {                                                   \
                    bfl[ni][0] = sm[SOFF_BL(bufn) + kc*LDT + n];               \
                    bfl[ni][1] = sm[SOFF_BL(bufn) + (kc+4)*LDT + n];           \
                }                                                              \
            }                                                                  \
            _Pragma("unroll")                                                  \
            for (int mi = 0; mi < 4; mi++)                                     \
                _Pragma("unroll")                                              \
                for (int ni = 0; ni < 4; ni++) {                               \
                    MMAOP(acc[mi][ni], afh[mi], bfh[ni]);                      \
                    MMAOP(acc[mi][ni], afl[mi], bfh[ni]);                      \
                    if (DO_BL) MMAOP(acc[mi][ni], afh[mi], bfl[ni]);           \
                }                                                              \
        }                                                                      \
    }

#define CORE_PROLOG_VARS                                                       \
    int tid  = threadIdx.x;                                                    \
    int lane = tid & 31;                                                       \
    int warp = tid >> 5;                                                       \
    int warpM = (warp >> 2) * 64;                                              \
    int warpN = (warp & 3) * 32;                                               \
    int ldRow  = tid >> 1;                                                     \
    int kpBase = (tid & 1) * 8;                                                \
    float acc[4][4][4];                                                        \
    _Pragma("unroll")                                                          \
    for (int mi = 0; mi < 4; mi++)                                             \
        _Pragma("unroll")                                                      \
        for (int ni = 0; ni < 4; ni++)                                         \
            _Pragma("unroll")                                                  \
            for (int e = 0; e < 4; e++) acc[mi][ni][e] = 0.f;

// ============ pre-split cores (GEMM kernels) ================================
// Load hi/lo packed words straight from global: row ldRow, 8 words from kpBase.
#define PRE_LOAD4(dst, base, woff)                                             \
    {                                                                          \
        uint4 u;                                                               \
        u = *(const uint4*)((base) + (woff));     dst[0]=u.x; dst[1]=u.y; dst[2]=u.z; dst[3]=u.w; \
        u = *(const uint4*)((base) + (woff) + 4); dst[4]=u.x; dst[5]=u.y; dst[6]=u.z; dst[7]=u.w; \
    }

#define PRE3_LOAD(t0)                                                          \
    {                                                                          \
        size_t woff = (size_t)ldRow * KW + ((size_t)(t0) << 4) + kpBase;       \
        size_t woffB = (size_t)ldRow * KW + ((size_t)(t0) << 4) + kpBase;      \
        PRE_LOAD4(arh, Agh, woff);                                             \
        PRE_LOAD4(arl, Agl, woff);                                             \
        PRE_LOAD4(brh, Bgh, woffB);                                            \
        PRE_LOAD4(brl, Bgl, woffB);                                            \
    }

#define PRE3_STORE(bufn)                                                       \
    {                                                                          \
        _Pragma("unroll")                                                      \
        for (int e = 0; e < 8; e++) {                                          \
            sm[SOFF_AH(bufn) + (kpBase+e)*LDT + ldRow] = arh[e];               \
            sm[SOFF_AL(bufn) + (kpBase+e)*LDT + ldRow] = arl[e];               \
            sm[SOFF_BH(bufn) + (kpBase+e)*LDT + ldRow] = brh[e];               \
            sm[SOFF_BL(bufn) + (kpBase+e)*LDT + ldRow] = brl[e];               \
        }                                                                      \
    }

#define PRE2_LOAD(t0)                                                          \
    {                                                                          \
        size_t woff = (size_t)ldRow * KW + ((size_t)(t0) << 4) + kpBase;       \
        PRE_LOAD4(arh, Agh, woff);                                             \
        PRE_LOAD4(arl, Agl, woff);                                             \
        PRE_LOAD4(brh, Bgh, woff);                                             \
    }

#define PRE2_STORE(bufn)                                                       \
    {                                                                          \
        _Pragma("unroll")                                                      \
        for (int e = 0; e < 8; e++) {                                          \
            sm[SOFF_AH(bufn) + (kpBase+e)*LDT + ldRow] = arh[e];               \
            sm[SOFF_AL(bufn) + (kpBase+e)*LDT + ldRow] = arl[e];               \
            sm[SOFF_BH(bufn) + (kpBase+e)*LDT + ldRow] = brh[e];               \
        }                                                                      \
    }

#define GEMM_EPILOG                                                            \
    _Pragma("unroll")                                                          \
    for (int mi = 0; mi < 4; mi++) {                                           \
        int r = rowBase + warpM + mi * 16 + (lane >> 2);                       \
        _Pragma("unroll")                                                      \
        for (int ni = 0; ni < 4; ni++) {                                       \
            int c = colBase + warpN + ni * 8 + (lane & 3) * 2;                 \
            *(float2*)(C + (size_t)r * N + c) =                                \
                make_float2(acc[mi][ni][0], acc[mi][ni][1]);                   \
            *(float2*)(C + (size_t)(r + 8) * N + c) =                          \
                make_float2(acc[mi][ni][2], acc[mi][ni][3]);                   \
        }                                                                      \
    }

// ---------------- fp32 -> packed hi/lo split kernels ------------------------
__global__ __launch_bounds__(256) void split_bf16_kernel(
    const float* __restrict__ src, unsigned* __restrict__ hi,
    unsigned* __restrict__ lo, int n4)
{
    int i = blockIdx.x * blockDim.x + threadIdx.x;
    if (i >= n4) return;
    float4 v = ((const float4*)src)[i];
    unsigned h0, l0, h1, l1;
    bfsplit2(v.x, v.y, h0, l0);
    bfsplit2(v.z, v.w, h1, l1);
    ((uint2*)hi)[i] = make_uint2(h0, h1);
    ((uint2*)lo)[i] = make_uint2(l0, l1);
}
__global__ __launch_bounds__(256) void split_f16_kernel(
    const float* __restrict__ src, unsigned* __restrict__ hi,
    unsigned* __restrict__ lo, int n4)
{
    int i = blockIdx.x * blockDim.x + threadIdx.x;
    if (i >= n4) return;
    float4 v = ((const float4*)src)[i];
    unsigned h0, l0, h1, l1;
    hsplit2(v.x, v.y, h0, l0);
    hsplit2(v.z, v.w, h1, l1);
    ((uint2*)hi)[i] = make_uint2(h0, h1);
    ((uint2*)lo)[i] = make_uint2(l0, l1);
}
// hi-only fp16 split (for wv/wo B operands)
__global__ __launch_bounds__(256) void split_f16h_kernel(
    const float* __restrict__ src, unsigned* __restrict__ hi, int n4)
{
    int i = blockIdx.x * blockDim.x + threadIdx.x;
    if (i >= n4) return;
    float4 v = ((const float4*)src)[i];
    __half2 a = __floats2half2_rn(v.x, v.y);
    __half2 b = __floats2half2_rn(v.z, v.w);
    ((uint2*)hi)[i] = make_uint2(*reinterpret_cast<unsigned*>(&a),
                                 *reinterpret_cast<unsigned*>(&b));
}

// ------- 3-term bf16 GEMM, pre-split operands -------------------------------
__global__ __launch_bounds__(256) void gemm_bf16_3t(
    const unsigned* __restrict__ Ah, const unsigned* __restrict__ Al,
    const unsigned* __restrict__ Bh, const unsigned* __restrict__ Bl,
    float* __restrict__ C, int K, int N)
{
    extern __shared__ unsigned sm[];
    int rowBase = blockIdx.y * 128;
    int colBase = blockIdx.x * 128;
    const int KW = K >> 1;
    const unsigned* Agh = Ah + (size_t)rowBase * KW;
    const unsigned* Agl = Al + (size_t)rowBase * KW;
    const unsigned* Bgh = Bh + (size_t)colBase * KW;
    const unsigned* Bgl = Bl + (size_t)colBase * KW;
    CORE_PROLOG_VARS;
    unsigned arh[8], arl[8], brh[8], brl[8];
    int kTiles = K >> 5;

    PRE3_LOAD(0);
    PRE3_STORE(0);
    __syncthreads();
    for (int t = 0; t < kTiles; t++) {
        int buf = t & 1;
        bool has = (t + 1 < kTiles);
        if (has) PRE3_LOAD(t + 1);
        CORE_COMPUTE_GEN(buf, mma_bf16, 1);
        if (has) PRE3_STORE(buf ^ 1);
        __syncthreads();
    }
    GEMM_EPILOG;
}

// ------- 2-term fp16 GEMM (A hi/lo, B hi), pre-split operands ---------------
__global__ __launch_bounds__(256) void gemm_f16_2t(
    const unsigned* __restrict__ Ah, const unsigned* __restrict__ Al,
    const unsigned* __restrict__ Bh,
    float* __restrict__ C, int K, int N)
{
    extern __shared__ unsigned sm[];
    int rowBase = blockIdx.y * 128;
    int colBase = blockIdx.x * 128;
    const int KW = K >> 1;
    const unsigned* Agh = Ah + (size_t)rowBase * KW;
    const unsigned* Agl = Al + (size_t)rowBase * KW;
    const unsigned* Bgh = Bh + (size_t)colBase * KW;
    CORE_PROLOG_VARS;
    unsigned arh[8], arl[8], brh[8];
    int kTiles = K >> 5;

    PRE2_LOAD(0);
    PRE2_STORE(0);
    __syncthreads();
    for (int t = 0; t < kTiles; t++) {
        int buf = t & 1;
        bool has = (t + 1 < kTiles);
        if (has) PRE2_LOAD(t + 1);
        CORE_COMPUTE_GEN(buf, mma_f16, 0);
        if (has) PRE2_STORE(buf ^ 1);
        __syncthreads();
    }
    GEMM_EPILOG;
}

// ---- FAVOR tensor-core kernel: C = A[M,128] @ B[128,128]^T + epilogue ------
// mode 0: featQ (row-max + exp); mode 1: featK (subtract sq); mode 2: out
__global__ __launch_bounds__(256) void favor_tc(
    const float* __restrict__ A, const float* __restrict__ Bglob,
    const float* __restrict__ sq, const int* __restrict__ mask,
    float* __restrict__ out, int mode)
{
    extern __shared__ unsigned sm[];
    __shared__ float red[128][4];
    int rowBase = blockIdx.y * 128;
    const int K = 128, N = 128;
    const float* Wg;
    if (mode == 2) {
        int bh = blockIdx.y >> 5;
        int b = bh >> 4, h = bh & 15;
        int bhk = b * 8 + (h >> 1);
        Wg = Bglob + (size_t)bhk * 128 * 128;
    } else {
        Wg = Bglob;
    }
    const float* Ag = A + (size_t)rowBase * K;
    CORE_PROLOG_VARS;
    int ldCol = (tid & 1) * 16;
    float ar[16], br[16];
    CORE_LOAD_REGS(0);
    CORE_STORE_SMEM(0);
    __syncthreads();
    for (int t = 0; t < 4; t++) {
        int buf = t & 1;
        bool has = (t + 1 < 4);
        if (has) CORE_LOAD_REGS((t + 1) << 5);
        CORE_COMPUTE_GEN(buf, mma_bf16, 1);
        if (has) CORE_STORE_SMEM(buf ^ 1);
        __syncthreads();
    }

    int mo = lane >> 2;
    if (mode == 0) {
        #pragma unroll
        for (int mi = 0; mi < 4; mi++) {
            float m0 = -1e30f, m1 = -1e30f;
            #pragma unroll
            for (int ni = 0; ni < 4; ni++) {
                m0 = fmaxf(m0, fmaxf(acc[mi][ni][0], acc[mi][ni][1]));
                m1 = fmaxf(m1, fmaxf(acc[mi][ni][2], acc[mi][ni][3]));
            }
            m0 = fmaxf(m0, __shfl_xor_sync(0xffffffffu, m0, 1));
            m0 = fmaxf(m0, __shfl_xor_sync(0xffffffffu, m0, 2));
            m1 = fmaxf(m1, __shfl_xor_sync(0xffffffffu, m1, 1));
            m1 = fmaxf(m1, __shfl_xor_sync(0xffffffffu, m1, 2));
            if ((lane & 3) == 0) {
                red[warpM + mi*16 + mo][warp & 3] = m0;
                red[warpM + mi*16 + mo + 8][warp & 3] = m1;
            }
        }
        __syncthreads();
        #pragma unroll
        for (int mi = 0; mi < 4; mi++) {
            int rl = warpM + mi*16 + mo;
            float rm0 = fmaxf(fmaxf(red[rl][0], red[rl][1]),
                              fmaxf(red[rl][2], red[rl][3]));
            float rm1 = fmaxf(fmaxf(red[rl+8][0], red[rl+8][1]),
                              fmaxf(red[rl+8][2], red[rl+8][3]));
            #pragma unroll
            for (int ni = 0; ni < 4; ni++) {
                int c = warpN + ni*8 + (lane & 3)*2;
                *(float2*)(out + (size_t)(rowBase + rl) * N + c) =
                    make_float2(expf(acc[mi][ni][0]-rm0)*INV_SQRT_M + EPSF,
                                expf(acc[mi][ni][1]-rm0)*INV_SQRT_M + EPSF);
                *(float2*)(out + (size_t)(rowBase + rl + 8) * N + c) =
                    make_float2(expf(acc[mi][ni][2]-rm1)*INV_SQRT_M + EPSF,
                                expf(acc[mi][ni][3]-rm1)*INV_SQRT_M + EPSF);
            }
        }
    } else if (mode == 1) {
        #pragma unroll
        for (int mi = 0; mi < 4; mi++) {
            int r0 = rowBase + warpM + mi*16 + mo;
            float s0 = sq[r0], s1 = sq[r0 + 8];
            #pragma unroll
            for (int ni = 0; ni < 4; ni++) {
                int c = warpN + ni*8 + (lane & 3)*2;
                *(float2*)(out + (size_t)r0 * N + c) =
                    make_float2(acc[mi][ni][0]-s0, acc[mi][ni][1]-s0);
                *(float2*)(out + (size_t)(r0 + 8) * N + c) =
                    make_float2(acc[mi][ni][2]-s1, acc[mi][ni][3]-s1);
            }
        }
    } else {
        #pragma unroll
        for (int mi = 0; mi < 4; mi++) {
            int rg = rowBase + warpM + mi*16 + mo;
            #pragma unroll
            for (int half = 0; half < 2; half++) {
                int r = rg + half * 8;
                int s = r & 4095;
                int bh = r >> 12;
                int b = bh >> 4, h = bh & 15;
                float vm = (mask[b * Ss + s] > 0) ? 1.f : 0.f;
                float scale = vm / (sq[r] + EPSF);   // sq carries g_dn here
                float* op = out + ((size_t)(b * Ss + s) * (Hh*HDd)) + h * HDd;
                #pragma unroll
                for (int ni = 0; ni < 4; ni++) {
                    int c = warpN + ni*8 + (lane & 3)*2;
                    *(float2*)(op + c) =
                        make_float2(acc[mi][ni][2*half]*scale,
                                    acc[mi][ni][2*half+1]*scale);
                }
            }
        }
    }
}

// ------------- RMSNorm + RoPE + d^{-1/4} scale, transpose to [b,h,s,d] ------
__global__ __launch_bounds__(128) void normrope_kernel(
    const float* __restrict__ qkv, const float* __restrict__ fc,
    const float* __restrict__ g, float* __restrict__ xout,
    float* __restrict__ sqout, int nh)
{
    int bs = blockIdx.x;
    int h  = blockIdx.y;
    int d  = threadIdx.x;
    float val = qkv[(size_t)bs * nh * HDd + h * HDd + d];

    float ss = val * val;
    #pragma unroll
    for (int o = 16; o > 0; o >>= 1) ss += __shfl_xor_sync(0xffffffffu, ss, o);
    __shared__ float wsum[4];
    int wid = d >> 5, lane = d & 31;
    if (lane == 0) wsum[wid] = ss;
    __syncthreads();
    float tot = wsum[0] + wsum[1] + wsum[2] + wsum[3];
    float inv = rsqrtf(tot * (1.0f / HDd) + 1e-5f);
    float xn = val * inv * g[d];

    __shared__ float row[HDd];
    row[d] = xn;
    __syncthreads();
    int i = d >> 1;
    float c  = fc[((size_t)bs * (HDd/2) + i) * 2 + 0];
    float sn = fc[((size_t)bs * (HDd/2) + i) * 2 + 1];
    float a  = row[2*i], b2 = row[2*i + 1];
    float r  = (d & 1) ? (a * sn + b2 * c) : (a * c - b2 * sn);
    r *= SCALE_QD;

    float s2 = r * r;
    #pragma unroll
    for (int o = 16; o > 0; o >>= 1) s2 += __shfl_xor_sync(0xffffffffu, s2, o);
    __syncthreads();
    if (lane == 0) wsum[wid] = s2;
    __syncthreads();
    float tot2 = wsum[0] + wsum[1] + wsum[2] + wsum[3];

    int b = bs / Ss, s = bs % Ss;
    xout[(((size_t)b * nh + h) * Ss + s) * HDd + d] = r;
    if (d == 0) sqout[((size_t)b * nh + h) * Ss + s] = 0.5f * tot2;
}

// ---------------- key column-max over S (two-stage) -------------------------
__global__ void kmax1_kernel() {
    int bh = blockIdx.x, ch = blockIdx.y, m = threadIdx.x;
    const float* p = g_kxp + ((size_t)bh * Ss + ch * 128) * Mm + m;
    float mx = -1e30f;
    #pragma unroll 4
    for (int s = 0; s < 128; s++) mx = fmaxf(mx, p[(size_t)s * Mm]);
    g_kmaxp[((size_t)bh * 32 + ch) * Mm + m] = mx;
}
__global__ void kmax2_kernel() {
    int bh = blockIdx.x, m = threadIdx.x;
    float mx = -1e30f;
    for (int c = 0; c < 32; c++) mx = fmaxf(mx, g_kmaxp[((size_t)bh*32 + c)*Mm + m]);
    g_kmax[bh * Mm + m] = mx;
}

__global__ void zero_kernel() {
    int i = blockIdx.x * blockDim.x + threadIdx.x;
    if (i < Bb*HKk*Mm*HDd) g_kvT[i] = 0.f;
    if (i < Bb*HKk*Mm)     g_ksum[i] = 0.f;
}

// -- kvT[d,m] += sum_s phi_k[s,m]*v[s,d] ; ksum[m] += sum_s phi_k[s,m] -------
__global__ __launch_bounds__(256) void kv_kernel(const int* __restrict__ mask)
{
    __shared__ float kps[16][128];
    __shared__ float vs [16][128];
    __shared__ float kmx[128];
    __shared__ float vmask[128];
    int bh = blockIdx.y;
    int b = bh / HKk, hk = bh % HKk;
    int s0 = blockIdx.x * 128;
    int tid = threadIdx.x;
    int tr = tid >> 4, tc = tid & 15;
    if (tid < 128) {
        kmx[tid] = g_kmax[bh * Mm + tid];
        vmask[tid] = (mask[b * Ss + s0 + tid] > 0) ? 1.f : 0.f;
    }
    __syncthreads();

    const float* KX = g_kxp + ((size_t)bh * Ss + s0) * Mm;
    const float* V  = g_v + ((size_t)(b * Ss + s0)) * (HKk*HDd) + hk * HDd;
    float acc[8][8];
    #pragma unroll
    for (int i=0;i<8;i++)
        #pragma unroll
        for (int j=0;j<8;j++) acc[i][j]=0.f;
    float ksacc = 0.f;

    for (int sc = 0; sc < 128; sc += 16) {
        #pragma unroll
        for (int it = 0; it < 2; it++) {
            int idx = tid + it * 256;
            int r = idx >> 5;
            int c4 = (idx & 31) << 2;
            float vm = vmask[sc + r];
            float4 x4 = *(const float4*)(KX + (size_t)(sc + r) * Mm + c4);
            kps[r][c4+0] = (expf(x4.x - kmx[c4+0]) * INV_SQRT_M + EPSF) * vm;
            kps[r][c4+1] = (expf(x4.y - kmx[c4+1]) * INV_SQRT_M + EPSF) * vm;
            kps[r][c4+2] = (expf(x4.z - kmx[c4+2]) * INV_SQRT_M + EPSF) * vm;
            kps[r][c4+3] = (expf(x4.w - kmx[c4+3]) * INV_SQRT_M + EPSF) * vm;
            float4 v4 = *(const float4*)(V + (size_t)(sc + r) * (HKk*HDd) + c4);
            vs[r][c4+0]=v4.x; vs[r][c4+1]=v4.y; vs[r][c4+2]=v4.z; vs[r][c4+3]=v4.w;
        }
        __syncthreads();
        #pragma unroll
        for (int ssi = 0; ssi < 16; ssi++) {
            float ra[8], rb[8];
            #pragma unroll
            for (int i=0;i<8;i++) ra[i]=kps[ssi][tr*8+i];
            #pragma unroll
            for (int j=0;j<8;j++) rb[j]=vs[ssi][tc*8+j];
            #pragma unroll
            for (int i=0;i<8;i++)
                #pragma unroll
                for (int j=0;j<8;j++) acc[i][j] += ra[i]*rb[j];
        }
        if (tid < 128) {
            #pragma unroll
            for (int ssi = 0; ssi < 16; ssi++) ksacc += kps[ssi][tid];
        }
        __syncthreads();
    }
    float* KV = g_kvT + (size_t)bh * Mm * HDd;
    #pragma unroll
    for (int i = 0; i < 8; i++)
        #pragma unroll
        for (int j = 0; j < 8; j++)
            atomicAdd(&KV[(size_t)(tc*8+j)*Mm + tr*8+i], acc[i][j]);
    if (tid < 128) atomicAdd(&g_ksum[bh * Mm + tid], ksacc);
}

// -------------- denominators: dn[row] = qphi[row,:]·ksum[bhk,:] -------------
__global__ __launch_bounds__(256) void dn_kernel() {
    int warp = threadIdx.x >> 5, lane = threadIdx.x & 31;
    int row = blockIdx.x * 8 + warp;
    int bh = row >> 12;
    int b = bh >> 4, h = bh & 15;
    int bhk = b * 8 + (h >> 1);
    float4 q = *(const float4*)(g_qphi + (size_t)row * Mm + lane * 4);
    float4 s = *(const float4*)(g_ksum + bhk * Mm + lane * 4);
    float v = q.x*s.x + q.y*s.y + q.z*s.z + q.w*s.w;
    #pragma unroll
    for (int o = 16; o > 0; o >>= 1) v += __shfl_xor_sync(0xffffffffu, v, o);
    if (lane == 0) g_dn[row] = v;
}

// ------------------------------- launch -------------------------------------
extern "C" void kernel_launch(void* const* d_in, const int* in_sizes, int n_in,
                              void* d_out, int out_size)
{
    const float* x    = (const float*)d_in[0];
    const int*   mask = (const int*)  d_in[1];
    const float* fc   = (const float*)d_in[2];
    const float* wq   = (const float*)d_in[3];
    const float* wk   = (const float*)d_in[4];
    const float* wv   = (const float*)d_in[5];
    const float* wo   = (const float*)d_in[6];
    const float* gq   = (const float*)d_in[7];
    const float* gk   = (const float*)d_in[8];
    const float* proj = (const float*)d_in[9];
    float* out = (float*)d_out;

    float *pq, *pk, *pv, *pqx, *pkx, *psqq, *psqk, *pqphi, *pkxp, *pkvT, *pdn, *pao;
    cudaGetSymbolAddress((void**)&pq,   g_q);
    cudaGetSymbolAddress((void**)&pk,   g_k);
    cudaGetSymbolAddress((void**)&pv,   g_v);
    cudaGetSymbolAddress((void**)&pqx,  g_qx);
    cudaGetSymbolAddress((void**)&pkx,  g_kx);
    cudaGetSymbolAddress((void**)&psqq, g_sqq);
    cudaGetSymbolAddress((void**)&psqk, g_sqk);
    cudaGetSymbolAddress((void**)&pqphi,g_qphi);
    cudaGetSymbolAddress((void**)&pkxp, g_kxp);
    cudaGetSymbolAddress((void**)&pkvT, g_kvT);
    cudaGetSymbolAddress((void**)&pdn,  g_dn);
    cudaGetSymbolAddress((void**)&pao,  g_ao);

    unsigned *xbh,*xbl,*xfh,*xfl,*wqh,*wql,*wkh,*wkl,*wvh,*woh,*aoh,*aol;
    cudaGetSymbolAddress((void**)&xbh, g_xbh); cudaGetSymbolAddress((void**)&xbl, g_xbl);
    cudaGetSymbolAddress((void**)&xfh, g_xfh); cudaGetSymbolAddress((void**)&xfl, g_xfl);
    cudaGetSymbolAddress((void**)&wqh, g_wqh); cudaGetSymbolAddress((void**)&wql, g_wql);
    cudaGetSymbolAddress((void**)&wkh, g_wkh); cudaGetSymbolAddress((void**)&wkl, g_wkl);
    cudaGetSymbolAddress((void**)&wvh, g_wvh);
    cudaGetSymbolAddress((void**)&woh, g_woh);
    cudaGetSymbolAddress((void**)&aoh, g_aoh); cudaGetSymbolAddress((void**)&aol, g_aol);

    cudaFuncSetAttribute(gemm_bf16_3t, cudaFuncAttributeMaxDynamicSharedMemorySize, DSMEM_BYTES);
    cudaFuncSetAttribute(gemm_f16_2t,  cudaFuncAttributeMaxDynamicSharedMemorySize, DSMEM2_BYTES);
    cudaFuncSetAttribute(favor_tc,     cudaFuncAttributeMaxDynamicSharedMemorySize, DSMEM_BYTES);

    // pre-split operands
    split_bf16_kernel<<<(Bb*Ss*DIMm/4 + 255)/256, 256>>>(x,  xbh, xbl, Bb*Ss*DIMm/4);
    split_f16_kernel <<<(Bb*Ss*DIMm/4 + 255)/256, 256>>>(x,  xfh, xfl, Bb*Ss*DIMm/4);
    split_bf16_kernel<<<(Hh*HDd*DIMm/4 + 255)/256, 256>>>(wq, wqh, wql, Hh*HDd*DIMm/4);
    split_bf16_kernel<<<(HKk*HDd*DIMm/4 + 255)/256, 256>>>(wk, wkh, wkl, HKk*HDd*DIMm/4);
    split_f16h_kernel<<<(HKk*HDd*DIMm/4 + 255)/256, 256>>>(wv, wvh, HKk*HDd*DIMm/4);
    split_f16h_kernel<<<(DIMm*Hh*HDd/4 + 255)/256, 256>>>(wo, woh, DIMm*Hh*HDd/4);

    // Q,K projections: 3-term bf16 (exp-sensitive path)
    gemm_bf16_3t<<<dim3((Hh*HDd)/128,  (Bb*Ss)/128), 256, DSMEM_BYTES>>>(xbh, xbl, wqh, wql, pq, DIMm, Hh*HDd);
    gemm_bf16_3t<<<dim3((HKk*HDd)/128, (Bb*Ss)/128), 256, DSMEM_BYTES>>>(xbh, xbl, wkh, wkl, pk, DIMm, HKk*HDd);
    // V projection: 2-term fp16 (linear path)
    gemm_f16_2t<<<dim3((HKk*HDd)/128, (Bb*Ss)/128), 256, DSMEM2_BYTES>>>(xfh, xfl, wvh, pv, DIMm, HKk*HDd);

    // RMSNorm + RoPE + scale
    normrope_kernel<<<dim3(Bb*Ss, Hh),  128>>>(pq, fc, gq, pqx, psqq, Hh);
    normrope_kernel<<<dim3(Bb*Ss, HKk), 128>>>(pk, fc, gk, pkx, psqk, HKk);

    // FAVOR feature projections on tensor cores
    favor_tc<<<dim3(1, (Bb*Hh*Ss)/128),  256, DSMEM_BYTES>>>(pqx, proj, psqq, mask, pqphi, 0);
    favor_tc<<<dim3(1, (Bb*HKk*Ss)/128), 256, DSMEM_BYTES>>>(pkx, proj, psqk, mask, pkxp, 1);

    // key column max over S
    kmax1_kernel<<<dim3(Bb*HKk, 32), 128>>>();
    kmax2_kernel<<<Bb*HKk, 128>>>();

    // kv / ksum contraction (kv stored transposed)
    zero_kernel<<<(Bb*HKk*Mm*HDd + 255)/256, 256>>>();
    kv_kernel<<<dim3(Ss/128, Bb*HKk), 256>>>(mask);

    // denominators, then attention output on tensor cores
    dn_kernel<<<(Bb*Hh*Ss)/8, 256>>>();
    favor_tc<<<dim3(1, (Bb*Hh*Ss)/128), 256, DSMEM_BYTES>>>(pqphi, pkvT, pdn, mask, pao, 2);

    // output projection: 2-term fp16, pre-split ao
    split_f16_kernel<<<(Bb*Ss*Hh*HDd/4 + 255)/256, 256>>>(pao, aoh, aol, Bb*Ss*Hh*HDd/4);
    gemm_f16_2t<<<dim3(DIMm/128, (Bb*Ss)/128), 256, DSMEM2_BYTES>>>(aoh, aol, woh, out, Hh*HDd, DIMm);
}

// round 9
// speedup vs baseline: 2.4233x; 1.0783x over previous
#include <cuda_runtime.h>
#include <cuda_bf16.h>
#include <cuda_fp16.h>
#include <math.h>
#include <stdint.h>

#define Bb  2
#define Ss  4096
#define DIMm 2048
#define Hh  16
#define HKk 8
#define HDd 128
#define Mm  128

#define INV_SQRT_M 0.08838834764831845f   // 128^{-0.5}
#define SCALE_QD   0.2973017787506803f    // 128^{-0.25}
#define EPSF 1e-6f

// ---------------- scratch (device globals; no allocations allowed) ----------
__device__ float g_v   [Bb*Ss*HKk*HDd];
__device__ float g_qx  [Bb*Hh*Ss*HDd];     // normed+roped+scaled, [b,h,s,d]
__device__ float g_kx  [Bb*HKk*Ss*HDd];
__device__ float g_sqq [Bb*Hh*Ss];
__device__ float g_sqk [Bb*HKk*Ss];
__device__ float g_qphi[Bb*Hh*Ss*Mm];      // [b,h,s,m]
__device__ float g_kxp [Bb*HKk*Ss*Mm];     // pre-exp key features
__device__ float g_kmaxp[Bb*HKk*32*Mm];
__device__ float g_kmax[Bb*HKk*Mm];
__device__ float g_kvT [Bb*HKk*HDd*Mm];    // TRANSPOSED kv: [d][m]
__device__ float g_ksum[Bb*HKk*Mm];
__device__ float g_dn  [Bb*Hh*Ss];         // denominators

// pre-split operand arrays (packed x2 words)
#define XW (Bb*Ss*DIMm/2)
__device__ unsigned g_xbh [XW];            // x bf16 hi  (q,k GEMMs)
__device__ unsigned g_xbl [XW];            // x bf16 lo
__device__ unsigned g_xfh [XW];            // x fp16 hi  (v GEMM)
__device__ unsigned g_xfl [XW];            // x fp16 lo
__device__ unsigned g_wqh [Hh*HDd*DIMm/2];
__device__ unsigned g_wql [Hh*HDd*DIMm/2];
__device__ unsigned g_wkh [HKk*HDd*DIMm/2];
__device__ unsigned g_wkl [HKk*HDd*DIMm/2];
__device__ unsigned g_wvh [HKk*HDd*DIMm/2];
__device__ unsigned g_woh [DIMm*Hh*HDd/2];
__device__ unsigned g_aoh [Bb*Ss*Hh*HDd/2];   // attention out, fp16 hi
__device__ unsigned g_aol [Bb*Ss*Hh*HDd/2];   // attention out, fp16 lo

// ---------------------------- split helpers ---------------------------------
__device__ __forceinline__ void bfsplit2(float x0, float x1, unsigned& hi, unsigned& lo) {
    __nv_bfloat162 h2 = __floats2bfloat162_rn(x0, x1);
    float2 hf = __bfloat1622float2(h2);
    __nv_bfloat162 l2 = __floats2bfloat162_rn(x0 - hf.x, x1 - hf.y);
    hi = *reinterpret_cast<unsigned*>(&h2);
    lo = *reinterpret_cast<unsigned*>(&l2);
}
__device__ __forceinline__ void hsplit2(float x0, float x1, unsigned& hi, unsigned& lo) {
    __half2 h2 = __floats2half2_rn(x0, x1);
    float2 hf = __half22float2(h2);
    __half2 l2 = __floats2half2_rn(x0 - hf.x, x1 - hf.y);
    hi = *reinterpret_cast<unsigned*>(&h2);
    lo = *reinterpret_cast<unsigned*>(&l2);
}

__device__ __forceinline__ void mma_bf16(float* d, const unsigned* a, const unsigned* b) {
    asm volatile(
        "mma.sync.aligned.m16n8k16.row.col.f32.bf16.bf16.f32 "
        "{%0,%1,%2,%3}, {%4,%5,%6,%7}, {%8,%9}, {%0,%1,%2,%3};\n"
        : "+f"(d[0]), "+f"(d[1]), "+f"(d[2]), "+f"(d[3])
        : "r"(a[0]), "r"(a[1]), "r"(a[2]), "r"(a[3]),
          "r"(b[0]), "r"(b[1]));
}
__device__ __forceinline__ void mma_f16(float* d, const unsigned* a, const unsigned* b) {
    asm volatile(
        "mma.sync.aligned.m16n8k16.row.col.f32.f16.f16.f32 "
        "{%0,%1,%2,%3}, {%4,%5,%6,%7}, {%8,%9}, {%0,%1,%2,%3};\n"
        : "+f"(d[0]), "+f"(d[1]), "+f"(d[2]), "+f"(d[3])
        : "r"(a[0]), "r"(a[1]), "r"(a[2]), "r"(a[3]),
          "r"(b[0]), "r"(b[1]));
}

// smem layout (dynamic, unsigned units): per array 2 bufs x 16 kpairs x LDT
#define LDT 136
#define SOFF_AH(b) ((unsigned)(b)*2176u)
#define SOFF_AL(b) (4352u  + (unsigned)(b)*2176u)
#define SOFF_BH(b) (8704u  + (unsigned)(b)*2176u)
#define SOFF_BL(b) (13056u + (unsigned)(b)*2176u)
#define DSMEM_BYTES (17408*4)   // 69632 (4 arrays)
#define DSMEM2_BYTES (13056*4)  // 52224 (3 arrays)

// ============ fp32-input core (used by favor_tc only) =======================
#define CORE_LOAD_REGS(k0)                                                     \
    {                                                                          \
        const float* ap = Ag + (size_t)ldRow * K + (k0) + ldCol;               \
        const float* bp = Wg + (size_t)ldRow * K + (k0) + ldCol;               \
        float4 t;                                                              \
        t = *(const float4*)(ap);      ar[0]=t.x; ar[1]=t.y; ar[2]=t.z; ar[3]=t.w;   \
        t = *(const float4*)(ap + 4);  ar[4]=t.x; ar[5]=t.y; ar[6]=t.z; ar[7]=t.w;   \
        t = *(const float4*)(ap + 8);  ar[8]=t.x; ar[9]=t.y; ar[10]=t.z; ar[11]=t.w; \
        t = *(const float4*)(ap + 12); ar[12]=t.x; ar[13]=t.y; ar[14]=t.z; ar[15]=t.w;\
        t = *(const float4*)(bp);      br[0]=t.x; br[1]=t.y; br[2]=t.z; br[3]=t.w;   \
        t = *(const float4*)(bp + 4);  br[4]=t.x; br[5]=t.y; br[6]=t.z; br[7]=t.w;   \
        t = *(const float4*)(bp + 8);  br[8]=t.x; br[9]=t.y; br[10]=t.z; br[11]=t.w; \
        t = *(const float4*)(bp + 12); br[12]=t.x; br[13]=t.y; br[14]=t.z; br[15]=t.w;\
    }

#define CORE_STORE_SMEM(bufn)                                                  \
    {                                                                          \
        _Pragma("unroll")                                                      \
        for (int e = 0; e < 8; e++) {                                          \
            unsigned hi, lo;                                                   \
            bfsplit2(ar[2*e], ar[2*e+1], hi, lo);                              \
            sm[SOFF_AH(bufn) + (kpBase+e)*LDT + ldRow] = hi;                   \
            sm[SOFF_AL(bufn) + (kpBase+e)*LDT + ldRow] = lo;                   \
            bfsplit2(br[2*e], br[2*e+1], hi, lo);                              \
            sm[SOFF_BH(bufn) + (kpBase+e)*LDT + ldRow] = hi;                   \
            sm[SOFF_BL(bufn) + (kpBase+e)*LDT + ldRow] = lo;                   \
        }                                                                      \
    }

#define CORE_COMPUTE_GEN(bufn, MMAOP, DO_BL)                                   \
    {                                                                          \
        _Pragma("unroll")                                                      \
        for (int h = 0; h < 2; h++) {                                          \
            int kc = h*8 + (lane & 3);                                         \
            int mo2 = lane >> 2;                                               \
            unsigned afh[4][4], afl[4][4], bfh[4][2], bfl[4][2];               \
            _Pragma("unroll")                                                  \
            for (int mi = 0; mi < 4; mi++) {                                   \
                int m = warpM + mi * 16 + mo2;                                 \
                afh[mi][0] = sm[SOFF_AH(bufn) + kc*LDT + m];                   \
                afh[mi][1] = sm[SOFF_AH(bufn) + kc*LDT + m + 8];               \
                afh[mi][2] = sm[SOFF_AH(bufn) + (kc+4)*LDT + m];               \
                afh[mi][3] = sm[SOFF_AH(bufn) + (kc+4)*LDT + m + 8];           \
                afl[mi][0] = sm[SOFF_AL(bufn) + kc*LDT + m];                   \
                afl[mi][1] = sm[SOFF_AL(bufn) + kc*LDT + m + 8];               \
                afl[mi][2] = sm[SOFF_AL(bufn) + (kc+4)*LDT + m];               \
                afl[mi][3] = sm[SOFF_AL(bufn) + (kc+4)*LDT + m + 8];           \
            }                                                                  \
            _Pragma("unroll")                                                  \
            for (int ni = 0; ni < 4; ni++) {                                   \
                int n = warpN + ni * 8 + mo2;                                  \
                bfh[ni][0] = sm[SOFF_BH(bufn) + kc*LDT + n];                   \
                bfh[ni][1] = sm[SOFF_BH(bufn) + (kc+4)*LDT + n];               \
                if (DO_BL) {                                                   \
                    bfl[ni][0] = sm[SOFF_BL(bufn) + kc*LDT + n];               \
                    bfl[ni][1] = sm[SOFF_BL(bufn) + (kc+4)*LDT + n];           \
                }                                                              \
            }                                                                  \
            _Pragma("unroll")                                                  \
            for (int mi = 0; mi < 4; mi++)                                     \
                _Pragma("unroll")                                              \
                for (int ni = 0; ni < 4; ni++) {                               \
                    MMAOP(acc[mi][ni], afh[mi], bfh[ni]);                      \
                    MMAOP(acc[mi][ni], afl[mi], bfh[ni]);                      \
                    if (DO_BL) MMAOP(acc[mi][ni], afh[mi], bfl[ni]);           \
                }                                                              \
        }                                                                      \
    }

#define CORE_PROLOG_VARS                                                       \
    int tid  = threadIdx.x;                                                    \
    int lane = tid & 31;                                                       \
    int warp = tid >> 5;                                                       \
    int warpM = (warp >> 2) * 64;                                              \
    int warpN = (warp & 3) * 32;                                               \
    int ldRow  = tid >> 1;                                                     \
    int kpBase = (tid & 1) * 8;                                                \
    float acc[4][4][4];                                                        \
    _Pragma("unroll")                                                          \
    for (int mi = 0; mi < 4; mi++)                                             \
        _Pragma("unroll")                                                      \
        for (int ni = 0; ni < 4; ni++)                                         \
            _Pragma("unroll")                                                  \
            for (int e = 0; e < 4; e++) acc[mi][ni][e] = 0.f;

// ============ pre-split cores ===============================================
#define PRE_LOAD4(dst, base, woff)                                             \
    {                                                                          \
        uint4 u;                                                               \
        u = *(const uint4*)((base) + (woff));     dst[0]=u.x; dst[1]=u.y; dst[2]=u.z; dst[3]=u.w; \
        u = *(const uint4*)((base) + (woff) + 4); dst[4]=u.x; dst[5]=u.y; dst[6]=u.z; dst[7]=u.w; \
    }

#define PRE3_LOAD(t0)                                                          \
    {                                                                          \
        size_t woff = (size_t)ldRow * KW + ((size_t)(t0) << 4) + kpBase;       \
        PRE_LOAD4(arh, Agh, woff);                                             \
        PRE_LOAD4(arl, Agl, woff);                                             \
        PRE_LOAD4(brh, Bgh, woff);                                             \
        PRE_LOAD4(brl, Bgl, woff);                                             \
    }

#define PRE3_STORE(bufn)                                                       \
    {                                                                          \
        _Pragma("unroll")                                                      \
        for (int e = 0; e < 8; e++) {                                          \
            sm[SOFF_AH(bufn) + (kpBase+e)*LDT + ldRow] = arh[e];               \
            sm[SOFF_AL(bufn) + (kpBase+e)*LDT + ldRow] = arl[e];               \
            sm[SOFF_BH(bufn) + (kpBase+e)*LDT + ldRow] = brh[e];               \
            sm[SOFF_BL(bufn) + (kpBase+e)*LDT + ldRow] = brl[e];               \
        }                                                                      \
    }

#define PRE2_LOAD(t0)                                                          \
    {                                                                          \
        size_t woff = (size_t)ldRow * KW + ((size_t)(t0) << 4) + kpBase;       \
        PRE_LOAD4(arh, Agh, woff);                                             \
        PRE_LOAD4(arl, Agl, woff);                                             \
        PRE_LOAD4(brh, Bgh, woff);                                             \
    }

#define PRE2_STORE(bufn)                                                       \
    {                                                                          \
        _Pragma("unroll")                                                      \
        for (int e = 0; e < 8; e++) {                                          \
            sm[SOFF_AH(bufn) + (kpBase+e)*LDT + ldRow] = arh[e];               \
            sm[SOFF_AL(bufn) + (kpBase+e)*LDT + ldRow] = arl[e];               \
            sm[SOFF_BH(bufn) + (kpBase+e)*LDT + ldRow] = brh[e];               \
        }                                                                      \
    }

// ---------------- fp32 -> packed hi/lo split kernels ------------------------
__global__ __launch_bounds__(256) void split_bf16_kernel(
    const float* __restrict__ src, unsigned* __restrict__ hi,
    unsigned* __restrict__ lo, int n4)
{
    int i = blockIdx.x * blockDim.x + threadIdx.x;
    if (i >= n4) return;
    float4 v = ((const float4*)src)[i];
    unsigned h0, l0, h1, l1;
    bfsplit2(v.x, v.y, h0, l0);
    bfsplit2(v.z, v.w, h1, l1);
    ((uint2*)hi)[i] = make_uint2(h0, h1);
    ((uint2*)lo)[i] = make_uint2(l0, l1);
}
__global__ __launch_bounds__(256) void split_f16_kernel(
    const float* __restrict__ src, unsigned* __restrict__ hi,
    unsigned* __restrict__ lo, int n4)
{
    int i = blockIdx.x * blockDim.x + threadIdx.x;
    if (i >= n4) return;
    float4 v = ((const float4*)src)[i];
    unsigned h0, l0, h1, l1;
    hsplit2(v.x, v.y, h0, l0);
    hsplit2(v.z, v.w, h1, l1);
    ((uint2*)hi)[i] = make_uint2(h0, h1);
    ((uint2*)lo)[i] = make_uint2(l0, l1);
}
__global__ __launch_bounds__(256) void split_f16h_kernel(
    const float* __restrict__ src, unsigned* __restrict__ hi, int n4)
{
    int i = blockIdx.x * blockDim.x + threadIdx.x;
    if (i >= n4) return;
    float4 v = ((const float4*)src)[i];
    __half2 a = __floats2half2_rn(v.x, v.y);
    __half2 b = __floats2half2_rn(v.z, v.w);
    ((uint2*)hi)[i] = make_uint2(*reinterpret_cast<unsigned*>(&a),
                                 *reinterpret_cast<unsigned*>(&b));
}

// ------- 3-term bf16 GEMM + fused RMSNorm/RoPE epilogue ---------------------
// Col tile (blockIdx.x) == head. Writes xout[b,h,s,d] + sqout (=0.5||x||^2).
__global__ __launch_bounds__(256) void gemm_qk_fused(
    const unsigned* __restrict__ Ah, const unsigned* __restrict__ Al,
    const unsigned* __restrict__ Bh, const unsigned* __restrict__ Bl,
    const float* __restrict__ fc, const float* __restrict__ gvec,
    float* __restrict__ xout, float* __restrict__ sqout, int K, int nh)
{
    extern __shared__ unsigned sm[];
    __shared__ float red2[128][4][2];
    __shared__ float gsh[128];
    int rowBase = blockIdx.y * 128;
    int colBase = blockIdx.x * 128;
    const int KW = K >> 1;
    const unsigned* Agh = Ah + (size_t)rowBase * KW;
    const unsigned* Agl = Al + (size_t)rowBase * KW;
    const unsigned* Bgh = Bh + (size_t)colBase * KW;
    const unsigned* Bgl = Bl + (size_t)colBase * KW;
    CORE_PROLOG_VARS;
    if (tid < 128) gsh[tid] = gvec[tid];
    unsigned arh[8], arl[8], brh[8], brl[8];
    int kTiles = K >> 5;

    PRE3_LOAD(0);
    PRE3_STORE(0);
    __syncthreads();
    for (int t = 0; t < kTiles; t++) {
        int buf = t & 1;
        bool has = (t + 1 < kTiles);
        if (has) PRE3_LOAD(t + 1);
        CORE_COMPUTE_GEN(buf, mma_bf16, 1);
        if (has) PRE3_STORE(buf ^ 1);
        __syncthreads();
    }

    // fused epilogue: rmsnorm + rope + scale + sq
    int mo = lane >> 2;
    #pragma unroll
    for (int mi = 0; mi < 4; mi++) {
        #pragma unroll
        for (int half = 0; half < 2; half++) {
            float s1 = 0.f, s2 = 0.f;
            #pragma unroll
            for (int ni = 0; ni < 4; ni++) {
                int c = warpN + ni*8 + (lane & 3)*2;
                float v0 = acc[mi][ni][2*half], v1 = acc[mi][ni][2*half+1];
                s1 += v0*v0 + v1*v1;
                float w0 = v0*gsh[c], w1 = v1*gsh[c+1];
                s2 += w0*w0 + w1*w1;
            }
            s1 += __shfl_xor_sync(0xffffffffu, s1, 1);
            s1 += __shfl_xor_sync(0xffffffffu, s1, 2);
            s2 += __shfl_xor_sync(0xffffffffu, s2, 1);
            s2 += __shfl_xor_sync(0xffffffffu, s2, 2);
            if ((lane & 3) == 0) {
                int rl = warpM + mi*16 + mo + half*8;
                red2[rl][warp & 3][0] = s1;
                red2[rl][warp & 3][1] = s2;
            }
        }
    }
    __syncthreads();
    #pragma unroll
    for (int mi = 0; mi < 4; mi++) {
        #pragma unroll
        for (int half = 0; half < 2; half++) {
            int rl = warpM + mi*16 + mo + half*8;
            float S1 = red2[rl][0][0]+red2[rl][1][0]+red2[rl][2][0]+red2[rl][3][0];
            float S2 = red2[rl][0][1]+red2[rl][1][1]+red2[rl][2][1]+red2[rl][3][1];
            float inv = rsqrtf(S1 * (1.0f/128.0f) + 1e-5f);
            int bs = rowBase + rl;
            int b = bs >> 12, s = bs & 4095;
            float* xp = xout + (((size_t)(b*nh + blockIdx.x))*Ss + s) * HDd;
            #pragma unroll
            for (int ni = 0; ni < 4; ni++) {
                int c = warpN + ni*8 + (lane & 3)*2;
                float a  = acc[mi][ni][2*half]   * inv * gsh[c];
                float b2 = acc[mi][ni][2*half+1] * inv * gsh[c+1];
                float2 cs = ((const float2*)fc)[(size_t)bs * (HDd/2) + (c >> 1)];
                float r0 = (a*cs.x - b2*cs.y) * SCALE_QD;
                float r1 = (a*cs.y + b2*cs.x) * SCALE_QD;
                *(float2*)(xp + c) = make_float2(r0, r1);
            }
            if ((warp & 3) == 0 && (lane & 3) == 0)
                sqout[((size_t)(b*nh + blockIdx.x))*Ss + s] =
                    0.5f * SCALE_QD * SCALE_QD * inv * inv * S2;
        }
    }
}

// ------- 2-term fp16 GEMM (A hi/lo, B hi), pre-split operands ---------------
__global__ __launch_bounds__(256) void gemm_f16_2t(
    const unsigned* __restrict__ Ah, const unsigned* __restrict__ Al,
    const unsigned* __restrict__ Bh,
    float* __restrict__ C, int K, int N)
{
    extern __shared__ unsigned sm[];
    int rowBase = blockIdx.y * 128;
    int colBase = blockIdx.x * 128;
    const int KW = K >> 1;
    const unsigned* Agh = Ah + (size_t)rowBase * KW;
    const unsigned* Agl = Al + (size_t)rowBase * KW;
    const unsigned* Bgh = Bh + (size_t)colBase * KW;
    CORE_PROLOG_VARS;
    unsigned arh[8], arl[8], brh[8];
    int kTiles = K >> 5;

    PRE2_LOAD(0);
    PRE2_STORE(0);
    __syncthreads();
    for (int t = 0; t < kTiles; t++) {
        int buf = t & 1;
        bool has = (t + 1 < kTiles);
        if (has) PRE2_LOAD(t + 1);
        CORE_COMPUTE_GEN(buf, mma_f16, 0);
        if (has) PRE2_STORE(buf ^ 1);
        __syncthreads();
    }

    #pragma unroll
    for (int mi = 0; mi < 4; mi++) {
        int r = rowBase + warpM + mi * 16 + (lane >> 2);
        #pragma unroll
        for (int ni = 0; ni < 4; ni++) {
            int c = colBase + warpN + ni * 8 + (lane & 3) * 2;
            *(float2*)(C + (size_t)r * N + c) =
                make_float2(acc[mi][ni][0], acc[mi][ni][1]);
            *(float2*)(C + (size_t)(r + 8) * N + c) =
                make_float2(acc[mi][ni][2], acc[mi][ni][3]);
        }
    }
}

// ---- FAVOR tensor-core kernel: C = A[M,128] @ B[128,128]^T + epilogue ------
// mode 0: featQ (row-max + exp); mode 1: featK (subtract sq);
// mode 2: out (mask/denom, writes packed fp16 hi/lo to outh/outl)
__global__ __launch_bounds__(256) void favor_tc(
    const float* __restrict__ A, const float* __restrict__ Bglob,
    const float* __restrict__ sq, const int* __restrict__ mask,
    float* __restrict__ out, unsigned* __restrict__ outh,
    unsigned* __restrict__ outl, int mode)
{
    extern __shared__ unsigned sm[];
    __shared__ float red[128][4];
    int rowBase = blockIdx.y * 128;
    const int K = 128, N = 128;
    const float* Wg;
    if (mode == 2) {
        int bh = blockIdx.y >> 5;
        int b = bh >> 4, h = bh & 15;
        int bhk = b * 8 + (h >> 1);
        Wg = Bglob + (size_t)bhk * 128 * 128;
    } else {
        Wg = Bglob;
    }
    const float* Ag = A + (size_t)rowBase * K;
    CORE_PROLOG_VARS;
    int ldCol = (tid & 1) * 16;
    float ar[16], br[16];
    CORE_LOAD_REGS(0);
    CORE_STORE_SMEM(0);
    __syncthreads();
    for (int t = 0; t < 4; t++) {
        int buf = t & 1;
        bool has = (t + 1 < 4);
        if (has) CORE_LOAD_REGS((t + 1) << 5);
        CORE_COMPUTE_GEN(buf, mma_bf16, 1);
        if (has) CORE_STORE_SMEM(buf ^ 1);
        __syncthreads();
    }

    int mo = lane >> 2;
    if (mode == 0) {
        #pragma unroll
        for (int mi = 0; mi < 4; mi++) {
            float m0 = -1e30f, m1 = -1e30f;
            #pragma unroll
            for (int ni = 0; ni < 4; ni++) {
                m0 = fmaxf(m0, fmaxf(acc[mi][ni][0], acc[mi][ni][1]));
                m1 = fmaxf(m1, fmaxf(acc[mi][ni][2], acc[mi][ni][3]));
            }
            m0 = fmaxf(m0, __shfl_xor_sync(0xffffffffu, m0, 1));
            m0 = fmaxf(m0, __shfl_xor_sync(0xffffffffu, m0, 2));
            m1 = fmaxf(m1, __shfl_xor_sync(0xffffffffu, m1, 1));
            m1 = fmaxf(m1, __shfl_xor_sync(0xffffffffu, m1, 2));
            if ((lane & 3) == 0) {
                red[warpM + mi*16 + mo][warp & 3] = m0;
                red[warpM + mi*16 + mo + 8][warp & 3] = m1;
            }
        }
        __syncthreads();
        #pragma unroll
        for (int mi = 0; mi < 4; mi++) {
            int rl = warpM + mi*16 + mo;
            float rm0 = fmaxf(fmaxf(red[rl][0], red[rl][1]),
                              fmaxf(red[rl][2], red[rl][3]));
            float rm1 = fmaxf(fmaxf(red[rl+8][0], red[rl+8][1]),
                              fmaxf(red[rl+8][2], red[rl+8][3]));
            #pragma unroll
            for (int ni = 0; ni < 4; ni++) {
                int c = warpN + ni*8 + (lane & 3)*2;
                *(float2*)(out + (size_t)(rowBase + rl) * N + c) =
                    make_float2(expf(acc[mi][ni][0]-rm0)*INV_SQRT_M + EPSF,
                                expf(acc[mi][ni][1]-rm0)*INV_SQRT_M + EPSF);
                *(float2*)(out + (size_t)(rowBase + rl + 8) * N + c) =
                    make_float2(expf(acc[mi][ni][2]-rm1)*INV_SQRT_M + EPSF,
                                expf(acc[mi][ni][3]-rm1)*INV_SQRT_M + EPSF);
            }
        }
    } else if (mode == 1) {
        #pragma unroll
        for (int mi = 0; mi < 4; mi++) {
            int r0 = rowBase + warpM + mi*16 + mo;
            float s0 = sq[r0], s1 = sq[r0 + 8];
            #pragma unroll
            for (int ni = 0; ni < 4; ni++) {
                int c = warpN + ni*8 + (lane & 3)*2;
                *(float2*)(out + (size_t)r0 * N + c) =
                    make_float2(acc[mi][ni][0]-s0, acc[mi][ni][1]-s0);
                *(float2*)(out + (size_t)(r0 + 8) * N + c) =
                    make_float2(acc[mi][ni][2]-s1, acc[mi][ni][3]-s1);
            }
        }
    } else {
        #pragma unroll
        for (int mi = 0; mi < 4; mi++) {
            int rg = rowBase + warpM + mi*16 + mo;
            #pragma unroll
            for (int half = 0; half < 2; half++) {
                int r = rg + half * 8;
                int s = r & 4095;
                int bh = r >> 12;
                int b = bh >> 4, h = bh & 15;
                float vm = (mask[b * Ss + s] > 0) ? 1.f : 0.f;
                float scale = vm / (sq[r] + EPSF);   // sq carries g_dn here
                size_t base = ((size_t)(b * Ss + s) * (Hh*HDd)) + h * HDd;
                #pragma unroll
                for (int ni = 0; ni < 4; ni++) {
                    int c = warpN + ni*8 + (lane & 3)*2;
                    unsigned hi, lo;
                    hsplit2(acc[mi][ni][2*half]*scale,
                            acc[mi][ni][2*half+1]*scale, hi, lo);
                    size_t w = (base + c) >> 1;
                    outh[w] = hi;
                    outl[w] = lo;
                }
            }
        }
    }
}

// ---------------- key column-max over S (two-stage) -------------------------
__global__ void kmax1_kernel() {
    int bh = blockIdx.x, ch = blockIdx.y, m = threadIdx.x;
    const float* p = g_kxp + ((size_t)bh * Ss + ch * 128) * Mm + m;
    float mx = -1e30f;
    #pragma unroll 4
    for (int s = 0; s < 128; s++) mx = fmaxf(mx, p[(size_t)s * Mm]);
    g_kmaxp[((size_t)bh * 32 + ch) * Mm + m] = mx;
}
__global__ void kmax2_kernel() {
    int bh = blockIdx.x, m = threadIdx.x;
    float mx = -1e30f;
    for (int c = 0; c < 32; c++) mx = fmaxf(mx, g_kmaxp[((size_t)bh*32 + c)*Mm + m]);
    g_kmax[bh * Mm + m] = mx;
}

__global__ void zero_kernel() {
    int i = blockIdx.x * blockDim.x + threadIdx.x;
    if (i < Bb*HKk*Mm*HDd) g_kvT[i] = 0.f;
    if (i < Bb*HKk*Mm)     g_ksum[i] = 0.f;
}

// -- kvT[d,m] += sum_s phi_k[s,m]*v[s,d] ; ksum[m] += sum_s phi_k[s,m] -------
__global__ __launch_bounds__(256) void kv_kernel(const int* __restrict__ mask)
{
    __shared__ float kps[16][128];
    __shared__ float vs [16][128];
    __shared__ float kmx[128];
    __shared__ float vmask[128];
    int bh = blockIdx.y;
    int b = bh / HKk, hk = bh % HKk;
    int s0 = blockIdx.x * 128;
    int tid = threadIdx.x;
    int tr = tid >> 4, tc = tid & 15;
    if (tid < 128) {
        kmx[tid] = g_kmax[bh * Mm + tid];
        vmask[tid] = (mask[b * Ss + s0 + tid] > 0) ? 1.f : 0.f;
    }
    __syncthreads();

    const float* KX = g_kxp + ((size_t)bh * Ss + s0) * Mm;
    const float* V  = g_v + ((size_t)(b * Ss + s0)) * (HKk*HDd) + hk * HDd;
    float acc[8][8];
    #pragma unroll
    for (int i=0;i<8;i++)
        #pragma unroll
        for (int j=0;j<8;j++) acc[i][j]=0.f;
    float ksacc = 0.f;

    for (int sc = 0; sc < 128; sc += 16) {
        #pragma unroll
        for (int it = 0; it < 2; it++) {
            int idx = tid + it * 256;
            int r = idx >> 5;
            int c4 = (idx & 31) << 2;
            float vm = vmask[sc + r];
            float4 x4 = *(const float4*)(KX + (size_t)(sc + r) * Mm + c4);
            kps[r][c4+0] = (expf(x4.x - kmx[c4+0]) * INV_SQRT_M + EPSF) * vm;
            kps[r][c4+1] = (expf(x4.y - kmx[c4+1]) * INV_SQRT_M + EPSF) * vm;
            kps[r][c4+2] = (expf(x4.z - kmx[c4+2]) * INV_SQRT_M + EPSF) * vm;
            kps[r][c4+3] = (expf(x4.w - kmx[c4+3]) * INV_SQRT_M + EPSF) * vm;
            float4 v4 = *(const float4*)(V + (size_t)(sc + r) * (HKk*HDd) + c4);
            vs[r][c4+0]=v4.x; vs[r][c4+1]=v4.y; vs[r][c4+2]=v4.z; vs[r][c4+3]=v4.w;
        }
        __syncthreads();
        #pragma unroll
        for (int ssi = 0; ssi < 16; ssi++) {
            float ra[8], rb[8];
            #pragma unroll
            for (int i=0;i<8;i++) ra[i]=kps[ssi][tr*8+i];
            #pragma unroll
            for (int j=0;j<8;j++) rb[j]=vs[ssi][tc*8+j];
            #pragma unroll
            for (int i=0;i<8;i++)
                #pragma unroll
                for (int j=0;j<8;j++) acc[i][j] += ra[i]*rb[j];
        }
        if (tid < 128) {
            #pragma unroll
            for (int ssi = 0; ssi < 16; ssi++) ksacc += kps[ssi][tid];
        }
        __syncthreads();
    }
    float* KV = g_kvT + (size_t)bh * Mm * HDd;
    #pragma unroll
    for (int i = 0; i < 8; i++)
        #pragma unroll
        for (int j = 0; j < 8; j++)
            atomicAdd(&KV[(size_t)(tc*8+j)*Mm + tr*8+i], acc[i][j]);
    if (tid < 128) atomicAdd(&g_ksum[bh * Mm + tid], ksacc);
}

// -------------- denominators: dn[row] = qphi[row,:]·ksum[bhk,:] -------------
__global__ __launch_bounds__(256) void dn_kernel() {
    int warp = threadIdx.x >> 5, lane = threadIdx.x & 31;
    int row = blockIdx.x * 8 + warp;
    int bh = row >> 12;
    int b = bh >> 4, h = bh & 15;
    int bhk = b * 8 + (h >> 1);
    float4 q = *(const float4*)(g_qphi + (size_t)row * Mm + lane * 4);
    float4 s = *(const float4*)(g_ksum + bhk * Mm + lane * 4);
    float v = q.x*s.x + q.y*s.y + q.z*s.z + q.w*s.w;
    #pragma unroll
    for (int o = 16; o > 0; o >>= 1) v += __shfl_xor_sync(0xffffffffu, v, o);
    if (lane == 0) g_dn[row] = v;
}

// ------------------------------- launch -------------------------------------
extern "C" void kernel_launch(void* const* d_in, const int* in_sizes, int n_in,
                              void* d_out, int out_size)
{
    const float* x    = (const float*)d_in[0];
    const int*   mask = (const int*)  d_in[1];
    const float* fc   = (const float*)d_in[2];
    const float* wq   = (const float*)d_in[3];
    const float* wk   = (const float*)d_in[4];
    const float* wv   = (const float*)d_in[5];
    const float* wo   = (const float*)d_in[6];
    const float* gq   = (const float*)d_in[7];
    const float* gk   = (const float*)d_in[8];
    const float* proj = (const float*)d_in[9];
    float* out = (float*)d_out;

    float *pv, *pqx, *pkx, *psqq, *psqk, *pqphi, *pkxp, *pkvT, *pdn;
    cudaGetSymbolAddress((void**)&pv,   g_v);
    cudaGetSymbolAddress((void**)&pqx,  g_qx);
    cudaGetSymbolAddress((void**)&pkx,  g_kx);
    cudaGetSymbolAddress((void**)&psqq, g_sqq);
    cudaGetSymbolAddress((void**)&psqk, g_sqk);
    cudaGetSymbolAddress((void**)&pqphi,g_qphi);
    cudaGetSymbolAddress((void**)&pkxp, g_kxp);
    cudaGetSymbolAddress((void**)&pkvT, g_kvT);
    cudaGetSymbolAddress((void**)&pdn,  g_dn);

    unsigned *xbh,*xbl,*xfh,*xfl,*wqh,*wql,*wkh,*wkl,*wvh,*woh,*aoh,*aol;
    cudaGetSymbolAddress((void**)&xbh, g_xbh); cudaGetSymbolAddress((void**)&xbl, g_xbl);
    cudaGetSymbolAddress((void**)&xfh, g_xfh); cudaGetSymbolAddress((void**)&xfl, g_xfl);
    cudaGetSymbolAddress((void**)&wqh, g_wqh); cudaGetSymbolAddress((void**)&wql, g_wql);
    cudaGetSymbolAddress((void**)&wkh, g_wkh); cudaGetSymbolAddress((void**)&wkl, g_wkl);
    cudaGetSymbolAddress((void**)&wvh, g_wvh);
    cudaGetSymbolAddress((void**)&woh, g_woh);
    cudaGetSymbolAddress((void**)&aoh, g_aoh); cudaGetSymbolAddress((void**)&aol, g_aol);

    cudaFuncSetAttribute(gemm_qk_fused, cudaFuncAttributeMaxDynamicSharedMemorySize, DSMEM_BYTES);
    cudaFuncSetAttribute(gemm_f16_2t,   cudaFuncAttributeMaxDynamicSharedMemorySize, DSMEM2_BYTES);
    cudaFuncSetAttribute(favor_tc,      cudaFuncAttributeMaxDynamicSharedMemorySize, DSMEM_BYTES);

    // pre-split operands
    split_bf16_kernel<<<(Bb*Ss*DIMm/4 + 255)/256, 256>>>(x,  xbh, xbl, Bb*Ss*DIMm/4);
    split_f16_kernel <<<(Bb*Ss*DIMm/4 + 255)/256, 256>>>(x,  xfh, xfl, Bb*Ss*DIMm/4);
    split_bf16_kernel<<<(Hh*HDd*DIMm/4 + 255)/256, 256>>>(wq, wqh, wql, Hh*HDd*DIMm/4);
    split_bf16_kernel<<<(HKk*HDd*DIMm/4 + 255)/256, 256>>>(wk, wkh, wkl, HKk*HDd*DIMm/4);
    split_f16h_kernel<<<(HKk*HDd*DIMm/4 + 255)/256, 256>>>(wv, wvh, HKk*HDd*DIMm/4);
    split_f16h_kernel<<<(DIMm*Hh*HDd/4 + 255)/256, 256>>>(wo, woh, DIMm*Hh*HDd/4);

    // Q,K projections with fused RMSNorm+RoPE epilogue
    gemm_qk_fused<<<dim3(Hh,  (Bb*Ss)/128), 256, DSMEM_BYTES>>>(
        xbh, xbl, wqh, wql, fc, gq, pqx, psqq, DIMm, Hh);
    gemm_qk_fused<<<dim3(HKk, (Bb*Ss)/128), 256, DSMEM_BYTES>>>(
        xbh, xbl, wkh, wkl, fc, gk, pkx, psqk, DIMm, HKk);
    // V projection: 2-term fp16
    gemm_f16_2t<<<dim3((HKk*HDd)/128, (Bb*Ss)/128), 256, DSMEM2_BYTES>>>(
        xfh, xfl, wvh, pv, DIMm, HKk*HDd);

    // FAVOR feature projections on tensor cores
    favor_tc<<<dim3(1, (Bb*Hh*Ss)/128),  256, DSMEM_BYTES>>>(
        pqx, proj, psqq, mask, pqphi, 0, 0, 0);
    favor_tc<<<dim3(1, (Bb*HKk*Ss)/128), 256, DSMEM_BYTES>>>(
        pkx, proj, psqk, mask, pkxp, 0, 0, 1);

    // key column max over S
    kmax1_kernel<<<dim3(Bb*HKk, 32), 128>>>();
    kmax2_kernel<<<Bb*HKk, 128>>>();

    // kv / ksum contraction (kv stored transposed)
    zero_kernel<<<(Bb*HKk*Mm*HDd + 255)/256, 256>>>();
    kv_kernel<<<dim3(Ss/128, Bb*HKk), 256>>>(mask);

    // denominators, then attention output (writes fp16 hi/lo directly)
    dn_kernel<<<(Bb*Hh*Ss)/8, 256>>>();
    favor_tc<<<dim3(1, (Bb*Hh*Ss)/128), 256, DSMEM_BYTES>>>(
        pqphi, pkvT, pdn, mask, 0, aoh, aol, 2);

    // output projection: 2-term fp16 over pre-split ao
    gemm_f16_2t<<<dim3(DIMm/128, (Bb*Ss)/128), 256, DSMEM2_BYTES>>>(
        aoh, aol, woh, out, Hh*HDd, DIMm);
}

// round 10
// speedup vs baseline: 2.5972x; 1.0718x over previous
#include <cuda_runtime.h>
#include <cuda_bf16.h>
#include <cuda_fp16.h>
#include <math.h>
#include <stdint.h>

#define Bb  2
#define Ss  4096
#define DIMm 2048
#define Hh  16
#define HKk 8
#define HDd 128
#define Mm  128

#define INV_SQRT_M 0.08838834764831845f   // 128^{-0.5}
#define SCALE_QD   0.2973017787506803f    // 128^{-0.25}
#define EPSF 1e-6f

// ---------------- scratch (device globals; no allocations allowed) ----------
__device__ float g_v   [Bb*Ss*HKk*HDd];
__device__ float g_qx  [Bb*Hh*Ss*HDd];     // normed+roped+scaled, [b,h,s,d]
__device__ float g_kx  [Bb*HKk*Ss*HDd];
__device__ float g_sqq [Bb*Hh*Ss];
__device__ float g_sqk [Bb*HKk*Ss];
__device__ float g_qphi[Bb*Hh*Ss*Mm];      // [b,h,s,m]
__device__ float g_kxp [Bb*HKk*Ss*Mm];     // pre-exp key features
__device__ float g_kmaxp[Bb*HKk*32*Mm];
__device__ float g_kmax[Bb*HKk*Mm];
__device__ float g_kvT [Bb*HKk*HDd*Mm];    // TRANSPOSED kv: [d][m]
__device__ float g_ksum[Bb*HKk*Mm];
__device__ float g_dn  [Bb*Hh*Ss];         // denominators

// pre-split operand arrays (packed fp16x2 words)
#define XW (Bb*Ss*DIMm/2)
__device__ unsigned g_xfh [XW];            // x fp16 hi  (q,k,v GEMMs)
__device__ unsigned g_xfl [XW];            // x fp16 lo
__device__ unsigned g_wqh [Hh*HDd*DIMm/2];    // fp16 hi only
__device__ unsigned g_wkh [HKk*HDd*DIMm/2];
__device__ unsigned g_wvh [HKk*HDd*DIMm/2];
__device__ unsigned g_woh [DIMm*Hh*HDd/2];
__device__ unsigned g_aoh [Bb*Ss*Hh*HDd/2];   // attention out, fp16 hi
__device__ unsigned g_aol [Bb*Ss*Hh*HDd/2];   // attention out, fp16 lo

// ---------------------------- split helpers ---------------------------------
__device__ __forceinline__ void bfsplit2(float x0, float x1, unsigned& hi, unsigned& lo) {
    __nv_bfloat162 h2 = __floats2bfloat162_rn(x0, x1);
    float2 hf = __bfloat1622float2(h2);
    __nv_bfloat162 l2 = __floats2bfloat162_rn(x0 - hf.x, x1 - hf.y);
    hi = *reinterpret_cast<unsigned*>(&h2);
    lo = *reinterpret_cast<unsigned*>(&l2);
}
__device__ __forceinline__ void hsplit2(float x0, float x1, unsigned& hi, unsigned& lo) {
    __half2 h2 = __floats2half2_rn(x0, x1);
    float2 hf = __half22float2(h2);
    __half2 l2 = __floats2half2_rn(x0 - hf.x, x1 - hf.y);
    hi = *reinterpret_cast<unsigned*>(&h2);
    lo = *reinterpret_cast<unsigned*>(&l2);
}

__device__ __forceinline__ void mma_bf16(float* d, const unsigned* a, const unsigned* b) {
    asm volatile(
        "mma.sync.aligned.m16n8k16.row.col.f32.bf16.bf16.f32 "
        "{%0,%1,%2,%3}, {%4,%5,%6,%7}, {%8,%9}, {%0,%1,%2,%3};\n"
        : "+f"(d[0]), "+f"(d[1]), "+f"(d[2]), "+f"(d[3])
        : "r"(a[0]), "r"(a[1]), "r"(a[2]), "r"(a[3]),
          "r"(b[0]), "r"(b[1]));
}
__device__ __forceinline__ void mma_f16(float* d, const unsigned* a, const unsigned* b) {
    asm volatile(
        "mma.sync.aligned.m16n8k16.row.col.f32.f16.f16.f32 "
        "{%0,%1,%2,%3}, {%4,%5,%6,%7}, {%8,%9}, {%0,%1,%2,%3};\n"
        : "+f"(d[0]), "+f"(d[1]), "+f"(d[2]), "+f"(d[3])
        : "r"(a[0]), "r"(a[1]), "r"(a[2]), "r"(a[3]),
          "r"(b[0]), "r"(b[1]));
}

// smem layout (dynamic, unsigned units): per array 2 bufs x 16 kpairs x LDT
#define LDT 136
#define SOFF_AH(b) ((unsigned)(b)*2176u)
#define SOFF_AL(b) (4352u  + (unsigned)(b)*2176u)
#define SOFF_BH(b) (8704u  + (unsigned)(b)*2176u)
#define SOFF_BL(b) (13056u + (unsigned)(b)*2176u)
#define DSMEM_BYTES (17408*4)   // 69632 (4 arrays, favor_tc)
#define DSMEM2_BYTES (13056*4)  // 52224 (3 arrays, 2-term kernels)

// ============ fp32-input core (used by favor_tc only) =======================
#define CORE_LOAD_REGS(k0)                                                     \
    {                                                                          \
        const float* ap = Ag + (size_t)ldRow * K + (k0) + ldCol;               \
        const float* bp = Wg + (size_t)ldRow * K + (k0) + ldCol;               \
        float4 t;                                                              \
        t = *(const float4*)(ap);      ar[0]=t.x; ar[1]=t.y; ar[2]=t.z; ar[3]=t.w;   \
        t = *(const float4*)(ap + 4);  ar[4]=t.x; ar[5]=t.y; ar[6]=t.z; ar[7]=t.w;   \
        t = *(const float4*)(ap + 8);  ar[8]=t.x; ar[9]=t.y; ar[10]=t.z; ar[11]=t.w; \
        t = *(const float4*)(ap + 12); ar[12]=t.x; ar[13]=t.y; ar[14]=t.z; ar[15]=t.w;\
        t = *(const float4*)(bp);      br[0]=t.x; br[1]=t.y; br[2]=t.z; br[3]=t.w;   \
        t = *(const float4*)(bp + 4);  br[4]=t.x; br[5]=t.y; br[6]=t.z; br[7]=t.w;   \
        t = *(const float4*)(bp + 8);  br[8]=t.x; br[9]=t.y; br[10]=t.z; br[11]=t.w; \
        t = *(const float4*)(bp + 12); br[12]=t.x; br[13]=t.y; br[14]=t.z; br[15]=t.w;\
    }

#define CORE_STORE_SMEM(bufn)                                                  \
    {                                                                          \
        _Pragma("unroll")                                                      \
        for (int e = 0; e < 8; e++) {                                          \
            unsigned hi, lo;                                                   \
            bfsplit2(ar[2*e], ar[2*e+1], hi, lo);                              \
            sm[SOFF_AH(bufn) + (kpBase+e)*LDT + ldRow] = hi;                   \
            sm[SOFF_AL(bufn) + (kpBase+e)*LDT + ldRow] = lo;                   \
            bfsplit2(br[2*e], br[2*e+1], hi, lo);                              \
            sm[SOFF_BH(bufn) + (kpBase+e)*LDT + ldRow] = hi;                   \
            sm[SOFF_BL(bufn) + (kpBase+e)*LDT + ldRow] = lo;                   \
        }                                                                      \
    }

#define CORE_COMPUTE_GEN(bufn, MMAOP, DO_BL)                                   \
    {                                                                          \
        _Pragma("unroll")                                                      \
        for (int h = 0; h < 2; h++) {                                          \
            int kc = h*8 + (lane & 3);                                         \
            int mo2 = lane >> 2;                                               \
            unsigned afh[4][4], afl[4][4], bfh[4][2], bfl[4][2];               \
            _Pragma("unroll")                                                  \
            for (int mi = 0; mi < 4; mi++) {                                   \
                int m = warpM + mi * 16 + mo2;                                 \
                afh[mi][0] = sm[SOFF_AH(bufn) + kc*LDT + m];                   \
                afh[mi][1] = sm[SOFF_AH(bufn) + kc*LDT + m + 8];               \
                afh[mi][2] = sm[SOFF_AH(bufn) + (kc+4)*LDT + m];               \
                afh[mi][3] = sm[SOFF_AH(bufn) + (kc+4)*LDT + m + 8];           \
                afl[mi][0] = sm[SOFF_AL(bufn) + kc*LDT + m];                   \
                afl[mi][1] = sm[SOFF_AL(bufn) + kc*LDT + m + 8];               \
                afl[mi][2] = sm[SOFF_AL(bufn) + (kc+4)*LDT + m];               \
                afl[mi][3] = sm[SOFF_AL(bufn) + (kc+4)*LDT + m + 8];           \
            }                                                                  \
            _Pragma("unroll")                                                  \
            for (int ni = 0; ni < 4; ni++) {                                   \
                int n = warpN + ni * 8 + mo2;                                  \
                bfh[ni][0] = sm[SOFF_BH(bufn) + kc*LDT + n];                   \
                bfh[ni][1] = sm[SOFF_BH(bufn) + (kc+4)*LDT + n];               \
                if (DO_BL) {                                                   \
                    bfl[ni][0] = sm[SOFF_BL(bufn) + kc*LDT + n];               \
                    bfl[ni][1] = sm[SOFF_BL(bufn) + (kc+4)*LDT + n];           \
                }                                                              \
            }                                                                  \
            _Pragma("unroll")                                                  \
            for (int mi = 0; mi < 4; mi++)                                     \
                _Pragma("unroll")                                              \
                for (int ni = 0; ni < 4; ni++) {                               \
                    MMAOP(acc[mi][ni], afh[mi], bfh[ni]);                      \
                    MMAOP(acc[mi][ni], afl[mi], bfh[ni]);                      \
                    if (DO_BL) MMAOP(acc[mi][ni], afh[mi], bfl[ni]);           \
                }                                                              \
        }                                                                      \
    }

#define CORE_PROLOG_VARS                                                       \
    int tid  = threadIdx.x;                                                    \
    int lane = tid & 31;                                                       \
    int warp = tid >> 5;                                                       \
    int warpM = (warp >> 2) * 64;                                              \
    int warpN = (warp & 3) * 32;                                               \
    int ldRow  = tid >> 1;                                                     \
    int kpBase = (tid & 1) * 8;                                                \
    float acc[4][4][4];                                                        \
    _Pragma("unroll")                                                          \
    for (int mi = 0; mi < 4; mi++)                                             \
        _Pragma("unroll")                                                      \
        for (int ni = 0; ni < 4; ni++)                                         \
            _Pragma("unroll")                                                  \
            for (int e = 0; e < 4; e++) acc[mi][ni][e] = 0.f;

// ============ pre-split cores ===============================================
#define PRE_LOAD4(dst, base, woff)                                             \
    {                                                                          \
        uint4 u;                                                               \
        u = *(const uint4*)((base) + (woff));     dst[0]=u.x; dst[1]=u.y; dst[2]=u.z; dst[3]=u.w; \
        u = *(const uint4*)((base) + (woff) + 4); dst[4]=u.x; dst[5]=u.y; dst[6]=u.z; dst[7]=u.w; \
    }

#define PRE2_LOAD(t0)                                                          \
    {                                                                          \
        size_t woff = (size_t)ldRow * KW + ((size_t)(t0) << 4) + kpBase;       \
        PRE_LOAD4(arh, Agh, woff);                                             \
        PRE_LOAD4(arl, Agl, woff);                                             \
        PRE_LOAD4(brh, Bgh, woff);                                             \
    }

#define PRE2_STORE(bufn)                                                       \
    {                                                                          \
        _Pragma("unroll")                                                      \
        for (int e = 0; e < 8; e++) {                                          \
            sm[SOFF_AH(bufn) + (kpBase+e)*LDT + ldRow] = arh[e];               \
            sm[SOFF_AL(bufn) + (kpBase+e)*LDT + ldRow] = arl[e];               \
            sm[SOFF_BH(bufn) + (kpBase+e)*LDT + ldRow] = brh[e];               \
        }                                                                      \
    }

// ---------------- fp32 -> packed hi/lo split kernels ------------------------
__global__ __launch_bounds__(256) void split_f16_kernel(
    const float* __restrict__ src, unsigned* __restrict__ hi,
    unsigned* __restrict__ lo, int n4)
{
    int i = blockIdx.x * blockDim.x + threadIdx.x;
    if (i >= n4) return;
    float4 v = ((const float4*)src)[i];
    unsigned h0, l0, h1, l1;
    hsplit2(v.x, v.y, h0, l0);
    hsplit2(v.z, v.w, h1, l1);
    ((uint2*)hi)[i] = make_uint2(h0, h1);
    ((uint2*)lo)[i] = make_uint2(l0, l1);
}
__global__ __launch_bounds__(256) void split_f16h_kernel(
    const float* __restrict__ src, unsigned* __restrict__ hi, int n4)
{
    int i = blockIdx.x * blockDim.x + threadIdx.x;
    if (i >= n4) return;
    float4 v = ((const float4*)src)[i];
    __half2 a = __floats2half2_rn(v.x, v.y);
    __half2 b = __floats2half2_rn(v.z, v.w);
    ((uint2*)hi)[i] = make_uint2(*reinterpret_cast<unsigned*>(&a),
                                 *reinterpret_cast<unsigned*>(&b));
}

// ------- 2-term fp16 GEMM + fused RMSNorm/RoPE epilogue ---------------------
// Col tile (blockIdx.x) == head. Writes xout[b,h,s,d] + sqout (=0.5||x||^2).
__global__ __launch_bounds__(256) void gemm_qk_fused(
    const unsigned* __restrict__ Ah, const unsigned* __restrict__ Al,
    const unsigned* __restrict__ Bh,
    const float* __restrict__ fc, const float* __restrict__ gvec,
    float* __restrict__ xout, float* __restrict__ sqout, int K, int nh)
{
    extern __shared__ unsigned sm[];
    __shared__ float red2[128][4][2];
    __shared__ float gsh[128];
    int rowBase = blockIdx.y * 128;
    int colBase = blockIdx.x * 128;
    const int KW = K >> 1;
    const unsigned* Agh = Ah + (size_t)rowBase * KW;
    const unsigned* Agl = Al + (size_t)rowBase * KW;
    const unsigned* Bgh = Bh + (size_t)colBase * KW;
    CORE_PROLOG_VARS;
    if (tid < 128) gsh[tid] = gvec[tid];
    unsigned arh[8], arl[8], brh[8];
    int kTiles = K >> 5;

    PRE2_LOAD(0);
    PRE2_STORE(0);
    __syncthreads();
    for (int t = 0; t < kTiles; t++) {
        int buf = t & 1;
        bool has = (t + 1 < kTiles);
        if (has) PRE2_LOAD(t + 1);
        CORE_COMPUTE_GEN(buf, mma_f16, 0);
        if (has) PRE2_STORE(buf ^ 1);
        __syncthreads();
    }

    // fused epilogue: rmsnorm + rope + scale + sq
    int mo = lane >> 2;
    #pragma unroll
    for (int mi = 0; mi < 4; mi++) {
        #pragma unroll
        for (int half = 0; half < 2; half++) {
            float s1 = 0.f, s2 = 0.f;
            #pragma unroll
            for (int ni = 0; ni < 4; ni++) {
                int c = warpN + ni*8 + (lane & 3)*2;
                float v0 = acc[mi][ni][2*half], v1 = acc[mi][ni][2*half+1];
                s1 += v0*v0 + v1*v1;
                float w0 = v0*gsh[c], w1 = v1*gsh[c+1];
                s2 += w0*w0 + w1*w1;
            }
            s1 += __shfl_xor_sync(0xffffffffu, s1, 1);
            s1 += __shfl_xor_sync(0xffffffffu, s1, 2);
            s2 += __shfl_xor_sync(0xffffffffu, s2, 1);
            s2 += __shfl_xor_sync(0xffffffffu, s2, 2);
            if ((lane & 3) == 0) {
                int rl = warpM + mi*16 + mo + half*8;
                red2[rl][warp & 3][0] = s1;
                red2[rl][warp & 3][1] = s2;
            }
        }
    }
    __syncthreads();
    #pragma unroll
    for (int mi = 0; mi < 4; mi++) {
        #pragma unroll
        for (int half = 0; half < 2; half++) {
            int rl = warpM + mi*16 + mo + half*8;
            float S1 = red2[rl][0][0]+red2[rl][1][0]+red2[rl][2][0]+red2[rl][3][0];
            float S2 = red2[rl][0][1]+red2[rl][1][1]+red2[rl][2][1]+red2[rl][3][1];
            float inv = rsqrtf(S1 * (1.0f/128.0f) + 1e-5f);
            int bs = rowBase + rl;
            int b = bs >> 12, s = bs & 4095;
            float* xp = xout + (((size_t)(b*nh + blockIdx.x))*Ss + s) * HDd;
            #pragma unroll
            for (int ni = 0; ni < 4; ni++) {
                int c = warpN + ni*8 + (lane & 3)*2;
                float a  = acc[mi][ni][2*half]   * inv * gsh[c];
                float b2 = acc[mi][ni][2*half+1] * inv * gsh[c+1];
                float2 cs = ((const float2*)fc)[(size_t)bs * (HDd/2) + (c >> 1)];
                float r0 = (a*cs.x - b2*cs.y) * SCALE_QD;
                float r1 = (a*cs.y + b2*cs.x) * SCALE_QD;
                *(float2*)(xp + c) = make_float2(r0, r1);
            }
            if ((warp & 3) == 0 && (lane & 3) == 0)
                sqout[((size_t)(b*nh + blockIdx.x))*Ss + s] =
                    0.5f * SCALE_QD * SCALE_QD * inv * inv * S2;
        }
    }
}

// ------- 2-term fp16 GEMM (A hi/lo, B hi), plain epilogue -------------------
__global__ __launch_bounds__(256) void gemm_f16_2t(
    const unsigned* __restrict__ Ah, const unsigned* __restrict__ Al,
    const unsigned* __restrict__ Bh,
    float* __restrict__ C, int K, int N)
{
    extern __shared__ unsigned sm[];
    int rowBase = blockIdx.y * 128;
    int colBase = blockIdx.x * 128;
    const int KW = K >> 1;
    const unsigned* Agh = Ah + (size_t)rowBase * KW;
    const unsigned* Agl = Al + (size_t)rowBase * KW;
    const unsigned* Bgh = Bh + (size_t)colBase * KW;
    CORE_PROLOG_VARS;
    unsigned arh[8], arl[8], brh[8];
    int kTiles = K >> 5;

    PRE2_LOAD(0);
    PRE2_STORE(0);
    __syncthreads();
    for (int t = 0; t < kTiles; t++) {
        int buf = t & 1;
        bool has = (t + 1 < kTiles);
        if (has) PRE2_LOAD(t + 1);
        CORE_COMPUTE_GEN(buf, mma_f16, 0);
        if (has) PRE2_STORE(buf ^ 1);
        __syncthreads();
    }

    #pragma unroll
    for (int mi = 0; mi < 4; mi++) {
        int r = rowBase + warpM + mi * 16 + (lane >> 2);
        #pragma unroll
        for (int ni = 0; ni < 4; ni++) {
            int c = colBase + warpN + ni * 8 + (lane & 3) * 2;
            *(float2*)(C + (size_t)r * N + c) =
                make_float2(acc[mi][ni][0], acc[mi][ni][1]);
            *(float2*)(C + (size_t)(r + 8) * N + c) =
                make_float2(acc[mi][ni][2], acc[mi][ni][3]);
        }
    }
}

// ---- FAVOR tensor-core kernel: C = A[M,128] @ B[128,128]^T + epilogue ------
// mode 0: featQ (row-max + exp); mode 1: featK (subtract sq);
// mode 2: out (mask/denom, writes packed fp16 hi/lo to outh/outl)
__global__ __launch_bounds__(256) void favor_tc(
    const float* __restrict__ A, const float* __restrict__ Bglob,
    const float* __restrict__ sq, const int* __restrict__ mask,
    float* __restrict__ out, unsigned* __restrict__ outh,
    unsigned* __restrict__ outl, int mode)
{
    extern __shared__ unsigned sm[];
    __shared__ float red[128][4];
    int rowBase = blockIdx.y * 128;
    const int K = 128, N = 128;
    const float* Wg;
    if (mode == 2) {
        int bh = blockIdx.y >> 5;
        int b = bh >> 4, h = bh & 15;
        int bhk = b * 8 + (h >> 1);
        Wg = Bglob + (size_t)bhk * 128 * 128;
    } else {
        Wg = Bglob;
    }
    const float* Ag = A + (size_t)rowBase * K;
    CORE_PROLOG_VARS;
    int ldCol = (tid & 1) * 16;
    float ar[16], br[16];
    CORE_LOAD_REGS(0);
    CORE_STORE_SMEM(0);
    __syncthreads();
    for (int t = 0; t < 4; t++) {
        int buf = t & 1;
        bool has = (t + 1 < 4);
        if (has) CORE_LOAD_REGS((t + 1) << 5);
        CORE_COMPUTE_GEN(buf, mma_bf16, 1);
        if (has) CORE_STORE_SMEM(buf ^ 1);
        __syncthreads();
    }

    int mo = lane >> 2;
    if (mode == 0) {
        #pragma unroll
        for (int mi = 0; mi < 4; mi++) {
            float m0 = -1e30f, m1 = -1e30f;
            #pragma unroll
            for (int ni = 0; ni < 4; ni++) {
                m0 = fmaxf(m0, fmaxf(acc[mi][ni][0], acc[mi][ni][1]));
                m1 = fmaxf(m1, fmaxf(acc[mi][ni][2], acc[mi][ni][3]));
            }
            m0 = fmaxf(m0, __shfl_xor_sync(0xffffffffu, m0, 1));
            m0 = fmaxf(m0, __shfl_xor_sync(0xffffffffu, m0, 2));
            m1 = fmaxf(m1, __shfl_xor_sync(0xffffffffu, m1, 1));
            m1 = fmaxf(m1, __shfl_xor_sync(0xffffffffu, m1, 2));
            if ((lane & 3) == 0) {
                red[warpM + mi*16 + mo][warp & 3] = m0;
                red[warpM + mi*16 + mo + 8][warp & 3] = m1;
            }
        }
        __syncthreads();
        #pragma unroll
        for (int mi = 0; mi < 4; mi++) {
            int rl = warpM + mi*16 + mo;
            float rm0 = fmaxf(fmaxf(red[rl][0], red[rl][1]),
                              fmaxf(red[rl][2], red[rl][3]));
            float rm1 = fmaxf(fmaxf(red[rl+8][0], red[rl+8][1]),
                              fmaxf(red[rl+8][2], red[rl+8][3]));
            #pragma unroll
            for (int ni = 0; ni < 4; ni++) {
                int c = warpN + ni*8 + (lane & 3)*2;
                *(float2*)(out + (size_t)(rowBase + rl) * N + c) =
                    make_float2(expf(acc[mi][ni][0]-rm0)*INV_SQRT_M + EPSF,
                                expf(acc[mi][ni][1]-rm0)*INV_SQRT_M + EPSF);
                *(float2*)(out + (size_t)(rowBase + rl + 8) * N + c) =
                    make_float2(expf(acc[mi][ni][2]-rm1)*INV_SQRT_M + EPSF,
                                expf(acc[mi][ni][3]-rm1)*INV_SQRT_M + EPSF);
            }
        }
    } else if (mode == 1) {
        #pragma unroll
        for (int mi = 0; mi < 4; mi++) {
            int r0 = rowBase + warpM + mi*16 + mo;
            float s0 = sq[r0], s1 = sq[r0 + 8];
            #pragma unroll
            for (int ni = 0; ni < 4; ni++) {
                int c = warpN + ni*8 + (lane & 3)*2;
                *(float2*)(out + (size_t)r0 * N + c) =
                    make_float2(acc[mi][ni][0]-s0, acc[mi][ni][1]-s0);
                *(float2*)(out + (size_t)(r0 + 8) * N + c) =
                    make_float2(acc[mi][ni][2]-s1, acc[mi][ni][3]-s1);
            }
        }
    } else {
        #pragma unroll
        for (int mi = 0; mi < 4; mi++) {
            int rg = rowBase + warpM + mi*16 + mo;
            #pragma unroll
            for (int half = 0; half < 2; half++) {
                int r = rg + half * 8;
                int s = r & 4095;
                int bh = r >> 12;
                int b = bh >> 4, h = bh & 15;
                float vm = (mask[b * Ss + s] > 0) ? 1.f : 0.f;
                float scale = vm / (sq[r] + EPSF);   // sq carries g_dn here
                size_t base = ((size_t)(b * Ss + s) * (Hh*HDd)) + h * HDd;
                #pragma unroll
                for (int ni = 0; ni < 4; ni++) {
                    int c = warpN + ni*8 + (lane & 3)*2;
                    unsigned hi, lo;
                    hsplit2(acc[mi][ni][2*half]*scale,
                            acc[mi][ni][2*half+1]*scale, hi, lo);
                    size_t w = (base + c) >> 1;
                    outh[w] = hi;
                    outl[w] = lo;
                }
            }
        }
    }
}

// ---------------- key column-max over S (two-stage) -------------------------
__global__ void kmax1_kernel() {
    int bh = blockIdx.x, ch = blockIdx.y, m = threadIdx.x;
    const float* p = g_kxp + ((size_t)bh * Ss + ch * 128) * Mm + m;
    float mx = -1e30f;
    #pragma unroll 4
    for (int s = 0; s < 128; s++) mx = fmaxf(mx, p[(size_t)s * Mm]);
    g_kmaxp[((size_t)bh * 32 + ch) * Mm + m] = mx;
}
__global__ void kmax2_kernel() {
    int bh = blockIdx.x, m = threadIdx.x;
    float mx = -1e30f;
    for (int c = 0; c < 32; c++) mx = fmaxf(mx, g_kmaxp[((size_t)bh*32 + c)*Mm + m]);
    g_kmax[bh * Mm + m] = mx;
}

__global__ void zero_kernel() {
    int i = blockIdx.x * blockDim.x + threadIdx.x;
    if (i < Bb*HKk*Mm*HDd) g_kvT[i] = 0.f;
    if (i < Bb*HKk*Mm)     g_ksum[i] = 0.f;
}

// -- kvT[d,m] += sum_s phi_k[s,m]*v[s,d] ; ksum[m] += sum_s phi_k[s,m] -------
__global__ __launch_bounds__(256) void kv_kernel(const int* __restrict__ mask)
{
    __shared__ float kps[16][128];
    __shared__ float vs [16][128];
    __shared__ float kmx[128];
    __shared__ float vmask[128];
    int bh = blockIdx.y;
    int b = bh / HKk, hk = bh % HKk;
    int s0 = blockIdx.x * 128;
    int tid = threadIdx.x;
    int tr = tid >> 4, tc = tid & 15;
    if (tid < 128) {
        kmx[tid] = g_kmax[bh * Mm + tid];
        vmask[tid] = (mask[b * Ss + s0 + tid] > 0) ? 1.f : 0.f;
    }
    __syncthreads();

    const float* KX = g_kxp + ((size_t)bh * Ss + s0) * Mm;
    const float* V  = g_v + ((size_t)(b * Ss + s0)) * (HKk*HDd) + hk * HDd;
    float acc[8][8];
    #pragma unroll
    for (int i=0;i<8;i++)
        #pragma unroll
        for (int j=0;j<8;j++) acc[i][j]=0.f;
    float ksacc = 0.f;

    for (int sc = 0; sc < 128; sc += 16) {
        #pragma unroll
        for (int it = 0; it < 2; it++) {
            int idx = tid + it * 256;
            int r = idx >> 5;
            int c4 = (idx & 31) << 2;
            float vm = vmask[sc + r];
            float4 x4 = *(const float4*)(KX + (size_t)(sc + r) * Mm + c4);
            kps[r][c4+0] = (expf(x4.x - kmx[c4+0]) * INV_SQRT_M + EPSF) * vm;
            kps[r][c4+1] = (expf(x4.y - kmx[c4+1]) * INV_SQRT_M + EPSF) * vm;
            kps[r][c4+2] = (expf(x4.z - kmx[c4+2]) * INV_SQRT_M + EPSF) * vm;
            kps[r][c4+3] = (expf(x4.w - kmx[c4+3]) * INV_SQRT_M + EPSF) * vm;
            float4 v4 = *(const float4*)(V + (size_t)(sc + r) * (HKk*HDd) + c4);
            vs[r][c4+0]=v4.x; vs[r][c4+1]=v4.y; vs[r][c4+2]=v4.z; vs[r][c4+3]=v4.w;
        }
        __syncthreads();
        #pragma unroll
        for (int ssi = 0; ssi < 16; ssi++) {
            float ra[8], rb[8];
            #pragma unroll
            for (int i=0;i<8;i++) ra[i]=kps[ssi][tr*8+i];
            #pragma unroll
            for (int j=0;j<8;j++) rb[j]=vs[ssi][tc*8+j];
            #pragma unroll
            for (int i=0;i<8;i++)
                #pragma unroll
                for (int j=0;j<8;j++) acc[i][j] += ra[i]*rb[j];
        }
        if (tid < 128) {
            #pragma unroll
            for (int ssi = 0; ssi < 16; ssi++) ksacc += kps[ssi][tid];
        }
        __syncthreads();
    }
    float* KV = g_kvT + (size_t)bh * Mm * HDd;
    #pragma unroll
    for (int i = 0; i < 8; i++)
        #pragma unroll
        for (int j = 0; j < 8; j++)
            atomicAdd(&KV[(size_t)(tc*8+j)*Mm + tr*8+i], acc[i][j]);
    if (tid < 128) atomicAdd(&g_ksum[bh * Mm + tid], ksacc);
}

// -------------- denominators: dn[row] = qphi[row,:]·ksum[bhk,:] -------------
__global__ __launch_bounds__(256) void dn_kernel() {
    int warp = threadIdx.x >> 5, lane = threadIdx.x & 31;
    int row = blockIdx.x * 8 + warp;
    int bh = row >> 12;
    int b = bh >> 4, h = bh & 15;
    int bhk = b * 8 + (h >> 1);
    float4 q = *(const float4*)(g_qphi + (size_t)row * Mm + lane * 4);
    float4 s = *(const float4*)(g_ksum + bhk * Mm + lane * 4);
    float v = q.x*s.x + q.y*s.y + q.z*s.z + q.w*s.w;
    #pragma unroll
    for (int o = 16; o > 0; o >>= 1) v += __shfl_xor_sync(0xffffffffu, v, o);
    if (lane == 0) g_dn[row] = v;
}

// ------------------------------- launch -------------------------------------
extern "C" void kernel_launch(void* const* d_in, const int* in_sizes, int n_in,
                              void* d_out, int out_size)
{
    const float* x    = (const float*)d_in[0];
    const int*   mask = (const int*)  d_in[1];
    const float* fc   = (const float*)d_in[2];
    const float* wq   = (const float*)d_in[3];
    const float* wk   = (const float*)d_in[4];
    const float* wv   = (const float*)d_in[5];
    const float* wo   = (const float*)d_in[6];
    const float* gq   = (const float*)d_in[7];
    const float* gk   = (const float*)d_in[8];
    const float* proj = (const float*)d_in[9];
    float* out = (float*)d_out;

    float *pv, *pqx, *pkx, *psqq, *psqk, *pqphi, *pkxp, *pkvT, *pdn;
    cudaGetSymbolAddress((void**)&pv,   g_v);
    cudaGetSymbolAddress((void**)&pqx,  g_qx);
    cudaGetSymbolAddress((void**)&pkx,  g_kx);
    cudaGetSymbolAddress((void**)&psqq, g_sqq);
    cudaGetSymbolAddress((void**)&psqk, g_sqk);
    cudaGetSymbolAddress((void**)&pqphi,g_qphi);
    cudaGetSymbolAddress((void**)&pkxp, g_kxp);
    cudaGetSymbolAddress((void**)&pkvT, g_kvT);
    cudaGetSymbolAddress((void**)&pdn,  g_dn);

    unsigned *xfh,*xfl,*wqh,*wkh,*wvh,*woh,*aoh,*aol;
    cudaGetSymbolAddress((void**)&xfh, g_xfh); cudaGetSymbolAddress((void**)&xfl, g_xfl);
    cudaGetSymbolAddress((void**)&wqh, g_wqh);
    cudaGetSymbolAddress((void**)&wkh, g_wkh);
    cudaGetSymbolAddress((void**)&wvh, g_wvh);
    cudaGetSymbolAddress((void**)&woh, g_woh);
    cudaGetSymbolAddress((void**)&aoh, g_aoh); cudaGetSymbolAddress((void**)&aol, g_aol);

    cudaFuncSetAttribute(gemm_qk_fused, cudaFuncAttributeMaxDynamicSharedMemorySize, DSMEM2_BYTES);
    cudaFuncSetAttribute(gemm_f16_2t,   cudaFuncAttributeMaxDynamicSharedMemorySize, DSMEM2_BYTES);
    cudaFuncSetAttribute(favor_tc,      cudaFuncAttributeMaxDynamicSharedMemorySize, DSMEM_BYTES);

    // pre-split operands (all fp16 now)
    split_f16_kernel <<<(Bb*Ss*DIMm/4 + 255)/256, 256>>>(x,  xfh, xfl, Bb*Ss*DIMm/4);
    split_f16h_kernel<<<(Hh*HDd*DIMm/4 + 255)/256, 256>>>(wq, wqh, Hh*HDd*DIMm/4);
    split_f16h_kernel<<<(HKk*HDd*DIMm/4 + 255)/256, 256>>>(wk, wkh, HKk*HDd*DIMm/4);
    split_f16h_kernel<<<(HKk*HDd*DIMm/4 + 255)/256, 256>>>(wv, wvh, HKk*HDd*DIMm/4);
    split_f16h_kernel<<<(DIMm*Hh*HDd/4 + 255)/256, 256>>>(wo, woh, DIMm*Hh*HDd/4);

    // Q,K projections (2-term fp16) with fused RMSNorm+RoPE epilogue
    gemm_qk_fused<<<dim3(Hh,  (Bb*Ss)/128), 256, DSMEM2_BYTES>>>(
        xfh, xfl, wqh, fc, gq, pqx, psqq, DIMm, Hh);
    gemm_qk_fused<<<dim3(HKk, (Bb*Ss)/128), 256, DSMEM2_BYTES>>>(
        xfh, xfl, wkh, fc, gk, pkx, psqk, DIMm, HKk);
    // V projection: 2-term fp16
    gemm_f16_2t<<<dim3((HKk*HDd)/128, (Bb*Ss)/128), 256, DSMEM2_BYTES>>>(
        xfh, xfl, wvh, pv, DIMm, HKk*HDd);

    // FAVOR feature projections on tensor cores (3-term bf16, fp32 inputs)
    favor_tc<<<dim3(1, (Bb*Hh*Ss)/128),  256, DSMEM_BYTES>>>(
        pqx, proj, psqq, mask, pqphi, 0, 0, 0);
    favor_tc<<<dim3(1, (Bb*HKk*Ss)/128), 256, DSMEM_BYTES>>>(
        pkx, proj, psqk, mask, pkxp, 0, 0, 1);

    // key column max over S
    kmax1_kernel<<<dim3(Bb*HKk, 32), 128>>>();
    kmax2_kernel<<<Bb*HKk, 128>>>();

    // kv / ksum contraction (kv stored transposed)
    zero_kernel<<<(Bb*HKk*Mm*HDd + 255)/256, 256>>>();
    kv_kernel<<<dim3(Ss/128, Bb*HKk), 256>>>(mask);

    // denominators, then attention output (writes fp16 hi/lo directly)
    dn_kernel<<<(Bb*Hh*Ss)/8, 256>>>();
    favor_tc<<<dim3(1, (Bb*Hh*Ss)/128), 256, DSMEM_BYTES>>>(
        pqphi, pkvT, pdn, mask, 0, aoh, aol, 2);

    // output projection: 2-term fp16 over pre-split ao
    gemm_f16_2t<<<dim3(DIMm/128, (Bb*Ss)/128), 256, DSMEM2_BYTES>>>(
        aoh, aol, woh, out, Hh*HDd, DIMm);
}

// round 11
// speedup vs baseline: 3.1703x; 1.2207x over previous
#include <cuda_runtime.h>
#include <cuda_bf16.h>
#include <cuda_fp16.h>
#include <math.h>
#include <stdint.h>

#define Bb  2
#define Ss  4096
#define DIMm 2048
#define Hh  16
#define HKk 8
#define HDd 128
#define Mm  128

#define INV_SQRT_M 0.08838834764831845f   // 128^{-0.5}
#define SCALE_QD   0.2973017787506803f    // 128^{-0.25}
#define EPSF 1e-6f

// ---------------- scratch (device globals; no allocations allowed) ----------
__device__ float g_v   [Bb*Ss*HKk*HDd];
__device__ float g_qx  [Bb*Hh*Ss*HDd];     // normed+roped+scaled, [b,h,s,d]
__device__ float g_kx  [Bb*HKk*Ss*HDd];
__device__ float g_sqq [Bb*Hh*Ss];
__device__ float g_sqk [Bb*HKk*Ss];
__device__ float g_qphi[Bb*Hh*Ss*Mm];      // [b,h,s,m]
__device__ float g_kxp [Bb*HKk*Ss*Mm];     // pre-exp key features
__device__ float g_kmaxp[Bb*HKk*32*Mm];
__device__ float g_kmax[Bb*HKk*Mm];
__device__ float g_kvT [Bb*HKk*HDd*Mm];    // TRANSPOSED kv: [d][m]
__device__ float g_ksum[Bb*HKk*Mm];
__device__ float g_dn  [Bb*Hh*Ss];         // denominators

// pre-split operand arrays (packed fp16x2 words)
#define XW (Bb*Ss*DIMm/2)
__device__ unsigned g_xfh [XW];            // x fp16 hi  (q,k,v GEMMs)
__device__ unsigned g_xfl [XW];            // x fp16 lo
__device__ unsigned g_wqh [Hh*HDd*DIMm/2];    // fp16 hi only
__device__ unsigned g_wkh [HKk*HDd*DIMm/2];
__device__ unsigned g_wvh [HKk*HDd*DIMm/2];
__device__ unsigned g_woh [DIMm*Hh*HDd/2];
__device__ unsigned g_aoh [Bb*Ss*Hh*HDd/2];   // attention out, fp16 hi
__device__ unsigned g_aol [Bb*Ss*Hh*HDd/2];   // attention out, fp16 lo

// ---------------------------- split helpers ---------------------------------
__device__ __forceinline__ void bfsplit2(float x0, float x1, unsigned& hi, unsigned& lo) {
    __nv_bfloat162 h2 = __floats2bfloat162_rn(x0, x1);
    float2 hf = __bfloat1622float2(h2);
    __nv_bfloat162 l2 = __floats2bfloat162_rn(x0 - hf.x, x1 - hf.y);
    hi = *reinterpret_cast<unsigned*>(&h2);
    lo = *reinterpret_cast<unsigned*>(&l2);
}
__device__ __forceinline__ void hsplit2(float x0, float x1, unsigned& hi, unsigned& lo) {
    __half2 h2 = __floats2half2_rn(x0, x1);
    float2 hf = __half22float2(h2);
    __half2 l2 = __floats2half2_rn(x0 - hf.x, x1 - hf.y);
    hi = *reinterpret_cast<unsigned*>(&h2);
    lo = *reinterpret_cast<unsigned*>(&l2);
}

__device__ __forceinline__ void mma_bf16(float* d, const unsigned* a, const unsigned* b) {
    asm volatile(
        "mma.sync.aligned.m16n8k16.row.col.f32.bf16.bf16.f32 "
        "{%0,%1,%2,%3}, {%4,%5,%6,%7}, {%8,%9}, {%0,%1,%2,%3};\n"
        : "+f"(d[0]), "+f"(d[1]), "+f"(d[2]), "+f"(d[3])
        : "r"(a[0]), "r"(a[1]), "r"(a[2]), "r"(a[3]),
          "r"(b[0]), "r"(b[1]));
}
__device__ __forceinline__ void mma_f16(float* d, const unsigned* a, const unsigned* b) {
    asm volatile(
        "mma.sync.aligned.m16n8k16.row.col.f32.f16.f16.f32 "
        "{%0,%1,%2,%3}, {%4,%5,%6,%7}, {%8,%9}, {%0,%1,%2,%3};\n"
        : "+f"(d[0]), "+f"(d[1]), "+f"(d[2]), "+f"(d[3])
        : "r"(a[0]), "r"(a[1]), "r"(a[2]), "r"(a[3]),
          "r"(b[0]), "r"(b[1]));
}

#define CP16(dst, src) asm volatile("cp.async.cg.shared.global [%0], [%1], 16;\n" :: "r"(dst), "l"(src) : "memory")
#define CP_COMMIT()    asm volatile("cp.async.commit_group;\n" ::: "memory")
#define CP_WAIT0()     asm volatile("cp.async.wait_group 0;\n" ::: "memory")
#define LDMX4(r, addr) asm volatile( \
    "ldmatrix.sync.aligned.m8n8.x4.shared.b16 {%0,%1,%2,%3}, [%4];" \
    : "=r"((r)[0]), "=r"((r)[1]), "=r"((r)[2]), "=r"((r)[3]) : "r"(addr))

// ===== NEW cp.async/ldmatrix smem layout (2-term fp16 GEMMs) =================
// per array-stage: 128 rows x 20 words (16 kpairs used + 4 pad) = 2560 words
#define P3 2560u
#define POFF_AH(st) ((unsigned)(st)*P3)
#define POFF_AL(st) (2u*P3 + (unsigned)(st)*P3)
#define POFF_BH(st) (4u*P3 + (unsigned)(st)*P3)
#define DSMEM3_BYTES (6*2560*4)   // 61440

#define CPA_LOAD(t0, st)                                                       \
    {                                                                          \
        int row = tid >> 1;                                                    \
        int ch  = (tid & 1) * 8;                                               \
        size_t g = (size_t)row * KW + ((size_t)(t0) << 4) + ch;                \
        unsigned d;                                                            \
        d = smb + (POFF_AH(st) + (unsigned)row*20u + ch)*4u;                   \
        CP16(d, Agh + g); CP16(d+16u, Agh + g + 4);                            \
        d = smb + (POFF_AL(st) + (unsigned)row*20u + ch)*4u;                   \
        CP16(d, Agl + g); CP16(d+16u, Agl + g + 4);                            \
        d = smb + (POFF_BH(st) + (unsigned)row*20u + ch)*4u;                   \
        CP16(d, Bgh + g); CP16(d+16u, Bgh + g + 4);                            \
        CP_COMMIT();                                                           \
    }

#define CPA_COMPUTE(st)                                                        \
    {                                                                          \
        _Pragma("unroll")                                                      \
        for (int h = 0; h < 2; h++) {                                          \
            int arow = (lane & 7) + ((lane >> 3) & 1) * 8;                     \
            int achw = 8*h + ((lane >> 4) & 1) * 4;                            \
            int brow = (lane & 7) + ((lane >> 4) & 1) * 8;                     \
            int bchw = 8*h + ((lane >> 3) & 1) * 4;                            \
            unsigned afh[4][4], afl[4][4], bf[2][4];                           \
            _Pragma("unroll")                                                  \
            for (int mi = 0; mi < 4; mi++) {                                   \
                unsigned ra = smb + (POFF_AH(st) +                             \
                    (unsigned)(warpM + mi*16 + arow)*20u + achw)*4u;           \
                LDMX4(afh[mi], ra);                                            \
                unsigned rl = smb + (POFF_AL(st) +                             \
                    (unsigned)(warpM + mi*16 + arow)*20u + achw)*4u;           \
                LDMX4(afl[mi], rl);                                            \
            }                                                                  \
            LDMX4(bf[0], smb + (POFF_BH(st) +                                  \
                (unsigned)(warpN + brow)*20u + bchw)*4u);                      \
            LDMX4(bf[1], smb + (POFF_BH(st) +                                  \
                (unsigned)(warpN + 16 + brow)*20u + bchw)*4u);                 \
            _Pragma("unroll")                                                  \
            for (int mi = 0; mi < 4; mi++) {                                   \
                mma_f16(acc[mi][0], afh[mi], &bf[0][0]);                       \
                mma_f16(acc[mi][0], afl[mi], &bf[0][0]);                       \
                mma_f16(acc[mi][1], afh[mi], &bf[0][2]);                       \
                mma_f16(acc[mi][1], afl[mi], &bf[0][2]);                       \
                mma_f16(acc[mi][2], afh[mi], &bf[1][0]);                       \
                mma_f16(acc[mi][2], afl[mi], &bf[1][0]);                       \
                mma_f16(acc[mi][3], afh[mi], &bf[1][2]);                       \
                mma_f16(acc[mi][3], afl[mi], &bf[1][2]);                       \
            }                                                                  \
        }                                                                      \
    }

#define CPA_MAINLOOP(KTILES)                                                   \
    CPA_LOAD(0, 0);                                                            \
    CP_WAIT0();                                                                \
    __syncthreads();                                                           \
    for (int t = 0; t < (KTILES); t++) {                                       \
        int st = t & 1;                                                        \
        bool has = (t + 1 < (KTILES));                                         \
        if (has) CPA_LOAD(t + 1, st ^ 1);                                      \
        CPA_COMPUTE(st);                                                       \
        if (has) CP_WAIT0();                                                   \
        __syncthreads();                                                       \
    }

// ===== OLD smem layout (favor_tc only, 3-term bf16, fp32 inputs) ============
#define LDT 136
#define SOFF_AH(b) ((unsigned)(b)*2176u)
#define SOFF_AL(b) (4352u  + (unsigned)(b)*2176u)
#define SOFF_BH(b) (8704u  + (unsigned)(b)*2176u)
#define SOFF_BL(b) (13056u + (unsigned)(b)*2176u)
#define DSMEM_BYTES (17408*4)   // 69632

#define CORE_LOAD_REGS(k0)                                                     \
    {                                                                          \
        const float* ap = Ag + (size_t)ldRow * K + (k0) + ldCol;               \
        const float* bp = Wg + (size_t)ldRow * K + (k0) + ldCol;               \
        float4 t;                                                              \
        t = *(const float4*)(ap);      ar[0]=t.x; ar[1]=t.y; ar[2]=t.z; ar[3]=t.w;   \
        t = *(const float4*)(ap + 4);  ar[4]=t.x; ar[5]=t.y; ar[6]=t.z; ar[7]=t.w;   \
        t = *(const float4*)(ap + 8);  ar[8]=t.x; ar[9]=t.y; ar[10]=t.z; ar[11]=t.w; \
        t = *(const float4*)(ap + 12); ar[12]=t.x; ar[13]=t.y; ar[14]=t.z; ar[15]=t.w;\
        t = *(const float4*)(bp);      br[0]=t.x; br[1]=t.y; br[2]=t.z; br[3]=t.w;   \
        t = *(const float4*)(bp + 4);  br[4]=t.x; br[5]=t.y; br[6]=t.z; br[7]=t.w;   \
        t = *(const float4*)(bp + 8);  br[8]=t.x; br[9]=t.y; br[10]=t.z; br[11]=t.w; \
        t = *(const float4*)(bp + 12); br[12]=t.x; br[13]=t.y; br[14]=t.z; br[15]=t.w;\
    }

#define CORE_STORE_SMEM(bufn)                                                  \
    {                                                                          \
        _Pragma("unroll")                                                      \
        for (int e = 0; e < 8; e++) {                                          \
            unsigned hi, lo;                                                   \
            bfsplit2(ar[2*e], ar[2*e+1], hi, lo);                              \
            sm[SOFF_AH(bufn) + (kpBase+e)*LDT + ldRow] = hi;                   \
            sm[SOFF_AL(bufn) + (kpBase+e)*LDT + ldRow] = lo;                   \
            bfsplit2(br[2*e], br[2*e+1], hi, lo);                              \
            sm[SOFF_BH(bufn) + (kpBase+e)*LDT + ldRow] = hi;                   \
            sm[SOFF_BL(bufn) + (kpBase+e)*LDT + ldRow] = lo;                   \
        }                                                                      \
    }

#define CORE_COMPUTE3(bufn)                                                    \
    {                                                                          \
        _Pragma("unroll")                                                      \
        for (int h = 0; h < 2; h++) {                                          \
            int kc = h*8 + (lane & 3);                                         \
            int mo2 = lane >> 2;                                               \
            unsigned afh[4][4], afl[4][4], bfh[4][2], bfl[4][2];               \
            _Pragma("unroll")                                                  \
            for (int mi = 0; mi < 4; mi++) {                                   \
                int m = warpM + mi * 16 + mo2;                                 \
                afh[mi][0] = sm[SOFF_AH(bufn) + kc*LDT + m];                   \
                afh[mi][1] = sm[SOFF_AH(bufn) + kc*LDT + m + 8];               \
                afh[mi][2] = sm[SOFF_AH(bufn) + (kc+4)*LDT + m];               \
                afh[mi][3] = sm[SOFF_AH(bufn) + (kc+4)*LDT + m + 8];           \
                afl[mi][0] = sm[SOFF_AL(bufn) + kc*LDT + m];                   \
                afl[mi][1] = sm[SOFF_AL(bufn) + kc*LDT + m + 8];               \
                afl[mi][2] = sm[SOFF_AL(bufn) + (kc+4)*LDT + m];               \
                afl[mi][3] = sm[SOFF_AL(bufn) + (kc+4)*LDT + m + 8];           \
            }                                                                  \
            _Pragma("unroll")                                                  \
            for (int ni = 0; ni < 4; ni++) {                                   \
                int n = warpN + ni * 8 + mo2;                                  \
                bfh[ni][0] = sm[SOFF_BH(bufn) + kc*LDT + n];                   \
                bfh[ni][1] = sm[SOFF_BH(bufn) + (kc+4)*LDT + n];               \
                bfl[ni][0] = sm[SOFF_BL(bufn) + kc*LDT + n];                   \
                bfl[ni][1] = sm[SOFF_BL(bufn) + (kc+4)*LDT + n];               \
            }                                                                  \
            _Pragma("unroll")                                                  \
            for (int mi = 0; mi < 4; mi++)                                     \
                _Pragma("unroll")                                              \
                for (int ni = 0; ni < 4; ni++) {                               \
                    mma_bf16(acc[mi][ni], afh[mi], bfh[ni]);                   \
                    mma_bf16(acc[mi][ni], afl[mi], bfh[ni]);                   \
                    mma_bf16(acc[mi][ni], afh[mi], bfl[ni]);                   \
                }                                                              \
        }                                                                      \
    }

#define CORE_PROLOG_VARS                                                       \
    int tid  = threadIdx.x;                                                    \
    int lane = tid & 31;                                                       \
    int warp = tid >> 5;                                                       \
    int warpM = (warp >> 2) * 64;                                              \
    int warpN = (warp & 3) * 32;                                               \
    float acc[4][4][4];                                                        \
    _Pragma("unroll")                                                          \
    for (int mi = 0; mi < 4; mi++)                                             \
        _Pragma("unroll")                                                      \
        for (int ni = 0; ni < 4; ni++)                                         \
            _Pragma("unroll")                                                  \
            for (int e = 0; e < 4; e++) acc[mi][ni][e] = 0.f;

// ---------------- fp32 -> packed hi/lo split kernels ------------------------
__global__ __launch_bounds__(256) void split_f16_kernel(
    const float* __restrict__ src, unsigned* __restrict__ hi,
    unsigned* __restrict__ lo, int n4)
{
    int i = blockIdx.x * blockDim.x + threadIdx.x;
    if (i >= n4) return;
    float4 v = ((const float4*)src)[i];
    unsigned h0, l0, h1, l1;
    hsplit2(v.x, v.y, h0, l0);
    hsplit2(v.z, v.w, h1, l1);
    ((uint2*)hi)[i] = make_uint2(h0, h1);
    ((uint2*)lo)[i] = make_uint2(l0, l1);
}
__global__ __launch_bounds__(256) void split_f16h_kernel(
    const float* __restrict__ src, unsigned* __restrict__ hi, int n4)
{
    int i = blockIdx.x * blockDim.x + threadIdx.x;
    if (i >= n4) return;
    float4 v = ((const float4*)src)[i];
    __half2 a = __floats2half2_rn(v.x, v.y);
    __half2 b = __floats2half2_rn(v.z, v.w);
    ((uint2*)hi)[i] = make_uint2(*reinterpret_cast<unsigned*>(&a),
                                 *reinterpret_cast<unsigned*>(&b));
}

// ------- 2-term fp16 GEMM + fused RMSNorm/RoPE epilogue (cp.async core) -----
__global__ __launch_bounds__(256) void gemm_qk_fused(
    const unsigned* __restrict__ Ah, const unsigned* __restrict__ Al,
    const unsigned* __restrict__ Bh,
    const float* __restrict__ fc, const float* __restrict__ gvec,
    float* __restrict__ xout, float* __restrict__ sqout, int K, int nh)
{
    extern __shared__ unsigned sm[];
    __shared__ float red2[128][4][2];
    __shared__ float gsh[128];
    int rowBase = blockIdx.y * 128;
    int colBase = blockIdx.x * 128;
    const int KW = K >> 1;
    const unsigned* Agh = Ah + (size_t)rowBase * KW;
    const unsigned* Agl = Al + (size_t)rowBase * KW;
    const unsigned* Bgh = Bh + (size_t)colBase * KW;
    CORE_PROLOG_VARS;
    unsigned smb;
    asm("{ .reg .u64 t; cvta.to.shared.u64 t, %1; cvt.u32.u64 %0, t; }" : "=r"(smb) : "l"(sm));
    if (tid < 128) gsh[tid] = gvec[tid];
    int kTiles = K >> 5;
    CPA_MAINLOOP(kTiles);

    // fused epilogue: rmsnorm + rope + scale + sq
    int mo = lane >> 2;
    #pragma unroll
    for (int mi = 0; mi < 4; mi++) {
        #pragma unroll
        for (int half = 0; half < 2; half++) {
            float s1 = 0.f, s2 = 0.f;
            #pragma unroll
            for (int ni = 0; ni < 4; ni++) {
                int c = warpN + ni*8 + (lane & 3)*2;
                float v0 = acc[mi][ni][2*half], v1 = acc[mi][ni][2*half+1];
                s1 += v0*v0 + v1*v1;
                float w0 = v0*gsh[c], w1 = v1*gsh[c+1];
                s2 += w0*w0 + w1*w1;
            }
            s1 += __shfl_xor_sync(0xffffffffu, s1, 1);
            s1 += __shfl_xor_sync(0xffffffffu, s1, 2);
            s2 += __shfl_xor_sync(0xffffffffu, s2, 1);
            s2 += __shfl_xor_sync(0xffffffffu, s2, 2);
            if ((lane & 3) == 0) {
                int rl = warpM + mi*16 + mo + half*8;
                red2[rl][warp & 3][0] = s1;
                red2[rl][warp & 3][1] = s2;
            }
        }
    }
    __syncthreads();
    #pragma unroll
    for (int mi = 0; mi < 4; mi++) {
        #pragma unroll
        for (int half = 0; half < 2; half++) {
            int rl = warpM + mi*16 + mo + half*8;
            float S1 = red2[rl][0][0]+red2[rl][1][0]+red2[rl][2][0]+red2[rl][3][0];
            float S2 = red2[rl][0][1]+red2[rl][1][1]+red2[rl][2][1]+red2[rl][3][1];
            float inv = rsqrtf(S1 * (1.0f/128.0f) + 1e-5f);
            int bs = rowBase + rl;
            int b = bs >> 12, s = bs & 4095;
            float* xp = xout + (((size_t)(b*nh + blockIdx.x))*Ss + s) * HDd;
            #pragma unroll
            for (int ni = 0; ni < 4; ni++) {
                int c = warpN + ni*8 + (lane & 3)*2;
                float a  = acc[mi][ni][2*half]   * inv * gsh[c];
                float b2 = acc[mi][ni][2*half+1] * inv * gsh[c+1];
                float2 cs = ((const float2*)fc)[(size_t)bs * (HDd/2) + (c >> 1)];
                float r0 = (a*cs.x - b2*cs.y) * SCALE_QD;
                float r1 = (a*cs.y + b2*cs.x) * SCALE_QD;
                *(float2*)(xp + c) = make_float2(r0, r1);
            }
            if ((warp & 3) == 0 && (lane & 3) == 0)
                sqout[((size_t)(b*nh + blockIdx.x))*Ss + s] =
                    0.5f * SCALE_QD * SCALE_QD * inv * inv * S2;
        }
    }
}

// ------- 2-term fp16 GEMM, plain epilogue (cp.async core) -------------------
__global__ __launch_bounds__(256) void gemm_f16_2t(
    const unsigned* __restrict__ Ah, const unsigned* __restrict__ Al,
    const unsigned* __restrict__ Bh,
    float* __restrict__ C, int K, int N)
{
    extern __shared__ unsigned sm[];
    int rowBase = blockIdx.y * 128;
    int colBase = blockIdx.x * 128;
    const int KW = K >> 1;
    const unsigned* Agh = Ah + (size_t)rowBase * KW;
    const unsigned* Agl = Al + (size_t)rowBase * KW;
    const unsigned* Bgh = Bh + (size_t)colBase * KW;
    CORE_PROLOG_VARS;
    unsigned smb;
    asm("{ .reg .u64 t; cvta.to.shared.u64 t, %1; cvt.u32.u64 %0, t; }" : "=r"(smb) : "l"(sm));
    int kTiles = K >> 5;
    CPA_MAINLOOP(kTiles);

    #pragma unroll
    for (int mi = 0; mi < 4; mi++) {
        int r = rowBase + warpM + mi * 16 + (lane >> 2);
        #pragma unroll
        for (int ni = 0; ni < 4; ni++) {
            int c = colBase + warpN + ni * 8 + (lane & 3) * 2;
            *(float2*)(C + (size_t)r * N + c) =
                make_float2(acc[mi][ni][0], acc[mi][ni][1]);
            *(float2*)(C + (size_t)(r + 8) * N + c) =
                make_float2(acc[mi][ni][2], acc[mi][ni][3]);
        }
    }
}

// ---- FAVOR tensor-core kernel: C = A[M,128] @ B[128,128]^T + epilogue ------
// mode 0: featQ (row-max + exp); mode 1: featK (subtract sq);
// mode 2: out (mask/denom, writes packed fp16 hi/lo to outh/outl)
__global__ __launch_bounds__(256) void favor_tc(
    const float* __restrict__ A, const float* __restrict__ Bglob,
    const float* __restrict__ sq, const int* __restrict__ mask,
    float* __restrict__ out, unsigned* __restrict__ outh,
    unsigned* __restrict__ outl, int mode)
{
    extern __shared__ unsigned sm[];
    __shared__ float red[128][4];
    int rowBase = blockIdx.y * 128;
    const int K = 128, N = 128;
    const float* Wg;
    if (mode == 2) {
        int bh = blockIdx.y >> 5;
        int b = bh >> 4, h = bh & 15;
        int bhk = b * 8 + (h >> 1);
        Wg = Bglob + (size_t)bhk * 128 * 128;
    } else {
        Wg = Bglob;
    }
    const float* Ag = A + (size_t)rowBase * K;
    CORE_PROLOG_VARS;
    int ldRow  = tid >> 1;
    int ldCol  = (tid & 1) * 16;
    int kpBase = (tid & 1) * 8;
    float ar[16], br[16];
    CORE_LOAD_REGS(0);
    CORE_STORE_SMEM(0);
    __syncthreads();
    for (int t = 0; t < 4; t++) {
        int buf = t & 1;
        bool has = (t + 1 < 4);
        if (has) CORE_LOAD_REGS((t + 1) << 5);
        CORE_COMPUTE3(buf);
        if (has) CORE_STORE_SMEM(buf ^ 1);
        __syncthreads();
    }

    int mo = lane >> 2;
    if (mode == 0) {
        #pragma unroll
        for (int mi = 0; mi < 4; mi++) {
            float m0 = -1e30f, m1 = -1e30f;
            #pragma unroll
            for (int ni = 0; ni < 4; ni++) {
                m0 = fmaxf(m0, fmaxf(acc[mi][ni][0], acc[mi][ni][1]));
                m1 = fmaxf(m1, fmaxf(acc[mi][ni][2], acc[mi][ni][3]));
            }
            m0 = fmaxf(m0, __shfl_xor_sync(0xffffffffu, m0, 1));
            m0 = fmaxf(m0, __shfl_xor_sync(0xffffffffu, m0, 2));
            m1 = fmaxf(m1, __shfl_xor_sync(0xffffffffu, m1, 1));
            m1 = fmaxf(m1, __shfl_xor_sync(0xffffffffu, m1, 2));
            if ((lane & 3) == 0) {
                red[warpM + mi*16 + mo][warp & 3] = m0;
                red[warpM + mi*16 + mo + 8][warp & 3] = m1;
            }
        }
        __syncthreads();
        #pragma unroll
        for (int mi = 0; mi < 4; mi++) {
            int rl = warpM + mi*16 + mo;
            float rm0 = fmaxf(fmaxf(red[rl][0], red[rl][1]),
                              fmaxf(red[rl][2], red[rl][3]));
            float rm1 = fmaxf(fmaxf(red[rl+8][0], red[rl+8][1]),
                              fmaxf(red[rl+8][2], red[rl+8][3]));
            #pragma unroll
            for (int ni = 0; ni < 4; ni++) {
                int c = warpN + ni*8 + (lane & 3)*2;
                *(float2*)(out + (size_t)(rowBase + rl) * N + c) =
                    make_float2(expf(acc[mi][ni][0]-rm0)*INV_SQRT_M + EPSF,
                                expf(acc[mi][ni][1]-rm0)*INV_SQRT_M + EPSF);
                *(float2*)(out + (size_t)(rowBase + rl + 8) * N + c) =
                    make_float2(expf(acc[mi][ni][2]-rm1)*INV_SQRT_M + EPSF,
                                expf(acc[mi][ni][3]-rm1)*INV_SQRT_M + EPSF);
            }
        }
    } else if (mode == 1) {
        #pragma unroll
        for (int mi = 0; mi < 4; mi++) {
            int r0 = rowBase + warpM + mi*16 + mo;
            float s0 = sq[r0], s1 = sq[r0 + 8];
            #pragma unroll
            for (int ni = 0; ni < 4; ni++) {
                int c = warpN + ni*8 + (lane & 3)*2;
                *(float2*)(out + (size_t)r0 * N + c) =
                    make_float2(acc[mi][ni][0]-s0, acc[mi][ni][1]-s0);
                *(float2*)(out + (size_t)(r0 + 8) * N + c) =
                    make_float2(acc[mi][ni][2]-s1, acc[mi][ni][3]-s1);
            }
        }
    } else {
        #pragma unroll
        for (int mi = 0; mi < 4; mi++) {
            int rg = rowBase + warpM + mi*16 + mo;
            #pragma unroll
            for (int half = 0; half < 2; half++) {
                int r = rg + half * 8;
                int s = r & 4095;
                int bh = r >> 12;
                int b = bh >> 4, h = bh & 15;
                float vm = (mask[b * Ss + s] > 0) ? 1.f : 0.f;
                float scale = vm / (sq[r] + EPSF);   // sq carries g_dn here
                size_t base = ((size_t)(b * Ss + s) * (Hh*HDd)) + h * HDd;
                #pragma unroll
                for (int ni = 0; ni < 4; ni++) {
                    int c = warpN + ni*8 + (lane & 3)*2;
                    unsigned hi, lo;
                    hsplit2(acc[mi][ni][2*half]*scale,
                            acc[mi][ni][2*half+1]*scale, hi, lo);
                    size_t w = (base + c) >> 1;
                    outh[w] = hi;
                    outl[w] = lo;
                }
            }
        }
    }
}

// ---------------- key column-max over S (two-stage) -------------------------
__global__ void kmax1_kernel() {
    int bh = blockIdx.x, ch = blockIdx.y, m = threadIdx.x;
    const float* p = g_kxp + ((size_t)bh * Ss + ch * 128) * Mm + m;
    float mx = -1e30f;
    #pragma unroll 4
    for (int s = 0; s < 128; s++) mx = fmaxf(mx, p[(size_t)s * Mm]);
    g_kmaxp[((size_t)bh * 32 + ch) * Mm + m] = mx;
}
__global__ void kmax2_kernel() {
    int bh = blockIdx.x, m = threadIdx.x;
    float mx = -1e30f;
    for (int c = 0; c < 32; c++) mx = fmaxf(mx, g_kmaxp[((size_t)bh*32 + c)*Mm + m]);
    g_kmax[bh * Mm + m] = mx;
}

__global__ void zero_kernel() {
    int i = blockIdx.x * blockDim.x + threadIdx.x;
    if (i < Bb*HKk*Mm*HDd) g_kvT[i] = 0.f;
    if (i < Bb*HKk*Mm)     g_ksum[i] = 0.f;
}

// -- kvT[d,m] += sum_s phi_k[s,m]*v[s,d] ; ksum[m] += sum_s phi_k[s,m] -------
__global__ __launch_bounds__(256) void kv_kernel(const int* __restrict__ mask)
{
    __shared__ float kps[16][128];
    __shared__ float vs [16][128];
    __shared__ float kmx[128];
    __shared__ float vmask[128];
    int bh = blockIdx.y;
    int b = bh / HKk, hk = bh % HKk;
    int s0 = blockIdx.x * 128;
    int tid = threadIdx.x;
    int tr = tid >> 4, tc = tid & 15;
    if (tid < 128) {
        kmx[tid] = g_kmax[bh * Mm + tid];
        vmask[tid] = (mask[b * Ss + s0 + tid] > 0) ? 1.f : 0.f;
    }
    __syncthreads();

    const float* KX = g_kxp + ((size_t)bh * Ss + s0) * Mm;
    const float* V  = g_v + ((size_t)(b * Ss + s0)) * (HKk*HDd) + hk * HDd;
    float acc[8][8];
    #pragma unroll
    for (int i=0;i<8;i++)
        #pragma unroll
        for (int j=0;j<8;j++) acc[i][j]=0.f;
    float ksacc = 0.f;

    for (int sc = 0; sc < 128; sc += 16) {
        #pragma unroll
        for (int it = 0; it < 2; it++) {
            int idx = tid + it * 256;
            int r = idx >> 5;
            int c4 = (idx & 31) << 2;
            float vm = vmask[sc + r];
            float4 x4 = *(const float4*)(KX + (size_t)(sc + r) * Mm + c4);
            kps[r][c4+0] = (expf(x4.x - kmx[c4+0]) * INV_SQRT_M + EPSF) * vm;
            kps[r][c4+1] = (expf(x4.y - kmx[c4+1]) * INV_SQRT_M + EPSF) * vm;
            kps[r][c4+2] = (expf(x4.z - kmx[c4+2]) * INV_SQRT_M + EPSF) * vm;
            kps[r][c4+3] = (expf(x4.w - kmx[c4+3]) * INV_SQRT_M + EPSF) * vm;
            float4 v4 = *(const float4*)(V + (size_t)(sc + r) * (HKk*HDd) + c4);
            vs[r][c4+0]=v4.x; vs[r][c4+1]=v4.y; vs[r][c4+2]=v4.z; vs[r][c4+3]=v4.w;
        }
        __syncthreads();
        #pragma unroll
        for (int ssi = 0; ssi < 16; ssi++) {
            float ra[8], rb[8];
            #pragma unroll
            for (int i=0;i<8;i++) ra[i]=kps[ssi][tr*8+i];
            #pragma unroll
            for (int j=0;j<8;j++) rb[j]=vs[ssi][tc*8+j];
            #pragma unroll
            for (int i=0;i<8;i++)
                #pragma unroll
                for (int j=0;j<8;j++) acc[i][j] += ra[i]*rb[j];
        }
        if (tid < 128) {
            #pragma unroll
            for (int ssi = 0; ssi < 16; ssi++) ksacc += kps[ssi][tid];
        }
        __syncthreads();
    }
    float* KV = g_kvT + (size_t)bh * Mm * HDd;
    #pragma unroll
    for (int i = 0; i < 8; i++)
        #pragma unroll
        for (int j = 0; j < 8; j++)
            atomicAdd(&KV[(size_t)(tc*8+j)*Mm + tr*8+i], acc[i][j]);
    if (tid < 128) atomicAdd(&g_ksum[bh * Mm + tid], ksacc);
}

// -------------- denominators: dn[row] = qphi[row,:]·ksum[bhk,:] -------------
__global__ __launch_bounds__(256) void dn_kernel() {
    int warp = threadIdx.x >> 5, lane = threadIdx.x & 31;
    int row = blockIdx.x * 8 + warp;
    int bh = row >> 12;
    int b = bh >> 4, h = bh & 15;
    int bhk = b * 8 + (h >> 1);
    float4 q = *(const float4*)(g_qphi + (size_t)row * Mm + lane * 4);
    float4 s = *(const float4*)(g_ksum + bhk * Mm + lane * 4);
    float v = q.x*s.x + q.y*s.y + q.z*s.z + q.w*s.w;
    #pragma unroll
    for (int o = 16; o > 0; o >>= 1) v += __shfl_xor_sync(0xffffffffu, v, o);
    if (lane == 0) g_dn[row] = v;
}

// ------------------------------- launch -------------------------------------
extern "C" void kernel_launch(void* const* d_in, const int* in_sizes, int n_in,
                              void* d_out, int out_size)
{
    const float* x    = (const float*)d_in[0];
    const int*   mask = (const int*)  d_in[1];
    const float* fc   = (const float*)d_in[2];
    const float* wq   = (const float*)d_in[3];
    const float* wk   = (const float*)d_in[4];
    const float* wv   = (const float*)d_in[5];
    const float* wo   = (const float*)d_in[6];
    const float* gq   = (const float*)d_in[7];
    const float* gk   = (const float*)d_in[8];
    const float* proj = (const float*)d_in[9];
    float* out = (float*)d_out;

    float *pv, *pqx, *pkx, *psqq, *psqk, *pqphi, *pkxp, *pkvT, *pdn;
    cudaGetSymbolAddress((void**)&pv,   g_v);
    cudaGetSymbolAddress((void**)&pqx,  g_qx);
    cudaGetSymbolAddress((void**)&pkx,  g_kx);
    cudaGetSymbolAddress((void**)&psqq, g_sqq);
    cudaGetSymbolAddress((void**)&psqk, g_sqk);
    cudaGetSymbolAddress((void**)&pqphi,g_qphi);
    cudaGetSymbolAddress((void**)&pkxp, g_kxp);
    cudaGetSymbolAddress((void**)&pkvT, g_kvT);
    cudaGetSymbolAddress((void**)&pdn,  g_dn);

    unsigned *xfh,*xfl,*wqh,*wkh,*wvh,*woh,*aoh,*aol;
    cudaGetSymbolAddress((void**)&xfh, g_xfh); cudaGetSymbolAddress((void**)&xfl, g_xfl);
    cudaGetSymbolAddress((void**)&wqh, g_wqh);
    cudaGetSymbolAddress((void**)&wkh, g_wkh);
    cudaGetSymbolAddress((void**)&wvh, g_wvh);
    cudaGetSymbolAddress((void**)&woh, g_woh);
    cudaGetSymbolAddress((void**)&aoh, g_aoh); cudaGetSymbolAddress((void**)&aol, g_aol);

    cudaFuncSetAttribute(gemm_qk_fused, cudaFuncAttributeMaxDynamicSharedMemorySize, DSMEM3_BYTES);
    cudaFuncSetAttribute(gemm_f16_2t,   cudaFuncAttributeMaxDynamicSharedMemorySize, DSMEM3_BYTES);
    cudaFuncSetAttribute(favor_tc,      cudaFuncAttributeMaxDynamicSharedMemorySize, DSMEM_BYTES);

    // pre-split operands (all fp16)
    split_f16_kernel <<<(Bb*Ss*DIMm/4 + 255)/256, 256>>>(x,  xfh, xfl, Bb*Ss*DIMm/4);
    split_f16h_kernel<<<(Hh*HDd*DIMm/4 + 255)/256, 256>>>(wq, wqh, Hh*HDd*DIMm/4);
    split_f16h_kernel<<<(HKk*HDd*DIMm/4 + 255)/256, 256>>>(wk, wkh, HKk*HDd*DIMm/4);
    split_f16h_kernel<<<(HKk*HDd*DIMm/4 + 255)/256, 256>>>(wv, wvh, HKk*HDd*DIMm/4);
    split_f16h_kernel<<<(DIMm*Hh*HDd/4 + 255)/256, 256>>>(wo, woh, DIMm*Hh*HDd/4);

    // Q,K projections (2-term fp16, cp.async/ldmatrix) + fused RMSNorm/RoPE
    gemm_qk_fused<<<dim3(Hh,  (Bb*Ss)/128), 256, DSMEM3_BYTES>>>(
        xfh, xfl, wqh, fc, gq, pqx, psqq, DIMm, Hh);
    gemm_qk_fused<<<dim3(HKk, (Bb*Ss)/128), 256, DSMEM3_BYTES>>>(
        xfh, xfl, wkh, fc, gk, pkx, psqk, DIMm, HKk);
    // V projection
    gemm_f16_2t<<<dim3((HKk*HDd)/128, (Bb*Ss)/128), 256, DSMEM3_BYTES>>>(
        xfh, xfl, wvh, pv, DIMm, HKk*HDd);

    // FAVOR feature projections on tensor cores (3-term bf16, fp32 inputs)
    favor_tc<<<dim3(1, (Bb*Hh*Ss)/128),  256, DSMEM_BYTES>>>(
        pqx, proj, psqq, mask, pqphi, 0, 0, 0);
    favor_tc<<<dim3(1, (Bb*HKk*Ss)/128), 256, DSMEM_BYTES>>>(
        pkx, proj, psqk, mask, pkxp, 0, 0, 1);

    // key column max over S
    kmax1_kernel<<<dim3(Bb*HKk, 32), 128>>>();
    kmax2_kernel<<<Bb*HKk, 128>>>();

    // kv / ksum contraction (kv stored transposed)
    zero_kernel<<<(Bb*HKk*Mm*HDd + 255)/256, 256>>>();
    kv_kernel<<<dim3(Ss/128, Bb*HKk), 256>>>(mask);

    // denominators, then attention output (writes fp16 hi/lo directly)
    dn_kernel<<<(Bb*Hh*Ss)/8, 256>>>();
    favor_tc<<<dim3(1, (Bb*Hh*Ss)/128), 256, DSMEM_BYTES>>>(
        pqphi, pkvT, pdn, mask, 0, aoh, aol, 2);

    // output projection
    gemm_f16_2t<<<dim3(DIMm/128, (Bb*Ss)/128), 256, DSMEM3_BYTES>>>(
        aoh, aol, woh, out, Hh*HDd, DIMm);
}

// round 12
// speedup vs baseline: 3.1954x; 1.0079x over previous
#include <cuda_runtime.h>
#include <cuda_bf16.h>
#include <cuda_fp16.h>
#include <math.h>
#include <stdint.h>

#define Bb  2
#define Ss  4096
#define DIMm 2048
#define Hh  16
#define HKk 8
#define HDd 128
#define Mm  128

#define INV_SQRT_M 0.08838834764831845f   // 128^{-0.5}
#define SCALE_QD   0.2973017787506803f    // 128^{-0.25}
#define EPSF 1e-6f

// ---------------- scratch (device globals; no allocations allowed) ----------
__device__ float g_v   [Bb*Ss*HKk*HDd];
__device__ float g_sqq [Bb*Hh*Ss];
__device__ float g_sqk [Bb*HKk*Ss];
__device__ float g_qphi[Bb*Hh*Ss*Mm];      // [b,h,s,m] fp32
__device__ float g_kxp [Bb*HKk*Ss*Mm];     // pre-exp key features fp32
__device__ unsigned g_kmaxe[Bb*HKk*Mm];    // encoded column max
__device__ float g_kvT [Bb*HKk*HDd*Mm];    // TRANSPOSED kv: [d][m]
__device__ float g_ksum[Bb*HKk*Mm];
__device__ float g_dn  [Bb*Hh*Ss];         // denominators

// pre-split operand arrays (packed x2 words)
#define XW (Bb*Ss*DIMm/2)
__device__ unsigned g_xfh [XW];            // x fp16 hi  (q,k,v GEMMs)
__device__ unsigned g_xfl [XW];            // x fp16 lo
__device__ unsigned g_wqh [Hh*HDd*DIMm/2];    // fp16 hi only
__device__ unsigned g_wkh [HKk*HDd*DIMm/2];
__device__ unsigned g_wvh [HKk*HDd*DIMm/2];
__device__ unsigned g_woh [DIMm*Hh*HDd/2];
__device__ unsigned g_aoh [Bb*Ss*Hh*HDd/2];   // attention out, fp16 hi
__device__ unsigned g_aol [Bb*Ss*Hh*HDd/2];   // attention out, fp16 lo
// bf16 hi/lo packed (favor operands)
__device__ unsigned g_qxh [Bb*Hh*Ss*HDd/2];
__device__ unsigned g_qxl [Bb*Hh*Ss*HDd/2];
__device__ unsigned g_kxh [Bb*HKk*Ss*HDd/2];
__device__ unsigned g_kxl [Bb*HKk*Ss*HDd/2];
__device__ unsigned g_pjh [Mm*HDd/2];
__device__ unsigned g_pjl [Mm*HDd/2];

// ---------------------------- helpers ---------------------------------------
__device__ __forceinline__ void bfsplit2(float x0, float x1, unsigned& hi, unsigned& lo) {
    __nv_bfloat162 h2 = __floats2bfloat162_rn(x0, x1);
    float2 hf = __bfloat1622float2(h2);
    __nv_bfloat162 l2 = __floats2bfloat162_rn(x0 - hf.x, x1 - hf.y);
    hi = *reinterpret_cast<unsigned*>(&h2);
    lo = *reinterpret_cast<unsigned*>(&l2);
}
__device__ __forceinline__ void hsplit2(float x0, float x1, unsigned& hi, unsigned& lo) {
    __half2 h2 = __floats2half2_rn(x0, x1);
    float2 hf = __half22float2(h2);
    __half2 l2 = __floats2half2_rn(x0 - hf.x, x1 - hf.y);
    hi = *reinterpret_cast<unsigned*>(&h2);
    lo = *reinterpret_cast<unsigned*>(&l2);
}
// order-preserving float<->unsigned encoding for atomicMax
__device__ __forceinline__ unsigned encf(float f) {
    int s = __float_as_int(f);
    return (s < 0) ? ~(unsigned)s : ((unsigned)s | 0x80000000u);
}
__device__ __forceinline__ float decf(unsigned u) {
    int s = (u & 0x80000000u) ? (int)(u & 0x7FFFFFFFu) : ~(int)u;
    return __int_as_float(s);
}

__device__ __forceinline__ void mma_bf16(float* d, const unsigned* a, const unsigned* b) {
    asm volatile(
        "mma.sync.aligned.m16n8k16.row.col.f32.bf16.bf16.f32 "
        "{%0,%1,%2,%3}, {%4,%5,%6,%7}, {%8,%9}, {%0,%1,%2,%3};\n"
        : "+f"(d[0]), "+f"(d[1]), "+f"(d[2]), "+f"(d[3])
        : "r"(a[0]), "r"(a[1]), "r"(a[2]), "r"(a[3]),
          "r"(b[0]), "r"(b[1]));
}
__device__ __forceinline__ void mma_f16(float* d, const unsigned* a, const unsigned* b) {
    asm volatile(
        "mma.sync.aligned.m16n8k16.row.col.f32.f16.f16.f32 "
        "{%0,%1,%2,%3}, {%4,%5,%6,%7}, {%8,%9}, {%0,%1,%2,%3};\n"
        : "+f"(d[0]), "+f"(d[1]), "+f"(d[2]), "+f"(d[3])
        : "r"(a[0]), "r"(a[1]), "r"(a[2]), "r"(a[3]),
          "r"(b[0]), "r"(b[1]));
}

#define CP16(dst, src) asm volatile("cp.async.cg.shared.global [%0], [%1], 16;\n" :: "r"(dst), "l"(src) : "memory")
#define CP_COMMIT()    asm volatile("cp.async.commit_group;\n" ::: "memory")
#define CP_WAIT0()     asm volatile("cp.async.wait_group 0;\n" ::: "memory")
#define LDMX4(r, addr) asm volatile( \
    "ldmatrix.sync.aligned.m8n8.x4.shared.b16 {%0,%1,%2,%3}, [%4];" \
    : "=r"((r)[0]), "=r"((r)[1]), "=r"((r)[2]), "=r"((r)[3]) : "r"(addr))

// ===== cp.async/ldmatrix smem layouts ========================================
// per array-stage: 128 rows x 20 words (16 kpairs used + 4 pad) = 2560 words
#define P3 2560u
#define POFF_AH(st) ((unsigned)(st)*P3)
#define POFF_AL(st) (2u*P3 + (unsigned)(st)*P3)
#define POFF_BH(st) (4u*P3 + (unsigned)(st)*P3)
#define POFF_BL(st) (6u*P3 + (unsigned)(st)*P3)
#define DSMEM3_BYTES (6*2560*4)   // 61440 (3 arrays, fp16 2-term)
#define DSMEM4_BYTES (8*2560*4)   // 81920 (4 arrays, bf16 3-term)

// ---- 2-term fp16 (GEMMs) ----
#define CPA_LOAD(t0, st)                                                       \
    {                                                                          \
        int row = tid >> 1;                                                    \
        int ch  = (tid & 1) * 8;                                               \
        size_t g = (size_t)row * KW + ((size_t)(t0) << 4) + ch;                \
        unsigned d;                                                            \
        d = smb + (POFF_AH(st) + (unsigned)row*20u + ch)*4u;                   \
        CP16(d, Agh + g); CP16(d+16u, Agh + g + 4);                            \
        d = smb + (POFF_AL(st) + (unsigned)row*20u + ch)*4u;                   \
        CP16(d, Agl + g); CP16(d+16u, Agl + g + 4);                            \
        d = smb + (POFF_BH(st) + (unsigned)row*20u + ch)*4u;                   \
        CP16(d, Bgh + g); CP16(d+16u, Bgh + g + 4);                            \
        CP_COMMIT();                                                           \
    }

#define CPA_COMPUTE(st)                                                        \
    {                                                                          \
        _Pragma("unroll")                                                      \
        for (int h = 0; h < 2; h++) {                                          \
            int arow = (lane & 7) + ((lane >> 3) & 1) * 8;                     \
            int achw = 8*h + ((lane >> 4) & 1) * 4;                            \
            int brow = (lane & 7) + ((lane >> 4) & 1) * 8;                     \
            int bchw = 8*h + ((lane >> 3) & 1) * 4;                            \
            unsigned afh[4][4], afl[4][4], bf[2][4];                           \
            _Pragma("unroll")                                                  \
            for (int mi = 0; mi < 4; mi++) {                                   \
                unsigned ra = smb + (POFF_AH(st) +                             \
                    (unsigned)(warpM + mi*16 + arow)*20u + achw)*4u;           \
                LDMX4(afh[mi], ra);                                            \
                unsigned rl = smb + (POFF_AL(st) +                             \
                    (unsigned)(warpM + mi*16 + arow)*20u + achw)*4u;           \
                LDMX4(afl[mi], rl);                                            \
            }                                                                  \
            LDMX4(bf[0], smb + (POFF_BH(st) +                                  \
                (unsigned)(warpN + brow)*20u + bchw)*4u);                      \
            LDMX4(bf[1], smb + (POFF_BH(st) +                                  \
                (unsigned)(warpN + 16 + brow)*20u + bchw)*4u);                 \
            _Pragma("unroll")                                                  \
            for (int mi = 0; mi < 4; mi++) {                                   \
                mma_f16(acc[mi][0], afh[mi], &bf[0][0]);                       \
                mma_f16(acc[mi][0], afl[mi], &bf[0][0]);                       \
                mma_f16(acc[mi][1], afh[mi], &bf[0][2]);                       \
                mma_f16(acc[mi][1], afl[mi], &bf[0][2]);                       \
                mma_f16(acc[mi][2], afh[mi], &bf[1][0]);                       \
                mma_f16(acc[mi][2], afl[mi], &bf[1][0]);                       \
                mma_f16(acc[mi][3], afh[mi], &bf[1][2]);                       \
                mma_f16(acc[mi][3], afl[mi], &bf[1][2]);                       \
            }                                                                  \
        }                                                                      \
    }

#define CPA_MAINLOOP(KTILES)                                                   \
    CPA_LOAD(0, 0);                                                            \
    CP_WAIT0();                                                                \
    __syncthreads();                                                           \
    for (int t = 0; t < (KTILES); t++) {                                       \
        int st = t & 1;                                                        \
        bool has = (t + 1 < (KTILES));                                         \
        if (has) CPA_LOAD(t + 1, st ^ 1);                                      \
        CPA_COMPUTE(st);                                                       \
        if (has) CP_WAIT0();                                                   \
        __syncthreads();                                                       \
    }

// ---- 3-term bf16 (favor kernels), 4 arrays ----
#define CPA4_LOAD(t0, st)                                                      \
    {                                                                          \
        int row = tid >> 1;                                                    \
        int ch  = (tid & 1) * 8;                                               \
        size_t g = (size_t)row * KW + ((size_t)(t0) << 4) + ch;                \
        unsigned d;                                                            \
        d = smb + (POFF_AH(st) + (unsigned)row*20u + ch)*4u;                   \
        CP16(d, Agh + g); CP16(d+16u, Agh + g + 4);                            \
        d = smb + (POFF_AL(st) + (unsigned)row*20u + ch)*4u;                   \
        CP16(d, Agl + g); CP16(d+16u, Agl + g + 4);                            \
        d = smb + (POFF_BH(st) + (unsigned)row*20u + ch)*4u;                   \
        CP16(d, Bgh + g); CP16(d+16u, Bgh + g + 4);                            \
        d = smb + (POFF_BL(st) + (unsigned)row*20u + ch)*4u;                   \
        CP16(d, Bgl + g); CP16(d+16u, Bgl + g + 4);                            \
        CP_COMMIT();                                                           \
    }

#define CPA4_COMPUTE(st)                                                       \
    {                                                                          \
        _Pragma("unroll")                                                      \
        for (int h = 0; h < 2; h++) {                                          \
            int arow = (lane & 7) + ((lane >> 3) & 1) * 8;                     \
            int achw = 8*h + ((lane >> 4) & 1) * 4;                            \
            int brow = (lane & 7) + ((lane >> 4) & 1) * 8;                     \
            int bchw = 8*h + ((lane >> 3) & 1) * 4;                            \
            unsigned afh[4][4], afl[4][4], bfh[2][4], bfl[2][4];               \
            _Pragma("unroll")                                                  \
            for (int mi = 0; mi < 4; mi++) {                                   \
                LDMX4(afh[mi], smb + (POFF_AH(st) +                            \
                    (unsigned)(warpM + mi*16 + arow)*20u + achw)*4u);          \
                LDMX4(afl[mi], smb + (POFF_AL(st) +                            \
                    (unsigned)(warpM + mi*16 + arow)*20u + achw)*4u);          \
            }                                                                  \
            LDMX4(bfh[0], smb + (POFF_BH(st) +                                 \
                (unsigned)(warpN + brow)*20u + bchw)*4u);                      \
            LDMX4(bfh[1], smb + (POFF_BH(st) +                                 \
                (unsigned)(warpN + 16 + brow)*20u + bchw)*4u);                 \
            LDMX4(bfl[0], smb + (POFF_BL(st) +                                 \
                (unsigned)(warpN + brow)*20u + bchw)*4u);                      \
            LDMX4(bfl[1], smb + (POFF_BL(st) +                                 \
                (unsigned)(warpN + 16 + brow)*20u + bchw)*4u);                 \
            _Pragma("unroll")                                                  \
            for (int mi = 0; mi < 4; mi++) {                                   \
                mma_bf16(acc[mi][0], afh[mi], &bfh[0][0]);                     \
                mma_bf16(acc[mi][0], afl[mi], &bfh[0][0]);                     \
                mma_bf16(acc[mi][0], afh[mi], &bfl[0][0]);                     \
                mma_bf16(acc[mi][1], afh[mi], &bfh[0][2]);                     \
                mma_bf16(acc[mi][1], afl[mi], &bfh[0][2]);                     \
                mma_bf16(acc[mi][1], afh[mi], &bfl[0][2]);                     \
                mma_bf16(acc[mi][2], afh[mi], &bfh[1][0]);                     \
                mma_bf16(acc[mi][2], afl[mi], &bfh[1][0]);                     \
                mma_bf16(acc[mi][2], afh[mi], &bfl[1][0]);                     \
                mma_bf16(acc[mi][3], afh[mi], &bfh[1][2]);                     \
                mma_bf16(acc[mi][3], afl[mi], &bfh[1][2]);                     \
                mma_bf16(acc[mi][3], afh[mi], &bfl[1][2]);                     \
            }                                                                  \
        }                                                                      \
    }

#define CPA4_MAINLOOP(KTILES)                                                  \
    CPA4_LOAD(0, 0);                                                           \
    CP_WAIT0();                                                                \
    __syncthreads();                                                           \
    for (int t = 0; t < (KTILES); t++) {                                       \
        int st = t & 1;                                                        \
        bool has = (t + 1 < (KTILES));                                         \
        if (has) CPA4_LOAD(t + 1, st ^ 1);                                     \
        CPA4_COMPUTE(st);                                                      \
        if (has) CP_WAIT0();                                                   \
        __syncthreads();                                                       \
    }

#define CORE_PROLOG_VARS                                                       \
    int tid  = threadIdx.x;                                                    \
    int lane = tid & 31;                                                       \
    int warp = tid >> 5;                                                       \
    int warpM = (warp >> 2) * 64;                                              \
    int warpN = (warp & 3) * 32;                                               \
    float acc[4][4][4];                                                        \
    _Pragma("unroll")                                                          \
    for (int mi = 0; mi < 4; mi++)                                             \
        _Pragma("unroll")                                                      \
        for (int ni = 0; ni < 4; ni++)                                         \
            _Pragma("unroll")                                                  \
            for (int e = 0; e < 4; e++) acc[mi][ni][e] = 0.f;

// ---------------- fp32 -> packed hi/lo split kernels ------------------------
__global__ __launch_bounds__(256) void split_f16_kernel(
    const float* __restrict__ src, unsigned* __restrict__ hi,
    unsigned* __restrict__ lo, int n4)
{
    int i = blockIdx.x * blockDim.x + threadIdx.x;
    if (i >= n4) return;
    float4 v = ((const float4*)src)[i];
    unsigned h0, l0, h1, l1;
    hsplit2(v.x, v.y, h0, l0);
    hsplit2(v.z, v.w, h1, l1);
    ((uint2*)hi)[i] = make_uint2(h0, h1);
    ((uint2*)lo)[i] = make_uint2(l0, l1);
}
__global__ __launch_bounds__(256) void split_f16h_kernel(
    const float* __restrict__ src, unsigned* __restrict__ hi, int n4)
{
    int i = blockIdx.x * blockDim.x + threadIdx.x;
    if (i >= n4) return;
    float4 v = ((const float4*)src)[i];
    __half2 a = __floats2half2_rn(v.x, v.y);
    __half2 b = __floats2half2_rn(v.z, v.w);
    ((uint2*)hi)[i] = make_uint2(*reinterpret_cast<unsigned*>(&a),
                                 *reinterpret_cast<unsigned*>(&b));
}
__global__ __launch_bounds__(256) void split_bf16_kernel(
    const float* __restrict__ src, unsigned* __restrict__ hi,
    unsigned* __restrict__ lo, int n4)
{
    int i = blockIdx.x * blockDim.x + threadIdx.x;
    if (i >= n4) return;
    float4 v = ((const float4*)src)[i];
    unsigned h0, l0, h1, l1;
    bfsplit2(v.x, v.y, h0, l0);
    bfsplit2(v.z, v.w, h1, l1);
    ((uint2*)hi)[i] = make_uint2(h0, h1);
    ((uint2*)lo)[i] = make_uint2(l0, l1);
}

// ------- 2-term fp16 GEMM + fused RMSNorm/RoPE epilogue (cp.async core) -----
// writes qx/kx as packed bf16 hi/lo + sq
__global__ __launch_bounds__(256) void gemm_qk_fused(
    const unsigned* __restrict__ Ah, const unsigned* __restrict__ Al,
    const unsigned* __restrict__ Bh,
    const float* __restrict__ fc, const float* __restrict__ gvec,
    unsigned* __restrict__ xouth, unsigned* __restrict__ xoutl,
    float* __restrict__ sqout, int K, int nh)
{
    extern __shared__ unsigned sm[];
    __shared__ float red2[128][4][2];
    __shared__ float gsh[128];
    int rowBase = blockIdx.y * 128;
    int colBase = blockIdx.x * 128;
    const int KW = K >> 1;
    const unsigned* Agh = Ah + (size_t)rowBase * KW;
    const unsigned* Agl = Al + (size_t)rowBase * KW;
    const unsigned* Bgh = Bh + (size_t)colBase * KW;
    CORE_PROLOG_VARS;
    unsigned smb;
    asm("{ .reg .u64 t; cvta.to.shared.u64 t, %1; cvt.u32.u64 %0, t; }" : "=r"(smb) : "l"(sm));
    if (tid < 128) gsh[tid] = gvec[tid];
    int kTiles = K >> 5;
    CPA_MAINLOOP(kTiles);

    // fused epilogue: rmsnorm + rope + scale + sq; write packed bf16 hi/lo
    int mo = lane >> 2;
    #pragma unroll
    for (int mi = 0; mi < 4; mi++) {
        #pragma unroll
        for (int half = 0; half < 2; half++) {
            float s1 = 0.f, s2 = 0.f;
            #pragma unroll
            for (int ni = 0; ni < 4; ni++) {
                int c = warpN + ni*8 + (lane & 3)*2;
                float v0 = acc[mi][ni][2*half], v1 = acc[mi][ni][2*half+1];
                s1 += v0*v0 + v1*v1;
                float w0 = v0*gsh[c], w1 = v1*gsh[c+1];
                s2 += w0*w0 + w1*w1;
            }
            s1 += __shfl_xor_sync(0xffffffffu, s1, 1);
            s1 += __shfl_xor_sync(0xffffffffu, s1, 2);
            s2 += __shfl_xor_sync(0xffffffffu, s2, 1);
            s2 += __shfl_xor_sync(0xffffffffu, s2, 2);
            if ((lane & 3) == 0) {
                int rl = warpM + mi*16 + mo + half*8;
                red2[rl][warp & 3][0] = s1;
                red2[rl][warp & 3][1] = s2;
            }
        }
    }
    __syncthreads();
    #pragma unroll
    for (int mi = 0; mi < 4; mi++) {
        #pragma unroll
        for (int half = 0; half < 2; half++) {
            int rl = warpM + mi*16 + mo + half*8;
            float S1 = red2[rl][0][0]+red2[rl][1][0]+red2[rl][2][0]+red2[rl][3][0];
            float S2 = red2[rl][0][1]+red2[rl][1][1]+red2[rl][2][1]+red2[rl][3][1];
            float inv = rsqrtf(S1 * (1.0f/128.0f) + 1e-5f);
            int bs = rowBase + rl;
            int b = bs >> 12, s = bs & 4095;
            size_t rowoff = (((size_t)(b*nh + blockIdx.x))*Ss + s) * (HDd/2);
            #pragma unroll
            for (int ni = 0; ni < 4; ni++) {
                int c = warpN + ni*8 + (lane & 3)*2;
                float a  = acc[mi][ni][2*half]   * inv * gsh[c];
                float b2 = acc[mi][ni][2*half+1] * inv * gsh[c+1];
                float2 cs = ((const float2*)fc)[(size_t)bs * (HDd/2) + (c >> 1)];
                float r0 = (a*cs.x - b2*cs.y) * SCALE_QD;
                float r1 = (a*cs.y + b2*cs.x) * SCALE_QD;
                unsigned hi, lo;
                bfsplit2(r0, r1, hi, lo);
                xouth[rowoff + (c >> 1)] = hi;
                xoutl[rowoff + (c >> 1)] = lo;
            }
            if ((warp & 3) == 0 && (lane & 3) == 0)
                sqout[((size_t)(b*nh + blockIdx.x))*Ss + s] =
                    0.5f * SCALE_QD * SCALE_QD * inv * inv * S2;
        }
    }
}

// ------- 2-term fp16 GEMM, plain epilogue (cp.async core) -------------------
__global__ __launch_bounds__(256) void gemm_f16_2t(
    const unsigned* __restrict__ Ah, const unsigned* __restrict__ Al,
    const unsigned* __restrict__ Bh,
    float* __restrict__ C, int K, int N)
{
    extern __shared__ unsigned sm[];
    int rowBase = blockIdx.y * 128;
    int colBase = blockIdx.x * 128;
    const int KW = K >> 1;
    const unsigned* Agh = Ah + (size_t)rowBase * KW;
    const unsigned* Agl = Al + (size_t)rowBase * KW;
    const unsigned* Bgh = Bh + (size_t)colBase * KW;
    CORE_PROLOG_VARS;
    unsigned smb;
    asm("{ .reg .u64 t; cvta.to.shared.u64 t, %1; cvt.u32.u64 %0, t; }" : "=r"(smb) : "l"(sm));
    int kTiles = K >> 5;
    CPA_MAINLOOP(kTiles);

    #pragma unroll
    for (int mi = 0; mi < 4; mi++) {
        int r = rowBase + warpM + mi * 16 + (lane >> 2);
        #pragma unroll
        for (int ni = 0; ni < 4; ni++) {
            int c = colBase + warpN + ni * 8 + (lane & 3) * 2;
            *(float2*)(C + (size_t)r * N + c) =
                make_float2(acc[mi][ni][0], acc[mi][ni][1]);
            *(float2*)(C + (size_t)(r + 8) * N + c) =
                make_float2(acc[mi][ni][2], acc[mi][ni][3]);
        }
    }
}

// ---- favor modes 0/1 with cp.async/ldmatrix 3-term bf16 core ---------------
// mode 0: featQ (row-max + exp -> qphi fp32)
// mode 1: featK (subtract sq -> kxp fp32, fold column max via atomicMax)
__global__ __launch_bounds__(256) void favor_cpa(
    const unsigned* __restrict__ Ah, const unsigned* __restrict__ Al,
    const unsigned* __restrict__ Bh, const unsigned* __restrict__ Bl,
    const float* __restrict__ sq, float* __restrict__ out,
    unsigned* __restrict__ kmaxe, int mode)
{
    extern __shared__ unsigned sm[];
    __shared__ float red[128][4];
    __shared__ unsigned smax[128];
    int rowBase = blockIdx.y * 128;
    const int KW = 64, N = 128;
    const unsigned* Agh = Ah + (size_t)rowBase * KW;
    const unsigned* Agl = Al + (size_t)rowBase * KW;
    const unsigned* Bgh = Bh;
    const unsigned* Bgl = Bl;
    CORE_PROLOG_VARS;
    unsigned smb;
    asm("{ .reg .u64 t; cvta.to.shared.u64 t, %1; cvt.u32.u64 %0, t; }" : "=r"(smb) : "l"(sm));
    if (mode == 1 && tid < 128) smax[tid] = 0u;
    CPA4_MAINLOOP(4);

    int mo = lane >> 2;
    if (mode == 0) {
        #pragma unroll
        for (int mi = 0; mi < 4; mi++) {
            float m0 = -1e30f, m1 = -1e30f;
            #pragma unroll
            for (int ni = 0; ni < 4; ni++) {
                m0 = fmaxf(m0, fmaxf(acc[mi][ni][0], acc[mi][ni][1]));
                m1 = fmaxf(m1, fmaxf(acc[mi][ni][2], acc[mi][ni][3]));
            }
            m0 = fmaxf(m0, __shfl_xor_sync(0xffffffffu, m0, 1));
            m0 = fmaxf(m0, __shfl_xor_sync(0xffffffffu, m0, 2));
            m1 = fmaxf(m1, __shfl_xor_sync(0xffffffffu, m1, 1));
            m1 = fmaxf(m1, __shfl_xor_sync(0xffffffffu, m1, 2));
            if ((lane & 3) == 0) {
                red[warpM + mi*16 + mo][warp & 3] = m0;
                red[warpM + mi*16 + mo + 8][warp & 3] = m1;
            }
        }
        __syncthreads();
        #pragma unroll
        for (int mi = 0; mi < 4; mi++) {
            int rl = warpM + mi*16 + mo;
            float rm0 = fmaxf(fmaxf(red[rl][0], red[rl][1]),
                              fmaxf(red[rl][2], red[rl][3]));
            float rm1 = fmaxf(fmaxf(red[rl+8][0], red[rl+8][1]),
                              fmaxf(red[rl+8][2], red[rl+8][3]));
            #pragma unroll
            for (int ni = 0; ni < 4; ni++) {
                int c = warpN + ni*8 + (lane & 3)*2;
                *(float2*)(out + (size_t)(rowBase + rl) * N + c) =
                    make_float2(__expf(acc[mi][ni][0]-rm0)*INV_SQRT_M + EPSF,
                                __expf(acc[mi][ni][1]-rm0)*INV_SQRT_M + EPSF);
                *(float2*)(out + (size_t)(rowBase + rl + 8) * N + c) =
                    make_float2(__expf(acc[mi][ni][2]-rm1)*INV_SQRT_M + EPSF,
                                __expf(acc[mi][ni][3]-rm1)*INV_SQRT_M + EPSF);
            }
        }
    } else {
        // mode 1: subtract sq, write kxp, and fold column max
        #pragma unroll
        for (int ni = 0; ni < 4; ni++) {
            float cm0 = -1e30f, cm1 = -1e30f;   // col maxima for e=0,1
            #pragma unroll
            for (int mi = 0; mi < 4; mi++) {
                int r0 = rowBase + warpM + mi*16 + mo;
                float s0 = sq[r0], s1 = sq[r0 + 8];
                int c = warpN + ni*8 + (lane & 3)*2;
                float o00 = acc[mi][ni][0]-s0, o01 = acc[mi][ni][1]-s0;
                float o10 = acc[mi][ni][2]-s1, o11 = acc[mi][ni][3]-s1;
                *(float2*)(out + (size_t)r0 * N + c)       = make_float2(o00, o01);
                *(float2*)(out + (size_t)(r0 + 8) * N + c) = make_float2(o10, o11);
                cm0 = fmaxf(cm0, fmaxf(o00, o10));
                cm1 = fmaxf(cm1, fmaxf(o01, o11));
            }
            // reduce over the 8 row-groups (lanes with same lane&3)
            cm0 = fmaxf(cm0, __shfl_xor_sync(0xffffffffu, cm0, 4));
            cm0 = fmaxf(cm0, __shfl_xor_sync(0xffffffffu, cm0, 8));
            cm0 = fmaxf(cm0, __shfl_xor_sync(0xffffffffu, cm0, 16));
            cm1 = fmaxf(cm1, __shfl_xor_sync(0xffffffffu, cm1, 4));
            cm1 = fmaxf(cm1, __shfl_xor_sync(0xffffffffu, cm1, 8));
            cm1 = fmaxf(cm1, __shfl_xor_sync(0xffffffffu, cm1, 16));
            if (mo == 0) {
                int c = warpN + ni*8 + (lane & 3)*2;
                atomicMax(&smax[c],   encf(cm0));
                atomicMax(&smax[c+1], encf(cm1));
            }
        }
        __syncthreads();
        if (tid < 128) {
            int bh = blockIdx.y >> 5;   // Ss/128 = 32 row-blocks per bh
            atomicMax(&kmaxe[bh * Mm + tid], smax[tid]);
        }
    }
}

// ---- mode-2 favor (old fp32-input core): out = qphi @ kvT + mask/denom -----
#define LDT 136
#define SOFF_AH2(b) ((unsigned)(b)*2176u)
#define SOFF_AL2(b) (4352u  + (unsigned)(b)*2176u)
#define SOFF_BH2(b) (8704u  + (unsigned)(b)*2176u)
#define SOFF_BL2(b) (13056u + (unsigned)(b)*2176u)
#define DSMEM_BYTES (17408*4)   // 69632

__global__ __launch_bounds__(256) void favor_out(
    const float* __restrict__ A, const float* __restrict__ Bglob,
    const float* __restrict__ sq, const int* __restrict__ mask,
    unsigned* __restrict__ outh, unsigned* __restrict__ outl)
{
    extern __shared__ unsigned sm[];
    int rowBase = blockIdx.y * 128;
    const int K = 128;
    int bh0 = blockIdx.y >> 5;
    int b0 = bh0 >> 4, h0 = bh0 & 15;
    const float* Wg = Bglob + (size_t)(b0 * 8 + (h0 >> 1)) * 128 * 128;
    const float* Ag = A + (size_t)rowBase * K;
    CORE_PROLOG_VARS;
    int ldRow  = tid >> 1;
    int ldCol  = (tid & 1) * 16;
    int kpBase = (tid & 1) * 8;
    float ar[16], br[16];
    #define FO_LOAD(k0)                                                        \
        {                                                                      \
            const float* ap = Ag + (size_t)ldRow * K + (k0) + ldCol;           \
            const float* bp = Wg + (size_t)ldRow * K + (k0) + ldCol;           \
            float4 t;                                                          \
            t = *(const float4*)(ap);      ar[0]=t.x; ar[1]=t.y; ar[2]=t.z; ar[3]=t.w;   \
            t = *(const float4*)(ap + 4);  ar[4]=t.x; ar[5]=t.y; ar[6]=t.z; ar[7]=t.w;   \
            t = *(const float4*)(ap + 8);  ar[8]=t.x; ar[9]=t.y; ar[10]=t.z; ar[11]=t.w; \
            t = *(const float4*)(ap + 12); ar[12]=t.x; ar[13]=t.y; ar[14]=t.z; ar[15]=t.w;\
            t = *(const float4*)(bp);      br[0]=t.x; br[1]=t.y; br[2]=t.z; br[3]=t.w;   \
            t = *(const float4*)(bp + 4);  br[4]=t.x; br[5]=t.y; br[6]=t.z; br[7]=t.w;   \
            t = *(const float4*)(bp + 8);  br[8]=t.x; br[9]=t.y; br[10]=t.z; br[11]=t.w; \
            t = *(const float4*)(bp + 12); br[12]=t.x; br[13]=t.y; br[14]=t.z; br[15]=t.w;\
        }
    #define FO_STORE(bufn)                                                     \
        {                                                                      \
            _Pragma("unroll")                                                  \
            for (int e = 0; e < 8; e++) {                                      \
                unsigned hi, lo;                                               \
                bfsplit2(ar[2*e], ar[2*e+1], hi, lo);                          \
                sm[SOFF_AH2(bufn) + (kpBase+e)*LDT + ldRow] = hi;              \
                sm[SOFF_AL2(bufn) + (kpBase+e)*LDT + ldRow] = lo;              \
                bfsplit2(br[2*e], br[2*e+1], hi, lo);                          \
                sm[SOFF_BH2(bufn) + (kpBase+e)*LDT + ldRow] = hi;              \
                sm[SOFF_BL2(bufn) + (kpBase+e)*LDT + ldRow] = lo;              \
            }                                                                  \
        }
    FO_LOAD(0);
    FO_STORE(0);
    __syncthreads();
    for (int t = 0; t < 4; t++) {
        int buf = t & 1;
        bool has = (t + 1 < 4);
        if (has) FO_LOAD((t + 1) << 5);
        {
            #pragma unroll
            for (int h = 0; h < 2; h++) {
                int kc = h*8 + (lane & 3);
                int mo2 = lane >> 2;
                unsigned afh[4][4], afl[4][4], bfh[4][2], bfl[4][2];
                #pragma unroll
                for (int mi = 0; mi < 4; mi++) {
                    int m = warpM + mi * 16 + mo2;
                    afh[mi][0] = sm[SOFF_AH2(buf) + kc*LDT + m];
                    afh[mi][1] = sm[SOFF_AH2(buf) + kc*LDT + m + 8];
                    afh[mi][2] = sm[SOFF_AH2(buf) + (kc+4)*LDT + m];
                    afh[mi][3] = sm[SOFF_AH2(buf) + (kc+4)*LDT + m + 8];
                    afl[mi][0] = sm[SOFF_AL2(buf) + kc*LDT + m];
                    afl[mi][1] = sm[SOFF_AL2(buf) + kc*LDT + m + 8];
                    afl[mi][2] = sm[SOFF_AL2(buf) + (kc+4)*LDT + m];
                    afl[mi][3] = sm[SOFF_AL2(buf) + (kc+4)*LDT + m + 8];
                }
                #pragma unroll
                for (int ni = 0; ni < 4; ni++) {
                    int n = warpN + ni * 8 + mo2;
                    bfh[ni][0] = sm[SOFF_BH2(buf) + kc*LDT + n];
                    bfh[ni][1] = sm[SOFF_BH2(buf) + (kc+4)*LDT + n];
                    bfl[ni][0] = sm[SOFF_BL2(buf) + kc*LDT + n];
                    bfl[ni][1] = sm[SOFF_BL2(buf) + (kc+4)*LDT + n];
                }
                #pragma unroll
                for (int mi = 0; mi < 4; mi++)
                    #pragma unroll
                    for (int ni = 0; ni < 4; ni++) {
                        mma_bf16(acc[mi][ni], afh[mi], bfh[ni]);
                        mma_bf16(acc[mi][ni], afl[mi], bfh[ni]);
                        mma_bf16(acc[mi][ni], afh[mi], bfl[ni]);
                    }
            }
        }
        if (has) FO_STORE(buf ^ 1);
        __syncthreads();
    }

    int mo = lane >> 2;
    #pragma unroll
    for (int mi = 0; mi < 4; mi++) {
        int rg = rowBase + warpM + mi*16 + mo;
        #pragma unroll
        for (int half = 0; half < 2; half++) {
            int r = rg + half * 8;
            int s = r & 4095;
            int bh = r >> 12;
            int b = bh >> 4, h = bh & 15;
            float vm = (mask[b * Ss + s] > 0) ? 1.f : 0.f;
            float scale = vm / (sq[r] + EPSF);   // sq carries g_dn here
            size_t base = ((size_t)(b * Ss + s) * (Hh*HDd)) + h * HDd;
            #pragma unroll
            for (int ni = 0; ni < 4; ni++) {
                int c = warpN + ni*8 + (lane & 3)*2;
                unsigned hi, lo;
                hsplit2(acc[mi][ni][2*half]*scale,
                        acc[mi][ni][2*half+1]*scale, hi, lo);
                size_t w = (base + c) >> 1;
                outh[w] = hi;
                outl[w] = lo;
            }
        }
    }
}

// ------------------- init: zero kvT/ksum, reset kmax encodings --------------
__global__ void init_kernel() {
    int i = blockIdx.x * blockDim.x + threadIdx.x;
    if (i < Bb*HKk*Mm*HDd) g_kvT[i] = 0.f;
    if (i < Bb*HKk*Mm) { g_ksum[i] = 0.f; g_kmaxe[i] = 0u; }
}

// -- kvT[d,m] += sum_s phi_k[s,m]*v[s,d] ; ksum[m] += sum_s phi_k[s,m] -------
__global__ __launch_bounds__(256) void kv_kernel(const int* __restrict__ mask)
{
    __shared__ float kps[16][128];
    __shared__ float vs [16][128];
    __shared__ float kmx[128];
    __shared__ float vmask[128];
    int bh = blockIdx.y;
    int b = bh / HKk, hk = bh % HKk;
    int s0 = blockIdx.x * 128;
    int tid = threadIdx.x;
    int tr = tid >> 4, tc = tid & 15;
    if (tid < 128) {
        kmx[tid] = decf(g_kmaxe[bh * Mm + tid]);
        vmask[tid] = (mask[b * Ss + s0 + tid] > 0) ? 1.f : 0.f;
    }
    __syncthreads();

    const float* KX = g_kxp + ((size_t)bh * Ss + s0) * Mm;
    const float* V  = g_v + ((size_t)(b * Ss + s0)) * (HKk*HDd) + hk * HDd;
    float acc[8][8];
    #pragma unroll
    for (int i=0;i<8;i++)
        #pragma unroll
        for (int j=0;j<8;j++) acc[i][j]=0.f;
    float ksacc = 0.f;

    for (int sc = 0; sc < 128; sc += 16) {
        #pragma unroll
        for (int it = 0; it < 2; it++) {
            int idx = tid + it * 256;
            int r = idx >> 5;
            int c4 = (idx & 31) << 2;
            float vm = vmask[sc + r];
            float4 x4 = *(const float4*)(KX + (size_t)(sc + r) * Mm + c4);
            kps[r][c4+0] = (__expf(x4.x - kmx[c4+0]) * INV_SQRT_M + EPSF) * vm;
            kps[r][c4+1] = (__expf(x4.y - kmx[c4+1]) * INV_SQRT_M + EPSF) * vm;
            kps[r][c4+2] = (__expf(x4.z - kmx[c4+2]) * INV_SQRT_M + EPSF) * vm;
            kps[r][c4+3] = (__expf(x4.w - kmx[c4+3]) * INV_SQRT_M + EPSF) * vm;
            float4 v4 = *(const float4*)(V + (size_t)(sc + r) * (HKk*HDd) + c4);
            vs[r][c4+0]=v4.x; vs[r][c4+1]=v4.y; vs[r][c4+2]=v4.z; vs[r][c4+3]=v4.w;
        }
        __syncthreads();
        #pragma unroll
        for (int ssi = 0; ssi < 16; ssi++) {
            float ra[8], rb[8];
            #pragma unroll
            for (int i=0;i<8;i++) ra[i]=kps[ssi][tr*8+i];
            #pragma unroll
            for (int j=0;j<8;j++) rb[j]=vs[ssi][tc*8+j];
            #pragma unroll
            for (int i=0;i<8;i++)
                #pragma unroll
                for (int j=0;j<8;j++) acc[i][j] += ra[i]*rb[j];
        }
        if (tid < 128) {
            #pragma unroll
            for (int ssi = 0; ssi < 16; ssi++) ksacc += kps[ssi][tid];
        }
        __syncthreads();
    }
    float* KV = g_kvT + (size_t)bh * Mm * HDd;
    #pragma unroll
    for (int i = 0; i < 8; i++)
        #pragma unroll
        for (int j = 0; j < 8; j++)
            atomicAdd(&KV[(size_t)(tc*8+j)*Mm + tr*8+i], acc[i][j]);
    if (tid < 128) atomicAdd(&g_ksum[bh * Mm + tid], ksacc);
}

// -------------- denominators: dn[row] = qphi[row,:]·ksum[bhk,:] -------------
__global__ __launch_bounds__(256) void dn_kernel() {
    int warp = threadIdx.x >> 5, lane = threadIdx.x & 31;
    int row = blockIdx.x * 8 + warp;
    int bh = row >> 12;
    int b = bh >> 4, h = bh & 15;
    int bhk = b * 8 + (h >> 1);
    float4 q = *(const float4*)(g_qphi + (size_t)row * Mm + lane * 4);
    float4 s = *(const float4*)(g_ksum + bhk * Mm + lane * 4);
    float v = q.x*s.x + q.y*s.y + q.z*s.z + q.w*s.w;
    #pragma unroll
    for (int o = 16; o > 0; o >>= 1) v += __shfl_xor_sync(0xffffffffu, v, o);
    if (lane == 0) g_dn[row] = v;
}

// ------------------------------- launch -------------------------------------
extern "C" void kernel_launch(void* const* d_in, const int* in_sizes, int n_in,
                              void* d_out, int out_size)
{
    const float* x    = (const float*)d_in[0];
    const int*   mask = (const int*)  d_in[1];
    const float* fc   = (const float*)d_in[2];
    const float* wq   = (const float*)d_in[3];
    const float* wk   = (const float*)d_in[4];
    const float* wv   = (const float*)d_in[5];
    const float* wo   = (const float*)d_in[6];
    const float* gq   = (const float*)d_in[7];
    const float* gk   = (const float*)d_in[8];
    const float* proj = (const float*)d_in[9];
    float* out = (float*)d_out;

    float *pv, *psqq, *psqk, *pqphi, *pkxp, *pkvT, *pdn;
    cudaGetSymbolAddress((void**)&pv,   g_v);
    cudaGetSymbolAddress((void**)&psqq, g_sqq);
    cudaGetSymbolAddress((void**)&psqk, g_sqk);
    cudaGetSymbolAddress((void**)&pqphi,g_qphi);
    cudaGetSymbolAddress((void**)&pkxp, g_kxp);
    cudaGetSymbolAddress((void**)&pkvT, g_kvT);
    cudaGetSymbolAddress((void**)&pdn,  g_dn);

    unsigned *xfh,*xfl,*wqh,*wkh,*wvh,*woh,*aoh,*aol;
    unsigned *qxh,*qxl,*kxh,*kxl,*pjh,*pjl,*kmaxe;
    cudaGetSymbolAddress((void**)&xfh, g_xfh); cudaGetSymbolAddress((void**)&xfl, g_xfl);
    cudaGetSymbolAddress((void**)&wqh, g_wqh);
    cudaGetSymbolAddress((void**)&wkh, g_wkh);
    cudaGetSymbolAddress((void**)&wvh, g_wvh);
    cudaGetSymbolAddress((void**)&woh, g_woh);
    cudaGetSymbolAddress((void**)&aoh, g_aoh); cudaGetSymbolAddress((void**)&aol, g_aol);
    cudaGetSymbolAddress((void**)&qxh, g_qxh); cudaGetSymbolAddress((void**)&qxl, g_qxl);
    cudaGetSymbolAddress((void**)&kxh, g_kxh); cudaGetSymbolAddress((void**)&kxl, g_kxl);
    cudaGetSymbolAddress((void**)&pjh, g_pjh); cudaGetSymbolAddress((void**)&pjl, g_pjl);
    cudaGetSymbolAddress((void**)&kmaxe, g_kmaxe);

    cudaFuncSetAttribute(gemm_qk_fused, cudaFuncAttributeMaxDynamicSharedMemorySize, DSMEM3_BYTES);
    cudaFuncSetAttribute(gemm_f16_2t,   cudaFuncAttributeMaxDynamicSharedMemorySize, DSMEM3_BYTES);
    cudaFuncSetAttribute(favor_cpa,     cudaFuncAttributeMaxDynamicSharedMemorySize, DSMEM4_BYTES);
    cudaFuncSetAttribute(favor_out,     cudaFuncAttributeMaxDynamicSharedMemorySize, DSMEM_BYTES);

    // pre-split operands
    split_f16_kernel <<<(Bb*Ss*DIMm/4 + 255)/256, 256>>>(x,  xfh, xfl, Bb*Ss*DIMm/4);
    split_f16h_kernel<<<(Hh*HDd*DIMm/4 + 255)/256, 256>>>(wq, wqh, Hh*HDd*DIMm/4);
    split_f16h_kernel<<<(HKk*HDd*DIMm/4 + 255)/256, 256>>>(wk, wkh, HKk*HDd*DIMm/4);
    split_f16h_kernel<<<(HKk*HDd*DIMm/4 + 255)/256, 256>>>(wv, wvh, HKk*HDd*DIMm/4);
    split_f16h_kernel<<<(DIMm*Hh*HDd/4 + 255)/256, 256>>>(wo, woh, DIMm*Hh*HDd/4);
    split_bf16_kernel<<<(Mm*HDd/4 + 255)/256, 256>>>(proj, pjh, pjl, Mm*HDd/4);
    init_kernel<<<(Bb*HKk*Mm*HDd + 255)/256, 256>>>();

    // Q,K projections (2-term fp16) + fused RMSNorm/RoPE -> packed bf16 hi/lo
    gemm_qk_fused<<<dim3(Hh,  (Bb*Ss)/128), 256, DSMEM3_BYTES>>>(
        xfh, xfl, wqh, fc, gq, qxh, qxl, psqq, DIMm, Hh);
    gemm_qk_fused<<<dim3(HKk, (Bb*Ss)/128), 256, DSMEM3_BYTES>>>(
        xfh, xfl, wkh, fc, gk, kxh, kxl, psqk, DIMm, HKk);
    // V projection
    gemm_f16_2t<<<dim3((HKk*HDd)/128, (Bb*Ss)/128), 256, DSMEM3_BYTES>>>(
        xfh, xfl, wvh, pv, DIMm, HKk*HDd);

    // FAVOR feature projections (cp.async/ldmatrix, 3-term bf16)
    favor_cpa<<<dim3(1, (Bb*Hh*Ss)/128),  256, DSMEM4_BYTES>>>(
        qxh, qxl, pjh, pjl, psqq, pqphi, kmaxe, 0);
    favor_cpa<<<dim3(1, (Bb*HKk*Ss)/128), 256, DSMEM4_BYTES>>>(
        kxh, kxl, pjh, pjl, psqk, pkxp, kmaxe, 1);

    // kv / ksum contraction (kv stored transposed; kmax folded into mode 1)
    kv_kernel<<<dim3(Ss/128, Bb*HKk), 256>>>(mask);

    // denominators, then attention output (writes fp16 hi/lo directly)
    dn_kernel<<<(Bb*Hh*Ss)/8, 256>>>();
    favor_out<<<dim3(1, (Bb*Hh*Ss)/128), 256, DSMEM_BYTES>>>(
        pqphi, pkvT, pdn, mask, aoh, aol);

    // output projection
    gemm_f16_2t<<<dim3(DIMm/128, (Bb*Ss)/128), 256, DSMEM3_BYTES>>>(
        aoh, aol, woh, out, Hh*HDd, DIMm);
}

// round 13
// speedup vs baseline: 3.3422x; 1.0460x over previous
#include <cuda_runtime.h>
#include <cuda_bf16.h>
#include <cuda_fp16.h>
#include <math.h>
#include <stdint.h>

#define Bb  2
#define Ss  4096
#define DIMm 2048
#define Hh  16
#define HKk 8
#define HDd 128
#define Mm  128

#define INV_SQRT_M 0.08838834764831845f   // 128^{-0.5}
#define SCALE_QD   0.2973017787506803f    // 128^{-0.25}
#define EPSF 1e-6f

// ---------------- scratch (device globals; no allocations allowed) ----------
__device__ float g_v   [Bb*Ss*HKk*HDd];
__device__ float g_sqq [Bb*Hh*Ss];
__device__ float g_sqk [Bb*HKk*Ss];
__device__ float g_qphi[Bb*Hh*Ss*Mm];      // [b,h,s,m] fp32
__device__ float g_kxp [Bb*HKk*Ss*Mm];     // pre-exp key features fp32
__device__ unsigned g_kmaxe[Bb*HKk*Mm];    // encoded column max
__device__ float g_kvT [Bb*HKk*HDd*Mm];    // TRANSPOSED kv: [d][m]
__device__ float g_ksum[Bb*HKk*Mm];
__device__ float g_dn  [Bb*Hh*Ss];         // denominators

// pre-split operand arrays (packed x2 words)
#define XW (Bb*Ss*DIMm/2)
__device__ unsigned g_xfh [XW];            // x fp16 hi  (q,k,v GEMMs)
__device__ unsigned g_xfl [XW];            // x fp16 lo
__device__ unsigned g_wqh [Hh*HDd*DIMm/2];    // fp16 hi only
__device__ unsigned g_wkh [HKk*HDd*DIMm/2];
__device__ unsigned g_wvh [HKk*HDd*DIMm/2];
__device__ unsigned g_woh [DIMm*Hh*HDd/2];
__device__ unsigned g_aoh [Bb*Ss*Hh*HDd/2];   // attention out, fp16 hi
__device__ unsigned g_aol [Bb*Ss*Hh*HDd/2];   // attention out, fp16 lo
// bf16 hi/lo packed (favor operands)
__device__ unsigned g_qxh [Bb*Hh*Ss*HDd/2];
__device__ unsigned g_qxl [Bb*Hh*Ss*HDd/2];
__device__ unsigned g_kxh [Bb*HKk*Ss*HDd/2];
__device__ unsigned g_kxl [Bb*HKk*Ss*HDd/2];
__device__ unsigned g_pjh [Mm*HDd/2];
__device__ unsigned g_pjl [Mm*HDd/2];

// ---------------------------- helpers ---------------------------------------
__device__ __forceinline__ void bfsplit2(float x0, float x1, unsigned& hi, unsigned& lo) {
    __nv_bfloat162 h2 = __floats2bfloat162_rn(x0, x1);
    float2 hf = __bfloat1622float2(h2);
    __nv_bfloat162 l2 = __floats2bfloat162_rn(x0 - hf.x, x1 - hf.y);
    hi = *reinterpret_cast<unsigned*>(&h2);
    lo = *reinterpret_cast<unsigned*>(&l2);
}
__device__ __forceinline__ void hsplit2(float x0, float x1, unsigned& hi, unsigned& lo) {
    __half2 h2 = __floats2half2_rn(x0, x1);
    float2 hf = __half22float2(h2);
    __half2 l2 = __floats2half2_rn(x0 - hf.x, x1 - hf.y);
    hi = *reinterpret_cast<unsigned*>(&h2);
    lo = *reinterpret_cast<unsigned*>(&l2);
}
// order-preserving float<->unsigned encoding for atomicMax
__device__ __forceinline__ unsigned encf(float f) {
    int s = __float_as_int(f);
    return (s < 0) ? ~(unsigned)s : ((unsigned)s | 0x80000000u);
}
__device__ __forceinline__ float decf(unsigned u) {
    int s = (u & 0x80000000u) ? (int)(u & 0x7FFFFFFFu) : ~(int)u;
    return __int_as_float(s);
}

__device__ __forceinline__ void mma_bf16(float* d, const unsigned* a, const unsigned* b) {
    asm volatile(
        "mma.sync.aligned.m16n8k16.row.col.f32.bf16.bf16.f32 "
        "{%0,%1,%2,%3}, {%4,%5,%6,%7}, {%8,%9}, {%0,%1,%2,%3};\n"
        : "+f"(d[0]), "+f"(d[1]), "+f"(d[2]), "+f"(d[3])
        : "r"(a[0]), "r"(a[1]), "r"(a[2]), "r"(a[3]),
          "r"(b[0]), "r"(b[1]));
}
__device__ __forceinline__ void mma_f16(float* d, const unsigned* a, const unsigned* b) {
    asm volatile(
        "mma.sync.aligned.m16n8k16.row.col.f32.f16.f16.f32 "
        "{%0,%1,%2,%3}, {%4,%5,%6,%7}, {%8,%9}, {%0,%1,%2,%3};\n"
        : "+f"(d[0]), "+f"(d[1]), "+f"(d[2]), "+f"(d[3])
        : "r"(a[0]), "r"(a[1]), "r"(a[2]), "r"(a[3]),
          "r"(b[0]), "r"(b[1]));
}

#define CP16(dst, src) asm volatile("cp.async.cg.shared.global [%0], [%1], 16;\n" :: "r"(dst), "l"(src) : "memory")
#define CP_COMMIT()    asm volatile("cp.async.commit_group;\n" ::: "memory")
#define CP_WAIT0()     asm volatile("cp.async.wait_group 0;\n" ::: "memory")
#define LDMX4(r, addr) asm volatile( \
    "ldmatrix.sync.aligned.m8n8.x4.shared.b16 {%0,%1,%2,%3}, [%4];" \
    : "=r"((r)[0]), "=r"((r)[1]), "=r"((r)[2]), "=r"((r)[3]) : "r"(addr))

// ===== cp.async/ldmatrix smem layouts ========================================
#define P3 2560u
#define POFF_AH(st) ((unsigned)(st)*P3)
#define POFF_AL(st) (2u*P3 + (unsigned)(st)*P3)
#define POFF_BH(st) (4u*P3 + (unsigned)(st)*P3)
#define POFF_BL(st) (6u*P3 + (unsigned)(st)*P3)
#define DSMEM3_BYTES (6*2560*4)   // 61440 (3 arrays, fp16 2-term)
#define DSMEM4_BYTES (8*2560*4)   // 81920 (4 arrays, bf16 3-term)

// ---- 2-term fp16 (GEMMs) ----
#define CPA_LOAD(t0, st)                                                       \
    {                                                                          \
        int row = tid >> 1;                                                    \
        int ch  = (tid & 1) * 8;                                               \
        size_t g = (size_t)row * KW + ((size_t)(t0) << 4) + ch;                \
        unsigned d;                                                            \
        d = smb + (POFF_AH(st) + (unsigned)row*20u + ch)*4u;                   \
        CP16(d, Agh + g); CP16(d+16u, Agh + g + 4);                            \
        d = smb + (POFF_AL(st) + (unsigned)row*20u + ch)*4u;                   \
        CP16(d, Agl + g); CP16(d+16u, Agl + g + 4);                            \
        d = smb + (POFF_BH(st) + (unsigned)row*20u + ch)*4u;                   \
        CP16(d, Bgh + g); CP16(d+16u, Bgh + g + 4);                            \
        CP_COMMIT();                                                           \
    }

#define CPA_COMPUTE(st)                                                        \
    {                                                                          \
        _Pragma("unroll")                                                      \
        for (int h = 0; h < 2; h++) {                                          \
            int arow = (lane & 7) + ((lane >> 3) & 1) * 8;                     \
            int achw = 8*h + ((lane >> 4) & 1) * 4;                            \
            int brow = (lane & 7) + ((lane >> 4) & 1) * 8;                     \
            int bchw = 8*h + ((lane >> 3) & 1) * 4;                            \
            unsigned afh[4][4], afl[4][4], bf[2][4];                           \
            _Pragma("unroll")                                                  \
            for (int mi = 0; mi < 4; mi++) {                                   \
                unsigned ra = smb + (POFF_AH(st) +                             \
                    (unsigned)(warpM + mi*16 + arow)*20u + achw)*4u;           \
                LDMX4(afh[mi], ra);                                            \
                unsigned rl = smb + (POFF_AL(st) +                             \
                    (unsigned)(warpM + mi*16 + arow)*20u + achw)*4u;           \
                LDMX4(afl[mi], rl);                                            \
            }                                                                  \
            LDMX4(bf[0], smb + (POFF_BH(st) +                                  \
                (unsigned)(warpN + brow)*20u + bchw)*4u);                      \
            LDMX4(bf[1], smb + (POFF_BH(st) +                                  \
                (unsigned)(warpN + 16 + brow)*20u + bchw)*4u);                 \
            _Pragma("unroll")                                                  \
            for (int mi = 0; mi < 4; mi++) {                                   \
                mma_f16(acc[mi][0], afh[mi], &bf[0][0]);                       \
                mma_f16(acc[mi][0], afl[mi], &bf[0][0]);                       \
                mma_f16(acc[mi][1], afh[mi], &bf[0][2]);                       \
                mma_f16(acc[mi][1], afl[mi], &bf[0][2]);                       \
                mma_f16(acc[mi][2], afh[mi], &bf[1][0]);                       \
                mma_f16(acc[mi][2], afl[mi], &bf[1][0]);                       \
                mma_f16(acc[mi][3], afh[mi], &bf[1][2]);                       \
                mma_f16(acc[mi][3], afl[mi], &bf[1][2]);                       \
            }                                                                  \
        }                                                                      \
    }

#define CPA_MAINLOOP(KTILES)                                                   \
    CPA_LOAD(0, 0);                                                            \
    CP_WAIT0();                                                                \
    __syncthreads();                                                           \
    for (int t = 0; t < (KTILES); t++) {                                       \
        int st = t & 1;                                                        \
        bool has = (t + 1 < (KTILES));                                         \
        if (has) CPA_LOAD(t + 1, st ^ 1);                                      \
        CPA_COMPUTE(st);                                                       \
        if (has) CP_WAIT0();                                                   \
        __syncthreads();                                                       \
    }

// ---- 3-term bf16 (favor kernels), 4 arrays ----
#define CPA4_LOAD(t0, st)                                                      \
    {                                                                          \
        int row = tid >> 1;                                                    \
        int ch  = (tid & 1) * 8;                                               \
        size_t g = (size_t)row * KW + ((size_t)(t0) << 4) + ch;                \
        unsigned d;                                                            \
        d = smb + (POFF_AH(st) + (unsigned)row*20u + ch)*4u;                   \
        CP16(d, Agh + g); CP16(d+16u, Agh + g + 4);                            \
        d = smb + (POFF_AL(st) + (unsigned)row*20u + ch)*4u;                   \
        CP16(d, Agl + g); CP16(d+16u, Agl + g + 4);                            \
        d = smb + (POFF_BH(st) + (unsigned)row*20u + ch)*4u;                   \
        CP16(d, Bgh + g); CP16(d+16u, Bgh + g + 4);                            \
        d = smb + (POFF_BL(st) + (unsigned)row*20u + ch)*4u;                   \
        CP16(d, Bgl + g); CP16(d+16u, Bgl + g + 4);                            \
        CP_COMMIT();                                                           \
    }

#define CPA4_COMPUTE(st)                                                       \
    {                                                                          \
        _Pragma("unroll")                                                      \
        for (int h = 0; h < 2; h++) {                                          \
            int arow = (lane & 7) + ((lane >> 3) & 1) * 8;                     \
            int achw = 8*h + ((lane >> 4) & 1) * 4;                            \
            int brow = (lane & 7) + ((lane >> 4) & 1) * 8;                     \
            int bchw = 8*h + ((lane >> 3) & 1) * 4;                            \
            unsigned afh[4][4], afl[4][4], bfh[2][4], bfl[2][4];               \
            _Pragma("unroll")                                                  \
            for (int mi = 0; mi < 4; mi++) {                                   \
                LDMX4(afh[mi], smb + (POFF_AH(st) +                            \
                    (unsigned)(warpM + mi*16 + arow)*20u + achw)*4u);          \
                LDMX4(afl[mi], smb + (POFF_AL(st) +                            \
                    (unsigned)(warpM + mi*16 + arow)*20u + achw)*4u);          \
            }                                                                  \
            LDMX4(bfh[0], smb + (POFF_BH(st) +                                 \
                (unsigned)(warpN + brow)*20u + bchw)*4u);                      \
            LDMX4(bfh[1], smb + (POFF_BH(st) +                                 \
                (unsigned)(warpN + 16 + brow)*20u + bchw)*4u);                 \
            LDMX4(bfl[0], smb + (POFF_BL(st) +                                 \
                (unsigned)(warpN + brow)*20u + bchw)*4u);                      \
            LDMX4(bfl[1], smb + (POFF_BL(st) +                                 \
                (unsigned)(warpN + 16 + brow)*20u + bchw)*4u);                 \
            _Pragma("unroll")                                                  \
            for (int mi = 0; mi < 4; mi++) {                                   \
                mma_bf16(acc[mi][0], afh[mi], &bfh[0][0]);                     \
                mma_bf16(acc[mi][0], afl[mi], &bfh[0][0]);                     \
                mma_bf16(acc[mi][0], afh[mi], &bfl[0][0]);                     \
                mma_bf16(acc[mi][1], afh[mi], &bfh[0][2]);                     \
                mma_bf16(acc[mi][1], afl[mi], &bfh[0][2]);                     \
                mma_bf16(acc[mi][1], afh[mi], &bfl[0][2]);                     \
                mma_bf16(acc[mi][2], afh[mi], &bfh[1][0]);                     \
                mma_bf16(acc[mi][2], afl[mi], &bfh[1][0]);                     \
                mma_bf16(acc[mi][2], afh[mi], &bfl[1][0]);                     \
                mma_bf16(acc[mi][3], afh[mi], &bfh[1][2]);                     \
                mma_bf16(acc[mi][3], afl[mi], &bfh[1][2]);                     \
                mma_bf16(acc[mi][3], afh[mi], &bfl[1][2]);                     \
            }                                                                  \
        }                                                                      \
    }

#define CPA4_MAINLOOP(KTILES)                                                  \
    CPA4_LOAD(0, 0);                                                           \
    CP_WAIT0();                                                                \
    __syncthreads();                                                           \
    for (int t = 0; t < (KTILES); t++) {                                       \
        int st = t & 1;                                                        \
        bool has = (t + 1 < (KTILES));                                         \
        if (has) CPA4_LOAD(t + 1, st ^ 1);                                     \
        CPA4_COMPUTE(st);                                                      \
        if (has) CP_WAIT0();                                                   \
        __syncthreads();                                                       \
    }

#define CORE_PROLOG_VARS                                                       \
    int tid  = threadIdx.x;                                                    \
    int lane = tid & 31;                                                       \
    int warp = tid >> 5;                                                       \
    int warpM = (warp >> 2) * 64;                                              \
    int warpN = (warp & 3) * 32;                                               \
    float acc[4][4][4];                                                        \
    _Pragma("unroll")                                                          \
    for (int mi = 0; mi < 4; mi++)                                             \
        _Pragma("unroll")                                                      \
        for (int ni = 0; ni < 4; ni++)                                         \
            _Pragma("unroll")                                                  \
            for (int e = 0; e < 4; e++) acc[mi][ni][e] = 0.f;

// ---------------- fp32 -> packed hi/lo split kernels ------------------------
__global__ __launch_bounds__(256) void split_f16_kernel(
    const float* __restrict__ src, unsigned* __restrict__ hi,
    unsigned* __restrict__ lo, int n4)
{
    int i = blockIdx.x * blockDim.x + threadIdx.x;
    if (i >= n4) return;
    float4 v = ((const float4*)src)[i];
    unsigned h0, l0, h1, l1;
    hsplit2(v.x, v.y, h0, l0);
    hsplit2(v.z, v.w, h1, l1);
    ((uint2*)hi)[i] = make_uint2(h0, h1);
    ((uint2*)lo)[i] = make_uint2(l0, l1);
}
__global__ __launch_bounds__(256) void split_f16h_kernel(
    const float* __restrict__ src, unsigned* __restrict__ hi, int n4)
{
    int i = blockIdx.x * blockDim.x + threadIdx.x;
    if (i >= n4) return;
    float4 v = ((const float4*)src)[i];
    __half2 a = __floats2half2_rn(v.x, v.y);
    __half2 b = __floats2half2_rn(v.z, v.w);
    ((uint2*)hi)[i] = make_uint2(*reinterpret_cast<unsigned*>(&a),
                                 *reinterpret_cast<unsigned*>(&b));
}
__global__ __launch_bounds__(256) void split_bf16_kernel(
    const float* __restrict__ src, unsigned* __restrict__ hi,
    unsigned* __restrict__ lo, int n4)
{
    int i = blockIdx.x * blockDim.x + threadIdx.x;
    if (i >= n4) return;
    float4 v = ((const float4*)src)[i];
    unsigned h0, l0, h1, l1;
    bfsplit2(v.x, v.y, h0, l0);
    bfsplit2(v.z, v.w, h1, l1);
    ((uint2*)hi)[i] = make_uint2(h0, h1);
    ((uint2*)lo)[i] = make_uint2(l0, l1);
}

// ------- 2-term fp16 GEMM + fused RMSNorm/RoPE epilogue (cp.async core) -----
__global__ __launch_bounds__(256) void gemm_qk_fused(
    const unsigned* __restrict__ Ah, const unsigned* __restrict__ Al,
    const unsigned* __restrict__ Bh,
    const float* __restrict__ fc, const float* __restrict__ gvec,
    unsigned* __restrict__ xouth, unsigned* __restrict__ xoutl,
    float* __restrict__ sqout, int K, int nh)
{
    extern __shared__ unsigned sm[];
    __shared__ float red2[128][4][2];
    __shared__ float gsh[128];
    int rowBase = blockIdx.y * 128;
    int colBase = blockIdx.x * 128;
    const int KW = K >> 1;
    const unsigned* Agh = Ah + (size_t)rowBase * KW;
    const unsigned* Agl = Al + (size_t)rowBase * KW;
    const unsigned* Bgh = Bh + (size_t)colBase * KW;
    CORE_PROLOG_VARS;
    unsigned smb;
    asm("{ .reg .u64 t; cvta.to.shared.u64 t, %1; cvt.u32.u64 %0, t; }" : "=r"(smb) : "l"(sm));
    if (tid < 128) gsh[tid] = gvec[tid];
    int kTiles = K >> 5;
    CPA_MAINLOOP(kTiles);

    int mo = lane >> 2;
    #pragma unroll
    for (int mi = 0; mi < 4; mi++) {
        #pragma unroll
        for (int half = 0; half < 2; half++) {
            float s1 = 0.f, s2 = 0.f;
            #pragma unroll
            for (int ni = 0; ni < 4; ni++) {
                int c = warpN + ni*8 + (lane & 3)*2;
                float v0 = acc[mi][ni][2*half], v1 = acc[mi][ni][2*half+1];
                s1 += v0*v0 + v1*v1;
                float w0 = v0*gsh[c], w1 = v1*gsh[c+1];
                s2 += w0*w0 + w1*w1;
            }
            s1 += __shfl_xor_sync(0xffffffffu, s1, 1);
            s1 += __shfl_xor_sync(0xffffffffu, s1, 2);
            s2 += __shfl_xor_sync(0xffffffffu, s2, 1);
            s2 += __shfl_xor_sync(0xffffffffu, s2, 2);
            if ((lane & 3) == 0) {
                int rl = warpM + mi*16 + mo + half*8;
                red2[rl][warp & 3][0] = s1;
                red2[rl][warp & 3][1] = s2;
            }
        }
    }
    __syncthreads();
    #pragma unroll
    for (int mi = 0; mi < 4; mi++) {
        #pragma unroll
        for (int half = 0; half < 2; half++) {
            int rl = warpM + mi*16 + mo + half*8;
            float S1 = red2[rl][0][0]+red2[rl][1][0]+red2[rl][2][0]+red2[rl][3][0];
            float S2 = red2[rl][0][1]+red2[rl][1][1]+red2[rl][2][1]+red2[rl][3][1];
            float inv = rsqrtf(S1 * (1.0f/128.0f) + 1e-5f);
            int bs = rowBase + rl;
            int b = bs >> 12, s = bs & 4095;
            size_t rowoff = (((size_t)(b*nh + blockIdx.x))*Ss + s) * (HDd/2);
            #pragma unroll
            for (int ni = 0; ni < 4; ni++) {
                int c = warpN + ni*8 + (lane & 3)*2;
                float a  = acc[mi][ni][2*half]   * inv * gsh[c];
                float b2 = acc[mi][ni][2*half+1] * inv * gsh[c+1];
                float2 cs = ((const float2*)fc)[(size_t)bs * (HDd/2) + (c >> 1)];
                float r0 = (a*cs.x - b2*cs.y) * SCALE_QD;
                float r1 = (a*cs.y + b2*cs.x) * SCALE_QD;
                unsigned hi, lo;
                bfsplit2(r0, r1, hi, lo);
                xouth[rowoff + (c >> 1)] = hi;
                xoutl[rowoff + (c >> 1)] = lo;
            }
            if ((warp & 3) == 0 && (lane & 3) == 0)
                sqout[((size_t)(b*nh + blockIdx.x))*Ss + s] =
                    0.5f * SCALE_QD * SCALE_QD * inv * inv * S2;
        }
    }
}

// ------- 2-term fp16 GEMM, plain epilogue (cp.async core) -------------------
__global__ __launch_bounds__(256) void gemm_f16_2t(
    const unsigned* __restrict__ Ah, const unsigned* __restrict__ Al,
    const unsigned* __restrict__ Bh,
    float* __restrict__ C, int K, int N)
{
    extern __shared__ unsigned sm[];
    int rowBase = blockIdx.y * 128;
    int colBase = blockIdx.x * 128;
    const int KW = K >> 1;
    const unsigned* Agh = Ah + (size_t)rowBase * KW;
    const unsigned* Agl = Al + (size_t)rowBase * KW;
    const unsigned* Bgh = Bh + (size_t)colBase * KW;
    CORE_PROLOG_VARS;
    unsigned smb;
    asm("{ .reg .u64 t; cvta.to.shared.u64 t, %1; cvt.u32.u64 %0, t; }" : "=r"(smb) : "l"(sm));
    int kTiles = K >> 5;
    CPA_MAINLOOP(kTiles);

    #pragma unroll
    for (int mi = 0; mi < 4; mi++) {
        int r = rowBase + warpM + mi * 16 + (lane >> 2);
        #pragma unroll
        for (int ni = 0; ni < 4; ni++) {
            int c = colBase + warpN + ni * 8 + (lane & 3) * 2;
            *(float2*)(C + (size_t)r * N + c) =
                make_float2(acc[mi][ni][0], acc[mi][ni][1]);
            *(float2*)(C + (size_t)(r + 8) * N + c) =
                make_float2(acc[mi][ni][2], acc[mi][ni][3]);
        }
    }
}

// ---- favor modes 0/1 with cp.async/ldmatrix 3-term bf16 core ---------------
__global__ __launch_bounds__(256) void favor_cpa(
    const unsigned* __restrict__ Ah, const unsigned* __restrict__ Al,
    const unsigned* __restrict__ Bh, const unsigned* __restrict__ Bl,
    const float* __restrict__ sq, float* __restrict__ out,
    unsigned* __restrict__ kmaxe, int mode)
{
    extern __shared__ unsigned sm[];
    __shared__ float red[128][4];
    __shared__ unsigned smax[128];
    int rowBase = blockIdx.y * 128;
    const int KW = 64, N = 128;
    const unsigned* Agh = Ah + (size_t)rowBase * KW;
    const unsigned* Agl = Al + (size_t)rowBase * KW;
    const unsigned* Bgh = Bh;
    const unsigned* Bgl = Bl;
    CORE_PROLOG_VARS;
    unsigned smb;
    asm("{ .reg .u64 t; cvta.to.shared.u64 t, %1; cvt.u32.u64 %0, t; }" : "=r"(smb) : "l"(sm));
    if (mode == 1 && tid < 128) smax[tid] = 0u;
    CPA4_MAINLOOP(4);

    int mo = lane >> 2;
    if (mode == 0) {
        #pragma unroll
        for (int mi = 0; mi < 4; mi++) {
            float m0 = -1e30f, m1 = -1e30f;
            #pragma unroll
            for (int ni = 0; ni < 4; ni++) {
                m0 = fmaxf(m0, fmaxf(acc[mi][ni][0], acc[mi][ni][1]));
                m1 = fmaxf(m1, fmaxf(acc[mi][ni][2], acc[mi][ni][3]));
            }
            m0 = fmaxf(m0, __shfl_xor_sync(0xffffffffu, m0, 1));
            m0 = fmaxf(m0, __shfl_xor_sync(0xffffffffu, m0, 2));
            m1 = fmaxf(m1, __shfl_xor_sync(0xffffffffu, m1, 1));
            m1 = fmaxf(m1, __shfl_xor_sync(0xffffffffu, m1, 2));
            if ((lane & 3) == 0) {
                red[warpM + mi*16 + mo][warp & 3] = m0;
                red[warpM + mi*16 + mo + 8][warp & 3] = m1;
            }
        }
        __syncthreads();
        #pragma unroll
        for (int mi = 0; mi < 4; mi++) {
            int rl = warpM + mi*16 + mo;
            float rm0 = fmaxf(fmaxf(red[rl][0], red[rl][1]),
                              fmaxf(red[rl][2], red[rl][3]));
            float rm1 = fmaxf(fmaxf(red[rl+8][0], red[rl+8][1]),
                              fmaxf(red[rl+8][2], red[rl+8][3]));
            #pragma unroll
            for (int ni = 0; ni < 4; ni++) {
                int c = warpN + ni*8 + (lane & 3)*2;
                *(float2*)(out + (size_t)(rowBase + rl) * N + c) =
                    make_float2(__expf(acc[mi][ni][0]-rm0)*INV_SQRT_M + EPSF,
                                __expf(acc[mi][ni][1]-rm0)*INV_SQRT_M + EPSF);
                *(float2*)(out + (size_t)(rowBase + rl + 8) * N + c) =
                    make_float2(__expf(acc[mi][ni][2]-rm1)*INV_SQRT_M + EPSF,
                                __expf(acc[mi][ni][3]-rm1)*INV_SQRT_M + EPSF);
            }
        }
    } else {
        #pragma unroll
        for (int ni = 0; ni < 4; ni++) {
            float cm0 = -1e30f, cm1 = -1e30f;
            #pragma unroll
            for (int mi = 0; mi < 4; mi++) {
                int r0 = rowBase + warpM + mi*16 + mo;
                float s0 = sq[r0], s1 = sq[r0 + 8];
                int c = warpN + ni*8 + (lane & 3)*2;
                float o00 = acc[mi][ni][0]-s0, o01 = acc[mi][ni][1]-s0;
                float o10 = acc[mi][ni][2]-s1, o11 = acc[mi][ni][3]-s1;
                *(float2*)(out + (size_t)r0 * N + c)       = make_float2(o00, o01);
                *(float2*)(out + (size_t)(r0 + 8) * N + c) = make_float2(o10, o11);
                cm0 = fmaxf(cm0, fmaxf(o00, o10));
                cm1 = fmaxf(cm1, fmaxf(o01, o11));
            }
            cm0 = fmaxf(cm0, __shfl_xor_sync(0xffffffffu, cm0, 4));
            cm0 = fmaxf(cm0, __shfl_xor_sync(0xffffffffu, cm0, 8));
            cm0 = fmaxf(cm0, __shfl_xor_sync(0xffffffffu, cm0, 16));
            cm1 = fmaxf(cm1, __shfl_xor_sync(0xffffffffu, cm1, 4));
            cm1 = fmaxf(cm1, __shfl_xor_sync(0xffffffffu, cm1, 8));
            cm1 = fmaxf(cm1, __shfl_xor_sync(0xffffffffu, cm1, 16));
            if (mo == 0) {
                int c = warpN + ni*8 + (lane & 3)*2;
                atomicMax(&smax[c],   encf(cm0));
                atomicMax(&smax[c+1], encf(cm1));
            }
        }
        __syncthreads();
        if (tid < 128) {
            int bh = blockIdx.y >> 5;
            atomicMax(&kmaxe[bh * Mm + tid], smax[tid]);
        }
    }
}

// ---- mode-2 favor (old fp32-input core): out = qphi @ kvT + mask/denom -----
#define LDT 136
#define SOFF_AH2(b) ((unsigned)(b)*2176u)
#define SOFF_AL2(b) (4352u  + (unsigned)(b)*2176u)
#define SOFF_BH2(b) (8704u  + (unsigned)(b)*2176u)
#define SOFF_BL2(b) (13056u + (unsigned)(b)*2176u)
#define DSMEM_BYTES (17408*4)   // 69632

__global__ __launch_bounds__(256) void favor_out(
    const float* __restrict__ A, const float* __restrict__ Bglob,
    const float* __restrict__ sq, const int* __restrict__ mask,
    unsigned* __restrict__ outh, unsigned* __restrict__ outl)
{
    extern __shared__ unsigned sm[];
    int rowBase = blockIdx.y * 128;
    const int K = 128;
    int bh0 = blockIdx.y >> 5;
    int b0 = bh0 >> 4, h0 = bh0 & 15;
    const float* Wg = Bglob + (size_t)(b0 * 8 + (h0 >> 1)) * 128 * 128;
    const float* Ag = A + (size_t)rowBase * K;
    CORE_PROLOG_VARS;
    int ldRow  = tid >> 1;
    int ldCol  = (tid & 1) * 16;
    int kpBase = (tid & 1) * 8;
    float ar[16], br[16];
    #define FO_LOAD(k0)                                                        \
        {                                                                      \
            const float* ap = Ag + (size_t)ldRow * K + (k0) + ldCol;           \
            const float* bp = Wg + (size_t)ldRow * K + (k0) + ldCol;           \
            float4 t;                                                          \
            t = *(const float4*)(ap);      ar[0]=t.x; ar[1]=t.y; ar[2]=t.z; ar[3]=t.w;   \
            t = *(const float4*)(ap + 4);  ar[4]=t.x; ar[5]=t.y; ar[6]=t.z; ar[7]=t.w;   \
            t = *(const float4*)(ap + 8);  ar[8]=t.x; ar[9]=t.y; ar[10]=t.z; ar[11]=t.w; \
            t = *(const float4*)(ap + 12); ar[12]=t.x; ar[13]=t.y; ar[14]=t.z; ar[15]=t.w;\
            t = *(const float4*)(bp);      br[0]=t.x; br[1]=t.y; br[2]=t.z; br[3]=t.w;   \
            t = *(const float4*)(bp + 4);  br[4]=t.x; br[5]=t.y; br[6]=t.z; br[7]=t.w;   \
            t = *(const float4*)(bp + 8);  br[8]=t.x; br[9]=t.y; br[10]=t.z; br[11]=t.w; \
            t = *(const float4*)(bp + 12); br[12]=t.x; br[13]=t.y; br[14]=t.z; br[15]=t.w;\
        }
    #define FO_STORE(bufn)                                                     \
        {                                                                      \
            _Pragma("unroll")                                                  \
            for (int e = 0; e < 8; e++) {                                      \
                unsigned hi, lo;                                               \
                bfsplit2(ar[2*e], ar[2*e+1], hi, lo);                          \
                sm[SOFF_AH2(bufn) + (kpBase+e)*LDT + ldRow] = hi;              \
                sm[SOFF_AL2(bufn) + (kpBase+e)*LDT + ldRow] = lo;              \
                bfsplit2(br[2*e], br[2*e+1], hi, lo);                          \
                sm[SOFF_BH2(bufn) + (kpBase+e)*LDT + ldRow] = hi;              \
                sm[SOFF_BL2(bufn) + (kpBase+e)*LDT + ldRow] = lo;              \
            }                                                                  \
        }
    FO_LOAD(0);
    FO_STORE(0);
    __syncthreads();
    for (int t = 0; t < 4; t++) {
        int buf = t & 1;
        bool has = (t + 1 < 4);
        if (has) FO_LOAD((t + 1) << 5);
        {
            #pragma unroll
            for (int h = 0; h < 2; h++) {
                int kc = h*8 + (lane & 3);
                int mo2 = lane >> 2;
                unsigned afh[4][4], afl[4][4], bfh[4][2], bfl[4][2];
                #pragma unroll
                for (int mi = 0; mi < 4; mi++) {
                    int m = warpM + mi * 16 + mo2;
                    afh[mi][0] = sm[SOFF_AH2(buf) + kc*LDT + m];
                    afh[mi][1] = sm[SOFF_AH2(buf) + kc*LDT + m + 8];
                    afh[mi][2] = sm[SOFF_AH2(buf) + (kc+4)*LDT + m];
                    afh[mi][3] = sm[SOFF_AH2(buf) + (kc+4)*LDT + m + 8];
                    afl[mi][0] = sm[SOFF_AL2(buf) + kc*LDT + m];
                    afl[mi][1] = sm[SOFF_AL2(buf) + kc*LDT + m + 8];
                    afl[mi][2] = sm[SOFF_AL2(buf) + (kc+4)*LDT + m];
                    afl[mi][3] = sm[SOFF_AL2(buf) + (kc+4)*LDT + m + 8];
                }
                #pragma unroll
                for (int ni = 0; ni < 4; ni++) {
                    int n = warpN + ni * 8 + mo2;
                    bfh[ni][0] = sm[SOFF_BH2(buf) + kc*LDT + n];
                    bfh[ni][1] = sm[SOFF_BH2(buf) + (kc+4)*LDT + n];
                    bfl[ni][0] = sm[SOFF_BL2(buf) + kc*LDT + n];
                    bfl[ni][1] = sm[SOFF_BL2(buf) + (kc+4)*LDT + n];
                }
                #pragma unroll
                for (int mi = 0; mi < 4; mi++)
                    #pragma unroll
                    for (int ni = 0; ni < 4; ni++) {
                        mma_bf16(acc[mi][ni], afh[mi], bfh[ni]);
                        mma_bf16(acc[mi][ni], afl[mi], bfh[ni]);
                        mma_bf16(acc[mi][ni], afh[mi], bfl[ni]);
                    }
            }
        }
        if (has) FO_STORE(buf ^ 1);
        __syncthreads();
    }

    int mo = lane >> 2;
    #pragma unroll
    for (int mi = 0; mi < 4; mi++) {
        int rg = rowBase + warpM + mi*16 + mo;
        #pragma unroll
        for (int half = 0; half < 2; half++) {
            int r = rg + half * 8;
            int s = r & 4095;
            int bh = r >> 12;
            int b = bh >> 4, h = bh & 15;
            float vm = (mask[b * Ss + s] > 0) ? 1.f : 0.f;
            float scale = vm / (sq[r] + EPSF);
            size_t base = ((size_t)(b * Ss + s) * (Hh*HDd)) + h * HDd;
            #pragma unroll
            for (int ni = 0; ni < 4; ni++) {
                int c = warpN + ni*8 + (lane & 3)*2;
                unsigned hi, lo;
                hsplit2(acc[mi][ni][2*half]*scale,
                        acc[mi][ni][2*half+1]*scale, hi, lo);
                size_t w = (base + c) >> 1;
                outh[w] = hi;
                outl[w] = lo;
            }
        }
    }
}

// ------------------- init: zero kvT/ksum, reset kmax encodings --------------
__global__ void init_kernel() {
    int i = blockIdx.x * blockDim.x + threadIdx.x;
    if (i < Bb*HKk*Mm*HDd) g_kvT[i] = 0.f;
    if (i < Bb*HKk*Mm) { g_ksum[i] = 0.f; g_kmaxe[i] = 0u; }
}

// -- kvT[d,m] += sum_s phi_k[s,m]*v[s,d] ; ksum[m] += sum_s phi_k[s,m] -------
__global__ __launch_bounds__(256) void kv_kernel(const int* __restrict__ mask)
{
    __shared__ float kps[16][128];
    __shared__ float vs [16][128];
    __shared__ float kmx[128];
    __shared__ float vmask[128];
    int bh = blockIdx.y;
    int b = bh / HKk, hk = bh % HKk;
    int s0 = blockIdx.x * 128;
    int tid = threadIdx.x;
    int tr = tid >> 4, tc = tid & 15;
    if (tid < 128) {
        kmx[tid] = decf(g_kmaxe[bh * Mm + tid]);
        vmask[tid] = (mask[b * Ss + s0 + tid] > 0) ? 1.f : 0.f;
    }
    __syncthreads();

    const float* KX = g_kxp + ((size_t)bh * Ss + s0) * Mm;
    const float* V  = g_v + ((size_t)(b * Ss + s0)) * (HKk*HDd) + hk * HDd;
    float acc[8][8];
    #pragma unroll
    for (int i=0;i<8;i++)
        #pragma unroll
        for (int j=0;j<8;j++) acc[i][j]=0.f;
    float ksacc = 0.f;

    for (int sc = 0; sc < 128; sc += 16) {
        #pragma unroll
        for (int it = 0; it < 2; it++) {
            int idx = tid + it * 256;
            int r = idx >> 5;
            int c4 = (idx & 31) << 2;
            float vm = vmask[sc + r];
            float4 x4 = *(const float4*)(KX + (size_t)(sc + r) * Mm + c4);
            kps[r][c4+0] = (__expf(x4.x - kmx[c4+0]) * INV_SQRT_M + EPSF) * vm;
            kps[r][c4+1] = (__expf(x4.y - kmx[c4+1]) * INV_SQRT_M + EPSF) * vm;
            kps[r][c4+2] = (__expf(x4.z - kmx[c4+2]) * INV_SQRT_M + EPSF) * vm;
            kps[r][c4+3] = (__expf(x4.w - kmx[c4+3]) * INV_SQRT_M + EPSF) * vm;
            float4 v4 = *(const float4*)(V + (size_t)(sc + r) * (HKk*HDd) + c4);
            vs[r][c4+0]=v4.x; vs[r][c4+1]=v4.y; vs[r][c4+2]=v4.z; vs[r][c4+3]=v4.w;
        }
        __syncthreads();
        #pragma unroll
        for (int ssi = 0; ssi < 16; ssi++) {
            float ra[8], rb[8];
            #pragma unroll
            for (int i=0;i<8;i++) ra[i]=kps[ssi][tr*8+i];
            #pragma unroll
            for (int j=0;j<8;j++) rb[j]=vs[ssi][tc*8+j];
            #pragma unroll
            for (int i=0;i<8;i++)
                #pragma unroll
                for (int j=0;j<8;j++) acc[i][j] += ra[i]*rb[j];
        }
        if (tid < 128) {
            #pragma unroll
            for (int ssi = 0; ssi < 16; ssi++) ksacc += kps[ssi][tid];
        }
        __syncthreads();
    }
    float* KV = g_kvT + (size_t)bh * Mm * HDd;
    #pragma unroll
    for (int i = 0; i < 8; i++)
        #pragma unroll
        for (int j = 0; j < 8; j++)
            atomicAdd(&KV[(size_t)(tc*8+j)*Mm + tr*8+i], acc[i][j]);
    if (tid < 128) atomicAdd(&g_ksum[bh * Mm + tid], ksacc);
}

// -------------- denominators: dn[row] = qphi[row,:]·ksum[bhk,:] -------------
__global__ __launch_bounds__(256) void dn_kernel() {
    int warp = threadIdx.x >> 5, lane = threadIdx.x & 31;
    int row = blockIdx.x * 8 + warp;
    int bh = row >> 12;
    int b = bh >> 4, h = bh & 15;
    int bhk = b * 8 + (h >> 1);
    float4 q = *(const float4*)(g_qphi + (size_t)row * Mm + lane * 4);
    float4 s = *(const float4*)(g_ksum + bhk * Mm + lane * 4);
    float v = q.x*s.x + q.y*s.y + q.z*s.z + q.w*s.w;
    #pragma unroll
    for (int o = 16; o > 0; o >>= 1) v += __shfl_xor_sync(0xffffffffu, v, o);
    if (lane == 0) g_dn[row] = v;
}

// ------------------------------- launch -------------------------------------
extern "C" void kernel_launch(void* const* d_in, const int* in_sizes, int n_in,
                              void* d_out, int out_size)
{
    const float* x    = (const float*)d_in[0];
    const int*   mask = (const int*)  d_in[1];
    const float* fc   = (const float*)d_in[2];
    const float* wq   = (const float*)d_in[3];
    const float* wk   = (const float*)d_in[4];
    const float* wv   = (const float*)d_in[5];
    const float* wo   = (const float*)d_in[6];
    const float* gq   = (const float*)d_in[7];
    const float* gk   = (const float*)d_in[8];
    const float* proj = (const float*)d_in[9];
    float* out = (float*)d_out;

    float *pv, *psqq, *psqk, *pqphi, *pkxp, *pkvT, *pdn;
    cudaGetSymbolAddress((void**)&pv,   g_v);
    cudaGetSymbolAddress((void**)&psqq, g_sqq);
    cudaGetSymbolAddress((void**)&psqk, g_sqk);
    cudaGetSymbolAddress((void**)&pqphi,g_qphi);
    cudaGetSymbolAddress((void**)&pkxp, g_kxp);
    cudaGetSymbolAddress((void**)&pkvT, g_kvT);
    cudaGetSymbolAddress((void**)&pdn,  g_dn);

    unsigned *xfh,*xfl,*wqh,*wkh,*wvh,*woh,*aoh,*aol;
    unsigned *qxh,*qxl,*kxh,*kxl,*pjh,*pjl,*kmaxe;
    cudaGetSymbolAddress((void**)&xfh, g_xfh); cudaGetSymbolAddress((void**)&xfl, g_xfl);
    cudaGetSymbolAddress((void**)&wqh, g_wqh);
    cudaGetSymbolAddress((void**)&wkh, g_wkh);
    cudaGetSymbolAddress((void**)&wvh, g_wvh);
    cudaGetSymbolAddress((void**)&woh, g_woh);
    cudaGetSymbolAddress((void**)&aoh, g_aoh); cudaGetSymbolAddress((void**)&aol, g_aol);
    cudaGetSymbolAddress((void**)&qxh, g_qxh); cudaGetSymbolAddress((void**)&qxl, g_qxl);
    cudaGetSymbolAddress((void**)&kxh, g_kxh); cudaGetSymbolAddress((void**)&kxl, g_kxl);
    cudaGetSymbolAddress((void**)&pjh, g_pjh); cudaGetSymbolAddress((void**)&pjl, g_pjl);
    cudaGetSymbolAddress((void**)&kmaxe, g_kmaxe);

    cudaFuncSetAttribute(gemm_qk_fused, cudaFuncAttributeMaxDynamicSharedMemorySize, DSMEM3_BYTES);
    cudaFuncSetAttribute(gemm_f16_2t,   cudaFuncAttributeMaxDynamicSharedMemorySize, DSMEM3_BYTES);
    cudaFuncSetAttribute(favor_cpa,     cudaFuncAttributeMaxDynamicSharedMemorySize, DSMEM4_BYTES);
    cudaFuncSetAttribute(favor_out,     cudaFuncAttributeMaxDynamicSharedMemorySize, DSMEM_BYTES);

    // side stream + events for graph-captured fork/join (host objects only;
    // created per call, intentionally not destroyed while capture may hold them)
    cudaStream_t sA;
    cudaStreamCreateWithFlags(&sA, cudaStreamNonBlocking);
    cudaEvent_t evFork, evFK, evKV;
    cudaEventCreateWithFlags(&evFork, cudaEventDisableTiming);
    cudaEventCreateWithFlags(&evFK,   cudaEventDisableTiming);
    cudaEventCreateWithFlags(&evKV,   cudaEventDisableTiming);

    // --- s0: pre-split operands + init ---------------------------------------
    split_f16_kernel <<<(Bb*Ss*DIMm/4 + 255)/256, 256>>>(x,  xfh, xfl, Bb*Ss*DIMm/4);
    split_f16h_kernel<<<(Hh*HDd*DIMm/4 + 255)/256, 256>>>(wq, wqh, Hh*HDd*DIMm/4);
    split_f16h_kernel<<<(HKk*HDd*DIMm/4 + 255)/256, 256>>>(wk, wkh, HKk*HDd*DIMm/4);
    split_f16h_kernel<<<(HKk*HDd*DIMm/4 + 255)/256, 256>>>(wv, wvh, HKk*HDd*DIMm/4);
    split_f16h_kernel<<<(DIMm*Hh*HDd/4 + 255)/256, 256>>>(wo, woh, DIMm*Hh*HDd/4);
    split_bf16_kernel<<<(Mm*HDd/4 + 255)/256, 256>>>(proj, pjh, pjl, Mm*HDd/4);
    init_kernel<<<(Bb*HKk*Mm*HDd + 255)/256, 256>>>();
    cudaEventRecord(evFork, 0);

    // --- sA: V projection (concurrent with K-path on s0) ---------------------
    cudaStreamWaitEvent(sA, evFork, 0);
    gemm_f16_2t<<<dim3((HKk*HDd)/128, (Bb*Ss)/128), 256, DSMEM3_BYTES, sA>>>(
        xfh, xfl, wvh, pv, DIMm, HKk*HDd);

    // --- s0: K projection + favorK -------------------------------------------
    gemm_qk_fused<<<dim3(HKk, (Bb*Ss)/128), 256, DSMEM3_BYTES>>>(
        xfh, xfl, wkh, fc, gk, kxh, kxl, psqk, DIMm, HKk);
    favor_cpa<<<dim3(1, (Bb*HKk*Ss)/128), 256, DSMEM4_BYTES>>>(
        kxh, kxl, pjh, pjl, psqk, pkxp, kmaxe, 1);
    cudaEventRecord(evFK, 0);

    // --- sA: kv contraction (MUFU/mem-bound; overlaps qGEMM on s0) -----------
    cudaStreamWaitEvent(sA, evFK, 0);
    kv_kernel<<<dim3(Ss/128, Bb*HKk), 256, 0, sA>>>(mask);
    cudaEventRecord(evKV, sA);

    // --- s0: Q projection + favorQ (tensor-bound; runs while kv runs) --------
    gemm_qk_fused<<<dim3(Hh, (Bb*Ss)/128), 256, DSMEM3_BYTES>>>(
        xfh, xfl, wqh, fc, gq, qxh, qxl, psqq, DIMm, Hh);
    favor_cpa<<<dim3(1, (Bb*Hh*Ss)/128), 256, DSMEM4_BYTES>>>(
        qxh, qxl, pjh, pjl, psqq, pqphi, kmaxe, 0);

    // --- s0: join kv, then denominators + attention out + output projection --
    cudaStreamWaitEvent(0, evKV, 0);
    dn_kernel<<<(Bb*Hh*Ss)/8, 256>>>();
    favor_out<<<dim3(1, (Bb*Hh*Ss)/128), 256, DSMEM_BYTES>>>(
        pqphi, pkvT, pdn, mask, aoh, aol);
    gemm_f16_2t<<<dim3(DIMm/128, (Bb*Ss)/128), 256, DSMEM3_BYTES>>>(
        aoh, aol, woh, out, Hh*HDd, DIMm);
}

// round 15
// speedup vs baseline: 3.5155x; 1.0518x over previous
#include <cuda_runtime.h>
#include <cuda_bf16.h>
#include <cuda_fp16.h>
#include <math.h>
#include <stdint.h>

#define Bb  2
#define Ss  4096
#define DIMm 2048
#define Hh  16
#define HKk 8
#define HDd 128
#define Mm  128

#define INV_SQRT_M 0.08838834764831845f   // 128^{-0.5}
#define SCALE_QD   0.2973017787506803f    // 128^{-0.25}
#define EPSF 1e-6f

// ---------------- scratch (device globals; no allocations allowed) ----------
__device__ float g_v   [Bb*Ss*HKk*HDd];
__device__ float g_sqq [Bb*Hh*Ss];
__device__ float g_sqk [Bb*HKk*Ss];
__device__ float g_qphi[Bb*Hh*Ss*Mm];      // [b,h,s,m] fp32
__device__ float g_kxp [Bb*HKk*Ss*Mm];     // pre-exp key features fp32
__device__ unsigned g_kmaxe[Bb*HKk*Mm];    // encoded column max
__device__ float g_kvT [Bb*HKk*HDd*Mm];    // TRANSPOSED kv: [d][m]
__device__ float g_ksum[Bb*HKk*Mm];
__device__ float g_dn  [Bb*Hh*Ss];         // denominators

// pre-split operand arrays (packed x2 words)
#define XW (Bb*Ss*DIMm/2)
__device__ unsigned g_xfh [XW];            // x fp16 hi  (q,k,v GEMMs)
__device__ unsigned g_xfl [XW];            // x fp16 lo
__device__ unsigned g_wqh [Hh*HDd*DIMm/2];    // fp16 hi only
__device__ unsigned g_wkh [HKk*HDd*DIMm/2];
__device__ unsigned g_wvh [HKk*HDd*DIMm/2];
__device__ unsigned g_woh [DIMm*Hh*HDd/2];
__device__ unsigned g_aoh [Bb*Ss*Hh*HDd/2];   // attention out, fp16 hi
__device__ unsigned g_aol [Bb*Ss*Hh*HDd/2];   // attention out, fp16 lo
// bf16 hi/lo packed (favor operands)
__device__ unsigned g_qxh [Bb*Hh*Ss*HDd/2];
__device__ unsigned g_qxl [Bb*Hh*Ss*HDd/2];
__device__ unsigned g_kxh [Bb*HKk*Ss*HDd/2];
__device__ unsigned g_kxl [Bb*HKk*Ss*HDd/2];
__device__ unsigned g_pjh [Mm*HDd/2];
__device__ unsigned g_pjl [Mm*HDd/2];

// ---------------------------- helpers ---------------------------------------
__device__ __forceinline__ void bfsplit2(float x0, float x1, unsigned& hi, unsigned& lo) {
    __nv_bfloat162 h2 = __floats2bfloat162_rn(x0, x1);
    float2 hf = __bfloat1622float2(h2);
    __nv_bfloat162 l2 = __floats2bfloat162_rn(x0 - hf.x, x1 - hf.y);
    hi = *reinterpret_cast<unsigned*>(&h2);
    lo = *reinterpret_cast<unsigned*>(&l2);
}
__device__ __forceinline__ void hsplit2(float x0, float x1, unsigned& hi, unsigned& lo) {
    __half2 h2 = __floats2half2_rn(x0, x1);
    float2 hf = __half22float2(h2);
    __half2 l2 = __floats2half2_rn(x0 - hf.x, x1 - hf.y);
    hi = *reinterpret_cast<unsigned*>(&h2);
    lo = *reinterpret_cast<unsigned*>(&l2);
}
// order-preserving float<->unsigned encoding for atomicMax
__device__ __forceinline__ unsigned encf(float f) {
    int s = __float_as_int(f);
    return (s < 0) ? ~(unsigned)s : ((unsigned)s | 0x80000000u);
}
__device__ __forceinline__ float decf(unsigned u) {
    int s = (u & 0x80000000u) ? (int)(u & 0x7FFFFFFFu) : ~(int)u;
    return __int_as_float(s);
}

__device__ __forceinline__ void mma_bf16(float* d, const unsigned* a, const unsigned* b) {
    asm volatile(
        "mma.sync.aligned.m16n8k16.row.col.f32.bf16.bf16.f32 "
        "{%0,%1,%2,%3}, {%4,%5,%6,%7}, {%8,%9}, {%0,%1,%2,%3};\n"
        : "+f"(d[0]), "+f"(d[1]), "+f"(d[2]), "+f"(d[3])
        : "r"(a[0]), "r"(a[1]), "r"(a[2]), "r"(a[3]),
          "r"(b[0]), "r"(b[1]));
}
__device__ __forceinline__ void mma_f16(float* d, const unsigned* a, const unsigned* b) {
    asm volatile(
        "mma.sync.aligned.m16n8k16.row.col.f32.f16.f16.f32 "
        "{%0,%1,%2,%3}, {%4,%5,%6,%7}, {%8,%9}, {%0,%1,%2,%3};\n"
        : "+f"(d[0]), "+f"(d[1]), "+f"(d[2]), "+f"(d[3])
        : "r"(a[0]), "r"(a[1]), "r"(a[2]), "r"(a[3]),
          "r"(b[0]), "r"(b[1]));
}

#define CP16(dst, src) asm volatile("cp.async.cg.shared.global [%0], [%1], 16;\n" :: "r"(dst), "l"(src) : "memory")
#define CP_COMMIT()    asm volatile("cp.async.commit_group;\n" ::: "memory")
#define CP_WAIT0()     asm volatile("cp.async.wait_group 0;\n" ::: "memory")
#define LDMX4(r, addr) asm volatile( \
    "ldmatrix.sync.aligned.m8n8.x4.shared.b16 {%0,%1,%2,%3}, [%4];" \
    : "=r"((r)[0]), "=r"((r)[1]), "=r"((r)[2]), "=r"((r)[3]) : "r"(addr))

// ===== cp.async/ldmatrix smem layouts ========================================
#define P3 2560u
#define POFF_AH(st) ((unsigned)(st)*P3)
#define POFF_AL(st) (2u*P3 + (unsigned)(st)*P3)
#define POFF_BH(st) (4u*P3 + (unsigned)(st)*P3)
#define POFF_BL(st) (6u*P3 + (unsigned)(st)*P3)
#define DSMEM3_BYTES (6*2560*4)   // 61440 (3 arrays, fp16 2-term)
#define DSMEM4_BYTES (8*2560*4)   // 81920 (4 arrays, bf16 3-term)

// ---- 2-term fp16 (GEMMs) ----
#define CPA_LOAD(t0, st)                                                       \
    {                                                                          \
        int row = tid >> 1;                                                    \
        int ch  = (tid & 1) * 8;                                               \
        size_t g = (size_t)row * KW + ((size_t)(t0) << 4) + ch;                \
        unsigned d;                                                            \
        d = smb + (POFF_AH(st) + (unsigned)row*20u + ch)*4u;                   \
        CP16(d, Agh + g); CP16(d+16u, Agh + g + 4);                            \
        d = smb + (POFF_AL(st) + (unsigned)row*20u + ch)*4u;                   \
        CP16(d, Agl + g); CP16(d+16u, Agl + g + 4);                            \
        d = smb + (POFF_BH(st) + (unsigned)row*20u + ch)*4u;                   \
        CP16(d, Bgh + g); CP16(d+16u, Bgh + g + 4);                            \
        CP_COMMIT();                                                           \
    }

#define CPA_COMPUTE(st)                                                        \
    {                                                                          \
        _Pragma("unroll")                                                      \
        for (int h = 0; h < 2; h++) {                                          \
            int arow = (lane & 7) + ((lane >> 3) & 1) * 8;                     \
            int achw = 8*h + ((lane >> 4) & 1) * 4;                            \
            int brow = (lane & 7) + ((lane >> 4) & 1) * 8;                     \
            int bchw = 8*h + ((lane >> 3) & 1) * 4;                            \
            unsigned afh[4][4], afl[4][4], bf[2][4];                           \
            _Pragma("unroll")                                                  \
            for (int mi = 0; mi < 4; mi++) {                                   \
                unsigned ra = smb + (POFF_AH(st) +                             \
                    (unsigned)(warpM + mi*16 + arow)*20u + achw)*4u;           \
                LDMX4(afh[mi], ra);                                            \
                unsigned rl = smb + (POFF_AL(st) +                             \
                    (unsigned)(warpM + mi*16 + arow)*20u + achw)*4u;           \
                LDMX4(afl[mi], rl);                                            \
            }                                                                  \
            LDMX4(bf[0], smb + (POFF_BH(st) +                                  \
                (unsigned)(warpN + brow)*20u + bchw)*4u);                      \
            LDMX4(bf[1], smb + (POFF_BH(st) +                                  \
                (unsigned)(warpN + 16 + brow)*20u + bchw)*4u);                 \
            _Pragma("unroll")                                                  \
            for (int mi = 0; mi < 4; mi++) {                                   \
                mma_f16(acc[mi][0], afh[mi], &bf[0][0]);                       \
                mma_f16(acc[mi][0], afl[mi], &bf[0][0]);                       \
                mma_f16(acc[mi][1], afh[mi], &bf[0][2]);                       \
                mma_f16(acc[mi][1], afl[mi], &bf[0][2]);                       \
                mma_f16(acc[mi][2], afh[mi], &bf[1][0]);                       \
                mma_f16(acc[mi][2], afl[mi], &bf[1][0]);                       \
                mma_f16(acc[mi][3], afh[mi], &bf[1][2]);                       \
                mma_f16(acc[mi][3], afl[mi], &bf[1][2]);                       \
            }                                                                  \
        }                                                                      \
    }

#define CPA_MAINLOOP(KTILES)                                                   \
    CPA_LOAD(0, 0);                                                            \
    CP_WAIT0();                                                                \
    __syncthreads();                                                           \
    for (int t = 0; t < (KTILES); t++) {                                       \
        int st = t & 1;                                                        \
        bool has = (t + 1 < (KTILES));                                         \
        if (has) CPA_LOAD(t + 1, st ^ 1);                                      \
        CPA_COMPUTE(st);                                                       \
        if (has) CP_WAIT0();                                                   \
        __syncthreads();                                                       \
    }

// ---- 3-term bf16 (favor kernels), 4 arrays ----
#define CPA4_LOAD(t0, st)                                                      \
    {                                                                          \
        int row = tid >> 1;                                                    \
        int ch  = (tid & 1) * 8;                                               \
        size_t g = (size_t)row * KW + ((size_t)(t0) << 4) + ch;                \
        unsigned d;                                                            \
        d = smb + (POFF_AH(st) + (unsigned)row*20u + ch)*4u;                   \
        CP16(d, Agh + g); CP16(d+16u, Agh + g + 4);                            \
        d = smb + (POFF_AL(st) + (unsigned)row*20u + ch)*4u;                   \
        CP16(d, Agl + g); CP16(d+16u, Agl + g + 4);                            \
        d = smb + (POFF_BH(st) + (unsigned)row*20u + ch)*4u;                   \
        CP16(d, Bgh + g); CP16(d+16u, Bgh + g + 4);                            \
        d = smb + (POFF_BL(st) + (unsigned)row*20u + ch)*4u;                   \
        CP16(d, Bgl + g); CP16(d+16u, Bgl + g + 4);                            \
        CP_COMMIT();                                                           \
    }

#define CPA4_COMPUTE(st)                                                       \
    {                                                                          \
        _Pragma("unroll")                                                      \
        for (int h = 0; h < 2; h++) {                                          \
            int arow = (lane & 7) + ((lane >> 3) & 1) * 8;                     \
            int achw = 8*h + ((lane >> 4) & 1) * 4;                            \
            int brow = (lane & 7) + ((lane >> 4) & 1) * 8;                     \
            int bchw = 8*h + ((lane >> 3) & 1) * 4;                            \
            unsigned afh[4][4], afl[4][4], bfh[2][4], bfl[2][4];               \
            _Pragma("unroll")                                                  \
            for (int mi = 0; mi < 4; mi++) {                                   \
                LDMX4(afh[mi], smb + (POFF_AH(st) +                            \
                    (unsigned)(warpM + mi*16 + arow)*20u + achw)*4u);          \
                LDMX4(afl[mi], smb + (POFF_AL(st) +                            \
                    (unsigned)(warpM + mi*16 + arow)*20u + achw)*4u);          \
            }                                                                  \
            LDMX4(bfh[0], smb + (POFF_BH(st) +                                 \
                (unsigned)(warpN + brow)*20u + bchw)*4u);                      \
            LDMX4(bfh[1], smb + (POFF_BH(st) +                                 \
                (unsigned)(warpN + 16 + brow)*20u + bchw)*4u);                 \
            LDMX4(bfl[0], smb + (POFF_BL(st) +                                 \
                (unsigned)(warpN + brow)*20u + bchw)*4u);                      \
            LDMX4(bfl[1], smb + (POFF_BL(st) +                                 \
                (unsigned)(warpN + 16 + brow)*20u + bchw)*4u);                 \
            _Pragma("unroll")                                                  \
            for (int mi = 0; mi < 4; mi++) {                                   \
                mma_bf16(acc[mi][0], afh[mi], &bfh[0][0]);                     \
                mma_bf16(acc[mi][0], afl[mi], &bfh[0][0]);                     \
                mma_bf16(acc[mi][0], afh[mi], &bfl[0][0]);                     \
                mma_bf16(acc[mi][1], afh[mi], &bfh[0][2]);                     \
                mma_bf16(acc[mi][1], afl[mi], &bfh[0][2]);                     \
                mma_bf16(acc[mi][1], afh[mi], &bfl[0][2]);                     \
                mma_bf16(acc[mi][2], afh[mi], &bfh[1][0]);                     \
                mma_bf16(acc[mi][2], afl[mi], &bfh[1][0]);                     \
                mma_bf16(acc[mi][2], afh[mi], &bfl[1][0]);                     \
                mma_bf16(acc[mi][3], afh[mi], &bfh[1][2]);                     \
                mma_bf16(acc[mi][3], afl[mi], &bfh[1][2]);                     \
                mma_bf16(acc[mi][3], afh[mi], &bfl[1][2]);                     \
            }                                                                  \
        }                                                                      \
    }

#define CPA4_MAINLOOP(KTILES)                                                  \
    CPA4_LOAD(0, 0);                                                           \
    CP_WAIT0();                                                                \
    __syncthreads();                                                           \
    for (int t = 0; t < (KTILES); t++) {                                       \
        int st = t & 1;                                                        \
        bool has = (t + 1 < (KTILES));                                         \
        if (has) CPA4_LOAD(t + 1, st ^ 1);                                     \
        CPA4_COMPUTE(st);                                                      \
        if (has) CP_WAIT0();                                                   \
        __syncthreads();                                                       \
    }

#define CORE_PROLOG_VARS                                                       \
    int tid  = threadIdx.x;                                                    \
    int lane = tid & 31;                                                       \
    int warp = tid >> 5;                                                       \
    int warpM = (warp >> 2) * 64;                                              \
    int warpN = (warp & 3) * 32;                                               \
    float acc[4][4][4];                                                        \
    _Pragma("unroll")                                                          \
    for (int mi = 0; mi < 4; mi++)                                             \
        _Pragma("unroll")                                                      \
        for (int ni = 0; ni < 4; ni++)                                         \
            _Pragma("unroll")                                                  \
            for (int e = 0; e < 4; e++) acc[mi][ni][e] = 0.f;

// ---------------- fp32 -> packed hi/lo split kernels (MLP=2) ----------------
__global__ __launch_bounds__(256) void split_f16_kernel(
    const float* __restrict__ src, unsigned* __restrict__ hi,
    unsigned* __restrict__ lo, int nHalf)
{
    int i = blockIdx.x * blockDim.x + threadIdx.x;
    if (i >= nHalf) return;
    float4 v0 = ((const float4*)src)[i];
    float4 v1 = ((const float4*)src)[i + nHalf];
    unsigned h0, l0, h1, l1;
    hsplit2(v0.x, v0.y, h0, l0);
    hsplit2(v0.z, v0.w, h1, l1);
    ((uint2*)hi)[i] = make_uint2(h0, h1);
    ((uint2*)lo)[i] = make_uint2(l0, l1);
    hsplit2(v1.x, v1.y, h0, l0);
    hsplit2(v1.z, v1.w, h1, l1);
    ((uint2*)hi)[i + nHalf] = make_uint2(h0, h1);
    ((uint2*)lo)[i + nHalf] = make_uint2(l0, l1);
}
__global__ __launch_bounds__(256) void split_f16h_kernel(
    const float* __restrict__ src, unsigned* __restrict__ hi, int nHalf)
{
    int i = blockIdx.x * blockDim.x + threadIdx.x;
    if (i >= nHalf) return;
    float4 v0 = ((const float4*)src)[i];
    float4 v1 = ((const float4*)src)[i + nHalf];
    __half2 a0 = __floats2half2_rn(v0.x, v0.y);
    __half2 b0 = __floats2half2_rn(v0.z, v0.w);
    __half2 a1 = __floats2half2_rn(v1.x, v1.y);
    __half2 b1 = __floats2half2_rn(v1.z, v1.w);
    ((uint2*)hi)[i] = make_uint2(*reinterpret_cast<unsigned*>(&a0),
                                 *reinterpret_cast<unsigned*>(&b0));
    ((uint2*)hi)[i + nHalf] = make_uint2(*reinterpret_cast<unsigned*>(&a1),
                                         *reinterpret_cast<unsigned*>(&b1));
}
__global__ __launch_bounds__(256) void split_bf16_kernel(
    const float* __restrict__ src, unsigned* __restrict__ hi,
    unsigned* __restrict__ lo, int n4)
{
    int i = blockIdx.x * blockDim.x + threadIdx.x;
    if (i >= n4) return;
    float4 v = ((const float4*)src)[i];
    unsigned h0, l0, h1, l1;
    bfsplit2(v.x, v.y, h0, l0);
    bfsplit2(v.z, v.w, h1, l1);
    ((uint2*)hi)[i] = make_uint2(h0, h1);
    ((uint2*)lo)[i] = make_uint2(l0, l1);
}

// ------- 2-term fp16 GEMM + fused RMSNorm/RoPE epilogue (cp.async core) -----
__global__ __launch_bounds__(256) void gemm_qk_fused(
    const unsigned* __restrict__ Ah, const unsigned* __restrict__ Al,
    const unsigned* __restrict__ Bh,
    const float* __restrict__ fc, const float* __restrict__ gvec,
    unsigned* __restrict__ xouth, unsigned* __restrict__ xoutl,
    float* __restrict__ sqout, int K, int nh)
{
    extern __shared__ unsigned sm[];
    __shared__ float red2[128][4][2];
    __shared__ float gsh[128];
    int rowBase = blockIdx.y * 128;
    int colBase = blockIdx.x * 128;
    const int KW = K >> 1;
    const unsigned* Agh = Ah + (size_t)rowBase * KW;
    const unsigned* Agl = Al + (size_t)rowBase * KW;
    const unsigned* Bgh = Bh + (size_t)colBase * KW;
    CORE_PROLOG_VARS;
    unsigned smb;
    asm("{ .reg .u64 t; cvta.to.shared.u64 t, %1; cvt.u32.u64 %0, t; }" : "=r"(smb) : "l"(sm));
    if (tid < 128) gsh[tid] = gvec[tid];
    int kTiles = K >> 5;
    CPA_MAINLOOP(kTiles);

    int mo = lane >> 2;
    #pragma unroll
    for (int mi = 0; mi < 4; mi++) {
        #pragma unroll
        for (int half = 0; half < 2; half++) {
            float s1 = 0.f, s2 = 0.f;
            #pragma unroll
            for (int ni = 0; ni < 4; ni++) {
                int c = warpN + ni*8 + (lane & 3)*2;
                float v0 = acc[mi][ni][2*half], v1 = acc[mi][ni][2*half+1];
                s1 += v0*v0 + v1*v1;
                float w0 = v0*gsh[c], w1 = v1*gsh[c+1];
                s2 += w0*w0 + w1*w1;
            }
            s1 += __shfl_xor_sync(0xffffffffu, s1, 1);
            s1 += __shfl_xor_sync(0xffffffffu, s1, 2);
            s2 += __shfl_xor_sync(0xffffffffu, s2, 1);
            s2 += __shfl_xor_sync(0xffffffffu, s2, 2);
            if ((lane & 3) == 0) {
                int rl = warpM + mi*16 + mo + half*8;
                red2[rl][warp & 3][0] = s1;
                red2[rl][warp & 3][1] = s2;
            }
        }
    }
    __syncthreads();
    #pragma unroll
    for (int mi = 0; mi < 4; mi++) {
        #pragma unroll
        for (int half = 0; half < 2; half++) {
            int rl = warpM + mi*16 + mo + half*8;
            float S1 = red2[rl][0][0]+red2[rl][1][0]+red2[rl][2][0]+red2[rl][3][0];
            float S2 = red2[rl][0][1]+red2[rl][1][1]+red2[rl][2][1]+red2[rl][3][1];
            float inv = rsqrtf(S1 * (1.0f/128.0f) + 1e-5f);
            int bs = rowBase + rl;
            int b = bs >> 12, s = bs & 4095;
            size_t rowoff = (((size_t)(b*nh + blockIdx.x))*Ss + s) * (HDd/2);
            #pragma unroll
            for (int ni = 0; ni < 4; ni++) {
                int c = warpN + ni*8 + (lane & 3)*2;
                float a  = acc[mi][ni][2*half]   * inv * gsh[c];
                float b2 = acc[mi][ni][2*half+1] * inv * gsh[c+1];
                float2 cs = ((const float2*)fc)[(size_t)bs * (HDd/2) + (c >> 1)];
                float r0 = (a*cs.x - b2*cs.y) * SCALE_QD;
                float r1 = (a*cs.y + b2*cs.x) * SCALE_QD;
                unsigned hi, lo;
                bfsplit2(r0, r1, hi, lo);
                xouth[rowoff + (c >> 1)] = hi;
                xoutl[rowoff + (c >> 1)] = lo;
            }
            if ((warp & 3) == 0 && (lane & 3) == 0)
                sqout[((size_t)(b*nh + blockIdx.x))*Ss + s] =
                    0.5f * SCALE_QD * SCALE_QD * inv * inv * S2;
        }
    }
}

// ------- 2-term fp16 GEMM, plain epilogue (cp.async core) -------------------
__global__ __launch_bounds__(256) void gemm_f16_2t(
    const unsigned* __restrict__ Ah, const unsigned* __restrict__ Al,
    const unsigned* __restrict__ Bh,
    float* __restrict__ C, int K, int N)
{
    extern __shared__ unsigned sm[];
    int rowBase = blockIdx.y * 128;
    int colBase = blockIdx.x * 128;
    const int KW = K >> 1;
    const unsigned* Agh = Ah + (size_t)rowBase * KW;
    const unsigned* Agl = Al + (size_t)rowBase * KW;
    const unsigned* Bgh = Bh + (size_t)colBase * KW;
    CORE_PROLOG_VARS;
    unsigned smb;
    asm("{ .reg .u64 t; cvta.to.shared.u64 t, %1; cvt.u32.u64 %0, t; }" : "=r"(smb) : "l"(sm));
    int kTiles = K >> 5;
    CPA_MAINLOOP(kTiles);

    #pragma unroll
    for (int mi = 0; mi < 4; mi++) {
        int r = rowBase + warpM + mi * 16 + (lane >> 2);
        #pragma unroll
        for (int ni = 0; ni < 4; ni++) {
            int c = colBase + warpN + ni * 8 + (lane & 3) * 2;
            *(float2*)(C + (size_t)r * N + c) =
                make_float2(acc[mi][ni][0], acc[mi][ni][1]);
            *(float2*)(C + (size_t)(r + 8) * N + c) =
                make_float2(acc[mi][ni][2], acc[mi][ni][3]);
        }
    }
}

// ---- favor modes 0/1 with cp.async/ldmatrix 3-term bf16 core ---------------
__global__ __launch_bounds__(256) void favor_cpa(
    const unsigned* __restrict__ Ah, const unsigned* __restrict__ Al,
    const unsigned* __restrict__ Bh, const unsigned* __restrict__ Bl,
    const float* __restrict__ sq, float* __restrict__ out,
    unsigned* __restrict__ kmaxe, int mode)
{
    extern __shared__ unsigned sm[];
    __shared__ float red[128][4];
    __shared__ unsigned smax[128];
    int rowBase = blockIdx.y * 128;
    const int KW = 64, N = 128;
    const unsigned* Agh = Ah + (size_t)rowBase * KW;
    const unsigned* Agl = Al + (size_t)rowBase * KW;
    const unsigned* Bgh = Bh;
    const unsigned* Bgl = Bl;
    CORE_PROLOG_VARS;
    unsigned smb;
    asm("{ .reg .u64 t; cvta.to.shared.u64 t, %1; cvt.u32.u64 %0, t; }" : "=r"(smb) : "l"(sm));
    if (mode == 1 && tid < 128) smax[tid] = 0u;
    CPA4_MAINLOOP(4);

    int mo = lane >> 2;
    if (mode == 0) {
        #pragma unroll
        for (int mi = 0; mi < 4; mi++) {
            float m0 = -1e30f, m1 = -1e30f;
            #pragma unroll
            for (int ni = 0; ni < 4; ni++) {
                m0 = fmaxf(m0, fmaxf(acc[mi][ni][0], acc[mi][ni][1]));
                m1 = fmaxf(m1, fmaxf(acc[mi][ni][2], acc[mi][ni][3]));
            }
            m0 = fmaxf(m0, __shfl_xor_sync(0xffffffffu, m0, 1));
            m0 = fmaxf(m0, __shfl_xor_sync(0xffffffffu, m0, 2));
            m1 = fmaxf(m1, __shfl_xor_sync(0xffffffffu, m1, 1));
            m1 = fmaxf(m1, __shfl_xor_sync(0xffffffffu, m1, 2));
            if ((lane & 3) == 0) {
                red[warpM + mi*16 + mo][warp & 3] = m0;
                red[warpM + mi*16 + mo + 8][warp & 3] = m1;
            }
        }
        __syncthreads();
        #pragma unroll
        for (int mi = 0; mi < 4; mi++) {
            int rl = warpM + mi*16 + mo;
            float rm0 = fmaxf(fmaxf(red[rl][0], red[rl][1]),
                              fmaxf(red[rl][2], red[rl][3]));
            float rm1 = fmaxf(fmaxf(red[rl+8][0], red[rl+8][1]),
                              fmaxf(red[rl+8][2], red[rl+8][3]));
            #pragma unroll
            for (int ni = 0; ni < 4; ni++) {
                int c = warpN + ni*8 + (lane & 3)*2;
                *(float2*)(out + (size_t)(rowBase + rl) * N + c) =
                    make_float2(__expf(acc[mi][ni][0]-rm0)*INV_SQRT_M + EPSF,
                                __expf(acc[mi][ni][1]-rm0)*INV_SQRT_M + EPSF);
                *(float2*)(out + (size_t)(rowBase + rl + 8) * N + c) =
                    make_float2(__expf(acc[mi][ni][2]-rm1)*INV_SQRT_M + EPSF,
                                __expf(acc[mi][ni][3]-rm1)*INV_SQRT_M + EPSF);
            }
        }
    } else {
        #pragma unroll
        for (int ni = 0; ni < 4; ni++) {
            float cm0 = -1e30f, cm1 = -1e30f;
            #pragma unroll
            for (int mi = 0; mi < 4; mi++) {
                int r0 = rowBase + warpM + mi*16 + mo;
                float s0 = sq[r0], s1 = sq[r0 + 8];
                int c = warpN + ni*8 + (lane & 3)*2;
                float o00 = acc[mi][ni][0]-s0, o01 = acc[mi][ni][1]-s0;
                float o10 = acc[mi][ni][2]-s1, o11 = acc[mi][ni][3]-s1;
                *(float2*)(out + (size_t)r0 * N + c)       = make_float2(o00, o01);
                *(float2*)(out + (size_t)(r0 + 8) * N + c) = make_float2(o10, o11);
                cm0 = fmaxf(cm0, fmaxf(o00, o10));
                cm1 = fmaxf(cm1, fmaxf(o01, o11));
            }
            cm0 = fmaxf(cm0, __shfl_xor_sync(0xffffffffu, cm0, 4));
            cm0 = fmaxf(cm0, __shfl_xor_sync(0xffffffffu, cm0, 8));
            cm0 = fmaxf(cm0, __shfl_xor_sync(0xffffffffu, cm0, 16));
            cm1 = fmaxf(cm1, __shfl_xor_sync(0xffffffffu, cm1, 4));
            cm1 = fmaxf(cm1, __shfl_xor_sync(0xffffffffu, cm1, 8));
            cm1 = fmaxf(cm1, __shfl_xor_sync(0xffffffffu, cm1, 16));
            if (mo == 0) {
                int c = warpN + ni*8 + (lane & 3)*2;
                atomicMax(&smax[c],   encf(cm0));
                atomicMax(&smax[c+1], encf(cm1));
            }
        }
        __syncthreads();
        if (tid < 128) {
            int bh = blockIdx.y >> 5;
            atomicMax(&kmaxe[bh * Mm + tid], smax[tid]);
        }
    }
}

// ---- mode-2 favor (old fp32-input core): out = qphi @ kvT + mask/denom -----
#define LDT 136
#define SOFF_AH2(b) ((unsigned)(b)*2176u)
#define SOFF_AL2(b) (4352u  + (unsigned)(b)*2176u)
#define SOFF_BH2(b) (8704u  + (unsigned)(b)*2176u)
#define SOFF_BL2(b) (13056u + (unsigned)(b)*2176u)
#define DSMEM_BYTES (17408*4)   // 69632

__global__ __launch_bounds__(256) void favor_out(
    const float* __restrict__ A, const float* __restrict__ Bglob,
    const float* __restrict__ sq, const int* __restrict__ mask,
    unsigned* __restrict__ outh, unsigned* __restrict__ outl)
{
    extern __shared__ unsigned sm[];
    int rowBase = blockIdx.y * 128;
    const int K = 128;
    int bh0 = blockIdx.y >> 5;
    int b0 = bh0 >> 4, h0 = bh0 & 15;
    const float* Wg = Bglob + (size_t)(b0 * 8 + (h0 >> 1)) * 128 * 128;
    const float* Ag = A + (size_t)rowBase * K;
    CORE_PROLOG_VARS;
    int ldRow  = tid >> 1;
    int ldCol  = (tid & 1) * 16;
    int kpBase = (tid & 1) * 8;
    float ar[16], br[16];
    #define FO_LOAD(k0)                                                        \
        {                                                                      \
            const float* ap = Ag + (size_t)ldRow * K + (k0) + ldCol;           \
            const float* bp = Wg + (size_t)ldRow * K + (k0) + ldCol;           \
            float4 t;                                                          \
            t = *(const float4*)(ap);      ar[0]=t.x; ar[1]=t.y; ar[2]=t.z; ar[3]=t.w;   \
            t = *(const float4*)(ap + 4);  ar[4]=t.x; ar[5]=t.y; ar[6]=t.z; ar[7]=t.w;   \
            t = *(const float4*)(ap + 8);  ar[8]=t.x; ar[9]=t.y; ar[10]=t.z; ar[11]=t.w; \
            t = *(const float4*)(ap + 12); ar[12]=t.x; ar[13]=t.y; ar[14]=t.z; ar[15]=t.w;\
            t = *(const float4*)(bp);      br[0]=t.x; br[1]=t.y; br[2]=t.z; br[3]=t.w;   \
            t = *(const float4*)(bp + 4);  br[4]=t.x; br[5]=t.y; br[6]=t.z; br[7]=t.w;   \
            t = *(const float4*)(bp + 8);  br[8]=t.x; br[9]=t.y; br[10]=t.z; br[11]=t.w; \
            t = *(const float4*)(bp + 12); br[12]=t.x; br[13]=t.y; br[14]=t.z; br[15]=t.w;\
        }
    #define FO_STORE(bufn)                                                     \
        {                                                                      \
            _Pragma("unroll")                                                  \
            for (int e = 0; e < 8; e++) {                                      \
                unsigned hi, lo;                                               \
                bfsplit2(ar[2*e], ar[2*e+1], hi, lo);                          \
                sm[SOFF_AH2(bufn) + (kpBase+e)*LDT + ldRow] = hi;              \
                sm[SOFF_AL2(bufn) + (kpBase+e)*LDT + ldRow] = lo;              \
                bfsplit2(br[2*e], br[2*e+1], hi, lo);                          \
                sm[SOFF_BH2(bufn) + (kpBase+e)*LDT + ldRow] = hi;              \
                sm[SOFF_BL2(bufn) + (kpBase+e)*LDT + ldRow] = lo;              \
            }                                                                  \
        }
    FO_LOAD(0);
    FO_STORE(0);
    __syncthreads();
    for (int t = 0; t < 4; t++) {
        int buf = t & 1;
        bool has = (t + 1 < 4);
        if (has) FO_LOAD((t + 1) << 5);
        {
            #pragma unroll
            for (int h = 0; h < 2; h++) {
                int kc = h*8 + (lane & 3);
                int mo2 = lane >> 2;
                unsigned afh[4][4], afl[4][4], bfh[4][2], bfl[4][2];
                #pragma unroll
                for (int mi = 0; mi < 4; mi++) {
                    int m = warpM + mi * 16 + mo2;
                    afh[mi][0] = sm[SOFF_AH2(buf) + kc*LDT + m];
                    afh[mi][1] = sm[SOFF_AH2(buf) + kc*LDT + m + 8];
                    afh[mi][2] = sm[SOFF_AH2(buf) + (kc+4)*LDT + m];
                    afh[mi][3] = sm[SOFF_AH2(buf) + (kc+4)*LDT + m + 8];
                    afl[mi][0] = sm[SOFF_AL2(buf) + kc*LDT + m];
                    afl[mi][1] = sm[SOFF_AL2(buf) + kc*LDT + m + 8];
                    afl[mi][2] = sm[SOFF_AL2(buf) + (kc+4)*LDT + m];
                    afl[mi][3] = sm[SOFF_AL2(buf) + (kc+4)*LDT + m + 8];
                }
                #pragma unroll
                for (int ni = 0; ni < 4; ni++) {
                    int n = warpN + ni * 8 + mo2;
                    bfh[ni][0] = sm[SOFF_BH2(buf) + kc*LDT + n];
                    bfh[ni][1] = sm[SOFF_BH2(buf) + (kc+4)*LDT + n];
                    bfl[ni][0] = sm[SOFF_BL2(buf) + kc*LDT + n];
                    bfl[ni][1] = sm[SOFF_BL2(buf) + (kc+4)*LDT + n];
                }
                #pragma unroll
                for (int mi = 0; mi < 4; mi++)
                    #pragma unroll
                    for (int ni = 0; ni < 4; ni++) {
                        mma_bf16(acc[mi][ni], afh[mi], bfh[ni]);
                        mma_bf16(acc[mi][ni], afl[mi], bfh[ni]);
                        mma_bf16(acc[mi][ni], afh[mi], bfl[ni]);
                    }
            }
        }
        if (has) FO_STORE(buf ^ 1);
        __syncthreads();
    }

    int mo = lane >> 2;
    #pragma unroll
    for (int mi = 0; mi < 4; mi++) {
        int rg = rowBase + warpM + mi*16 + mo;
        #pragma unroll
        for (int half = 0; half < 2; half++) {
            int r = rg + half * 8;
            int s = r & 4095;
            int bh = r >> 12;
            int b = bh >> 4, h = bh & 15;
            float vm = (mask[b * Ss + s] > 0) ? 1.f : 0.f;
            float scale = vm / (sq[r] + EPSF);
            size_t base = ((size_t)(b * Ss + s) * (Hh*HDd)) + h * HDd;
            #pragma unroll
            for (int ni = 0; ni < 4; ni++) {
                int c = warpN + ni*8 + (lane & 3)*2;
                unsigned hi, lo;
                hsplit2(acc[mi][ni][2*half]*scale,
                        acc[mi][ni][2*half+1]*scale, hi, lo);
                size_t w = (base + c) >> 1;
                outh[w] = hi;
                outl[w] = lo;
            }
        }
    }
}

// ------------------- init: zero kvT/ksum, reset kmax encodings --------------
__global__ void init_kernel() {
    int i = blockIdx.x * blockDim.x + threadIdx.x;
    if (i < Bb*HKk*Mm*HDd) g_kvT[i] = 0.f;
    if (i < Bb*HKk*Mm) { g_ksum[i] = 0.f; g_kmaxe[i] = 0u; }
}

// -- kvT[d,m] += sum_s phi_k[s,m]*v[s,d] ; ksum[m] += sum_s phi_k[s,m] -------
__global__ __launch_bounds__(256) void kv_kernel(const int* __restrict__ mask)
{
    __shared__ float kps[16][128];
    __shared__ float vs [16][128];
    __shared__ float kmx[128];
    __shared__ float vmask[128];
    int bh = blockIdx.y;
    int b = bh / HKk, hk = bh % HKk;
    int s0 = blockIdx.x * 128;
    int tid = threadIdx.x;
    int tr = tid >> 4, tc = tid & 15;
    if (tid < 128) {
        kmx[tid] = decf(g_kmaxe[bh * Mm + tid]);
        vmask[tid] = (mask[b * Ss + s0 + tid] > 0) ? 1.f : 0.f;
    }
    __syncthreads();

    const float* KX = g_kxp + ((size_t)bh * Ss + s0) * Mm;
    const float* V  = g_v + ((size_t)(b * Ss + s0)) * (HKk*HDd) + hk * HDd;
    float acc[8][8];
    #pragma unroll
    for (int i=0;i<8;i++)
        #pragma unroll
        for (int j=0;j<8;j++) acc[i][j]=0.f;
    float ksacc = 0.f;

    for (int sc = 0; sc < 128; sc += 16) {
        #pragma unroll
        for (int it = 0; it < 2; it++) {
            int idx = tid + it * 256;
            int r = idx >> 5;
            int c4 = (idx & 31) << 2;
            float vm = vmask[sc + r];
            float4 x4 = *(const float4*)(KX + (size_t)(sc + r) * Mm + c4);
            kps[r][c4+0] = (__expf(x4.x - kmx[c4+0]) * INV_SQRT_M + EPSF) * vm;
            kps[r][c4+1] = (__expf(x4.y - kmx[c4+1]) * INV_SQRT_M + EPSF) * vm;
            kps[r][c4+2] = (__expf(x4.z - kmx[c4+2]) * INV_SQRT_M + EPSF) * vm;
            kps[r][c4+3] = (__expf(x4.w - kmx[c4+3]) * INV_SQRT_M + EPSF) * vm;
            float4 v4 = *(const float4*)(V + (size_t)(sc + r) * (HKk*HDd) + c4);
            vs[r][c4+0]=v4.x; vs[r][c4+1]=v4.y; vs[r][c4+2]=v4.z; vs[r][c4+3]=v4.w;
        }
        __syncthreads();
        #pragma unroll
        for (int ssi = 0; ssi < 16; ssi++) {
            float ra[8], rb[8];
            #pragma unroll
            for (int i=0;i<8;i++) ra[i]=kps[ssi][tr*8+i];
            #pragma unroll
            for (int j=0;j<8;j++) rb[j]=vs[ssi][tc*8+j];
            #pragma unroll
            for (int i=0;i<8;i++)
                #pragma unroll
                for (int j=0;j<8;j++) acc[i][j] += ra[i]*rb[j];
        }
        if (tid < 128) {
            #pragma unroll
            for (int ssi = 0; ssi < 16; ssi++) ksacc += kps[ssi][tid];
        }
        __syncthreads();
    }
    float* KV = g_kvT + (size_t)bh * Mm * HDd;
    #pragma unroll
    for (int i = 0; i < 8; i++)
        #pragma unroll
        for (int j = 0; j < 8; j++)
            atomicAdd(&KV[(size_t)(tc*8+j)*Mm + tr*8+i], acc[i][j]);
    if (tid < 128) atomicAdd(&g_ksum[bh * Mm + tid], ksacc);
}

// -------------- denominators: dn[row] = qphi[row,:]·ksum[bhk,:] -------------
__global__ __launch_bounds__(256) void dn_kernel() {
    int warp = threadIdx.x >> 5, lane = threadIdx.x & 31;
    int row = blockIdx.x * 8 + warp;
    int bh = row >> 12;
    int b = bh >> 4, h = bh & 15;
    int bhk = b * 8 + (h >> 1);
    float4 q = *(const float4*)(g_qphi + (size_t)row * Mm + lane * 4);
    float4 s = *(const float4*)(g_ksum + bhk * Mm + lane * 4);
    float v = q.x*s.x + q.y*s.y + q.z*s.z + q.w*s.w;
    #pragma unroll
    for (int o = 16; o > 0; o >>= 1) v += __shfl_xor_sync(0xffffffffu, v, o);
    if (lane == 0) g_dn[row] = v;
}

// ------------------------------- launch -------------------------------------
extern "C" void kernel_launch(void* const* d_in, const int* in_sizes, int n_in,
                              void* d_out, int out_size)
{
    const float* x    = (const float*)d_in[0];
    const int*   mask = (const int*)  d_in[1];
    const float* fc   = (const float*)d_in[2];
    const float* wq   = (const float*)d_in[3];
    const float* wk   = (const float*)d_in[4];
    const float* wv   = (const float*)d_in[5];
    const float* wo   = (const float*)d_in[6];
    const float* gq   = (const float*)d_in[7];
    const float* gk   = (const float*)d_in[8];
    const float* proj = (const float*)d_in[9];
    float* out = (float*)d_out;

    float *pv, *psqq, *psqk, *pqphi, *pkxp, *pkvT, *pdn;
    cudaGetSymbolAddress((void**)&pv,   g_v);
    cudaGetSymbolAddress((void**)&psqq, g_sqq);
    cudaGetSymbolAddress((void**)&psqk, g_sqk);
    cudaGetSymbolAddress((void**)&pqphi,g_qphi);
    cudaGetSymbolAddress((void**)&pkxp, g_kxp);
    cudaGetSymbolAddress((void**)&pkvT, g_kvT);
    cudaGetSymbolAddress((void**)&pdn,  g_dn);

    unsigned *xfh,*xfl,*wqh,*wkh,*wvh,*woh,*aoh,*aol;
    unsigned *qxh,*qxl,*kxh,*kxl,*pjh,*pjl,*kmaxe;
    cudaGetSymbolAddress((void**)&xfh, g_xfh); cudaGetSymbolAddress((void**)&xfl, g_xfl);
    cudaGetSymbolAddress((void**)&wqh, g_wqh);
    cudaGetSymbolAddress((void**)&wkh, g_wkh);
    cudaGetSymbolAddress((void**)&wvh, g_wvh);
    cudaGetSymbolAddress((void**)&woh, g_woh);
    cudaGetSymbolAddress((void**)&aoh, g_aoh); cudaGetSymbolAddress((void**)&aol, g_aol);
    cudaGetSymbolAddress((void**)&qxh, g_qxh); cudaGetSymbolAddress((void**)&qxl, g_qxl);
    cudaGetSymbolAddress((void**)&kxh, g_kxh); cudaGetSymbolAddress((void**)&kxl, g_kxl);
    cudaGetSymbolAddress((void**)&pjh, g_pjh); cudaGetSymbolAddress((void**)&pjl, g_pjl);
    cudaGetSymbolAddress((void**)&kmaxe, g_kmaxe);

    cudaFuncSetAttribute(gemm_qk_fused, cudaFuncAttributeMaxDynamicSharedMemorySize, DSMEM3_BYTES);
    cudaFuncSetAttribute(gemm_f16_2t,   cudaFuncAttributeMaxDynamicSharedMemorySize, DSMEM3_BYTES);
    cudaFuncSetAttribute(favor_cpa,     cudaFuncAttributeMaxDynamicSharedMemorySize, DSMEM4_BYTES);
    cudaFuncSetAttribute(favor_out,     cudaFuncAttributeMaxDynamicSharedMemorySize, DSMEM_BYTES);

    // side stream + events (host objects; created per call, not destroyed
    // while capture may reference them)
    cudaStream_t sA;
    cudaStreamCreateWithFlags(&sA, cudaStreamNonBlocking);
    cudaEvent_t evX, evW, evK, evKV;
    cudaEventCreateWithFlags(&evX,  cudaEventDisableTiming);
    cudaEventCreateWithFlags(&evW,  cudaEventDisableTiming);
    cudaEventCreateWithFlags(&evK,  cudaEventDisableTiming);
    cudaEventCreateWithFlags(&evKV, cudaEventDisableTiming);

    // --- s0: x split (MLP=2), fork point ------------------------------------
    split_f16_kernel <<<(Bb*Ss*DIMm/8 + 255)/256, 256>>>(x,  xfh, xfl, Bb*Ss*DIMm/8);
    cudaEventRecord(evX, 0);

    // --- sA: FIRST op is the event wait (forks sA into the capture) ----------
    cudaStreamWaitEvent(sA, evX, 0);
    split_f16h_kernel<<<(Hh*HDd*DIMm/8 + 255)/256, 256, 0, sA>>>(wq, wqh, Hh*HDd*DIMm/8);
    split_f16h_kernel<<<(HKk*HDd*DIMm/8 + 255)/256, 256, 0, sA>>>(wv, wvh, HKk*HDd*DIMm/8);
    split_f16h_kernel<<<(DIMm*Hh*HDd/8 + 255)/256, 256, 0, sA>>>(wo, woh, DIMm*Hh*HDd/8);
    split_bf16_kernel<<<(Mm*HDd/4 + 255)/256, 256, 0, sA>>>(proj, pjh, pjl, Mm*HDd/4);
    init_kernel<<<(Bb*HKk*Mm*HDd + 255)/256, 256, 0, sA>>>();
    cudaEventRecord(evW, sA);

    // --- s0: wk split + K projection -----------------------------------------
    split_f16h_kernel<<<(HKk*HDd*DIMm/8 + 255)/256, 256>>>(wk, wkh, HKk*HDd*DIMm/8);
    gemm_qk_fused<<<dim3(HKk, (Bb*Ss)/128), 256, DSMEM3_BYTES>>>(
        xfh, xfl, wkh, fc, gk, kxh, kxl, psqk, DIMm, HKk);
    cudaEventRecord(evK, 0);

    // --- sA: V projection -> favorK -> kv (in qGEMM's shadow) ----------------
    gemm_f16_2t<<<dim3((HKk*HDd)/128, (Bb*Ss)/128), 256, DSMEM3_BYTES, sA>>>(
        xfh, xfl, wvh, pv, DIMm, HKk*HDd);
    cudaStreamWaitEvent(sA, evK, 0);
    favor_cpa<<<dim3(1, (Bb*HKk*Ss)/128), 256, DSMEM4_BYTES, sA>>>(
        kxh, kxl, pjh, pjl, psqk, pkxp, kmaxe, 1);
    kv_kernel<<<dim3(Ss/128, Bb*HKk), 256, 0, sA>>>(mask);
    cudaEventRecord(evKV, sA);

    // --- s0: Q projection + favorQ (needs wqh/pj from sA) --------------------
    cudaStreamWaitEvent(0, evW, 0);
    gemm_qk_fused<<<dim3(Hh, (Bb*Ss)/128), 256, DSMEM3_BYTES>>>(
        xfh, xfl, wqh, fc, gq, qxh, qxl, psqq, DIMm, Hh);
    favor_cpa<<<dim3(1, (Bb*Hh*Ss)/128), 256, DSMEM4_BYTES>>>(
        qxh, qxl, pjh, pjl, psqq, pqphi, kmaxe, 0);

    // --- s0: join kv, then denominators + attention out + output projection --
    cudaStreamWaitEvent(0, evKV, 0);
    dn_kernel<<<(Bb*Hh*Ss)/8, 256>>>();
    favor_out<<<dim3(1, (Bb*Hh*Ss)/128), 256, DSMEM_BYTES>>>(
        pqphi, pkvT, pdn, mask, aoh, aol);
    gemm_f16_2t<<<dim3(DIMm/128, (Bb*Ss)/128), 256, DSMEM3_BYTES>>>(
        aoh, aol, woh, out, Hh*HDd, DIMm);
}